// round 6
// baseline (speedup 1.0000x reference)
#include <cuda_runtime.h>
#include <cstdint>
#include <cstddef>

#define NB 2
#define NT 2048
#define ND 1024
#define NH 16
#define NLAY 2
#define NE 8
#define NV 32000
#define NN (NB*NT)
#define NCAP 1024
#define NFF 4096

// ---------------- device scratch ----------------
__device__ float g_x   [(size_t)NN*ND];
__device__ float g_ln  [(size_t)NN*ND];
__device__ float g_qkv [(size_t)NN*3*ND];
__device__ float g_attn[(size_t)NN*ND];
__device__ float g_sc  [(size_t)NB*NH*NT*NT];
__device__ float g_route[NN*NE];
__device__ float g_noise[NN*NE];
__device__ float g_eps  [NN*NE];
__device__ float g_gate [NN*NE];
__device__ unsigned char g_mask[NN];
__device__ int   g_sel [NE*NCAP];
__device__ int   g_slot[NE*NN];
__device__ int   g_cnt [NE];
__device__ float g_xt  [(size_t)NE*NCAP*ND];
__device__ float g_h1  [(size_t)NE*NCAP*NFF];
__device__ float g_eo  [(size_t)NE*NCAP*ND];
__device__ float g_log [(size_t)NN*NV];
__device__ float g_nll [NN];
__device__ float g_vld [NN];
// tf32-rounded weight copies
__device__ float g_wqkv_t[(size_t)NLAY*ND*3*ND];
__device__ float g_wout_t[(size_t)NLAY*ND*ND];
__device__ float g_we1_t [(size_t)NLAY*NE*ND*NFF];
__device__ float g_we2_t [(size_t)NLAY*NE*NFF*ND];
__device__ float g_tok_t [(size_t)NV*ND];

// ---------------- threefry2x32 (matches JAX) ----------------
__host__ __device__ __forceinline__ void threefry(unsigned k0, unsigned k1,
                                                  unsigned x0, unsigned x1,
                                                  unsigned& o0, unsigned& o1) {
    unsigned ks2 = k0 ^ k1 ^ 0x1BD11BDAu;
    x0 += k0; x1 += k1;
#define TFR(r) { x0 += x1; x1 = (x1 << (r)) | (x1 >> (32 - (r))); x1 ^= x0; }
    TFR(13) TFR(15) TFR(26) TFR(6)  x0 += k1;  x1 += ks2 + 1u;
    TFR(17) TFR(29) TFR(16) TFR(24) x0 += ks2; x1 += k0 + 2u;
    TFR(13) TFR(15) TFR(26) TFR(6)  x0 += k0;  x1 += k1 + 3u;
    TFR(17) TFR(29) TFR(16) TFR(24) x0 += k1;  x1 += ks2 + 4u;
    TFR(13) TFR(15) TFR(26) TFR(6)  x0 += ks2; x1 += k0 + 5u;
#undef TFR
    o0 = x0; o1 = x1;
}

// XLA ErfInv32 (Giles) polynomial
__device__ __forceinline__ float xla_erfinv(float x) {
    float w = -log1pf(-x * x);
    float p;
    if (w < 5.f) {
        w -= 2.5f;
        p = 2.81022636e-08f;
        p = fmaf(p, w, 3.43273939e-07f);
        p = fmaf(p, w, -3.5233877e-06f);
        p = fmaf(p, w, -4.39150654e-06f);
        p = fmaf(p, w, 0.00021858087f);
        p = fmaf(p, w, -0.00125372503f);
        p = fmaf(p, w, -0.00417768164f);
        p = fmaf(p, w, 0.246640727f);
        p = fmaf(p, w, 1.50140941f);
    } else {
        w = sqrtf(w) - 3.f;
        p = -0.000200214257f;
        p = fmaf(p, w, 0.000100950558f);
        p = fmaf(p, w, 0.00134934322f);
        p = fmaf(p, w, -0.00367342844f);
        p = fmaf(p, w, 0.00573950773f);
        p = fmaf(p, w, -0.0076224613f);
        p = fmaf(p, w, 0.00943887047f);
        p = fmaf(p, w, 1.00167406f);
        p = fmaf(p, w, 2.83297682f);
    }
    return p * x;
}

__device__ __forceinline__ float bits_to_normal(unsigned bits) {
    float f = __uint_as_float((bits >> 9) | 0x3F800000u) - 1.0f;
    const float lo = -0.99999994f;
    float u = fmaf(f, 2.0f, lo);
    u = fmaxf(u, lo);
    return 1.41421356237f * xla_erfinv(u);
}

// ---------------- tf32 helpers ----------------
__device__ __forceinline__ unsigned f2tf(float f) {
    unsigned u; asm("cvt.rna.tf32.f32 %0, %1;" : "=r"(u) : "f"(f)); return u;
}
__device__ __forceinline__ float tfr(float f) { return __uint_as_float(f2tf(f)); }

__device__ __forceinline__ void mma_tf32(float* c, const unsigned* a, const unsigned* b) {
    asm volatile("mma.sync.aligned.m16n8k8.row.col.f32.tf32.tf32.f32 "
        "{%0,%1,%2,%3}, {%4,%5,%6,%7}, {%8,%9}, {%0,%1,%2,%3};"
        : "+f"(c[0]), "+f"(c[1]), "+f"(c[2]), "+f"(c[3])
        : "r"(a[0]), "r"(a[1]), "r"(a[2]), "r"(a[3]), "r"(b[0]), "r"(b[1]));
}

// round f32 array to tf32-valued f32 (vectorized)
__global__ void cvt_tf32_kernel(const float* __restrict__ in, float* __restrict__ out, size_t n4) {
    size_t i = (size_t)blockIdx.x * 256 + threadIdx.x;
    if (i >= n4) return;
    float4 v = ((const float4*)in)[i];
    v.x = tfr(v.x); v.y = tfr(v.y); v.z = tfr(v.z); v.w = tfr(v.w);
    ((float4*)out)[i] = v;
}

// ---------------- universal tf32 tensor-core GEMM ----------------
// Inputs MUST already be tf32-valued floats (raw bits passed to mma).
// C[M,N] = A[M,K] (row-major, lda) * B (BNK? [N,K] : [K,N], ldb)
// CAUSAL: skip tiles with n0 >= m0+BM. PVLIM: Keff = (by+1)*BM. ROUND: tf32-round outputs.
template<int TH, int BM, int BN, int WR, int WC, bool BNK, bool BIAS, bool RELU,
         bool ACCUM, bool CAUSAL, bool PVLIM, bool ROUND>
__global__ void __launch_bounds__(TH)
tc_gemm(const float* __restrict__ A, const float* __restrict__ B,
        const float* __restrict__ bias, float* __restrict__ C,
        int K, int lda, int ldb, int ldc, int zdiv,
        size_t sA, size_t sA2, size_t sB, size_t sB2,
        size_t sC, size_t sC2, size_t sBias, float scale)
{
    constexpr int BK = 16;
    constexpr int WM = BM / WR, WN = BN / WC;
    constexpr int MT = WM / 16, NT4 = WN / 8;
    constexpr int ANV = (BM * BK) / (4 * TH);
    constexpr int BNV = (BN * BK) / (4 * TH);

    const int m0 = blockIdx.y * BM, n0 = blockIdx.x * BN;
    if (CAUSAL && n0 >= m0 + BM) return;

    const int tid = threadIdx.x, lane = tid & 31, warp = tid >> 5;
    const int wr = warp / WC, wc = warp % WC;
    const int g = lane >> 2, t = lane & 3;

    {
        int z = blockIdx.z, z1 = z / zdiv, z0 = z - z1 * zdiv;
        A += (size_t)z1 * sA + (size_t)z0 * sA2;
        B += (size_t)z1 * sB + (size_t)z0 * sB2;
        C += (size_t)z1 * sC + (size_t)z0 * sC2;
        if (BIAS) bias += (size_t)z1 * sBias;
    }

    int Keff = K;
    if (PVLIM) { int ke = ((int)blockIdx.y + 1) * BM; if (ke < Keff) Keff = ke; }
    const int nk = Keff / BK;

    extern __shared__ unsigned sh[];
    unsigned (*As)[20] = (unsigned(*)[20])sh;                 // [2*BM][20]
    unsigned (*Bs)[20] = (unsigned(*)[20])(sh + 2 * BM * 20); // [2*BN][20]

    uint4 pa[ANV], pb[BNV];

    auto gload = [&](int k0) {
#pragma unroll
        for (int i = 0; i < ANV; i++) {
            int idx = tid + i * TH;
            int m = idx >> 2, c4 = (idx & 3) << 2;
            pa[i] = *(const uint4*)(A + (size_t)(m0 + m) * lda + k0 + c4);
        }
        if (BNK) {
#pragma unroll
            for (int i = 0; i < BNV; i++) {
                int idx = tid + i * TH;
                int n = idx >> 2, c4 = (idx & 3) << 2;
                pb[i] = *(const uint4*)(B + (size_t)(n0 + n) * ldb + k0 + c4);
            }
        } else {
#pragma unroll
            for (int i = 0; i < BNV; i++) {
                int idx = tid + i * TH;
                int kk = idx / (BN / 4), c4 = (idx % (BN / 4)) << 2;
                pb[i] = *(const uint4*)(B + (size_t)(k0 + kk) * ldb + n0 + c4);
            }
        }
    };
    auto sstore = [&](int buf) {
#pragma unroll
        for (int i = 0; i < ANV; i++) {
            int idx = tid + i * TH;
            int m = idx >> 2, c4 = (idx & 3) << 2;
            *(uint4*)&As[buf * BM + m][c4] = pa[i];
        }
        if (BNK) {
#pragma unroll
            for (int i = 0; i < BNV; i++) {
                int idx = tid + i * TH;
                int n = idx >> 2, c4 = (idx & 3) << 2;
                *(uint4*)&Bs[buf * BN + n][c4] = pb[i];
            }
        } else {
#pragma unroll
            for (int i = 0; i < BNV; i++) {
                int idx = tid + i * TH;
                int kk = idx / (BN / 4), c4 = (idx % (BN / 4)) << 2;
                Bs[buf * BN + c4 + 0][kk] = pb[i].x;
                Bs[buf * BN + c4 + 1][kk] = pb[i].y;
                Bs[buf * BN + c4 + 2][kk] = pb[i].z;
                Bs[buf * BN + c4 + 3][kk] = pb[i].w;
            }
        }
    };

    float acc[MT][NT4][4] = {};

    gload(0);
    sstore(0);
    __syncthreads();

    int buf = 0;
    for (int ks = 0; ks < nk; ks++) {
        if (ks + 1 < nk) gload((ks + 1) * BK);
#pragma unroll
        for (int k8 = 0; k8 < 2; k8++) {
            unsigned af[MT][4], bf[NT4][2];
#pragma unroll
            for (int mt = 0; mt < MT; mt++) {
                int m = buf * BM + wr * WM + mt * 16;
                af[mt][0] = As[m + g][k8 * 8 + t];
                af[mt][1] = As[m + g + 8][k8 * 8 + t];
                af[mt][2] = As[m + g][k8 * 8 + t + 4];
                af[mt][3] = As[m + g + 8][k8 * 8 + t + 4];
            }
#pragma unroll
            for (int nt = 0; nt < NT4; nt++) {
                int n = buf * BN + wc * WN + nt * 8;
                bf[nt][0] = Bs[n + g][k8 * 8 + t];
                bf[nt][1] = Bs[n + g][k8 * 8 + t + 4];
            }
#pragma unroll
            for (int mt = 0; mt < MT; mt++)
#pragma unroll
                for (int nt = 0; nt < NT4; nt++)
                    mma_tf32(acc[mt][nt], af[mt], bf[nt]);
        }
        if (ks + 1 < nk) sstore(buf ^ 1);
        __syncthreads();
        buf ^= 1;
    }

#pragma unroll
    for (int mt = 0; mt < MT; mt++) {
#pragma unroll
        for (int nt = 0; nt < NT4; nt++) {
            int r0 = m0 + wr * WM + mt * 16 + g;
            int c0 = n0 + wc * WN + nt * 8 + 2 * t;
            float v0 = acc[mt][nt][0] * scale, v1 = acc[mt][nt][1] * scale;
            float v2 = acc[mt][nt][2] * scale, v3 = acc[mt][nt][3] * scale;
            if (BIAS) {
                float b0 = bias[c0], b1 = bias[c0 + 1];
                v0 += b0; v1 += b1; v2 += b0; v3 += b1;
            }
            if (RELU) {
                v0 = fmaxf(v0, 0.f); v1 = fmaxf(v1, 0.f);
                v2 = fmaxf(v2, 0.f); v3 = fmaxf(v3, 0.f);
            }
            if (ROUND) { v0 = tfr(v0); v1 = tfr(v1); v2 = tfr(v2); v3 = tfr(v3); }
            float* p0 = C + (size_t)r0 * ldc + c0;
            float* p1 = C + (size_t)(r0 + 8) * ldc + c0;
            if (ACCUM) {
                float2 o0 = *(float2*)p0, o1 = *(float2*)p1;
                v0 += o0.x; v1 += o0.y; v2 += o1.x; v3 += o1.y;
            }
            *(float2*)p0 = make_float2(v0, v1);
            *(float2*)p1 = make_float2(v2, v3);
        }
    }
}

// ---------------- small kernels ----------------
__global__ void embed_kernel(const int* __restrict__ ids, const float* __restrict__ tok,
                             const float* __restrict__ pos, float* __restrict__ x) {
    int n = blockIdx.x, t = n % NT, id = ids[n];
    const float* te = tok + (size_t)id * ND;
    const float* pe = pos + (size_t)t * ND;
    float* dst = x + (size_t)n * ND;
    for (int d = threadIdx.x; d < ND; d += 256) dst[d] = te[d] + pe[d];
}

// warp-per-row LN: 8 rows per 256-thread block; outputs tf32-rounded
__global__ void ln_kernel(const float* __restrict__ x, const float* __restrict__ w,
                          const float* __restrict__ b, float* __restrict__ out) {
    int row = blockIdx.x * 8 + (threadIdx.x >> 5);
    int lane = threadIdx.x & 31;
    const float4* p = (const float4*)(x + (size_t)row * ND);
    float4 v[8];
    float s = 0.f;
#pragma unroll
    for (int i = 0; i < 8; i++) {
        v[i] = p[lane + i * 32];
        s += v[i].x + v[i].y + v[i].z + v[i].w;
    }
#pragma unroll
    for (int o = 16; o; o >>= 1) s += __shfl_xor_sync(~0u, s, o);
    float mu = s * (1.0f / ND);
    float q = 0.f;
#pragma unroll
    for (int i = 0; i < 8; i++) {
        float a = v[i].x - mu, c = v[i].y - mu, d = v[i].z - mu, e = v[i].w - mu;
        q += a * a + c * c + d * d + e * e;
    }
#pragma unroll
    for (int o = 16; o; o >>= 1) q += __shfl_xor_sync(~0u, q, o);
    float rs = rsqrtf(q * (1.0f / ND) + 1e-5f);
    const float4* wp = (const float4*)w;
    const float4* bp = (const float4*)b;
    float4* op = (float4*)(out + (size_t)row * ND);
#pragma unroll
    for (int i = 0; i < 8; i++) {
        int j = lane + i * 32;
        float4 wv = wp[j], bv = bp[j], r;
        r.x = tfr((v[i].x - mu) * rs * wv.x + bv.x);
        r.y = tfr((v[i].y - mu) * rs * wv.y + bv.y);
        r.z = tfr((v[i].z - mu) * rs * wv.z + bv.z);
        r.w = tfr((v[i].w - mu) * rs * wv.w + bv.w);
        op[j] = r;
    }
}

__global__ void rope_kernel(float* __restrict__ qkv) {
    int n = blockIdx.x, t = n % NT;
    float* base = qkv + (size_t)n * 3072;
#pragma unroll
    for (int item = threadIdx.x; item < 512; item += 256) {
        int h = item >> 5, i = item & 31;
        float ang = (float)t * expf((float)(2 * i) * (-0.14391156831212806f));
        float s = sinf(ang), c = cosf(ang);
        float* q = base + h * 64;
        float* k = q + 1024;
        float q1 = q[i], q2 = q[i + 32];
        q[i] = tfr(q1 * c - q2 * s); q[i + 32] = tfr(q2 * c + q1 * s);
        float k1 = k[i], k2 = k[i + 32];
        k[i] = tfr(k1 * c - k2 * s); k[i + 32] = tfr(k2 * c + k1 * s);
    }
}

__global__ void attn_softmax_kernel(float* __restrict__ sc) {
    int r = blockIdx.x, tid = threadIdx.x;
    float* row = sc + (size_t)blockIdx.y * NT * NT + (size_t)r * NT;
    int n = r + 1;
    __shared__ float red[128];
    float m = -3.4e38f;
    for (int j = tid; j < n; j += 128) m = fmaxf(m, row[j]);
    red[tid] = m; __syncthreads();
    for (int s = 64; s; s >>= 1) { if (tid < s) red[tid] = fmaxf(red[tid], red[tid + s]); __syncthreads(); }
    m = red[0]; __syncthreads();
    float sum = 0.f;
    for (int j = tid; j < n; j += 128) { float e = expf(row[j] - m); row[j] = e; sum += e; }
    red[tid] = sum; __syncthreads();
    for (int s = 64; s; s >>= 1) { if (tid < s) red[tid] += red[tid + s]; __syncthreads(); }
    float inv = 1.0f / red[0];
    for (int j = tid; j < n; j += 128) row[j] = tfr(row[j] * inv);
    int rup = ((r >> 8) + 1) << 8;   // zero-pad to 256-tile boundary (QK tile extent)
    for (int j = n + tid; j < rup; j += 128) row[j] = 0.f;
}

// ---------------- MoE ----------------
__global__ void route_kernel(const float* __restrict__ ln, const float* __restrict__ wr,
                             const float* __restrict__ br, const float* __restrict__ wn,
                             const float* __restrict__ bn, float* __restrict__ route,
                             float* __restrict__ noise) {
    int n = blockIdx.x, tid = threadIdx.x;
    __shared__ float xs[ND];
    for (int d = tid; d < ND; d += 256) xs[d] = ln[(size_t)n * ND + d];
    __syncthreads();
    int w = tid >> 5, lane = tid & 31;
    float sr = 0.f, sn = 0.f;
    for (int d = lane; d < ND; d += 32) {
        float xv = xs[d];
        sr += xv * wr[(size_t)d * NE + w];
        sn += xv * wn[(size_t)d * NE + w];
    }
    for (int o = 16; o; o >>= 1) { sr += __shfl_down_sync(~0u, sr, o); sn += __shfl_down_sync(~0u, sn, o); }
    if (!lane) { route[n * NE + w] = sr + br[w]; noise[n * NE + w] = sn + bn[w]; }
}

__global__ void eps_kernel(unsigned k0, unsigned k1, float* __restrict__ eps) {
    int i = blockIdx.x * 256 + threadIdx.x;
    if (i >= NN * NE) return;
    unsigned o0, o1;
    threefry(k0, k1, 0u, (unsigned)i, o0, o1);
    eps[i] = bits_to_normal(o0 ^ o1);
}

__global__ void topk_kernel(const float* __restrict__ route, const float* __restrict__ noise,
                            const float* __restrict__ eps, float* __restrict__ gate,
                            unsigned char* __restrict__ mask) {
    int n = blockIdx.x * 256 + threadIdx.x;
    if (n >= NN) return;
    float nv[NE];
#pragma unroll
    for (int e = 0; e < NE; e++) {
        float x = noise[n * NE + e];
        float sp = fmaxf(x, 0.f) + log1pf(expf(-fabsf(x)));
        nv[e] = route[n * NE + e] + eps[n * NE + e] * sp;
    }
    int i1 = 0; float v1 = nv[0];
#pragma unroll
    for (int e = 1; e < NE; e++) if (nv[e] > v1) { v1 = nv[e]; i1 = e; }
    int i2 = -1; float v2 = -3.4e38f;
#pragma unroll
    for (int e = 0; e < NE; e++) if (e != i1 && nv[e] > v2) { v2 = nv[e]; i2 = e; }
    float e2 = expf(v2 - v1);
    float Z = 1.0f + e2;
#pragma unroll
    for (int e = 0; e < NE; e++)
        gate[n * NE + e] = (e == i1) ? (1.0f / Z) : ((e == i2) ? (e2 / Z) : 0.f);
    mask[n] = (unsigned char)((1u << i1) | (1u << i2));
}

__global__ void select_kernel(const unsigned char* __restrict__ mask, int* __restrict__ sel,
                              int* __restrict__ slot, int* __restrict__ cnt) {
    int e = blockIdx.x, lane = threadIdx.x;
    int base = 0;
    for (int n0 = 0; n0 < NN; n0 += 32) {
        int n = n0 + lane;
        bool f = (mask[n] >> e) & 1;
        unsigned bal = __ballot_sync(0xffffffffu, f);
        int pos = base + __popc(bal & ((1u << lane) - 1u));
        int sl = (f && pos < NCAP) ? pos : -1;
        slot[(size_t)e * NN + n] = sl;
        if (sl >= 0) sel[e * NCAP + sl] = n;
        base += __popc(bal);
    }
    if (!lane) cnt[e] = base < NCAP ? base : NCAP;
}

__global__ void gather_kernel(const float* __restrict__ ln, const int* __restrict__ sel,
                              const int* __restrict__ cnt, float* __restrict__ xt) {
    int s = blockIdx.x;
    int e = s / NCAP, i = s % NCAP;
    float* dst = xt + (size_t)s * ND;
    if (i < cnt[e]) {
        const float* src = ln + (size_t)sel[s] * ND;
        for (int d = threadIdx.x; d < ND; d += 256) dst[d] = src[d];
    } else {
        for (int d = threadIdx.x; d < ND; d += 256) dst[d] = 0.f;
    }
}

__global__ void moe_scatter_kernel(const float* __restrict__ eo, const int* __restrict__ slot,
                                   const float* __restrict__ gate, float* __restrict__ x) {
    int n = blockIdx.x, tid = threadIdx.x;
    __shared__ int ss[NE];
    __shared__ float gg[NE];
    if (tid < NE) { ss[tid] = slot[(size_t)tid * NN + n]; gg[tid] = gate[n * NE + tid]; }
    __syncthreads();
    for (int d = tid; d < ND; d += 256) {
        float acc = 0.f;
#pragma unroll
        for (int e = 0; e < NE; e++) {
            int s = ss[e];
            if (s >= 0) acc += gg[e] * eo[((size_t)e * NCAP + s) * ND + d];
        }
        x[(size_t)n * ND + d] += acc;
    }
}

// ---------------- loss ----------------
__global__ void loss_kernel(const float* __restrict__ logits, const int* __restrict__ ids,
                            float* __restrict__ nll, float* __restrict__ vld) {
    int n = blockIdx.x, tid = threadIdx.x;
    int b = n / NT, t = n % NT;
    if (t == NT - 1) { if (!tid) { nll[n] = 0.f; vld[n] = 0.f; } return; }
    int tgt = ids[b * NT + t + 1];
    const float* row = logits + (size_t)n * NV;
    float m = -3.4e38f, s = 0.f;
    for (int j = tid; j < NV; j += 256) {
        float l = row[j];
        if (l > m) { s = s * expf(m - l) + 1.0f; m = l; }
        else s += expf(l - m);
    }
    __shared__ float sm[256], ssum[256];
    sm[tid] = m; ssum[tid] = s; __syncthreads();
    for (int st = 128; st; st >>= 1) {
        if (tid < st) {
            float m1 = sm[tid], s1 = ssum[tid], m2 = sm[tid + st], s2 = ssum[tid + st];
            float M = fmaxf(m1, m2);
            ssum[tid] = s1 * expf(m1 - M) + s2 * expf(m2 - M);
            sm[tid] = M;
        }
        __syncthreads();
    }
    if (!tid) {
        float lse = sm[0] + logf(ssum[0]);
        float v = (tgt != 2) ? 1.f : 0.f;
        nll[n] = -(row[tgt] - lse) * v;
        vld[n] = v;
    }
}

__global__ void reduce_kernel(const float* __restrict__ nll, const float* __restrict__ vld,
                              float* __restrict__ out) {
    __shared__ float s1[256], s2[256];
    int tid = threadIdx.x;
    float a = 0.f, b = 0.f;
    for (int i = tid; i < NN; i += 256) { a += nll[i]; b += vld[i]; }
    s1[tid] = a; s2[tid] = b; __syncthreads();
    for (int st = 128; st; st >>= 1) { if (tid < st) { s1[tid] += s1[tid + st]; s2[tid] += s2[tid + st]; } __syncthreads(); }
    if (!tid) out[0] = s1[0] / fmaxf(s2[0], 1.0f);
}

// ---------------- host launch ----------------
#define SMEM_BYTES(BM, BN) ((2*(BM)*20 + 2*(BN)*20) * 4)

extern "C" void kernel_launch(void* const* d_in, const int* in_sizes, int n_in,
                              void* d_out, int out_size) {
    const int*   ids     = (const int*)d_in[0];
    const float* tok_emb = (const float*)d_in[1];
    const float* pos_emb = (const float*)d_in[2];
    const float* ln1_w   = (const float*)d_in[3];
    const float* ln1_b   = (const float*)d_in[4];
    const float* ln2_w   = (const float*)d_in[5];
    const float* ln2_b   = (const float*)d_in[6];
    const float* w_qkv   = (const float*)d_in[7];
    const float* w_out   = (const float*)d_in[8];
    const float* w_route = (const float*)d_in[9];
    const float* b_route = (const float*)d_in[10];
    const float* w_noise = (const float*)d_in[11];
    const float* b_noise = (const float*)d_in[12];
    const float* w_e1    = (const float*)d_in[13];
    const float* b_e1    = (const float*)d_in[14];
    const float* w_e2    = (const float*)d_in[15];
    const float* b_e2    = (const float*)d_in[16];
    const float* lnf_w   = (const float*)d_in[17];
    const float* lnf_b   = (const float*)d_in[18];
    float* out = (float*)d_out;

    float *x, *ln, *qkv, *attn, *sc, *route, *noise, *eps, *gate, *xt, *h1, *eo, *lg, *nll, *vld;
    float *wqkv_t, *wout_t, *we1_t, *we2_t, *tok_t;
    unsigned char* mask; int *sel, *slot, *cnt;
    cudaGetSymbolAddress((void**)&x, g_x);       cudaGetSymbolAddress((void**)&ln, g_ln);
    cudaGetSymbolAddress((void**)&qkv, g_qkv);   cudaGetSymbolAddress((void**)&attn, g_attn);
    cudaGetSymbolAddress((void**)&sc, g_sc);     cudaGetSymbolAddress((void**)&route, g_route);
    cudaGetSymbolAddress((void**)&noise, g_noise); cudaGetSymbolAddress((void**)&eps, g_eps);
    cudaGetSymbolAddress((void**)&gate, g_gate); cudaGetSymbolAddress((void**)&mask, g_mask);
    cudaGetSymbolAddress((void**)&sel, g_sel);   cudaGetSymbolAddress((void**)&slot, g_slot);
    cudaGetSymbolAddress((void**)&cnt, g_cnt);   cudaGetSymbolAddress((void**)&xt, g_xt);
    cudaGetSymbolAddress((void**)&h1, g_h1);     cudaGetSymbolAddress((void**)&eo, g_eo);
    cudaGetSymbolAddress((void**)&lg, g_log);    cudaGetSymbolAddress((void**)&nll, g_nll);
    cudaGetSymbolAddress((void**)&vld, g_vld);
    cudaGetSymbolAddress((void**)&wqkv_t, g_wqkv_t); cudaGetSymbolAddress((void**)&wout_t, g_wout_t);
    cudaGetSymbolAddress((void**)&we1_t, g_we1_t);   cudaGetSymbolAddress((void**)&we2_t, g_we2_t);
    cudaGetSymbolAddress((void**)&tok_t, g_tok_t);

    constexpr int BIG_SMEM = SMEM_BYTES(256, 128);
    constexpr int MED_SMEM = SMEM_BYTES(128, 128);
    constexpr int PV_SMEM  = SMEM_BYTES(128, 64);
    auto* kqkv   = tc_gemm<512,256,128,4,4,false,false,false,false,false,false,true >;
    auto* kqk    = tc_gemm<512,256,128,4,4,true, false,false,false,true, false,false>;
    auto* kpv    = tc_gemm<256,128, 64,4,2,false,false,false,false,false,true ,true >;
    auto* kproj  = tc_gemm<256,128,128,2,4,false,false,false,true, false,false,false>;
    auto* kfc1   = tc_gemm<512,256,128,4,4,false,true, true, false,false,false,true >;
    auto* kfc2   = tc_gemm<256,128,128,2,4,false,true, false,false,false,false,false>;
    auto* kvocab = tc_gemm<512,256,128,4,4,true, false,false,false,false,false,false>;
    cudaFuncSetAttribute(kqkv,   cudaFuncAttributeMaxDynamicSharedMemorySize, BIG_SMEM);
    cudaFuncSetAttribute(kqk,    cudaFuncAttributeMaxDynamicSharedMemorySize, BIG_SMEM);
    cudaFuncSetAttribute(kfc1,   cudaFuncAttributeMaxDynamicSharedMemorySize, BIG_SMEM);
    cudaFuncSetAttribute(kvocab, cudaFuncAttributeMaxDynamicSharedMemorySize, BIG_SMEM);

    // pre-round all GEMM weight operands to tf32 values
    {
        size_t n;
        n = (size_t)NLAY * ND * 3 * ND / 4;
        cvt_tf32_kernel<<<(unsigned)((n + 255) / 256), 256>>>(w_qkv, wqkv_t, n);
        n = (size_t)NLAY * ND * ND / 4;
        cvt_tf32_kernel<<<(unsigned)((n + 255) / 256), 256>>>(w_out, wout_t, n);
        n = (size_t)NLAY * NE * ND * NFF / 4;
        cvt_tf32_kernel<<<(unsigned)((n + 255) / 256), 256>>>(w_e1, we1_t, n);
        n = (size_t)NLAY * NE * NFF * ND / 4;
        cvt_tf32_kernel<<<(unsigned)((n + 255) / 256), 256>>>(w_e2, we2_t, n);
        n = (size_t)NV * ND / 4;
        cvt_tf32_kernel<<<(unsigned)((n + 255) / 256), 256>>>(tok_emb, tok_t, n);
    }

    embed_kernel<<<NN, 256>>>(ids, tok_emb, pos_emb, x);

    for (int l = 0; l < NLAY; l++) {
        // ---- attention block ----
        ln_kernel<<<NN / 8, 256>>>(x, ln1_w + l * ND, ln1_b + l * ND, ln);
        kqkv<<<dim3(24, 16, 1), 512, BIG_SMEM>>>(
            ln, wqkv_t + (size_t)l * ND * 3 * ND, nullptr, qkv,
            ND, ND, 3 * ND, 3 * ND, 1, 0, 0, 0, 0, 0, 0, 0, 1.0f);
        rope_kernel<<<NN, 256>>>(qkv);
        kqk<<<dim3(16, 8, NB * NH), 512, BIG_SMEM>>>(
            qkv, qkv + 1024, nullptr, sc,
            64, 3072, 3072, NT, NH,
            (size_t)NT * 3072, 64, (size_t)NT * 3072, 64,
            (size_t)NH * NT * NT, (size_t)NT * NT, 0, 0.125f);
        attn_softmax_kernel<<<dim3(NT, NB * NH), 128>>>(sc);
        kpv<<<dim3(1, 16, NB * NH), 256, PV_SMEM>>>(
            sc, qkv + 2048, nullptr, attn,
            NT, NT, 3072, ND, NH,
            (size_t)NH * NT * NT, (size_t)NT * NT, (size_t)NT * 3072, 64,
            (size_t)NT * ND, 64, 0, 1.0f);
        kproj<<<dim3(8, 32, 1), 256, MED_SMEM>>>(
            attn, wout_t + (size_t)l * ND * ND, nullptr, x,
            ND, ND, ND, ND, 1, 0, 0, 0, 0, 0, 0, 0, 1.0f);

        // ---- MoE block ----
        ln_kernel<<<NN / 8, 256>>>(x, ln2_w + l * ND, ln2_b + l * ND, ln);
        route_kernel<<<NN, 256>>>(ln, w_route + (size_t)l * ND * NE, b_route + l * NE,
                                  w_noise + (size_t)l * ND * NE, b_noise + l * NE, route, noise);
        unsigned k0, k1;
        threefry(0u, 1234u, 0u, (unsigned)l, k0, k1);
        eps_kernel<<<(NN * NE + 255) / 256, 256>>>(k0, k1, eps);
        topk_kernel<<<(NN + 255) / 256, 256>>>(route, noise, eps, gate, mask);
        select_kernel<<<NE, 32>>>(mask, sel, slot, cnt);
        gather_kernel<<<NE * NCAP, 256>>>(ln, sel, cnt, xt);
        kfc1<<<dim3(32, 4, NE), 512, BIG_SMEM>>>(
            xt, we1_t + (size_t)l * NE * ND * NFF, b_e1 + (size_t)l * NE * NFF, h1,
            ND, ND, NFF, NFF, 1,
            (size_t)NCAP * ND, 0, (size_t)ND * NFF, 0,
            (size_t)NCAP * NFF, 0, NFF, 1.0f);
        kfc2<<<dim3(8, 8, NE), 256, MED_SMEM>>>(
            h1, we2_t + (size_t)l * NE * NFF * ND, b_e2 + (size_t)l * NE * ND, eo,
            NFF, NFF, ND, ND, 1,
            (size_t)NCAP * NFF, 0, (size_t)NFF * ND, 0,
            (size_t)NCAP * ND, 0, ND, 1.0f);
        moe_scatter_kernel<<<NN, 256>>>(eo, slot, gate, x);
    }

    ln_kernel<<<NN / 8, 256>>>(x, lnf_w, lnf_b, ln);
    kvocab<<<dim3(NV / 128, 16, 1), 512, BIG_SMEM>>>(
        ln, tok_t, nullptr, lg,
        ND, ND, ND, NV, 1, 0, 0, 0, 0, 0, 0, 0, 1.0f);
    loss_kernel<<<NN, 256>>>(lg, ids, nll, vld);
    reduce_kernel<<<1, 256>>>(nll, vld, out);
}

// round 8
// speedup vs baseline: 2.0365x; 2.0365x over previous
#include <cuda_runtime.h>
#include <cuda_fp16.h>
#include <cstdint>
#include <cstddef>

#define NB 2
#define NT 2048
#define ND 1024
#define NH 16
#define NLAY 2
#define NE 8
#define NV 32000
#define NN (NB*NT)
#define NCAP 1024
#define NFF 4096

// ---------------- device scratch ----------------
__device__ float  g_x   [(size_t)NN*ND];
__device__ __half g_ln16[(size_t)NN*ND];
__device__ __half g_qkv16[(size_t)NN*3*ND];
__device__ __half g_attn16[(size_t)NN*ND];
__device__ float  g_sc  [(size_t)NB*NH*NT*NT];
__device__ __half g_p16 [(size_t)NB*NH*NT*NT];
__device__ float  g_route[NN*NE];
__device__ float  g_noise[NN*NE];
__device__ float  g_eps  [NN*NE];
__device__ float  g_gate [NN*NE];
__device__ unsigned char g_mask[NN];
__device__ int    g_sel [NE*NCAP];
__device__ int    g_slot[NE*NN];
__device__ int    g_cnt [NE];
__device__ __half g_xt16[(size_t)NE*NCAP*ND];
__device__ __half g_h116[(size_t)NE*NCAP*NFF];
__device__ float  g_eo  [(size_t)NE*NCAP*ND];
__device__ float  g_log [(size_t)NN*NV];
__device__ float  g_nll [NN];
__device__ float  g_vld [NN];
// fp16, TRANSPOSED ([N,K]) weight copies
__device__ __half g_wqkv16[(size_t)NLAY*ND*3*ND];
__device__ __half g_wout16[(size_t)NLAY*ND*ND];
__device__ __half g_we116 [(size_t)NLAY*NE*ND*NFF];
__device__ __half g_we216 [(size_t)NLAY*NE*NFF*ND];
__device__ __half g_tok16 [(size_t)NV*ND];

// ---------------- threefry2x32 (matches JAX) ----------------
__host__ __device__ __forceinline__ void threefry(unsigned k0, unsigned k1,
                                                  unsigned x0, unsigned x1,
                                                  unsigned& o0, unsigned& o1) {
    unsigned ks2 = k0 ^ k1 ^ 0x1BD11BDAu;
    x0 += k0; x1 += k1;
#define TFR(r) { x0 += x1; x1 = (x1 << (r)) | (x1 >> (32 - (r))); x1 ^= x0; }
    TFR(13) TFR(15) TFR(26) TFR(6)  x0 += k1;  x1 += ks2 + 1u;
    TFR(17) TFR(29) TFR(16) TFR(24) x0 += ks2; x1 += k0 + 2u;
    TFR(13) TFR(15) TFR(26) TFR(6)  x0 += k0;  x1 += k1 + 3u;
    TFR(17) TFR(29) TFR(16) TFR(24) x0 += k1;  x1 += ks2 + 4u;
    TFR(13) TFR(15) TFR(26) TFR(6)  x0 += ks2; x1 += k0 + 5u;
#undef TFR
    o0 = x0; o1 = x1;
}

// XLA ErfInv32 (Giles) polynomial
__device__ __forceinline__ float xla_erfinv(float x) {
    float w = -log1pf(-x * x);
    float p;
    if (w < 5.f) {
        w -= 2.5f;
        p = 2.81022636e-08f;
        p = fmaf(p, w, 3.43273939e-07f);
        p = fmaf(p, w, -3.5233877e-06f);
        p = fmaf(p, w, -4.39150654e-06f);
        p = fmaf(p, w, 0.00021858087f);
        p = fmaf(p, w, -0.00125372503f);
        p = fmaf(p, w, -0.00417768164f);
        p = fmaf(p, w, 0.246640727f);
        p = fmaf(p, w, 1.50140941f);
    } else {
        w = sqrtf(w) - 3.f;
        p = -0.000200214257f;
        p = fmaf(p, w, 0.000100950558f);
        p = fmaf(p, w, 0.00134934322f);
        p = fmaf(p, w, -0.00367342844f);
        p = fmaf(p, w, 0.00573950773f);
        p = fmaf(p, w, -0.0076224613f);
        p = fmaf(p, w, 0.00943887047f);
        p = fmaf(p, w, 1.00167406f);
        p = fmaf(p, w, 2.83297682f);
    }
    return p * x;
}

__device__ __forceinline__ float bits_to_normal(unsigned bits) {
    float f = __uint_as_float((bits >> 9) | 0x3F800000u) - 1.0f;
    const float lo = -0.99999994f;
    float u = fmaf(f, 2.0f, lo);
    u = fmaxf(u, lo);
    return 1.41421356237f * xla_erfinv(u);
}

// ---------------- fp16 mma helper ----------------
__device__ __forceinline__ void mma_f16(float* c, const unsigned* a, const unsigned* b) {
    asm volatile("mma.sync.aligned.m16n8k16.row.col.f32.f16.f16.f32 "
        "{%0,%1,%2,%3}, {%4,%5,%6,%7}, {%8,%9}, {%0,%1,%2,%3};"
        : "+f"(c[0]), "+f"(c[1]), "+f"(c[2]), "+f"(c[3])
        : "r"(a[0]), "r"(a[1]), "r"(a[2]), "r"(a[3]), "r"(b[0]), "r"(b[1]));
}

// ---------------- weight prep ----------------
// transpose [R,C] -> [C,R] with fp16 convert, batched over z
__global__ void tr_h_kernel(const float* __restrict__ in, __half* __restrict__ out,
                            int R, int C) {
    __shared__ float tile[32][33];
    in += (size_t)blockIdx.z * R * C;
    out += (size_t)blockIdx.z * R * C;
    int c0 = blockIdx.x * 32, r0 = blockIdx.y * 32;
    int tx = threadIdx.x, ty = threadIdx.y;  // 32 x 8
#pragma unroll
    for (int j = ty; j < 32; j += 8)
        tile[j][tx] = in[(size_t)(r0 + j) * C + c0 + tx];
    __syncthreads();
#pragma unroll
    for (int j = ty; j < 32; j += 8)
        out[(size_t)(c0 + j) * R + r0 + tx] = __float2half_rn(tile[tx][j]);
}

__global__ void cvt_h_kernel(const float* __restrict__ in, __half* __restrict__ out, size_t n4) {
    size_t i = (size_t)blockIdx.x * 256 + threadIdx.x;
    if (i >= n4) return;
    float4 v = ((const float4*)in)[i];
    __half2* o = (__half2*)out;
    o[i * 2] = __floats2half2_rn(v.x, v.y);
    o[i * 2 + 1] = __floats2half2_rn(v.z, v.w);
}

// ---------------- universal fp16 tensor-core GEMM ----------------
// C[M,N] = A[M,K](half,row,lda) * B(half; BNK? [N,K] : [K,N], ldb)
// CAUSAL: skip tiles with n0 >= m0+BM. PVLIM: Keff=(by+1)*BM. OUTH: half output.
template<int TH, int BM, int BN, int WR, int WC, bool BNK, bool BIAS, bool RELU,
         bool ACCUM, bool CAUSAL, bool PVLIM, bool OUTH>
__global__ void __launch_bounds__(TH)
hgemm(const __half* __restrict__ A, const __half* __restrict__ B,
      const float* __restrict__ bias, void* __restrict__ Cv,
      int K, int lda, int ldb, int ldc, int zdiv,
      size_t sA, size_t sA2, size_t sB, size_t sB2,
      size_t sC, size_t sC2, size_t sBias, float scale)
{
    constexpr int BK = 32;
    constexpr int WM = BM / WR, WN = BN / WC;
    constexpr int MT = WM / 16, NT4 = WN / 8;
    constexpr int ANV = (BM * BK) / (8 * TH);   // uint4 loads (8 halves)
    constexpr int BNV = (BN * BK) / (8 * TH);
    constexpr int BNU = (BN * BK) / (2 * TH);   // uint loads for transpose path

    const int m0 = blockIdx.y * BM, n0 = blockIdx.x * BN;
    if (CAUSAL && n0 >= m0 + BM) return;

    const int tid = threadIdx.x, lane = tid & 31, warp = tid >> 5;
    const int wr = warp / WC, wc = warp % WC;
    const int g = lane >> 2, t = lane & 3;

    {
        int z = blockIdx.z, z1 = z / zdiv, z0 = z - z1 * zdiv;
        A += (size_t)z1 * sA + (size_t)z0 * sA2;
        B += (size_t)z1 * sB + (size_t)z0 * sB2;
        Cv = (char*)Cv + ((size_t)z1 * sC + (size_t)z0 * sC2) * (OUTH ? 2 : 4);
        if (BIAS) bias += (size_t)z1 * sBias;
    }

    int Keff = K;
    if (PVLIM) { int ke = ((int)blockIdx.y + 1) * BM; if (ke < Keff) Keff = ke; }
    const int nk = Keff / BK;

    extern __shared__ __half shh[];
    __half (*As)[40] = (__half(*)[40])shh;                    // [2*BM][40]
    __half (*Bs)[40] = (__half(*)[40])(shh + 2 * BM * 40);    // [2*BN][40]
    uint32_t* As32 = (uint32_t*)As;  // row stride 20 u32
    uint32_t* Bs32 = (uint32_t*)Bs;

    uint4 pa[ANV];
    uint4 pb[BNV ? BNV : 1];
    unsigned pbu[BNU ? BNU : 1];

    auto gload = [&](int k0) {
#pragma unroll
        for (int i = 0; i < ANV; i++) {
            int idx = tid + i * TH;
            int row = idx >> 2, q = idx & 3;
            pa[i] = *(const uint4*)(A + (size_t)(m0 + row) * lda + k0 + q * 8);
        }
        if (BNK) {
#pragma unroll
            for (int i = 0; i < BNV; i++) {
                int idx = tid + i * TH;
                int row = idx >> 2, q = idx & 3;
                pb[i] = *(const uint4*)(B + (size_t)(n0 + row) * ldb + k0 + q * 8);
            }
        } else {
#pragma unroll
            for (int i = 0; i < BNU; i++) {
                int idx = tid + i * TH;
                int kk = idx / (BN / 2), nc = idx % (BN / 2);
                pbu[i] = *(const unsigned*)(B + (size_t)(k0 + kk) * ldb + n0 + nc * 2);
            }
        }
    };
    auto sstore = [&](int buf) {
#pragma unroll
        for (int i = 0; i < ANV; i++) {
            int idx = tid + i * TH;
            int row = idx >> 2, q = idx & 3;
            *(uint4*)&As[buf * BM + row][q * 8] = pa[i];
        }
        if (BNK) {
#pragma unroll
            for (int i = 0; i < BNV; i++) {
                int idx = tid + i * TH;
                int row = idx >> 2, q = idx & 3;
                *(uint4*)&Bs[buf * BN + row][q * 8] = pb[i];
            }
        } else {
#pragma unroll
            for (int i = 0; i < BNU; i++) {
                int idx = tid + i * TH;
                int kk = idx / (BN / 2), nc = idx % (BN / 2);
                __half2 h = *(__half2*)&pbu[i];
                Bs[buf * BN + nc * 2][kk] = __low2half(h);
                Bs[buf * BN + nc * 2 + 1][kk] = __high2half(h);
            }
        }
    };

    float acc[MT][NT4][4] = {};

    gload(0);
    sstore(0);
    __syncthreads();

    int buf = 0;
    for (int ks = 0; ks < nk; ks++) {
        if (ks + 1 < nk) gload((ks + 1) * BK);
#pragma unroll
        for (int kh = 0; kh < 2; kh++) {
            unsigned af[MT][4], bf[NT4][2];
#pragma unroll
            for (int mt = 0; mt < MT; mt++) {
                int m = buf * BM + wr * WM + mt * 16;
                af[mt][0] = As32[(m + g) * 20 + kh * 8 + t];
                af[mt][1] = As32[(m + g + 8) * 20 + kh * 8 + t];
                af[mt][2] = As32[(m + g) * 20 + kh * 8 + t + 4];
                af[mt][3] = As32[(m + g + 8) * 20 + kh * 8 + t + 4];
            }
#pragma unroll
            for (int nt = 0; nt < NT4; nt++) {
                int n = buf * BN + wc * WN + nt * 8;
                bf[nt][0] = Bs32[(n + g) * 20 + kh * 8 + t];
                bf[nt][1] = Bs32[(n + g) * 20 + kh * 8 + t + 4];
            }
#pragma unroll
            for (int mt = 0; mt < MT; mt++)
#pragma unroll
                for (int nt = 0; nt < NT4; nt++)
                    mma_f16(acc[mt][nt], af[mt], bf[nt]);
        }
        if (ks + 1 < nk) sstore(buf ^ 1);
        __syncthreads();
        buf ^= 1;
    }

    __half* Ch = (__half*)Cv;
    float*  Cf = (float*)Cv;
#pragma unroll
    for (int mt = 0; mt < MT; mt++) {
#pragma unroll
        for (int nt = 0; nt < NT4; nt++) {
            int r0 = m0 + wr * WM + mt * 16 + g;
            int c0 = n0 + wc * WN + nt * 8 + 2 * t;
            float v0 = acc[mt][nt][0] * scale, v1 = acc[mt][nt][1] * scale;
            float v2 = acc[mt][nt][2] * scale, v3 = acc[mt][nt][3] * scale;
            if (BIAS) {
                float b0 = bias[c0], b1 = bias[c0 + 1];
                v0 += b0; v1 += b1; v2 += b0; v3 += b1;
            }
            if (RELU) {
                v0 = fmaxf(v0, 0.f); v1 = fmaxf(v1, 0.f);
                v2 = fmaxf(v2, 0.f); v3 = fmaxf(v3, 0.f);
            }
            if (OUTH) {
                *(__half2*)(Ch + (size_t)r0 * ldc + c0) = __floats2half2_rn(v0, v1);
                *(__half2*)(Ch + (size_t)(r0 + 8) * ldc + c0) = __floats2half2_rn(v2, v3);
            } else {
                float* p0 = Cf + (size_t)r0 * ldc + c0;
                float* p1 = Cf + (size_t)(r0 + 8) * ldc + c0;
                if (ACCUM) {
                    float2 o0 = *(float2*)p0, o1 = *(float2*)p1;
                    v0 += o0.x; v1 += o0.y; v2 += o1.x; v3 += o1.y;
                }
                *(float2*)p0 = make_float2(v0, v1);
                *(float2*)p1 = make_float2(v2, v3);
            }
        }
    }
}

// ---------------- small kernels ----------------
__global__ void embed_kernel(const int* __restrict__ ids, const float* __restrict__ tok,
                             const float* __restrict__ pos, float* __restrict__ x) {
    int n = blockIdx.x, t = n % NT, id = ids[n];
    const float* te = tok + (size_t)id * ND;
    const float* pe = pos + (size_t)t * ND;
    float* dst = x + (size_t)n * ND;
    for (int d = threadIdx.x; d < ND; d += 256) dst[d] = te[d] + pe[d];
}

// warp-per-row LN, fp16 output
__global__ void ln_kernel(const float* __restrict__ x, const float* __restrict__ w,
                          const float* __restrict__ b, __half* __restrict__ out) {
    int row = blockIdx.x * 8 + (threadIdx.x >> 5);
    int lane = threadIdx.x & 31;
    const float4* p = (const float4*)(x + (size_t)row * ND);
    float4 v[8];
    float s = 0.f;
#pragma unroll
    for (int i = 0; i < 8; i++) {
        v[i] = p[lane + i * 32];
        s += v[i].x + v[i].y + v[i].z + v[i].w;
    }
#pragma unroll
    for (int o = 16; o; o >>= 1) s += __shfl_xor_sync(~0u, s, o);
    float mu = s * (1.0f / ND);
    float q = 0.f;
#pragma unroll
    for (int i = 0; i < 8; i++) {
        float a = v[i].x - mu, c = v[i].y - mu, d = v[i].z - mu, e = v[i].w - mu;
        q += a * a + c * c + d * d + e * e;
    }
#pragma unroll
    for (int o = 16; o; o >>= 1) q += __shfl_xor_sync(~0u, q, o);
    float rs = rsqrtf(q * (1.0f / ND) + 1e-5f);
    const float4* wp = (const float4*)w;
    const float4* bp = (const float4*)b;
    __half2* op = (__half2*)(out + (size_t)row * ND);
#pragma unroll
    for (int i = 0; i < 8; i++) {
        int j = lane + i * 32;
        float4 wv = wp[j], bv = bp[j];
        op[j * 2] = __floats2half2_rn((v[i].x - mu) * rs * wv.x + bv.x,
                                      (v[i].y - mu) * rs * wv.y + bv.y);
        op[j * 2 + 1] = __floats2half2_rn((v[i].z - mu) * rs * wv.z + bv.z,
                                          (v[i].w - mu) * rs * wv.w + bv.w);
    }
}

__global__ void rope_kernel(__half* __restrict__ qkv) {
    int n = blockIdx.x, t = n % NT;
    __half* base = qkv + (size_t)n * 3072;
#pragma unroll
    for (int item = threadIdx.x; item < 512; item += 256) {
        int h = item >> 5, i = item & 31;
        float ang = (float)t * expf((float)(2 * i) * (-0.14391156831212806f));
        float s = sinf(ang), c = cosf(ang);
        __half* q = base + h * 64;
        __half* k = q + 1024;
        float q1 = __half2float(q[i]), q2 = __half2float(q[i + 32]);
        q[i] = __float2half_rn(q1 * c - q2 * s);
        q[i + 32] = __float2half_rn(q2 * c + q1 * s);
        float k1 = __half2float(k[i]), k2 = __half2float(k[i + 32]);
        k[i] = __float2half_rn(k1 * c - k2 * s);
        k[i + 32] = __float2half_rn(k2 * c + k1 * s);
    }
}

__global__ void attn_softmax_kernel(const float* __restrict__ sc, __half* __restrict__ p16) {
    int r = blockIdx.x, tid = threadIdx.x;
    size_t off = (size_t)blockIdx.y * NT * NT + (size_t)r * NT;
    const float* row = sc + off;
    __half* prow = p16 + off;
    int n = r + 1;
    __shared__ float red[128];
    __shared__ float ex[128];  // staging not needed; direct two-pass
    (void)ex;
    float m = -3.4e38f;
    for (int j = tid; j < n; j += 128) m = fmaxf(m, row[j]);
    red[tid] = m; __syncthreads();
    for (int s = 64; s; s >>= 1) { if (tid < s) red[tid] = fmaxf(red[tid], red[tid + s]); __syncthreads(); }
    m = red[0]; __syncthreads();
    float sum = 0.f;
    for (int j = tid; j < n; j += 128) sum += expf(row[j] - m);
    red[tid] = sum; __syncthreads();
    for (int s = 64; s; s >>= 1) { if (tid < s) red[tid] += red[tid + s]; __syncthreads(); }
    float inv = 1.0f / red[0];
    for (int j = tid; j < n; j += 128) prow[j] = __float2half_rn(expf(row[j] - m) * inv);
    int rup = ((r >> 8) + 1) << 8;   // zero-pad to 256 boundary
    for (int j = n + tid; j < rup; j += 128) prow[j] = __float2half_rn(0.f);
}

// ---------------- MoE ----------------
__global__ void route_kernel(const __half* __restrict__ ln, const float* __restrict__ wr,
                             const float* __restrict__ br, const float* __restrict__ wn,
                             const float* __restrict__ bn, float* __restrict__ route,
                             float* __restrict__ noise) {
    int n = blockIdx.x, tid = threadIdx.x;
    __shared__ float xs[ND];
    for (int d = tid; d < ND; d += 256) xs[d] = __half2float(ln[(size_t)n * ND + d]);
    __syncthreads();
    int w = tid >> 5, lane = tid & 31;
    float sr = 0.f, sn = 0.f;
    for (int d = lane; d < ND; d += 32) {
        float xv = xs[d];
        sr += xv * wr[(size_t)d * NE + w];
        sn += xv * wn[(size_t)d * NE + w];
    }
    for (int o = 16; o; o >>= 1) { sr += __shfl_down_sync(~0u, sr, o); sn += __shfl_down_sync(~0u, sn, o); }
    if (!lane) { route[n * NE + w] = sr + br[w]; noise[n * NE + w] = sn + bn[w]; }
}

__global__ void eps_kernel(unsigned k0, unsigned k1, float* __restrict__ eps) {
    int i = blockIdx.x * 256 + threadIdx.x;
    if (i >= NN * NE) return;
    unsigned o0, o1;
    threefry(k0, k1, 0u, (unsigned)i, o0, o1);
    eps[i] = bits_to_normal(o0 ^ o1);
}

__global__ void topk_kernel(const float* __restrict__ route, const float* __restrict__ noise,
                            const float* __restrict__ eps, float* __restrict__ gate,
                            unsigned char* __restrict__ mask) {
    int n = blockIdx.x * 256 + threadIdx.x;
    if (n >= NN) return;
    float nv[NE];
#pragma unroll
    for (int e = 0; e < NE; e++) {
        float x = noise[n * NE + e];
        float sp = fmaxf(x, 0.f) + log1pf(expf(-fabsf(x)));
        nv[e] = route[n * NE + e] + eps[n * NE + e] * sp;
    }
    int i1 = 0; float v1 = nv[0];
#pragma unroll
    for (int e = 1; e < NE; e++) if (nv[e] > v1) { v1 = nv[e]; i1 = e; }
    int i2 = -1; float v2 = -3.4e38f;
#pragma unroll
    for (int e = 0; e < NE; e++) if (e != i1 && nv[e] > v2) { v2 = nv[e]; i2 = e; }
    float e2 = expf(v2 - v1);
    float Z = 1.0f + e2;
#pragma unroll
    for (int e = 0; e < NE; e++)
        gate[n * NE + e] = (e == i1) ? (1.0f / Z) : ((e == i2) ? (e2 / Z) : 0.f);
    mask[n] = (unsigned char)((1u << i1) | (1u << i2));
}

__global__ void select_kernel(const unsigned char* __restrict__ mask, int* __restrict__ sel,
                              int* __restrict__ slot, int* __restrict__ cnt) {
    int e = blockIdx.x, lane = threadIdx.x;
    int base = 0;
    for (int n0 = 0; n0 < NN; n0 += 32) {
        int n = n0 + lane;
        bool f = (mask[n] >> e) & 1;
        unsigned bal = __ballot_sync(0xffffffffu, f);
        int pos = base + __popc(bal & ((1u << lane) - 1u));
        int sl = (f && pos < NCAP) ? pos : -1;
        slot[(size_t)e * NN + n] = sl;
        if (sl >= 0) sel[e * NCAP + sl] = n;
        base += __popc(bal);
    }
    if (!lane) cnt[e] = base < NCAP ? base : NCAP;
}

__global__ void gather_kernel(const __half* __restrict__ ln, const int* __restrict__ sel,
                              const int* __restrict__ cnt, __half* __restrict__ xt) {
    int s = blockIdx.x;
    int e = s / NCAP, i = s % NCAP;
    int* dst = (int*)(xt + (size_t)s * ND);
    if (i < cnt[e]) {
        const int* src = (const int*)(ln + (size_t)sel[s] * ND);
        for (int d = threadIdx.x; d < ND / 2; d += 256) dst[d] = src[d];
    } else {
        for (int d = threadIdx.x; d < ND / 2; d += 256) dst[d] = 0;
    }
}

__global__ void moe_scatter_kernel(const float* __restrict__ eo, const int* __restrict__ slot,
                                   const float* __restrict__ gate, float* __restrict__ x) {
    int n = blockIdx.x, tid = threadIdx.x;
    __shared__ int ss[NE];
    __shared__ float gg[NE];
    if (tid < NE) { ss[tid] = slot[(size_t)tid * NN + n]; gg[tid] = gate[n * NE + tid]; }
    __syncthreads();
    for (int d = tid; d < ND; d += 256) {
        float acc = 0.f;
#pragma unroll
        for (int e = 0; e < NE; e++) {
            int s = ss[e];
            if (s >= 0) acc += gg[e] * eo[((size_t)e * NCAP + s) * ND + d];
        }
        x[(size_t)n * ND + d] += acc;
    }
}

// ---------------- loss ----------------
__global__ void loss_kernel(const float* __restrict__ logits, const int* __restrict__ ids,
                            float* __restrict__ nll, float* __restrict__ vld) {
    int n = blockIdx.x, tid = threadIdx.x;
    int b = n / NT, t = n % NT;
    if (t == NT - 1) { if (!tid) { nll[n] = 0.f; vld[n] = 0.f; } return; }
    int tgt = ids[b * NT + t + 1];
    const float* row = logits + (size_t)n * NV;
    float m = -3.4e38f, s = 0.f;
    for (int j = tid; j < NV; j += 256) {
        float l = row[j];
        if (l > m) { s = s * expf(m - l) + 1.0f; m = l; }
        else s += expf(l - m);
    }
    __shared__ float sm[256], ssum[256];
    sm[tid] = m; ssum[tid] = s; __syncthreads();
    for (int st = 128; st; st >>= 1) {
        if (tid < st) {
            float m1 = sm[tid], s1 = ssum[tid], m2 = sm[tid + st], s2 = ssum[tid + st];
            float M = fmaxf(m1, m2);
            ssum[tid] = s1 * expf(m1 - M) + s2 * expf(m2 - M);
            sm[tid] = M;
        }
        __syncthreads();
    }
    if (!tid) {
        float lse = sm[0] + logf(ssum[0]);
        float v = (tgt != 2) ? 1.f : 0.f;
        nll[n] = -(row[tgt] - lse) * v;
        vld[n] = v;
    }
}

__global__ void reduce_kernel(const float* __restrict__ nll, const float* __restrict__ vld,
                              float* __restrict__ out) {
    __shared__ float s1[256], s2[256];
    int tid = threadIdx.x;
    float a = 0.f, b = 0.f;
    for (int i = tid; i < NN; i += 256) { a += nll[i]; b += vld[i]; }
    s1[tid] = a; s2[tid] = b; __syncthreads();
    for (int st = 128; st; st >>= 1) { if (tid < st) { s1[tid] += s1[tid + st]; s2[tid] += s2[tid + st]; } __syncthreads(); }
    if (!tid) out[0] = s1[0] / fmaxf(s2[0], 1.0f);
}

// ---------------- host launch ----------------
#define H_SMEM(BM, BN) ((2*(BM)*40 + 2*(BN)*40) * 2)

extern "C" void kernel_launch(void* const* d_in, const int* in_sizes, int n_in,
                              void* d_out, int out_size) {
    const int*   ids     = (const int*)d_in[0];
    const float* tok_emb = (const float*)d_in[1];
    const float* pos_emb = (const float*)d_in[2];
    const float* ln1_w   = (const float*)d_in[3];
    const float* ln1_b   = (const float*)d_in[4];
    const float* ln2_w   = (const float*)d_in[5];
    const float* ln2_b   = (const float*)d_in[6];
    const float* w_qkv   = (const float*)d_in[7];
    const float* w_out   = (const float*)d_in[8];
    const float* w_route = (const float*)d_in[9];
    const float* b_route = (const float*)d_in[10];
    const float* w_noise = (const float*)d_in[11];
    const float* b_noise = (const float*)d_in[12];
    const float* w_e1    = (const float*)d_in[13];
    const float* b_e1    = (const float*)d_in[14];
    const float* w_e2    = (const float*)d_in[15];
    const float* b_e2    = (const float*)d_in[16];
    const float* lnf_w   = (const float*)d_in[17];
    const float* lnf_b   = (const float*)d_in[18];
    float* out = (float*)d_out;

    float *x, *sc, *route, *noise, *eps, *gate, *eo, *lg, *nll, *vld;
    __half *ln16, *qkv16, *attn16, *p16, *xt16, *h116;
    __half *wqkv16, *wout16, *we116, *we216, *tok16;
    unsigned char* mask; int *sel, *slot, *cnt;
    cudaGetSymbolAddress((void**)&x, g_x);
    cudaGetSymbolAddress((void**)&ln16, g_ln16);
    cudaGetSymbolAddress((void**)&qkv16, g_qkv16);
    cudaGetSymbolAddress((void**)&attn16, g_attn16);
    cudaGetSymbolAddress((void**)&sc, g_sc);
    cudaGetSymbolAddress((void**)&p16, g_p16);
    cudaGetSymbolAddress((void**)&route, g_route);
    cudaGetSymbolAddress((void**)&noise, g_noise);
    cudaGetSymbolAddress((void**)&eps, g_eps);
    cudaGetSymbolAddress((void**)&gate, g_gate);
    cudaGetSymbolAddress((void**)&mask, g_mask);
    cudaGetSymbolAddress((void**)&sel, g_sel);
    cudaGetSymbolAddress((void**)&slot, g_slot);
    cudaGetSymbolAddress((void**)&cnt, g_cnt);
    cudaGetSymbolAddress((void**)&xt16, g_xt16);
    cudaGetSymbolAddress((void**)&h116, g_h116);
    cudaGetSymbolAddress((void**)&eo, g_eo);
    cudaGetSymbolAddress((void**)&lg, g_log);
    cudaGetSymbolAddress((void**)&nll, g_nll);
    cudaGetSymbolAddress((void**)&vld, g_vld);
    cudaGetSymbolAddress((void**)&wqkv16, g_wqkv16);
    cudaGetSymbolAddress((void**)&wout16, g_wout16);
    cudaGetSymbolAddress((void**)&we116, g_we116);
    cudaGetSymbolAddress((void**)&we216, g_we216);
    cudaGetSymbolAddress((void**)&tok16, g_tok16);

    constexpr int BIG_SMEM = H_SMEM(256, 128);  // 61440
    constexpr int PV_SMEM  = H_SMEM(128, 64);   // 30720
    auto* kqkv = hgemm<512,256,128,4,4,true ,false,false,false,false,false,true >;
    auto* kqk  = hgemm<512,256,128,4,4,true ,false,false,false,true ,false,false>;
    auto* kpv  = hgemm<256,128, 64,4,2,false,false,false,false,false,true ,true >;
    auto* kproj= hgemm<512,256,128,4,4,true ,false,false,true ,false,false,false>;
    auto* kfc1 = hgemm<512,256,128,4,4,true ,true ,true ,false,false,false,true >;
    auto* kfc2 = hgemm<512,256,128,4,4,true ,true ,false,false,false,false,false>;
    auto* kvoc = hgemm<512,256,128,4,4,true ,false,false,false,false,false,false>;
    cudaFuncSetAttribute(kqkv, cudaFuncAttributeMaxDynamicSharedMemorySize, BIG_SMEM);
    cudaFuncSetAttribute(kqk,  cudaFuncAttributeMaxDynamicSharedMemorySize, BIG_SMEM);
    cudaFuncSetAttribute(kproj,cudaFuncAttributeMaxDynamicSharedMemorySize, BIG_SMEM);
    cudaFuncSetAttribute(kfc1, cudaFuncAttributeMaxDynamicSharedMemorySize, BIG_SMEM);
    cudaFuncSetAttribute(kfc2, cudaFuncAttributeMaxDynamicSharedMemorySize, BIG_SMEM);
    cudaFuncSetAttribute(kvoc, cudaFuncAttributeMaxDynamicSharedMemorySize, BIG_SMEM);

    // weight prep: transpose+convert to [N,K] fp16; tok_emb converted in place layout
    tr_h_kernel<<<dim3(3*ND/32, ND/32, NLAY), dim3(32,8)>>>(w_qkv, wqkv16, ND, 3*ND);
    tr_h_kernel<<<dim3(ND/32, ND/32, NLAY), dim3(32,8)>>>(w_out, wout16, ND, ND);
    tr_h_kernel<<<dim3(NFF/32, ND/32, NLAY*NE), dim3(32,8)>>>(w_e1, we116, ND, NFF);
    tr_h_kernel<<<dim3(ND/32, NFF/32, NLAY*NE), dim3(32,8)>>>(w_e2, we216, NFF, ND);
    {
        size_t n = (size_t)NV * ND / 4;
        cvt_h_kernel<<<(unsigned)((n + 255) / 256), 256>>>(tok_emb, tok16, n);
    }

    embed_kernel<<<NN, 256>>>(ids, tok_emb, pos_emb, x);

    for (int l = 0; l < NLAY; l++) {
        // ---- attention ----
        ln_kernel<<<NN / 8, 256>>>(x, ln1_w + l * ND, ln1_b + l * ND, ln16);
        // qkv16 = ln16 @ wqkv16^T : M=4096, N=3072, K=1024
        kqkv<<<dim3(24, 16, 1), 512, BIG_SMEM>>>(
            ln16, wqkv16 + (size_t)l * ND * 3 * ND, nullptr, qkv16,
            ND, ND, ND, 3 * ND, 1, 0, 0, 0, 0, 0, 0, 0, 1.0f);
        rope_kernel<<<NN, 256>>>(qkv16);
        // sc = Q @ K^T * 0.125 : per (b,h), causal tiles
        kqk<<<dim3(16, 8, NB * NH), 512, BIG_SMEM>>>(
            qkv16, qkv16 + 1024, nullptr, sc,
            64, 3072, 3072, NT, NH,
            (size_t)NT * 3072, 64, (size_t)NT * 3072, 64,
            (size_t)NH * NT * NT, (size_t)NT * NT, 0, 0.125f);
        attn_softmax_kernel<<<dim3(NT, NB * NH), 128>>>(sc, p16);
        // attn16 = P @ V : per (b,h)
        kpv<<<dim3(1, 16, NB * NH), 256, PV_SMEM>>>(
            p16, qkv16 + 2048, nullptr, attn16,
            NT, NT, 3072, ND, NH,
            (size_t)NH * NT * NT, (size_t)NT * NT, (size_t)NT * 3072, 64,
            (size_t)NT * ND, 64, 0, 1.0f);
        // x += attn16 @ wout16^T
        kproj<<<dim3(8, 16, 1), 512, BIG_SMEM>>>(
            attn16, wout16 + (size_t)l * ND * ND, nullptr, x,
            ND, ND, ND, ND, 1, 0, 0, 0, 0, 0, 0, 0, 1.0f);

        // ---- MoE ----
        ln_kernel<<<NN / 8, 256>>>(x, ln2_w + l * ND, ln2_b + l * ND, ln16);
        route_kernel<<<NN, 256>>>(ln16, w_route + (size_t)l * ND * NE, b_route + l * NE,
                                  w_noise + (size_t)l * ND * NE, b_noise + l * NE, route, noise);
        unsigned k0, k1;
        threefry(0u, 1234u, 0u, (unsigned)l, k0, k1);
        eps_kernel<<<(NN * NE + 255) / 256, 256>>>(k0, k1, eps);
        topk_kernel<<<(NN + 255) / 256, 256>>>(route, noise, eps, gate, mask);
        select_kernel<<<NE, 32>>>(mask, sel, slot, cnt);
        gather_kernel<<<NE * NCAP, 256>>>(ln16, sel, cnt, xt16);
        // h116 = relu(xt16 @ we116^T + b_e1) : z=8, M=1024, N=4096, K=1024
        kfc1<<<dim3(32, 4, NE), 512, BIG_SMEM>>>(
            xt16, we116 + (size_t)l * NE * ND * NFF, b_e1 + (size_t)l * NE * NFF, h116,
            ND, ND, ND, NFF, 1,
            (size_t)NCAP * ND, 0, (size_t)NFF * ND, 0,
            (size_t)NCAP * NFF, 0, NFF, 1.0f);
        // eo = h116 @ we216^T + b_e2 : z=8, M=1024, N=1024, K=4096
        kfc2<<<dim3(8, 4, NE), 512, BIG_SMEM>>>(
            h116, we216 + (size_t)l * NE * NFF * ND, b_e2 + (size_t)l * NE * ND, eo,
            NFF, NFF, NFF, ND, 1,
            (size_t)NCAP * NFF, 0, (size_t)ND * NFF, 0,
            (size_t)NCAP * ND, 0, ND, 1.0f);
        moe_scatter_kernel<<<NN, 256>>>(eo, slot, gate, x);
    }

    ln_kernel<<<NN / 8, 256>>>(x, lnf_w, lnf_b, ln16);
    // lg = ln16 @ tok16^T : M=4096, N=32000, K=1024
    kvoc<<<dim3(NV / 128, 16, 1), 512, BIG_SMEM>>>(
        ln16, tok16, nullptr, lg,
        ND, ND, ND, NV, 1, 0, 0, 0, 0, 0, 0, 0, 1.0f);
    loss_kernel<<<NN, 256>>>(lg, ids, nll, vld);
    reduce_kernel<<<1, 256>>>(nll, vld, out);
}

// round 9
// speedup vs baseline: 2.3973x; 1.1772x over previous
#include <cuda_runtime.h>
#include <cuda_fp16.h>
#include <cstdint>
#include <cstddef>

#define NB 2
#define NT 2048
#define ND 1024
#define NH 16
#define NLAY 2
#define NE 8
#define NV 32000
#define NN (NB*NT)
#define NCAP 1024
#define NFF 4096

// ---------------- device scratch ----------------
__device__ float  g_x   [(size_t)NN*ND];
__device__ __half g_ln16[(size_t)NN*ND];
__device__ __half g_qkv16[(size_t)NN*3*ND];
__device__ __half g_attn16[(size_t)NN*ND];
__device__ __half g_p16 [(size_t)NB*NH*NT*NT];   // scores then probs (fp16)
__device__ float  g_route[NN*NE];
__device__ float  g_noise[NN*NE];
__device__ float  g_eps  [NN*NE];
__device__ float  g_gate [NN*NE];
__device__ unsigned char g_mask[NN];
__device__ int    g_sel [NE*NCAP];
__device__ int    g_slot[NE*NN];
__device__ int    g_cnt [NE];
__device__ __half g_xt16[(size_t)NE*NCAP*ND];
__device__ __half g_h116[(size_t)NE*NCAP*NFF];
__device__ float  g_eo  [(size_t)NE*NCAP*ND];
__device__ float  g_log [(size_t)NN*NV];
__device__ float  g_nll [NN];
__device__ float  g_vld [NN];
// fp16, TRANSPOSED ([N,K]) weight copies
__device__ __half g_wqkv16[(size_t)NLAY*ND*3*ND];
__device__ __half g_wout16[(size_t)NLAY*ND*ND];
__device__ __half g_we116 [(size_t)NLAY*NE*ND*NFF];
__device__ __half g_we216 [(size_t)NLAY*NE*NFF*ND];
__device__ __half g_tok16 [(size_t)NV*ND];

// ---------------- threefry2x32 (matches JAX) ----------------
__host__ __device__ __forceinline__ void threefry(unsigned k0, unsigned k1,
                                                  unsigned x0, unsigned x1,
                                                  unsigned& o0, unsigned& o1) {
    unsigned ks2 = k0 ^ k1 ^ 0x1BD11BDAu;
    x0 += k0; x1 += k1;
#define TFR(r) { x0 += x1; x1 = (x1 << (r)) | (x1 >> (32 - (r))); x1 ^= x0; }
    TFR(13) TFR(15) TFR(26) TFR(6)  x0 += k1;  x1 += ks2 + 1u;
    TFR(17) TFR(29) TFR(16) TFR(24) x0 += ks2; x1 += k0 + 2u;
    TFR(13) TFR(15) TFR(26) TFR(6)  x0 += k0;  x1 += k1 + 3u;
    TFR(17) TFR(29) TFR(16) TFR(24) x0 += k1;  x1 += ks2 + 4u;
    TFR(13) TFR(15) TFR(26) TFR(6)  x0 += ks2; x1 += k0 + 5u;
#undef TFR
    o0 = x0; o1 = x1;
}

// XLA ErfInv32 (Giles) polynomial
__device__ __forceinline__ float xla_erfinv(float x) {
    float w = -log1pf(-x * x);
    float p;
    if (w < 5.f) {
        w -= 2.5f;
        p = 2.81022636e-08f;
        p = fmaf(p, w, 3.43273939e-07f);
        p = fmaf(p, w, -3.5233877e-06f);
        p = fmaf(p, w, -4.39150654e-06f);
        p = fmaf(p, w, 0.00021858087f);
        p = fmaf(p, w, -0.00125372503f);
        p = fmaf(p, w, -0.00417768164f);
        p = fmaf(p, w, 0.246640727f);
        p = fmaf(p, w, 1.50140941f);
    } else {
        w = sqrtf(w) - 3.f;
        p = -0.000200214257f;
        p = fmaf(p, w, 0.000100950558f);
        p = fmaf(p, w, 0.00134934322f);
        p = fmaf(p, w, -0.00367342844f);
        p = fmaf(p, w, 0.00573950773f);
        p = fmaf(p, w, -0.0076224613f);
        p = fmaf(p, w, 0.00943887047f);
        p = fmaf(p, w, 1.00167406f);
        p = fmaf(p, w, 2.83297682f);
    }
    return p * x;
}

__device__ __forceinline__ float bits_to_normal(unsigned bits) {
    float f = __uint_as_float((bits >> 9) | 0x3F800000u) - 1.0f;
    const float lo = -0.99999994f;
    float u = fmaf(f, 2.0f, lo);
    u = fmaxf(u, lo);
    return 1.41421356237f * xla_erfinv(u);
}

// ---------------- mma / ldmatrix helpers ----------------
__device__ __forceinline__ void mma_f16(float* c, const unsigned* a, const unsigned* b) {
    asm volatile("mma.sync.aligned.m16n8k16.row.col.f32.f16.f16.f32 "
        "{%0,%1,%2,%3}, {%4,%5,%6,%7}, {%8,%9}, {%0,%1,%2,%3};"
        : "+f"(c[0]), "+f"(c[1]), "+f"(c[2]), "+f"(c[3])
        : "r"(a[0]), "r"(a[1]), "r"(a[2]), "r"(a[3]), "r"(b[0]), "r"(b[1]));
}
__device__ __forceinline__ void ldsm4(unsigned& d0, unsigned& d1, unsigned& d2, unsigned& d3,
                                      uint32_t addr) {
    asm volatile("ldmatrix.sync.aligned.m8n8.x4.shared.b16 {%0,%1,%2,%3}, [%4];"
        : "=r"(d0), "=r"(d1), "=r"(d2), "=r"(d3) : "r"(addr));
}
__device__ __forceinline__ uint32_t smem_u32(const void* p) {
    uint32_t a;
    asm("{ .reg .u64 t; cvta.to.shared.u64 t, %1; cvt.u32.u64 %0, t; }" : "=r"(a) : "l"(p));
    return a;
}

// ---------------- weight prep ----------------
// transpose [R,C] -> [C,R] fp16, 64(R)x32(C) tiles, batched over z
__global__ void tr_h_kernel(const float* __restrict__ in, __half* __restrict__ out,
                            int R, int C) {
    __shared__ float tile[32][65];   // [col][row]
    in += (size_t)blockIdx.z * R * C;
    out += (size_t)blockIdx.z * R * C;
    int c0 = blockIdx.x * 32, r0 = blockIdx.y * 64;
    int tx = threadIdx.x, ty = threadIdx.y;  // 32 x 8
#pragma unroll
    for (int j = ty; j < 64; j += 8)
        tile[tx][j] = in[(size_t)(r0 + j) * C + c0 + tx];
    __syncthreads();
#pragma unroll
    for (int j = ty; j < 32; j += 8) {
        __half2 h2 = __floats2half2_rn(tile[j][2 * tx], tile[j][2 * tx + 1]);
        *((__half2*)(out + (size_t)(c0 + j) * R + r0) + tx) = h2;
    }
}

__global__ void cvt_h_kernel(const float* __restrict__ in, __half* __restrict__ out, size_t n4) {
    size_t i = (size_t)blockIdx.x * 256 + threadIdx.x;
    if (i >= n4) return;
    float4 v = ((const float4*)in)[i];
    __half2* o = (__half2*)out;
    o[i * 2] = __floats2half2_rn(v.x, v.y);
    o[i * 2 + 1] = __floats2half2_rn(v.z, v.w);
}

// ---------------- universal fp16 tensor-core GEMM (ldmatrix mainloop) ----------------
// C[M,N] = A[M,K](half,row,lda) * B(half; BNK? [N,K] : [K,N], ldb); BK=64.
// CAUSAL: skip tiles with n0 >= m0+BM. PVLIM: Keff=(by+1)*BM. OUTH: half output.
template<int TH, int BM, int BN, int WR, int WC, bool BNK, bool BIAS, bool RELU,
         bool ACCUM, bool CAUSAL, bool PVLIM, bool OUTH>
__global__ void __launch_bounds__(TH)
hgemm(const __half* __restrict__ A, const __half* __restrict__ B,
      const float* __restrict__ bias, void* __restrict__ Cv,
      int K, int lda, int ldb, int ldc, int zdiv,
      size_t sA, size_t sA2, size_t sB, size_t sB2,
      size_t sC, size_t sC2, size_t sBias, float scale)
{
    constexpr int BK = 64;
    constexpr int LDS = 72;                 // halves per smem row (144B = 36 banks)
    constexpr int WM = BM / WR, WN = BN / WC;
    constexpr int MT = WM / 16, NT4 = WN / 8, NP = NT4 / 2;
    constexpr int ANV = (BM * BK) / (8 * TH);
    constexpr int BNV = (BN * BK) / (8 * TH);
    constexpr int BNU = (BN * BK) / (2 * TH);
    constexpr uint32_t ABYTES = 2u * BM * LDS * 2;   // Bs byte offset

    const int m0 = blockIdx.y * BM, n0 = blockIdx.x * BN;
    if (CAUSAL && n0 >= m0 + BM) return;

    const int tid = threadIdx.x, lane = tid & 31, warp = tid >> 5;
    const int wr = warp / WC, wc = warp % WC;
    const int g = lane >> 2, t = lane & 3;

    {
        int z = blockIdx.z, z1 = z / zdiv, z0 = z - z1 * zdiv;
        A += (size_t)z1 * sA + (size_t)z0 * sA2;
        B += (size_t)z1 * sB + (size_t)z0 * sB2;
        Cv = (char*)Cv + ((size_t)z1 * sC + (size_t)z0 * sC2) * (OUTH ? 2 : 4);
        if (BIAS) bias += (size_t)z1 * sBias;
    }

    int Keff = K;
    if (PVLIM) { int ke = ((int)blockIdx.y + 1) * BM; if (ke < Keff) Keff = ke; }
    const int nk = Keff / BK;

    extern __shared__ __half shh[];
    __half (*As)[LDS] = (__half(*)[LDS])shh;                   // [2*BM][72]
    __half (*Bs)[LDS] = (__half(*)[LDS])(shh + 2 * BM * LDS);  // [2*BN][72]
    const uint32_t sbase = smem_u32(shh);

    // ldmatrix per-lane offsets
    const int a_r = lane & 15;
    const int a_c8 = (lane >> 4) * 8;
    const int b_r = (lane & 7) + (lane >> 4) * 8;
    const int b_c8 = ((lane >> 3) & 1) * 8;
    const int mwb = wr * WM, nwb = wc * WN;

    uint4 pa[ANV];
    uint4 pb[BNV ? BNV : 1];
    unsigned pbu[BNU ? BNU : 1];

    auto gload = [&](int k0) {
#pragma unroll
        for (int i = 0; i < ANV; i++) {
            int idx = tid + i * TH;
            int row = idx >> 3, q = idx & 7;
            pa[i] = *(const uint4*)(A + (size_t)(m0 + row) * lda + k0 + q * 8);
        }
        if (BNK) {
#pragma unroll
            for (int i = 0; i < BNV; i++) {
                int idx = tid + i * TH;
                int row = idx >> 3, q = idx & 7;
                pb[i] = *(const uint4*)(B + (size_t)(n0 + row) * ldb + k0 + q * 8);
            }
        } else {
#pragma unroll
            for (int i = 0; i < BNU; i++) {
                int idx = tid + i * TH;
                int kk = idx / (BN / 2), nc = idx % (BN / 2);
                pbu[i] = *(const unsigned*)(B + (size_t)(k0 + kk) * ldb + n0 + nc * 2);
            }
        }
    };
    auto sstore = [&](int buf) {
#pragma unroll
        for (int i = 0; i < ANV; i++) {
            int idx = tid + i * TH;
            int row = idx >> 3, q = idx & 7;
            *(uint4*)&As[buf * BM + row][q * 8] = pa[i];
        }
        if (BNK) {
#pragma unroll
            for (int i = 0; i < BNV; i++) {
                int idx = tid + i * TH;
                int row = idx >> 3, q = idx & 7;
                *(uint4*)&Bs[buf * BN + row][q * 8] = pb[i];
            }
        } else {
#pragma unroll
            for (int i = 0; i < BNU; i++) {
                int idx = tid + i * TH;
                int kk = idx / (BN / 2), nc = idx % (BN / 2);
                __half2 h = *(__half2*)&pbu[i];
                Bs[buf * BN + nc * 2][kk] = __low2half(h);
                Bs[buf * BN + nc * 2 + 1][kk] = __high2half(h);
            }
        }
    };

    float acc[MT][NT4][4] = {};

    gload(0);
    sstore(0);
    __syncthreads();

    int buf = 0;
    for (int ks = 0; ks < nk; ks++) {
        if (ks + 1 < nk) gload((ks + 1) * BK);
#pragma unroll
        for (int kq = 0; kq < 4; kq++) {        // 4 x k16 per BK=64
            unsigned af[MT][4], bf[NT4][2];
#pragma unroll
            for (int mt = 0; mt < MT; mt++) {
                uint32_t ad = sbase +
                    (uint32_t)(((buf * BM + mwb + mt * 16 + a_r) * LDS + kq * 16 + a_c8) * 2);
                ldsm4(af[mt][0], af[mt][1], af[mt][2], af[mt][3], ad);
            }
#pragma unroll
            for (int np = 0; np < NP; np++) {
                uint32_t bd = sbase + ABYTES +
                    (uint32_t)(((buf * BN + nwb + np * 16 + b_r) * LDS + kq * 16 + b_c8) * 2);
                ldsm4(bf[2 * np][0], bf[2 * np][1], bf[2 * np + 1][0], bf[2 * np + 1][1], bd);
            }
#pragma unroll
            for (int mt = 0; mt < MT; mt++)
#pragma unroll
                for (int nt = 0; nt < NT4; nt++)
                    mma_f16(acc[mt][nt], af[mt], bf[nt]);
        }
        if (ks + 1 < nk) sstore(buf ^ 1);
        __syncthreads();
        buf ^= 1;
    }

    __half* Ch = (__half*)Cv;
    float*  Cf = (float*)Cv;
#pragma unroll
    for (int mt = 0; mt < MT; mt++) {
#pragma unroll
        for (int nt = 0; nt < NT4; nt++) {
            int r0 = m0 + mwb + mt * 16 + g;
            int c0 = n0 + nwb + nt * 8 + 2 * t;
            float v0 = acc[mt][nt][0] * scale, v1 = acc[mt][nt][1] * scale;
            float v2 = acc[mt][nt][2] * scale, v3 = acc[mt][nt][3] * scale;
            if (BIAS) {
                float b0 = bias[c0], b1 = bias[c0 + 1];
                v0 += b0; v1 += b1; v2 += b0; v3 += b1;
            }
            if (RELU) {
                v0 = fmaxf(v0, 0.f); v1 = fmaxf(v1, 0.f);
                v2 = fmaxf(v2, 0.f); v3 = fmaxf(v3, 0.f);
            }
            if (OUTH) {
                *(__half2*)(Ch + (size_t)r0 * ldc + c0) = __floats2half2_rn(v0, v1);
                *(__half2*)(Ch + (size_t)(r0 + 8) * ldc + c0) = __floats2half2_rn(v2, v3);
            } else {
                float* p0 = Cf + (size_t)r0 * ldc + c0;
                float* p1 = Cf + (size_t)(r0 + 8) * ldc + c0;
                if (ACCUM) {
                    float2 o0 = *(float2*)p0, o1 = *(float2*)p1;
                    v0 += o0.x; v1 += o0.y; v2 += o1.x; v3 += o1.y;
                }
                *(float2*)p0 = make_float2(v0, v1);
                *(float2*)p1 = make_float2(v2, v3);
            }
        }
    }
}

// ---------------- small kernels ----------------
__global__ void embed_kernel(const int* __restrict__ ids, const float* __restrict__ tok,
                             const float* __restrict__ pos, float* __restrict__ x) {
    int n = blockIdx.x, t = n % NT, id = ids[n];
    const float* te = tok + (size_t)id * ND;
    const float* pe = pos + (size_t)t * ND;
    float* dst = x + (size_t)n * ND;
    for (int d = threadIdx.x; d < ND; d += 256) dst[d] = te[d] + pe[d];
}

__global__ void ln_kernel(const float* __restrict__ x, const float* __restrict__ w,
                          const float* __restrict__ b, __half* __restrict__ out) {
    int row = blockIdx.x * 8 + (threadIdx.x >> 5);
    int lane = threadIdx.x & 31;
    const float4* p = (const float4*)(x + (size_t)row * ND);
    float4 v[8];
    float s = 0.f;
#pragma unroll
    for (int i = 0; i < 8; i++) {
        v[i] = p[lane + i * 32];
        s += v[i].x + v[i].y + v[i].z + v[i].w;
    }
#pragma unroll
    for (int o = 16; o; o >>= 1) s += __shfl_xor_sync(~0u, s, o);
    float mu = s * (1.0f / ND);
    float q = 0.f;
#pragma unroll
    for (int i = 0; i < 8; i++) {
        float a = v[i].x - mu, c = v[i].y - mu, d = v[i].z - mu, e = v[i].w - mu;
        q += a * a + c * c + d * d + e * e;
    }
#pragma unroll
    for (int o = 16; o; o >>= 1) q += __shfl_xor_sync(~0u, q, o);
    float rs = rsqrtf(q * (1.0f / ND) + 1e-5f);
    const float4* wp = (const float4*)w;
    const float4* bp = (const float4*)b;
    __half2* op = (__half2*)(out + (size_t)row * ND);
#pragma unroll
    for (int i = 0; i < 8; i++) {
        int j = lane + i * 32;
        float4 wv = wp[j], bv = bp[j];
        op[j * 2] = __floats2half2_rn((v[i].x - mu) * rs * wv.x + bv.x,
                                      (v[i].y - mu) * rs * wv.y + bv.y);
        op[j * 2 + 1] = __floats2half2_rn((v[i].z - mu) * rs * wv.z + bv.z,
                                          (v[i].w - mu) * rs * wv.w + bv.w);
    }
}

__global__ void rope_kernel(__half* __restrict__ qkv) {
    int n = blockIdx.x, t = n % NT;
    __half* base = qkv + (size_t)n * 3072;
#pragma unroll
    for (int item = threadIdx.x; item < 512; item += 256) {
        int h = item >> 5, i = item & 31;
        float ang = (float)t * expf((float)(2 * i) * (-0.14391156831212806f));
        float s = sinf(ang), c = cosf(ang);
        __half* q = base + h * 64;
        __half* k = q + 1024;
        float q1 = __half2float(q[i]), q2 = __half2float(q[i + 32]);
        q[i] = __float2half_rn(q1 * c - q2 * s);
        q[i + 32] = __float2half_rn(q2 * c + q1 * s);
        float k1 = __half2float(k[i]), k2 = __half2float(k[i + 32]);
        k[i] = __float2half_rn(k1 * c - k2 * s);
        k[i + 32] = __float2half_rn(k2 * c + k1 * s);
    }
}

// softmax on fp16 scores, in-place -> fp16 probs; zero-pad to 256 boundary
__global__ void attn_softmax_kernel(__half* __restrict__ sc) {
    int r = blockIdx.x, tid = threadIdx.x;
    __half* row = sc + (size_t)blockIdx.y * NT * NT + (size_t)r * NT;
    int n = r + 1;
    __shared__ float red[128];
    float m = -3.4e38f;
    for (int j = tid; j < n; j += 128) m = fmaxf(m, __half2float(row[j]));
    red[tid] = m; __syncthreads();
    for (int s = 64; s; s >>= 1) { if (tid < s) red[tid] = fmaxf(red[tid], red[tid + s]); __syncthreads(); }
    m = red[0]; __syncthreads();
    float sum = 0.f;
    for (int j = tid; j < n; j += 128) sum += expf(__half2float(row[j]) - m);
    red[tid] = sum; __syncthreads();
    for (int s = 64; s; s >>= 1) { if (tid < s) red[tid] += red[tid + s]; __syncthreads(); }
    float inv = 1.0f / red[0];
    for (int j = tid; j < n; j += 128)
        row[j] = __float2half_rn(expf(__half2float(row[j]) - m) * inv);
    int rup = ((r >> 8) + 1) << 8;
    for (int j = n + tid; j < rup; j += 128) row[j] = __float2half_rn(0.f);
}

// ---------------- MoE ----------------
__global__ void route_kernel(const __half* __restrict__ ln, const float* __restrict__ wr,
                             const float* __restrict__ br, const float* __restrict__ wn,
                             const float* __restrict__ bn, float* __restrict__ route,
                             float* __restrict__ noise) {
    int n = blockIdx.x, tid = threadIdx.x;
    __shared__ float xs[ND];
    for (int d = tid; d < ND; d += 256) xs[d] = __half2float(ln[(size_t)n * ND + d]);
    __syncthreads();
    int w = tid >> 5, lane = tid & 31;
    float sr = 0.f, sn = 0.f;
    for (int d = lane; d < ND; d += 32) {
        float xv = xs[d];
        sr += xv * wr[(size_t)d * NE + w];
        sn += xv * wn[(size_t)d * NE + w];
    }
    for (int o = 16; o; o >>= 1) { sr += __shfl_down_sync(~0u, sr, o); sn += __shfl_down_sync(~0u, sn, o); }
    if (!lane) { route[n * NE + w] = sr + br[w]; noise[n * NE + w] = sn + bn[w]; }
}

__global__ void eps_kernel(unsigned k0, unsigned k1, float* __restrict__ eps) {
    int i = blockIdx.x * 256 + threadIdx.x;
    if (i >= NN * NE) return;
    unsigned o0, o1;
    threefry(k0, k1, 0u, (unsigned)i, o0, o1);
    eps[i] = bits_to_normal(o0 ^ o1);
}

__global__ void topk_kernel(const float* __restrict__ route, const float* __restrict__ noise,
                            const float* __restrict__ eps, float* __restrict__ gate,
                            unsigned char* __restrict__ mask) {
    int n = blockIdx.x * 256 + threadIdx.x;
    if (n >= NN) return;
    float nv[NE];
#pragma unroll
    for (int e = 0; e < NE; e++) {
        float x = noise[n * NE + e];
        float sp = fmaxf(x, 0.f) + log1pf(expf(-fabsf(x)));
        nv[e] = route[n * NE + e] + eps[n * NE + e] * sp;
    }
    int i1 = 0; float v1 = nv[0];
#pragma unroll
    for (int e = 1; e < NE; e++) if (nv[e] > v1) { v1 = nv[e]; i1 = e; }
    int i2 = -1; float v2 = -3.4e38f;
#pragma unroll
    for (int e = 0; e < NE; e++) if (e != i1 && nv[e] > v2) { v2 = nv[e]; i2 = e; }
    float e2 = expf(v2 - v1);
    float Z = 1.0f + e2;
#pragma unroll
    for (int e = 0; e < NE; e++)
        gate[n * NE + e] = (e == i1) ? (1.0f / Z) : ((e == i2) ? (e2 / Z) : 0.f);
    mask[n] = (unsigned char)((1u << i1) | (1u << i2));
}

__global__ void select_kernel(const unsigned char* __restrict__ mask, int* __restrict__ sel,
                              int* __restrict__ slot, int* __restrict__ cnt) {
    int e = blockIdx.x, lane = threadIdx.x;
    int base = 0;
    for (int n0 = 0; n0 < NN; n0 += 32) {
        int n = n0 + lane;
        bool f = (mask[n] >> e) & 1;
        unsigned bal = __ballot_sync(0xffffffffu, f);
        int pos = base + __popc(bal & ((1u << lane) - 1u));
        int sl = (f && pos < NCAP) ? pos : -1;
        slot[(size_t)e * NN + n] = sl;
        if (sl >= 0) sel[e * NCAP + sl] = n;
        base += __popc(bal);
    }
    if (!lane) cnt[e] = base < NCAP ? base : NCAP;
}

__global__ void gather_kernel(const __half* __restrict__ ln, const int* __restrict__ sel,
                              const int* __restrict__ cnt, __half* __restrict__ xt) {
    int s = blockIdx.x;
    int e = s / NCAP, i = s % NCAP;
    int* dst = (int*)(xt + (size_t)s * ND);
    if (i < cnt[e]) {
        const int* src = (const int*)(ln + (size_t)sel[s] * ND);
        for (int d = threadIdx.x; d < ND / 2; d += 256) dst[d] = src[d];
    } else {
        for (int d = threadIdx.x; d < ND / 2; d += 256) dst[d] = 0;
    }
}

__global__ void moe_scatter_kernel(const float* __restrict__ eo, const int* __restrict__ slot,
                                   const float* __restrict__ gate, float* __restrict__ x) {
    int n = blockIdx.x, tid = threadIdx.x;
    __shared__ int ss[NE];
    __shared__ float gg[NE];
    if (tid < NE) { ss[tid] = slot[(size_t)tid * NN + n]; gg[tid] = gate[n * NE + tid]; }
    __syncthreads();
    for (int d = tid; d < ND; d += 256) {
        float acc = 0.f;
#pragma unroll
        for (int e = 0; e < NE; e++) {
            int s = ss[e];
            if (s >= 0) acc += gg[e] * eo[((size_t)e * NCAP + s) * ND + d];
        }
        x[(size_t)n * ND + d] += acc;
    }
}

// ---------------- loss ----------------
__global__ void loss_kernel(const float* __restrict__ logits, const int* __restrict__ ids,
                            float* __restrict__ nll, float* __restrict__ vld) {
    int n = blockIdx.x, tid = threadIdx.x;
    int b = n / NT, t = n % NT;
    if (t == NT - 1) { if (!tid) { nll[n] = 0.f; vld[n] = 0.f; } return; }
    int tgt = ids[b * NT + t + 1];
    const float* row = logits + (size_t)n * NV;
    float m = -3.4e38f, s = 0.f;
    for (int j = tid; j < NV; j += 256) {
        float l = row[j];
        if (l > m) { s = s * expf(m - l) + 1.0f; m = l; }
        else s += expf(l - m);
    }
    __shared__ float sm[256], ssum[256];
    sm[tid] = m; ssum[tid] = s; __syncthreads();
    for (int st = 128; st; st >>= 1) {
        if (tid < st) {
            float m1 = sm[tid], s1 = ssum[tid], m2 = sm[tid + st], s2 = ssum[tid + st];
            float M = fmaxf(m1, m2);
            ssum[tid] = s1 * expf(m1 - M) + s2 * expf(m2 - M);
            sm[tid] = M;
        }
        __syncthreads();
    }
    if (!tid) {
        float lse = sm[0] + logf(ssum[0]);
        float v = (tgt != 2) ? 1.f : 0.f;
        nll[n] = -(row[tgt] - lse) * v;
        vld[n] = v;
    }
}

__global__ void reduce_kernel(const float* __restrict__ nll, const float* __restrict__ vld,
                              float* __restrict__ out) {
    __shared__ float s1[256], s2[256];
    int tid = threadIdx.x;
    float a = 0.f, b = 0.f;
    for (int i = tid; i < NN; i += 256) { a += nll[i]; b += vld[i]; }
    s1[tid] = a; s2[tid] = b; __syncthreads();
    for (int st = 128; st; st >>= 1) { if (tid < st) { s1[tid] += s1[tid + st]; s2[tid] += s2[tid + st]; } __syncthreads(); }
    if (!tid) out[0] = s1[0] / fmaxf(s2[0], 1.0f);
}

// ---------------- host launch ----------------
#define H_SMEM(BM, BN) ((2*(BM) + 2*(BN)) * 72 * 2)

extern "C" void kernel_launch(void* const* d_in, const int* in_sizes, int n_in,
                              void* d_out, int out_size) {
    const int*   ids     = (const int*)d_in[0];
    const float* tok_emb = (const float*)d_in[1];
    const float* pos_emb = (const float*)d_in[2];
    const float* ln1_w   = (const float*)d_in[3];
    const float* ln1_b   = (const float*)d_in[4];
    const float* ln2_w   = (const float*)d_in[5];
    const float* ln2_b   = (const float*)d_in[6];
    const float* w_qkv   = (const float*)d_in[7];
    const float* w_out   = (const float*)d_in[8];
    const float* w_route = (const float*)d_in[9];
    const float* b_route = (const float*)d_in[10];
    const float* w_noise = (const float*)d_in[11];
    const float* b_noise = (const float*)d_in[12];
    const float* w_e1    = (const float*)d_in[13];
    const float* b_e1    = (const float*)d_in[14];
    const float* w_e2    = (const float*)d_in[15];
    const float* b_e2    = (const float*)d_in[16];
    const float* lnf_w   = (const float*)d_in[17];
    const float* lnf_b   = (const float*)d_in[18];
    float* out = (float*)d_out;

    float *x, *route, *noise, *eps, *gate, *eo, *lg, *nll, *vld;
    __half *ln16, *qkv16, *attn16, *p16, *xt16, *h116;
    __half *wqkv16, *wout16, *we116, *we216, *tok16;
    unsigned char* mask; int *sel, *slot, *cnt;
    cudaGetSymbolAddress((void**)&x, g_x);
    cudaGetSymbolAddress((void**)&ln16, g_ln16);
    cudaGetSymbolAddress((void**)&qkv16, g_qkv16);
    cudaGetSymbolAddress((void**)&attn16, g_attn16);
    cudaGetSymbolAddress((void**)&p16, g_p16);
    cudaGetSymbolAddress((void**)&route, g_route);
    cudaGetSymbolAddress((void**)&noise, g_noise);
    cudaGetSymbolAddress((void**)&eps, g_eps);
    cudaGetSymbolAddress((void**)&gate, g_gate);
    cudaGetSymbolAddress((void**)&mask, g_mask);
    cudaGetSymbolAddress((void**)&sel, g_sel);
    cudaGetSymbolAddress((void**)&slot, g_slot);
    cudaGetSymbolAddress((void**)&cnt, g_cnt);
    cudaGetSymbolAddress((void**)&xt16, g_xt16);
    cudaGetSymbolAddress((void**)&h116, g_h116);
    cudaGetSymbolAddress((void**)&eo, g_eo);
    cudaGetSymbolAddress((void**)&lg, g_log);
    cudaGetSymbolAddress((void**)&nll, g_nll);
    cudaGetSymbolAddress((void**)&vld, g_vld);
    cudaGetSymbolAddress((void**)&wqkv16, g_wqkv16);
    cudaGetSymbolAddress((void**)&wout16, g_wout16);
    cudaGetSymbolAddress((void**)&we116, g_we116);
    cudaGetSymbolAddress((void**)&we216, g_we216);
    cudaGetSymbolAddress((void**)&tok16, g_tok16);

    constexpr int BIG_SMEM = H_SMEM(256, 128);  // 110592
    constexpr int PV_SMEM  = H_SMEM(128, 64);   // 55296
    auto* kqkv = hgemm<512,256,128,4,4,true ,false,false,false,false,false,true >;
    auto* kqk  = hgemm<512,256,128,4,4,true ,false,false,false,true ,false,true >;
    auto* kpv  = hgemm<256,128, 64,4,2,false,false,false,false,false,true ,true >;
    auto* kproj= hgemm<512,256,128,4,4,true ,false,false,true ,false,false,false>;
    auto* kfc1 = hgemm<512,256,128,4,4,true ,true ,true ,false,false,false,true >;
    auto* kfc2 = hgemm<512,256,128,4,4,true ,true ,false,false,false,false,false>;
    auto* kvoc = hgemm<512,256,128,4,4,true ,false,false,false,false,false,false>;
    cudaFuncSetAttribute(kqkv, cudaFuncAttributeMaxDynamicSharedMemorySize, BIG_SMEM);
    cudaFuncSetAttribute(kqk,  cudaFuncAttributeMaxDynamicSharedMemorySize, BIG_SMEM);
    cudaFuncSetAttribute(kpv,  cudaFuncAttributeMaxDynamicSharedMemorySize, PV_SMEM);
    cudaFuncSetAttribute(kproj,cudaFuncAttributeMaxDynamicSharedMemorySize, BIG_SMEM);
    cudaFuncSetAttribute(kfc1, cudaFuncAttributeMaxDynamicSharedMemorySize, BIG_SMEM);
    cudaFuncSetAttribute(kfc2, cudaFuncAttributeMaxDynamicSharedMemorySize, BIG_SMEM);
    cudaFuncSetAttribute(kvoc, cudaFuncAttributeMaxDynamicSharedMemorySize, BIG_SMEM);

    // weight prep: transpose+convert to [N,K] fp16; tok_emb converted (already [N,K])
    tr_h_kernel<<<dim3(3*ND/32, ND/64, NLAY), dim3(32,8)>>>(w_qkv, wqkv16, ND, 3*ND);
    tr_h_kernel<<<dim3(ND/32, ND/64, NLAY), dim3(32,8)>>>(w_out, wout16, ND, ND);
    tr_h_kernel<<<dim3(NFF/32, ND/64, NLAY*NE), dim3(32,8)>>>(w_e1, we116, ND, NFF);
    tr_h_kernel<<<dim3(ND/32, NFF/64, NLAY*NE), dim3(32,8)>>>(w_e2, we216, NFF, ND);
    {
        size_t n = (size_t)NV * ND / 4;
        cvt_h_kernel<<<(unsigned)((n + 255) / 256), 256>>>(tok_emb, tok16, n);
    }

    embed_kernel<<<NN, 256>>>(ids, tok_emb, pos_emb, x);

    for (int l = 0; l < NLAY; l++) {
        // ---- attention ----
        ln_kernel<<<NN / 8, 256>>>(x, ln1_w + l * ND, ln1_b + l * ND, ln16);
        kqkv<<<dim3(24, 16, 1), 512, BIG_SMEM>>>(
            ln16, wqkv16 + (size_t)l * ND * 3 * ND, nullptr, qkv16,
            ND, ND, ND, 3 * ND, 1, 0, 0, 0, 0, 0, 0, 0, 1.0f);
        rope_kernel<<<NN, 256>>>(qkv16);
        // fp16 scores -> p16 (causal tiles), scale 0.125
        kqk<<<dim3(16, 8, NB * NH), 512, BIG_SMEM>>>(
            qkv16, qkv16 + 1024, nullptr, p16,
            64, 3072, 3072, NT, NH,
            (size_t)NT * 3072, 64, (size_t)NT * 3072, 64,
            (size_t)NH * NT * NT, (size_t)NT * NT, 0, 0.125f);
        attn_softmax_kernel<<<dim3(NT, NB * NH), 128>>>(p16);
        kpv<<<dim3(1, 16, NB * NH), 256, PV_SMEM>>>(
            p16, qkv16 + 2048, nullptr, attn16,
            NT, NT, 3072, ND, NH,
            (size_t)NH * NT * NT, (size_t)NT * NT, (size_t)NT * 3072, 64,
            (size_t)NT * ND, 64, 0, 1.0f);
        kproj<<<dim3(8, 16, 1), 512, BIG_SMEM>>>(
            attn16, wout16 + (size_t)l * ND * ND, nullptr, x,
            ND, ND, ND, ND, 1, 0, 0, 0, 0, 0, 0, 0, 1.0f);

        // ---- MoE ----
        ln_kernel<<<NN / 8, 256>>>(x, ln2_w + l * ND, ln2_b + l * ND, ln16);
        route_kernel<<<NN, 256>>>(ln16, w_route + (size_t)l * ND * NE, b_route + l * NE,
                                  w_noise + (size_t)l * ND * NE, b_noise + l * NE, route, noise);
        unsigned k0, k1;
        threefry(0u, 1234u, 0u, (unsigned)l, k0, k1);
        eps_kernel<<<(NN * NE + 255) / 256, 256>>>(k0, k1, eps);
        topk_kernel<<<(NN + 255) / 256, 256>>>(route, noise, eps, gate, mask);
        select_kernel<<<NE, 32>>>(mask, sel, slot, cnt);
        gather_kernel<<<NE * NCAP, 256>>>(ln16, sel, cnt, xt16);
        kfc1<<<dim3(32, 4, NE), 512, BIG_SMEM>>>(
            xt16, we116 + (size_t)l * NE * ND * NFF, b_e1 + (size_t)l * NE * NFF, h116,
            ND, ND, ND, NFF, 1,
            (size_t)NCAP * ND, 0, (size_t)NFF * ND, 0,
            (size_t)NCAP * NFF, 0, NFF, 1.0f);
        kfc2<<<dim3(8, 4, NE), 512, BIG_SMEM>>>(
            h116, we216 + (size_t)l * NE * NFF * ND, b_e2 + (size_t)l * NE * ND, eo,
            NFF, NFF, NFF, ND, 1,
            (size_t)NCAP * NFF, 0, (size_t)ND * NFF, 0,
            (size_t)NCAP * ND, 0, ND, 1.0f);
        moe_scatter_kernel<<<NN, 256>>>(eo, slot, gate, x);
    }

    ln_kernel<<<NN / 8, 256>>>(x, lnf_w, lnf_b, ln16);
    kvoc<<<dim3(NV / 128, 16, 1), 512, BIG_SMEM>>>(
        ln16, tok16, nullptr, lg,
        ND, ND, ND, NV, 1, 0, 0, 0, 0, 0, 0, 0, 1.0f);
    loss_kernel<<<NN, 256>>>(lg, ids, nll, vld);
    reduce_kernel<<<1, 256>>>(nll, vld, out);
}

// round 10
// speedup vs baseline: 2.5927x; 1.0815x over previous
#include <cuda_runtime.h>
#include <cuda_fp16.h>
#include <cstdint>
#include <cstddef>

#define NB 2
#define NT 2048
#define ND 1024
#define NH 16
#define NLAY 2
#define NE 8
#define NV 32000
#define NN (NB*NT)
#define NCAP 1024
#define NFF 4096

// ---------------- device scratch ----------------
__device__ float  g_x   [(size_t)NN*ND];
__device__ __half g_ln16[(size_t)NN*ND];
__device__ __half g_qkv16[(size_t)NN*3*ND];
__device__ __half g_attn16[(size_t)NN*ND];
__device__ __half g_p16 [(size_t)NB*NH*NT*NT];
__device__ float  g_route[NN*NE];
__device__ float  g_noise[NN*NE];
__device__ float  g_eps  [NN*NE];
__device__ float  g_gate [NN*NE];
__device__ unsigned char g_mask[NN];
__device__ int    g_sel [NE*NCAP];
__device__ int    g_slot[NE*NN];
__device__ int    g_cnt [NE];
__device__ __half g_xt16[(size_t)NE*NCAP*ND];
__device__ __half g_h116[(size_t)NE*NCAP*NFF];
__device__ float  g_eo  [(size_t)NE*NCAP*ND];
__device__ __half g_log16[(size_t)NN*NV];
__device__ float  g_nll [NN];
__device__ float  g_vld [NN];
// fp16, TRANSPOSED ([N,K]) weight copies
__device__ __half g_wqkv16[(size_t)NLAY*ND*3*ND];
__device__ __half g_wout16[(size_t)NLAY*ND*ND];
__device__ __half g_we116 [(size_t)NLAY*NE*ND*NFF];
__device__ __half g_we216 [(size_t)NLAY*NE*NFF*ND];
__device__ __half g_tok16 [(size_t)NV*ND];

// ---------------- threefry2x32 (matches JAX) ----------------
__host__ __device__ __forceinline__ void threefry(unsigned k0, unsigned k1,
                                                  unsigned x0, unsigned x1,
                                                  unsigned& o0, unsigned& o1) {
    unsigned ks2 = k0 ^ k1 ^ 0x1BD11BDAu;
    x0 += k0; x1 += k1;
#define TFR(r) { x0 += x1; x1 = (x1 << (r)) | (x1 >> (32 - (r))); x1 ^= x0; }
    TFR(13) TFR(15) TFR(26) TFR(6)  x0 += k1;  x1 += ks2 + 1u;
    TFR(17) TFR(29) TFR(16) TFR(24) x0 += ks2; x1 += k0 + 2u;
    TFR(13) TFR(15) TFR(26) TFR(6)  x0 += k0;  x1 += k1 + 3u;
    TFR(17) TFR(29) TFR(16) TFR(24) x0 += k1;  x1 += ks2 + 4u;
    TFR(13) TFR(15) TFR(26) TFR(6)  x0 += ks2; x1 += k0 + 5u;
#undef TFR
    o0 = x0; o1 = x1;
}

// XLA ErfInv32 (Giles) polynomial
__device__ __forceinline__ float xla_erfinv(float x) {
    float w = -log1pf(-x * x);
    float p;
    if (w < 5.f) {
        w -= 2.5f;
        p = 2.81022636e-08f;
        p = fmaf(p, w, 3.43273939e-07f);
        p = fmaf(p, w, -3.5233877e-06f);
        p = fmaf(p, w, -4.39150654e-06f);
        p = fmaf(p, w, 0.00021858087f);
        p = fmaf(p, w, -0.00125372503f);
        p = fmaf(p, w, -0.00417768164f);
        p = fmaf(p, w, 0.246640727f);
        p = fmaf(p, w, 1.50140941f);
    } else {
        w = sqrtf(w) - 3.f;
        p = -0.000200214257f;
        p = fmaf(p, w, 0.000100950558f);
        p = fmaf(p, w, 0.00134934322f);
        p = fmaf(p, w, -0.00367342844f);
        p = fmaf(p, w, 0.00573950773f);
        p = fmaf(p, w, -0.0076224613f);
        p = fmaf(p, w, 0.00943887047f);
        p = fmaf(p, w, 1.00167406f);
        p = fmaf(p, w, 2.83297682f);
    }
    return p * x;
}

__device__ __forceinline__ float bits_to_normal(unsigned bits) {
    float f = __uint_as_float((bits >> 9) | 0x3F800000u) - 1.0f;
    const float lo = -0.99999994f;
    float u = fmaf(f, 2.0f, lo);
    u = fmaxf(u, lo);
    return 1.41421356237f * xla_erfinv(u);
}

// ---------------- mma / ldmatrix / cp.async helpers ----------------
__device__ __forceinline__ void mma_f16(float* c, const unsigned* a, const unsigned* b) {
    asm volatile("mma.sync.aligned.m16n8k16.row.col.f32.f16.f16.f32 "
        "{%0,%1,%2,%3}, {%4,%5,%6,%7}, {%8,%9}, {%0,%1,%2,%3};"
        : "+f"(c[0]), "+f"(c[1]), "+f"(c[2]), "+f"(c[3])
        : "r"(a[0]), "r"(a[1]), "r"(a[2]), "r"(a[3]), "r"(b[0]), "r"(b[1]));
}
__device__ __forceinline__ void ldsm4(unsigned& d0, unsigned& d1, unsigned& d2, unsigned& d3,
                                      uint32_t addr) {
    asm volatile("ldmatrix.sync.aligned.m8n8.x4.shared.b16 {%0,%1,%2,%3}, [%4];"
        : "=r"(d0), "=r"(d1), "=r"(d2), "=r"(d3) : "r"(addr));
}
__device__ __forceinline__ uint32_t smem_u32(const void* p) {
    uint32_t a;
    asm("{ .reg .u64 t; cvta.to.shared.u64 t, %1; cvt.u32.u64 %0, t; }" : "=r"(a) : "l"(p));
    return a;
}
__device__ __forceinline__ void cpa16(uint32_t dst, const void* src) {
    asm volatile("cp.async.ca.shared.global [%0], [%1], 16;" :: "r"(dst), "l"(src));
}
#define CPA_COMMIT() asm volatile("cp.async.commit_group;" ::: "memory")
#define CPA_WAIT(n)  asm volatile("cp.async.wait_group %0;" :: "n"(n) : "memory")

// ---------------- weight prep ----------------
__global__ void tr_h_kernel(const float* __restrict__ in, __half* __restrict__ out,
                            int R, int C) {
    __shared__ float tile[32][65];
    in += (size_t)blockIdx.z * R * C;
    out += (size_t)blockIdx.z * R * C;
    int c0 = blockIdx.x * 32, r0 = blockIdx.y * 64;
    int tx = threadIdx.x, ty = threadIdx.y;
#pragma unroll
    for (int j = ty; j < 64; j += 8)
        tile[tx][j] = in[(size_t)(r0 + j) * C + c0 + tx];
    __syncthreads();
#pragma unroll
    for (int j = ty; j < 32; j += 8) {
        __half2 h2 = __floats2half2_rn(tile[j][2 * tx], tile[j][2 * tx + 1]);
        *((__half2*)(out + (size_t)(c0 + j) * R + r0) + tx) = h2;
    }
}

__global__ void cvt_h_kernel(const float* __restrict__ in, __half* __restrict__ out, size_t n4) {
    size_t i = (size_t)blockIdx.x * 256 + threadIdx.x;
    if (i >= n4) return;
    float4 v = ((const float4*)in)[i];
    __half2* o = (__half2*)out;
    o[i * 2] = __floats2half2_rn(v.x, v.y);
    o[i * 2 + 1] = __floats2half2_rn(v.z, v.w);
}

// ---------------- cp.async 3-stage fp16 GEMM (B is [N,K]) ----------------
// C[M,N] = A[M,K](half,row,lda) * B[N,K](half,row,ldb)^T; BK=64.
template<int TH, int BM, int BN, int WR, int WC, bool BIAS, bool RELU,
         bool ACCUM, bool CAUSAL, bool OUTH>
__global__ void __launch_bounds__(TH)
hgemm_ca(const __half* __restrict__ A, const __half* __restrict__ B,
         const float* __restrict__ bias, void* __restrict__ Cv,
         int K, int lda, int ldb, int ldc, int zdiv,
         size_t sA, size_t sA2, size_t sB, size_t sB2,
         size_t sC, size_t sC2, size_t sBias, float scale)
{
    constexpr int BK = 64;
    constexpr int LDS = 72;
    constexpr int WM = BM / WR, WN = BN / WC;
    constexpr int MT = WM / 16, NT4 = WN / 8, NP = NT4 / 2;
    constexpr int ANV = (BM * 8) / TH;      // 16B chunks per thread for A
    constexpr int BNV = (BN * 8) / TH;
    constexpr int STG = (BM + BN) * LDS;    // halves per stage

    const int m0 = blockIdx.y * BM, n0 = blockIdx.x * BN;
    if (CAUSAL && n0 >= m0 + BM) return;

    const int tid = threadIdx.x, lane = tid & 31, warp = tid >> 5;
    const int wr = warp / WC, wc = warp % WC;
    const int g = lane >> 2, t = lane & 3;

    {
        int z = blockIdx.z, z1 = z / zdiv, z0 = z - z1 * zdiv;
        A += (size_t)z1 * sA + (size_t)z0 * sA2;
        B += (size_t)z1 * sB + (size_t)z0 * sB2;
        Cv = (char*)Cv + ((size_t)z1 * sC + (size_t)z0 * sC2) * (OUTH ? 2 : 4);
        if (BIAS) bias += (size_t)z1 * sBias;
    }

    const int nk = K / BK;

    extern __shared__ __half shh[];
    const uint32_t sbase = smem_u32(shh);

    const int a_r = lane & 15, a_c8 = (lane >> 4) * 8;
    const int b_r = (lane & 7) + (lane >> 4) * 8, b_c8 = ((lane >> 3) & 1) * 8;
    const int mwb = wr * WM, nwb = wc * WN;

    // per-thread load coordinates (16B chunks; 8 chunks per 64-half row)
    const int ar = tid >> 3, aq = tid & 7;       // plus i*TH/8 rows
    auto issue = [&](int ks, int st) {
        uint32_t so = sbase + (uint32_t)(st * STG) * 2;
        const __half* Ac = A + (size_t)m0 * lda + ks * BK;
        const __half* Bc = B + (size_t)n0 * ldb + ks * BK;
#pragma unroll
        for (int i = 0; i < ANV; i++) {
            int row = ar + i * (TH >> 3);
            cpa16(so + (uint32_t)(row * LDS + aq * 8) * 2,
                  Ac + (size_t)row * lda + aq * 8);
        }
#pragma unroll
        for (int i = 0; i < BNV; i++) {
            int row = ar + i * (TH >> 3);
            cpa16(so + (uint32_t)((BM + row) * LDS + aq * 8) * 2,
                  Bc + (size_t)row * ldb + aq * 8);
        }
        CPA_COMMIT();
    };

    float acc[MT][NT4][4] = {};

    issue(0, 0);
    if (nk > 1) issue(1, 1);
    if (nk > 1) { CPA_WAIT(1); } else { CPA_WAIT(0); }
    __syncthreads();

    for (int ks = 0; ks < nk; ks++) {
        int cur = ks % 3;
        bool more2 = (ks + 2 < nk);
        if (more2) issue(ks + 2, (ks + 2) % 3);
        uint32_t abase = sbase + (uint32_t)(cur * STG) * 2;
        uint32_t bbase = abase + (uint32_t)(BM * LDS) * 2;
#pragma unroll
        for (int kq = 0; kq < 4; kq++) {
            unsigned af[MT][4], bf[NT4][2];
#pragma unroll
            for (int mt = 0; mt < MT; mt++) {
                uint32_t ad = abase +
                    (uint32_t)(((mwb + mt * 16 + a_r) * LDS + kq * 16 + a_c8) * 2);
                ldsm4(af[mt][0], af[mt][1], af[mt][2], af[mt][3], ad);
            }
#pragma unroll
            for (int np = 0; np < NP; np++) {
                uint32_t bd = bbase +
                    (uint32_t)(((nwb + np * 16 + b_r) * LDS + kq * 16 + b_c8) * 2);
                ldsm4(bf[2 * np][0], bf[2 * np][1], bf[2 * np + 1][0], bf[2 * np + 1][1], bd);
            }
#pragma unroll
            for (int mt = 0; mt < MT; mt++)
#pragma unroll
                for (int nt = 0; nt < NT4; nt++)
                    mma_f16(acc[mt][nt], af[mt], bf[nt]);
        }
        if (ks + 1 < nk) {
            if (more2) { CPA_WAIT(1); } else { CPA_WAIT(0); }
            __syncthreads();
        }
    }

    __half* Ch = (__half*)Cv;
    float*  Cf = (float*)Cv;
#pragma unroll
    for (int mt = 0; mt < MT; mt++) {
#pragma unroll
        for (int nt = 0; nt < NT4; nt++) {
            int r0 = m0 + mwb + mt * 16 + g;
            int c0 = n0 + nwb + nt * 8 + 2 * t;
            float v0 = acc[mt][nt][0] * scale, v1 = acc[mt][nt][1] * scale;
            float v2 = acc[mt][nt][2] * scale, v3 = acc[mt][nt][3] * scale;
            if (BIAS) {
                float b0 = bias[c0], b1 = bias[c0 + 1];
                v0 += b0; v1 += b1; v2 += b0; v3 += b1;
            }
            if (RELU) {
                v0 = fmaxf(v0, 0.f); v1 = fmaxf(v1, 0.f);
                v2 = fmaxf(v2, 0.f); v3 = fmaxf(v3, 0.f);
            }
            if (OUTH) {
                *(__half2*)(Ch + (size_t)r0 * ldc + c0) = __floats2half2_rn(v0, v1);
                *(__half2*)(Ch + (size_t)(r0 + 8) * ldc + c0) = __floats2half2_rn(v2, v3);
            } else {
                float* p0 = Cf + (size_t)r0 * ldc + c0;
                float* p1 = Cf + (size_t)(r0 + 8) * ldc + c0;
                if (ACCUM) {
                    float2 o0 = *(float2*)p0, o1 = *(float2*)p1;
                    v0 += o0.x; v1 += o0.y; v2 += o1.x; v3 += o1.y;
                }
                *(float2*)p0 = make_float2(v0, v1);
                *(float2*)p1 = make_float2(v2, v3);
            }
        }
    }
}

// ---------------- register-staged fp16 GEMM (PV only: B=[K,N], PVLIM) ----------------
template<int TH, int BM, int BN, int WR, int WC, bool OUTH>
__global__ void __launch_bounds__(TH)
hgemm_pv(const __half* __restrict__ A, const __half* __restrict__ B,
         void* __restrict__ Cv,
         int K, int lda, int ldb, int ldc, int zdiv,
         size_t sA, size_t sA2, size_t sB, size_t sB2,
         size_t sC, size_t sC2)
{
    constexpr int BK = 64;
    constexpr int LDS = 72;
    constexpr int WM = BM / WR, WN = BN / WC;
    constexpr int MT = WM / 16, NT4 = WN / 8, NP = NT4 / 2;
    constexpr int ANV = (BM * BK) / (8 * TH);
    constexpr int BNU = (BN * BK) / (2 * TH);
    constexpr uint32_t ABYTES = 2u * BM * LDS * 2;

    const int m0 = blockIdx.y * BM, n0 = blockIdx.x * BN;
    const int tid = threadIdx.x, lane = tid & 31, warp = tid >> 5;
    const int wr = warp / WC, wc = warp % WC;
    const int g = lane >> 2, t = lane & 3;

    {
        int z = blockIdx.z, z1 = z / zdiv, z0 = z - z1 * zdiv;
        A += (size_t)z1 * sA + (size_t)z0 * sA2;
        B += (size_t)z1 * sB + (size_t)z0 * sB2;
        Cv = (char*)Cv + ((size_t)z1 * sC + (size_t)z0 * sC2) * (OUTH ? 2 : 4);
    }

    int Keff = ((int)blockIdx.y + 1) * BM;
    if (Keff > K) Keff = K;
    const int nk = Keff / BK;

    extern __shared__ __half shh[];
    __half (*As)[LDS] = (__half(*)[LDS])shh;
    __half (*Bs)[LDS] = (__half(*)[LDS])(shh + 2 * BM * LDS);
    const uint32_t sbase = smem_u32(shh);

    const int a_r = lane & 15, a_c8 = (lane >> 4) * 8;
    const int b_r = (lane & 7) + (lane >> 4) * 8, b_c8 = ((lane >> 3) & 1) * 8;
    const int mwb = wr * WM, nwb = wc * WN;

    uint4 pa[ANV];
    unsigned pbu[BNU];

    auto gload = [&](int k0) {
#pragma unroll
        for (int i = 0; i < ANV; i++) {
            int idx = tid + i * TH;
            int row = idx >> 3, q = idx & 7;
            pa[i] = *(const uint4*)(A + (size_t)(m0 + row) * lda + k0 + q * 8);
        }
#pragma unroll
        for (int i = 0; i < BNU; i++) {
            int idx = tid + i * TH;
            int kk = idx / (BN / 2), nc = idx % (BN / 2);
            pbu[i] = *(const unsigned*)(B + (size_t)(k0 + kk) * ldb + n0 + nc * 2);
        }
    };
    auto sstore = [&](int buf) {
#pragma unroll
        for (int i = 0; i < ANV; i++) {
            int idx = tid + i * TH;
            int row = idx >> 3, q = idx & 7;
            *(uint4*)&As[buf * BM + row][q * 8] = pa[i];
        }
#pragma unroll
        for (int i = 0; i < BNU; i++) {
            int idx = tid + i * TH;
            int kk = idx / (BN / 2), nc = idx % (BN / 2);
            __half2 h = *(__half2*)&pbu[i];
            Bs[buf * BN + nc * 2][kk] = __low2half(h);
            Bs[buf * BN + nc * 2 + 1][kk] = __high2half(h);
        }
    };

    float acc[MT][NT4][4] = {};

    gload(0);
    sstore(0);
    __syncthreads();

    int buf = 0;
    for (int ks = 0; ks < nk; ks++) {
        if (ks + 1 < nk) gload((ks + 1) * BK);
#pragma unroll
        for (int kq = 0; kq < 4; kq++) {
            unsigned af[MT][4], bf[NT4][2];
#pragma unroll
            for (int mt = 0; mt < MT; mt++) {
                uint32_t ad = sbase +
                    (uint32_t)(((buf * BM + mwb + mt * 16 + a_r) * LDS + kq * 16 + a_c8) * 2);
                ldsm4(af[mt][0], af[mt][1], af[mt][2], af[mt][3], ad);
            }
#pragma unroll
            for (int np = 0; np < NP; np++) {
                uint32_t bd = sbase + ABYTES +
                    (uint32_t)(((buf * BN + nwb + np * 16 + b_r) * LDS + kq * 16 + b_c8) * 2);
                ldsm4(bf[2 * np][0], bf[2 * np][1], bf[2 * np + 1][0], bf[2 * np + 1][1], bd);
            }
#pragma unroll
            for (int mt = 0; mt < MT; mt++)
#pragma unroll
                for (int nt = 0; nt < NT4; nt++)
                    mma_f16(acc[mt][nt], af[mt], bf[nt]);
        }
        if (ks + 1 < nk) sstore(buf ^ 1);
        __syncthreads();
        buf ^= 1;
    }

    __half* Ch = (__half*)Cv;
#pragma unroll
    for (int mt = 0; mt < MT; mt++) {
#pragma unroll
        for (int nt = 0; nt < NT4; nt++) {
            int r0 = m0 + mwb + mt * 16 + g;
            int c0 = n0 + nwb + nt * 8 + 2 * t;
            *(__half2*)(Ch + (size_t)r0 * ldc + c0) =
                __floats2half2_rn(acc[mt][nt][0], acc[mt][nt][1]);
            *(__half2*)(Ch + (size_t)(r0 + 8) * ldc + c0) =
                __floats2half2_rn(acc[mt][nt][2], acc[mt][nt][3]);
        }
    }
}

// ---------------- small kernels ----------------
__global__ void embed_kernel(const int* __restrict__ ids, const float* __restrict__ tok,
                             const float* __restrict__ pos, float* __restrict__ x) {
    int n = blockIdx.x, t = n % NT, id = ids[n];
    const float* te = tok + (size_t)id * ND;
    const float* pe = pos + (size_t)t * ND;
    float* dst = x + (size_t)n * ND;
    for (int d = threadIdx.x; d < ND; d += 256) dst[d] = te[d] + pe[d];
}

__global__ void ln_kernel(const float* __restrict__ x, const float* __restrict__ w,
                          const float* __restrict__ b, __half* __restrict__ out) {
    int row = blockIdx.x * 8 + (threadIdx.x >> 5);
    int lane = threadIdx.x & 31;
    const float4* p = (const float4*)(x + (size_t)row * ND);
    float4 v[8];
    float s = 0.f;
#pragma unroll
    for (int i = 0; i < 8; i++) {
        v[i] = p[lane + i * 32];
        s += v[i].x + v[i].y + v[i].z + v[i].w;
    }
#pragma unroll
    for (int o = 16; o; o >>= 1) s += __shfl_xor_sync(~0u, s, o);
    float mu = s * (1.0f / ND);
    float q = 0.f;
#pragma unroll
    for (int i = 0; i < 8; i++) {
        float a = v[i].x - mu, c = v[i].y - mu, d = v[i].z - mu, e = v[i].w - mu;
        q += a * a + c * c + d * d + e * e;
    }
#pragma unroll
    for (int o = 16; o; o >>= 1) q += __shfl_xor_sync(~0u, q, o);
    float rs = rsqrtf(q * (1.0f / ND) + 1e-5f);
    const float4* wp = (const float4*)w;
    const float4* bp = (const float4*)b;
    __half2* op = (__half2*)(out + (size_t)row * ND);
#pragma unroll
    for (int i = 0; i < 8; i++) {
        int j = lane + i * 32;
        float4 wv = wp[j], bv = bp[j];
        op[j * 2] = __floats2half2_rn((v[i].x - mu) * rs * wv.x + bv.x,
                                      (v[i].y - mu) * rs * wv.y + bv.y);
        op[j * 2 + 1] = __floats2half2_rn((v[i].z - mu) * rs * wv.z + bv.z,
                                          (v[i].w - mu) * rs * wv.w + bv.w);
    }
}

__global__ void rope_kernel(__half* __restrict__ qkv) {
    int n = blockIdx.x, t = n % NT;
    __half* base = qkv + (size_t)n * 3072;
#pragma unroll
    for (int item = threadIdx.x; item < 512; item += 256) {
        int h = item >> 5, i = item & 31;
        float ang = (float)t * expf((float)(2 * i) * (-0.14391156831212806f));
        float s = sinf(ang), c = cosf(ang);
        __half* q = base + h * 64;
        __half* k = q + 1024;
        float q1 = __half2float(q[i]), q2 = __half2float(q[i + 32]);
        q[i] = __float2half_rn(q1 * c - q2 * s);
        q[i + 32] = __float2half_rn(q2 * c + q1 * s);
        float k1 = __half2float(k[i]), k2 = __half2float(k[i + 32]);
        k[i] = __float2half_rn(k1 * c - k2 * s);
        k[i + 32] = __float2half_rn(k2 * c + k1 * s);
    }
}

__global__ void attn_softmax_kernel(__half* __restrict__ sc) {
    int r = blockIdx.x, tid = threadIdx.x;
    __half* row = sc + (size_t)blockIdx.y * NT * NT + (size_t)r * NT;
    int n = r + 1;
    __shared__ float red[128];
    float m = -3.4e38f;
    for (int j = tid; j < n; j += 128) m = fmaxf(m, __half2float(row[j]));
    red[tid] = m; __syncthreads();
    for (int s = 64; s; s >>= 1) { if (tid < s) red[tid] = fmaxf(red[tid], red[tid + s]); __syncthreads(); }
    m = red[0]; __syncthreads();
    float sum = 0.f;
    for (int j = tid; j < n; j += 128) sum += expf(__half2float(row[j]) - m);
    red[tid] = sum; __syncthreads();
    for (int s = 64; s; s >>= 1) { if (tid < s) red[tid] += red[tid + s]; __syncthreads(); }
    float inv = 1.0f / red[0];
    for (int j = tid; j < n; j += 128)
        row[j] = __float2half_rn(expf(__half2float(row[j]) - m) * inv);
    int rup = ((r >> 8) + 1) << 8;
    for (int j = n + tid; j < rup; j += 128) row[j] = __float2half_rn(0.f);
}

// ---------------- MoE ----------------
__global__ void route_kernel(const __half* __restrict__ ln, const float* __restrict__ wr,
                             const float* __restrict__ br, const float* __restrict__ wn,
                             const float* __restrict__ bn, float* __restrict__ route,
                             float* __restrict__ noise) {
    int n = blockIdx.x, tid = threadIdx.x;
    __shared__ float xs[ND];
    for (int d = tid; d < ND; d += 256) xs[d] = __half2float(ln[(size_t)n * ND + d]);
    __syncthreads();
    int w = tid >> 5, lane = tid & 31;
    float sr = 0.f, sn = 0.f;
    for (int d = lane; d < ND; d += 32) {
        float xv = xs[d];
        sr += xv * wr[(size_t)d * NE + w];
        sn += xv * wn[(size_t)d * NE + w];
    }
    for (int o = 16; o; o >>= 1) { sr += __shfl_down_sync(~0u, sr, o); sn += __shfl_down_sync(~0u, sn, o); }
    if (!lane) { route[n * NE + w] = sr + br[w]; noise[n * NE + w] = sn + bn[w]; }
}

__global__ void eps_kernel(unsigned k0, unsigned k1, float* __restrict__ eps) {
    int i = blockIdx.x * 256 + threadIdx.x;
    if (i >= NN * NE) return;
    unsigned o0, o1;
    threefry(k0, k1, 0u, (unsigned)i, o0, o1);
    eps[i] = bits_to_normal(o0 ^ o1);
}

__global__ void topk_kernel(const float* __restrict__ route, const float* __restrict__ noise,
                            const float* __restrict__ eps, float* __restrict__ gate,
                            unsigned char* __restrict__ mask) {
    int n = blockIdx.x * 256 + threadIdx.x;
    if (n >= NN) return;
    float nv[NE];
#pragma unroll
    for (int e = 0; e < NE; e++) {
        float x = noise[n * NE + e];
        float sp = fmaxf(x, 0.f) + log1pf(expf(-fabsf(x)));
        nv[e] = route[n * NE + e] + eps[n * NE + e] * sp;
    }
    int i1 = 0; float v1 = nv[0];
#pragma unroll
    for (int e = 1; e < NE; e++) if (nv[e] > v1) { v1 = nv[e]; i1 = e; }
    int i2 = -1; float v2 = -3.4e38f;
#pragma unroll
    for (int e = 0; e < NE; e++) if (e != i1 && nv[e] > v2) { v2 = nv[e]; i2 = e; }
    float e2 = expf(v2 - v1);
    float Z = 1.0f + e2;
#pragma unroll
    for (int e = 0; e < NE; e++)
        gate[n * NE + e] = (e == i1) ? (1.0f / Z) : ((e == i2) ? (e2 / Z) : 0.f);
    mask[n] = (unsigned char)((1u << i1) | (1u << i2));
}

__global__ void select_kernel(const unsigned char* __restrict__ mask, int* __restrict__ sel,
                              int* __restrict__ slot, int* __restrict__ cnt) {
    int e = blockIdx.x, lane = threadIdx.x;
    int base = 0;
    for (int n0 = 0; n0 < NN; n0 += 32) {
        int n = n0 + lane;
        bool f = (mask[n] >> e) & 1;
        unsigned bal = __ballot_sync(0xffffffffu, f);
        int pos = base + __popc(bal & ((1u << lane) - 1u));
        int sl = (f && pos < NCAP) ? pos : -1;
        slot[(size_t)e * NN + n] = sl;
        if (sl >= 0) sel[e * NCAP + sl] = n;
        base += __popc(bal);
    }
    if (!lane) cnt[e] = base < NCAP ? base : NCAP;
}

__global__ void gather_kernel(const __half* __restrict__ ln, const int* __restrict__ sel,
                              const int* __restrict__ cnt, __half* __restrict__ xt) {
    int s = blockIdx.x;
    int e = s / NCAP, i = s % NCAP;
    int* dst = (int*)(xt + (size_t)s * ND);
    if (i < cnt[e]) {
        const int* src = (const int*)(ln + (size_t)sel[s] * ND);
        for (int d = threadIdx.x; d < ND / 2; d += 256) dst[d] = src[d];
    } else {
        for (int d = threadIdx.x; d < ND / 2; d += 256) dst[d] = 0;
    }
}

__global__ void moe_scatter_kernel(const float* __restrict__ eo, const int* __restrict__ slot,
                                   const float* __restrict__ gate, float* __restrict__ x) {
    int n = blockIdx.x, tid = threadIdx.x;
    __shared__ int ss[NE];
    __shared__ float gg[NE];
    if (tid < NE) { ss[tid] = slot[(size_t)tid * NN + n]; gg[tid] = gate[n * NE + tid]; }
    __syncthreads();
    for (int d = tid; d < ND; d += 256) {
        float acc = 0.f;
#pragma unroll
        for (int e = 0; e < NE; e++) {
            int s = ss[e];
            if (s >= 0) acc += gg[e] * eo[((size_t)e * NCAP + s) * ND + d];
        }
        x[(size_t)n * ND + d] += acc;
    }
}

// ---------------- loss (fp16 logits) ----------------
__global__ void loss_kernel(const __half* __restrict__ logits, const int* __restrict__ ids,
                            float* __restrict__ nll, float* __restrict__ vld) {
    int n = blockIdx.x, tid = threadIdx.x;
    int b = n / NT, t = n % NT;
    if (t == NT - 1) { if (!tid) { nll[n] = 0.f; vld[n] = 0.f; } return; }
    int tgt = ids[b * NT + t + 1];
    const __half2* row2 = (const __half2*)(logits + (size_t)n * NV);
    float m = -3.4e38f, s = 0.f;
    for (int j = tid; j < NV / 2; j += 256) {
        float2 l = __half22float2(row2[j]);
        float mx = fmaxf(l.x, l.y);
        if (mx > m) { s = s * expf(m - mx); m = mx; }
        s += expf(l.x - m) + expf(l.y - m);
    }
    __shared__ float sm[256], ssum[256];
    sm[tid] = m; ssum[tid] = s; __syncthreads();
    for (int st = 128; st; st >>= 1) {
        if (tid < st) {
            float m1 = sm[tid], s1 = ssum[tid], m2 = sm[tid + st], s2 = ssum[tid + st];
            float M = fmaxf(m1, m2);
            ssum[tid] = s1 * expf(m1 - M) + s2 * expf(m2 - M);
            sm[tid] = M;
        }
        __syncthreads();
    }
    if (!tid) {
        float lse = sm[0] + logf(ssum[0]);
        float v = (tgt != 2) ? 1.f : 0.f;
        float lt = __half2float(logits[(size_t)n * NV + tgt]);
        nll[n] = -(lt - lse) * v;
        vld[n] = v;
    }
}

__global__ void reduce_kernel(const float* __restrict__ nll, const float* __restrict__ vld,
                              float* __restrict__ out) {
    __shared__ float s1[256], s2[256];
    int tid = threadIdx.x;
    float a = 0.f, b = 0.f;
    for (int i = tid; i < NN; i += 256) { a += nll[i]; b += vld[i]; }
    s1[tid] = a; s2[tid] = b; __syncthreads();
    for (int st = 128; st; st >>= 1) { if (tid < st) { s1[tid] += s1[tid + st]; s2[tid] += s2[tid + st]; } __syncthreads(); }
    if (!tid) out[0] = s1[0] / fmaxf(s2[0], 1.0f);
}

// ---------------- host launch ----------------
#define CA_SMEM(BM, BN) (3 * ((BM) + (BN)) * 72 * 2)
#define PV_SMEM_SZ ((2*128 + 2*64) * 72 * 2)

extern "C" void kernel_launch(void* const* d_in, const int* in_sizes, int n_in,
                              void* d_out, int out_size) {
    const int*   ids     = (const int*)d_in[0];
    const float* tok_emb = (const float*)d_in[1];
    const float* pos_emb = (const float*)d_in[2];
    const float* ln1_w   = (const float*)d_in[3];
    const float* ln1_b   = (const float*)d_in[4];
    const float* ln2_w   = (const float*)d_in[5];
    const float* ln2_b   = (const float*)d_in[6];
    const float* w_qkv   = (const float*)d_in[7];
    const float* w_out   = (const float*)d_in[8];
    const float* w_route = (const float*)d_in[9];
    const float* b_route = (const float*)d_in[10];
    const float* w_noise = (const float*)d_in[11];
    const float* b_noise = (const float*)d_in[12];
    const float* w_e1    = (const float*)d_in[13];
    const float* b_e1    = (const float*)d_in[14];
    const float* w_e2    = (const float*)d_in[15];
    const float* b_e2    = (const float*)d_in[16];
    const float* lnf_w   = (const float*)d_in[17];
    const float* lnf_b   = (const float*)d_in[18];
    float* out = (float*)d_out;

    float *x, *route, *noise, *eps, *gate, *eo, *nll, *vld;
    __half *ln16, *qkv16, *attn16, *p16, *xt16, *h116, *lg16;
    __half *wqkv16, *wout16, *we116, *we216, *tok16;
    unsigned char* mask; int *sel, *slot, *cnt;
    cudaGetSymbolAddress((void**)&x, g_x);
    cudaGetSymbolAddress((void**)&ln16, g_ln16);
    cudaGetSymbolAddress((void**)&qkv16, g_qkv16);
    cudaGetSymbolAddress((void**)&attn16, g_attn16);
    cudaGetSymbolAddress((void**)&p16, g_p16);
    cudaGetSymbolAddress((void**)&route, g_route);
    cudaGetSymbolAddress((void**)&noise, g_noise);
    cudaGetSymbolAddress((void**)&eps, g_eps);
    cudaGetSymbolAddress((void**)&gate, g_gate);
    cudaGetSymbolAddress((void**)&mask, g_mask);
    cudaGetSymbolAddress((void**)&sel, g_sel);
    cudaGetSymbolAddress((void**)&slot, g_slot);
    cudaGetSymbolAddress((void**)&cnt, g_cnt);
    cudaGetSymbolAddress((void**)&xt16, g_xt16);
    cudaGetSymbolAddress((void**)&h116, g_h116);
    cudaGetSymbolAddress((void**)&eo, g_eo);
    cudaGetSymbolAddress((void**)&lg16, g_log16);
    cudaGetSymbolAddress((void**)&nll, g_nll);
    cudaGetSymbolAddress((void**)&vld, g_vld);
    cudaGetSymbolAddress((void**)&wqkv16, g_wqkv16);
    cudaGetSymbolAddress((void**)&wout16, g_wout16);
    cudaGetSymbolAddress((void**)&we116, g_we116);
    cudaGetSymbolAddress((void**)&we216, g_we216);
    cudaGetSymbolAddress((void**)&tok16, g_tok16);

    constexpr int BIG = CA_SMEM(256, 128);   // 165888
    auto* kqkv = hgemm_ca<512,256,128,4,4,false,false,false,false,true >;
    auto* kqk  = hgemm_ca<512,256,128,4,4,false,false,false,true ,true >;
    auto* kproj= hgemm_ca<512,256,128,4,4,false,false,true ,false,false>;
    auto* kfc1 = hgemm_ca<512,256,128,4,4,true ,true ,false,false,true >;
    auto* kfc2 = hgemm_ca<512,256,128,4,4,true ,false,false,false,false>;
    auto* kvoc = hgemm_ca<512,256,128,4,4,false,false,false,false,true >;
    auto* kpv  = hgemm_pv<256,128, 64,4,2,true>;
    cudaFuncSetAttribute(kqkv, cudaFuncAttributeMaxDynamicSharedMemorySize, BIG);
    cudaFuncSetAttribute(kqk,  cudaFuncAttributeMaxDynamicSharedMemorySize, BIG);
    cudaFuncSetAttribute(kproj,cudaFuncAttributeMaxDynamicSharedMemorySize, BIG);
    cudaFuncSetAttribute(kfc1, cudaFuncAttributeMaxDynamicSharedMemorySize, BIG);
    cudaFuncSetAttribute(kfc2, cudaFuncAttributeMaxDynamicSharedMemorySize, BIG);
    cudaFuncSetAttribute(kvoc, cudaFuncAttributeMaxDynamicSharedMemorySize, BIG);
    cudaFuncSetAttribute(kpv,  cudaFuncAttributeMaxDynamicSharedMemorySize, PV_SMEM_SZ);

    tr_h_kernel<<<dim3(3*ND/32, ND/64, NLAY), dim3(32,8)>>>(w_qkv, wqkv16, ND, 3*ND);
    tr_h_kernel<<<dim3(ND/32, ND/64, NLAY), dim3(32,8)>>>(w_out, wout16, ND, ND);
    tr_h_kernel<<<dim3(NFF/32, ND/64, NLAY*NE), dim3(32,8)>>>(w_e1, we116, ND, NFF);
    tr_h_kernel<<<dim3(ND/32, NFF/64, NLAY*NE), dim3(32,8)>>>(w_e2, we216, NFF, ND);
    {
        size_t n = (size_t)NV * ND / 4;
        cvt_h_kernel<<<(unsigned)((n + 255) / 256), 256>>>(tok_emb, tok16, n);
    }

    embed_kernel<<<NN, 256>>>(ids, tok_emb, pos_emb, x);

    for (int l = 0; l < NLAY; l++) {
        // ---- attention ----
        ln_kernel<<<NN / 8, 256>>>(x, ln1_w + l * ND, ln1_b + l * ND, ln16);
        kqkv<<<dim3(24, 16, 1), 512, BIG>>>(
            ln16, wqkv16 + (size_t)l * ND * 3 * ND, nullptr, qkv16,
            ND, ND, ND, 3 * ND, 1, 0, 0, 0, 0, 0, 0, 0, 1.0f);
        rope_kernel<<<NN, 256>>>(qkv16);
        kqk<<<dim3(16, 8, NB * NH), 512, BIG>>>(
            qkv16, qkv16 + 1024, nullptr, p16,
            64, 3072, 3072, NT, NH,
            (size_t)NT * 3072, 64, (size_t)NT * 3072, 64,
            (size_t)NH * NT * NT, (size_t)NT * NT, 0, 0.125f);
        attn_softmax_kernel<<<dim3(NT, NB * NH), 128>>>(p16);
        kpv<<<dim3(1, 16, NB * NH), 256, PV_SMEM_SZ>>>(
            p16, qkv16 + 2048, attn16,
            NT, NT, 3072, ND, NH,
            (size_t)NH * NT * NT, (size_t)NT * NT, (size_t)NT * 3072, 64,
            (size_t)NT * ND, 64);
        kproj<<<dim3(8, 16, 1), 512, BIG>>>(
            attn16, wout16 + (size_t)l * ND * ND, nullptr, x,
            ND, ND, ND, ND, 1, 0, 0, 0, 0, 0, 0, 0, 1.0f);

        // ---- MoE ----
        ln_kernel<<<NN / 8, 256>>>(x, ln2_w + l * ND, ln2_b + l * ND, ln16);
        route_kernel<<<NN, 256>>>(ln16, w_route + (size_t)l * ND * NE, b_route + l * NE,
                                  w_noise + (size_t)l * ND * NE, b_noise + l * NE, route, noise);
        unsigned k0, k1;
        threefry(0u, 1234u, 0u, (unsigned)l, k0, k1);
        eps_kernel<<<(NN * NE + 255) / 256, 256>>>(k0, k1, eps);
        topk_kernel<<<(NN + 255) / 256, 256>>>(route, noise, eps, gate, mask);
        select_kernel<<<NE, 32>>>(mask, sel, slot, cnt);
        gather_kernel<<<NE * NCAP, 256>>>(ln16, sel, cnt, xt16);
        kfc1<<<dim3(32, 4, NE), 512, BIG>>>(
            xt16, we116 + (size_t)l * NE * ND * NFF, b_e1 + (size_t)l * NE * NFF, h116,
            ND, ND, ND, NFF, 1,
            (size_t)NCAP * ND, 0, (size_t)NFF * ND, 0,
            (size_t)NCAP * NFF, 0, NFF, 1.0f);
        kfc2<<<dim3(8, 4, NE), 512, BIG>>>(
            h116, we216 + (size_t)l * NE * NFF * ND, b_e2 + (size_t)l * NE * ND, eo,
            NFF, NFF, NFF, ND, 1,
            (size_t)NCAP * NFF, 0, (size_t)ND * NFF, 0,
            (size_t)NCAP * ND, 0, ND, 1.0f);
        moe_scatter_kernel<<<NN, 256>>>(eo, slot, gate, x);
    }

    ln_kernel<<<NN / 8, 256>>>(x, lnf_w, lnf_b, ln16);
    kvoc<<<dim3(NV / 128, 16, 1), 512, BIG>>>(
        ln16, tok16, nullptr, lg16,
        ND, ND, ND, NV, 1, 0, 0, 0, 0, 0, 0, 0, 1.0f);
    loss_kernel<<<NN, 256>>>(lg16, ids, nll, vld);
    reduce_kernel<<<1, 256>>>(nll, vld, out);
}

// round 11
// speedup vs baseline: 2.7258x; 1.0514x over previous
#include <cuda_runtime.h>
#include <cuda_fp16.h>
#include <cstdint>
#include <cstddef>

#define NB 2
#define NT 2048
#define ND 1024
#define NH 16
#define NLAY 2
#define NE 8
#define NV 32000
#define NN (NB*NT)
#define NCAP 1024
#define NFF 4096

// ---------------- device scratch ----------------
__device__ float  g_x   [(size_t)NN*ND];
__device__ __half g_ln16[(size_t)NN*ND];
__device__ __half g_qkv16[(size_t)NN*3*ND];
__device__ __half g_attn16[(size_t)NN*ND];
__device__ __half g_p16 [(size_t)NB*NH*NT*NT];
__device__ float  g_route[NN*NE];
__device__ float  g_noise[NN*NE];
__device__ float  g_eps  [NN*NE];
__device__ float  g_gate [NN*NE];
__device__ unsigned char g_mask[NN];
__device__ int    g_sel [NE*NCAP];
__device__ int    g_slot[NE*NN];
__device__ int    g_cnt [NE];
__device__ __half g_xt16[(size_t)NE*NCAP*ND];
__device__ __half g_h116[(size_t)NE*NCAP*NFF];
__device__ float  g_eo  [(size_t)NE*NCAP*ND];
__device__ __half g_log16[(size_t)NN*NV];
__device__ float  g_nll [NN];
__device__ float  g_vld [NN];
// fp16 weight copies (ORIGINAL [K,N] layout — no transpose)
__device__ __half g_wqkv16[(size_t)NLAY*ND*3*ND];
__device__ __half g_wout16[(size_t)NLAY*ND*ND];
__device__ __half g_we116 [(size_t)NLAY*NE*ND*NFF];
__device__ __half g_we216 [(size_t)NLAY*NE*NFF*ND];
__device__ __half g_tok16 [(size_t)NV*ND];        // [N,K] naturally

// ---------------- threefry2x32 (matches JAX) ----------------
__host__ __device__ __forceinline__ void threefry(unsigned k0, unsigned k1,
                                                  unsigned x0, unsigned x1,
                                                  unsigned& o0, unsigned& o1) {
    unsigned ks2 = k0 ^ k1 ^ 0x1BD11BDAu;
    x0 += k0; x1 += k1;
#define TFR(r) { x0 += x1; x1 = (x1 << (r)) | (x1 >> (32 - (r))); x1 ^= x0; }
    TFR(13) TFR(15) TFR(26) TFR(6)  x0 += k1;  x1 += ks2 + 1u;
    TFR(17) TFR(29) TFR(16) TFR(24) x0 += ks2; x1 += k0 + 2u;
    TFR(13) TFR(15) TFR(26) TFR(6)  x0 += k0;  x1 += k1 + 3u;
    TFR(17) TFR(29) TFR(16) TFR(24) x0 += k1;  x1 += ks2 + 4u;
    TFR(13) TFR(15) TFR(26) TFR(6)  x0 += ks2; x1 += k0 + 5u;
#undef TFR
    o0 = x0; o1 = x1;
}

__device__ __forceinline__ float xla_erfinv(float x) {
    float w = -log1pf(-x * x);
    float p;
    if (w < 5.f) {
        w -= 2.5f;
        p = 2.81022636e-08f;
        p = fmaf(p, w, 3.43273939e-07f);
        p = fmaf(p, w, -3.5233877e-06f);
        p = fmaf(p, w, -4.39150654e-06f);
        p = fmaf(p, w, 0.00021858087f);
        p = fmaf(p, w, -0.00125372503f);
        p = fmaf(p, w, -0.00417768164f);
        p = fmaf(p, w, 0.246640727f);
        p = fmaf(p, w, 1.50140941f);
    } else {
        w = sqrtf(w) - 3.f;
        p = -0.000200214257f;
        p = fmaf(p, w, 0.000100950558f);
        p = fmaf(p, w, 0.00134934322f);
        p = fmaf(p, w, -0.00367342844f);
        p = fmaf(p, w, 0.00573950773f);
        p = fmaf(p, w, -0.0076224613f);
        p = fmaf(p, w, 0.00943887047f);
        p = fmaf(p, w, 1.00167406f);
        p = fmaf(p, w, 2.83297682f);
    }
    return p * x;
}

__device__ __forceinline__ float bits_to_normal(unsigned bits) {
    float f = __uint_as_float((bits >> 9) | 0x3F800000u) - 1.0f;
    const float lo = -0.99999994f;
    float u = fmaf(f, 2.0f, lo);
    u = fmaxf(u, lo);
    return 1.41421356237f * xla_erfinv(u);
}

// ---------------- mma / ldmatrix / cp.async helpers ----------------
__device__ __forceinline__ void mma_f16(float* c, const unsigned* a, const unsigned* b) {
    asm volatile("mma.sync.aligned.m16n8k16.row.col.f32.f16.f16.f32 "
        "{%0,%1,%2,%3}, {%4,%5,%6,%7}, {%8,%9}, {%0,%1,%2,%3};"
        : "+f"(c[0]), "+f"(c[1]), "+f"(c[2]), "+f"(c[3])
        : "r"(a[0]), "r"(a[1]), "r"(a[2]), "r"(a[3]), "r"(b[0]), "r"(b[1]));
}
__device__ __forceinline__ void ldsm4(unsigned& d0, unsigned& d1, unsigned& d2, unsigned& d3,
                                      uint32_t addr) {
    asm volatile("ldmatrix.sync.aligned.m8n8.x4.shared.b16 {%0,%1,%2,%3}, [%4];"
        : "=r"(d0), "=r"(d1), "=r"(d2), "=r"(d3) : "r"(addr));
}
__device__ __forceinline__ void ldsm4t(unsigned& d0, unsigned& d1, unsigned& d2, unsigned& d3,
                                       uint32_t addr) {
    asm volatile("ldmatrix.sync.aligned.m8n8.x4.trans.shared.b16 {%0,%1,%2,%3}, [%4];"
        : "=r"(d0), "=r"(d1), "=r"(d2), "=r"(d3) : "r"(addr));
}
__device__ __forceinline__ uint32_t smem_u32(const void* p) {
    uint32_t a;
    asm("{ .reg .u64 t; cvta.to.shared.u64 t, %1; cvt.u32.u64 %0, t; }" : "=r"(a) : "l"(p));
    return a;
}
__device__ __forceinline__ void cpa16(uint32_t dst, const void* src) {
    asm volatile("cp.async.ca.shared.global [%0], [%1], 16;" :: "r"(dst), "l"(src));
}
#define CPA_COMMIT() asm volatile("cp.async.commit_group;" ::: "memory")
#define CPA_WAIT(n)  asm volatile("cp.async.wait_group %0;" :: "n"(n) : "memory")

// ---------------- weight prep: plain fp32 -> fp16 convert ----------------
__global__ void cvt_h_kernel(const float* __restrict__ in, __half* __restrict__ out, size_t n4) {
    size_t i = (size_t)blockIdx.x * 256 + threadIdx.x;
    if (i >= n4) return;
    float4 v = ((const float4*)in)[i];
    __half2* o = (__half2*)out;
    o[i * 2] = __floats2half2_rn(v.x, v.y);
    o[i * 2 + 1] = __floats2half2_rn(v.z, v.w);
}

// ---------------- cp.async 3-stage fp16 GEMM ----------------
// C[M,N] = A[M,K](half,row,lda) * B
//   BNK=true : B[N,K] row-major (ldb = K-stride), ldmatrix non-trans
//   BNK=false: B[K,N] row-major (ldb = N-stride), ldmatrix trans
// CAUSAL: skip tiles with n0 >= m0+BM. PVLIM: Keff=(by+1)*BM. OUTH: half out.
template<int TH, int BM, int BN, int WR, int WC, bool BNK, bool BIAS, bool RELU,
         bool ACCUM, bool CAUSAL, bool PVLIM, bool OUTH>
__global__ void __launch_bounds__(TH)
hgemm_ca(const __half* __restrict__ A, const __half* __restrict__ B,
         const float* __restrict__ bias, void* __restrict__ Cv,
         int K, int lda, int ldb, int ldc, int zdiv,
         size_t sA, size_t sA2, size_t sB, size_t sB2,
         size_t sC, size_t sC2, size_t sBias, float scale)
{
    constexpr int BK = 64;
    constexpr int LDS = 72;                       // A row pitch (halves)
    constexpr int BNP = BN + 8;                   // B row pitch for BNK=false
    constexpr int WM = BM / WR, WN = BN / WC;
    constexpr int MT = WM / 16, NT4 = WN / 8, NP = NT4 / 2;
    constexpr int ANV = (BM * 8) / TH;            // A 16B chunks per thread
    constexpr int BNV = BNK ? (BN * 8) / TH : (BK * BN) / (8 * TH);
    constexpr int STG = BNK ? (BM + BN) * LDS : BM * LDS + BK * BNP;  // halves/stage

    const int m0 = blockIdx.y * BM, n0 = blockIdx.x * BN;
    if (CAUSAL && n0 >= m0 + BM) return;

    const int tid = threadIdx.x, lane = tid & 31, warp = tid >> 5;
    const int wr = warp / WC, wc = warp % WC;
    const int g = lane >> 2, t = lane & 3;

    {
        int z = blockIdx.z, z1 = z / zdiv, z0 = z - z1 * zdiv;
        A += (size_t)z1 * sA + (size_t)z0 * sA2;
        B += (size_t)z1 * sB + (size_t)z0 * sB2;
        Cv = (char*)Cv + ((size_t)z1 * sC + (size_t)z0 * sC2) * (OUTH ? 2 : 4);
        if (BIAS) bias += (size_t)z1 * sBias;
    }

    int Keff = K;
    if (PVLIM) { int ke = ((int)blockIdx.y + 1) * BM; if (ke < Keff) Keff = ke; }
    const int nk = Keff / BK;

    extern __shared__ __half shh[];
    const uint32_t sbase = smem_u32(shh);

    const int a_r = lane & 15, a_c8 = (lane >> 4) * 8;
    // BNK=true fragment lane mapping (non-trans)
    const int b_r = (lane & 7) + (lane >> 4) * 8, b_c8 = ((lane >> 3) & 1) * 8;
    // BNK=false fragment lane mapping (trans): quads over (k-low/high) x (n-low/high)
    const int q8 = lane & 7, quad = lane >> 3;
    const int bt_k = (quad & 1) * 8 + q8, bt_n8 = (quad >> 1) * 8;
    const int mwb = wr * WM, nwb = wc * WN;

    const int ar = tid >> 3, aq = tid & 7;
    auto issue = [&](int ks, int st) {
        uint32_t so = sbase + (uint32_t)(st * STG) * 2;
        const __half* Ac = A + (size_t)m0 * lda + ks * BK;
#pragma unroll
        for (int i = 0; i < ANV; i++) {
            int row = ar + i * (TH >> 3);
            cpa16(so + (uint32_t)(row * LDS + aq * 8) * 2,
                  Ac + (size_t)row * lda + aq * 8);
        }
        if (BNK) {
            const __half* Bc = B + (size_t)n0 * ldb + ks * BK;
#pragma unroll
            for (int i = 0; i < BNV; i++) {
                int row = ar + i * (TH >> 3);
                cpa16(so + (uint32_t)((BM + row) * LDS + aq * 8) * 2,
                      Bc + (size_t)row * ldb + aq * 8);
            }
        } else {
            const __half* Bc = B + (size_t)(ks * BK) * ldb + n0;
#pragma unroll
            for (int i = 0; i < BNV; i++) {
                int idx = tid + i * TH;
                int kk = idx / (BN / 8), nq = idx % (BN / 8);
                cpa16(so + (uint32_t)(BM * LDS + kk * BNP + nq * 8) * 2,
                      Bc + (size_t)kk * ldb + nq * 8);
            }
        }
        CPA_COMMIT();
    };

    float acc[MT][NT4][4] = {};

    issue(0, 0);
    if (nk > 1) issue(1, 1);
    if (nk > 1) { CPA_WAIT(1); } else { CPA_WAIT(0); }
    __syncthreads();

    for (int ks = 0; ks < nk; ks++) {
        int cur = ks % 3;
        bool more2 = (ks + 2 < nk);
        if (more2) issue(ks + 2, (ks + 2) % 3);
        uint32_t abase = sbase + (uint32_t)(cur * STG) * 2;
        uint32_t bbase = abase + (uint32_t)(BM * LDS) * 2;
#pragma unroll
        for (int kq = 0; kq < 4; kq++) {
            unsigned af[MT][4], bf[NT4][2];
#pragma unroll
            for (int mt = 0; mt < MT; mt++) {
                uint32_t ad = abase +
                    (uint32_t)(((mwb + mt * 16 + a_r) * LDS + kq * 16 + a_c8) * 2);
                ldsm4(af[mt][0], af[mt][1], af[mt][2], af[mt][3], ad);
            }
            if (BNK) {
#pragma unroll
                for (int np = 0; np < NP; np++) {
                    uint32_t bd = bbase +
                        (uint32_t)(((nwb + np * 16 + b_r) * LDS + kq * 16 + b_c8) * 2);
                    ldsm4(bf[2*np][0], bf[2*np][1], bf[2*np+1][0], bf[2*np+1][1], bd);
                }
            } else {
#pragma unroll
                for (int np = 0; np < NP; np++) {
                    uint32_t bd = bbase +
                        (uint32_t)(((kq * 16 + bt_k) * BNP + nwb + np * 16 + bt_n8) * 2);
                    ldsm4t(bf[2*np][0], bf[2*np][1], bf[2*np+1][0], bf[2*np+1][1], bd);
                }
            }
#pragma unroll
            for (int mt = 0; mt < MT; mt++)
#pragma unroll
                for (int nt = 0; nt < NT4; nt++)
                    mma_f16(acc[mt][nt], af[mt], bf[nt]);
        }
        if (ks + 1 < nk) {
            if (more2) { CPA_WAIT(1); } else { CPA_WAIT(0); }
            __syncthreads();
        }
    }

    __half* Ch = (__half*)Cv;
    float*  Cf = (float*)Cv;
#pragma unroll
    for (int mt = 0; mt < MT; mt++) {
#pragma unroll
        for (int nt = 0; nt < NT4; nt++) {
            int r0 = m0 + mwb + mt * 16 + g;
            int c0 = n0 + nwb + nt * 8 + 2 * t;
            float v0 = acc[mt][nt][0] * scale, v1 = acc[mt][nt][1] * scale;
            float v2 = acc[mt][nt][2] * scale, v3 = acc[mt][nt][3] * scale;
            if (BIAS) {
                float b0 = bias[c0], b1 = bias[c0 + 1];
                v0 += b0; v1 += b1; v2 += b0; v3 += b1;
            }
            if (RELU) {
                v0 = fmaxf(v0, 0.f); v1 = fmaxf(v1, 0.f);
                v2 = fmaxf(v2, 0.f); v3 = fmaxf(v3, 0.f);
            }
            if (OUTH) {
                *(__half2*)(Ch + (size_t)r0 * ldc + c0) = __floats2half2_rn(v0, v1);
                *(__half2*)(Ch + (size_t)(r0 + 8) * ldc + c0) = __floats2half2_rn(v2, v3);
            } else {
                float* p0 = Cf + (size_t)r0 * ldc + c0;
                float* p1 = Cf + (size_t)(r0 + 8) * ldc + c0;
                if (ACCUM) {
                    float2 o0 = *(float2*)p0, o1 = *(float2*)p1;
                    v0 += o0.x; v1 += o0.y; v2 += o1.x; v3 += o1.y;
                }
                *(float2*)p0 = make_float2(v0, v1);
                *(float2*)p1 = make_float2(v2, v3);
            }
        }
    }
}

// ---------------- small kernels ----------------
__global__ void embed_kernel(const int* __restrict__ ids, const float* __restrict__ tok,
                             const float* __restrict__ pos, float* __restrict__ x) {
    int n = blockIdx.x, t = n % NT, id = ids[n];
    const float* te = tok + (size_t)id * ND;
    const float* pe = pos + (size_t)t * ND;
    float* dst = x + (size_t)n * ND;
    for (int d = threadIdx.x; d < ND; d += 256) dst[d] = te[d] + pe[d];
}

__global__ void ln_kernel(const float* __restrict__ x, const float* __restrict__ w,
                          const float* __restrict__ b, __half* __restrict__ out) {
    int row = blockIdx.x * 8 + (threadIdx.x >> 5);
    int lane = threadIdx.x & 31;
    const float4* p = (const float4*)(x + (size_t)row * ND);
    float4 v[8];
    float s = 0.f;
#pragma unroll
    for (int i = 0; i < 8; i++) {
        v[i] = p[lane + i * 32];
        s += v[i].x + v[i].y + v[i].z + v[i].w;
    }
#pragma unroll
    for (int o = 16; o; o >>= 1) s += __shfl_xor_sync(~0u, s, o);
    float mu = s * (1.0f / ND);
    float q = 0.f;
#pragma unroll
    for (int i = 0; i < 8; i++) {
        float a = v[i].x - mu, c = v[i].y - mu, d = v[i].z - mu, e = v[i].w - mu;
        q += a * a + c * c + d * d + e * e;
    }
#pragma unroll
    for (int o = 16; o; o >>= 1) q += __shfl_xor_sync(~0u, q, o);
    float rs = rsqrtf(q * (1.0f / ND) + 1e-5f);
    const float4* wp = (const float4*)w;
    const float4* bp = (const float4*)b;
    __half2* op = (__half2*)(out + (size_t)row * ND);
#pragma unroll
    for (int i = 0; i < 8; i++) {
        int j = lane + i * 32;
        float4 wv = wp[j], bv = bp[j];
        op[j * 2] = __floats2half2_rn((v[i].x - mu) * rs * wv.x + bv.x,
                                      (v[i].y - mu) * rs * wv.y + bv.y);
        op[j * 2 + 1] = __floats2half2_rn((v[i].z - mu) * rs * wv.z + bv.z,
                                          (v[i].w - mu) * rs * wv.w + bv.w);
    }
}

__global__ void rope_kernel(__half* __restrict__ qkv) {
    int n = blockIdx.x, t = n % NT;
    __half* base = qkv + (size_t)n * 3072;
#pragma unroll
    for (int item = threadIdx.x; item < 512; item += 256) {
        int h = item >> 5, i = item & 31;
        float ang = (float)t * expf((float)(2 * i) * (-0.14391156831212806f));
        float s = sinf(ang), c = cosf(ang);
        __half* q = base + h * 64;
        __half* k = q + 1024;
        float q1 = __half2float(q[i]), q2 = __half2float(q[i + 32]);
        q[i] = __float2half_rn(q1 * c - q2 * s);
        q[i + 32] = __float2half_rn(q2 * c + q1 * s);
        float k1 = __half2float(k[i]), k2 = __half2float(k[i + 32]);
        k[i] = __float2half_rn(k1 * c - k2 * s);
        k[i + 32] = __float2half_rn(k2 * c + k1 * s);
    }
}

__global__ void attn_softmax_kernel(__half* __restrict__ sc) {
    int r = blockIdx.x, tid = threadIdx.x;
    __half* row = sc + (size_t)blockIdx.y * NT * NT + (size_t)r * NT;
    int n = r + 1;
    __shared__ float red[128];
    float m = -3.4e38f;
    for (int j = tid; j < n; j += 128) m = fmaxf(m, __half2float(row[j]));
    red[tid] = m; __syncthreads();
    for (int s = 64; s; s >>= 1) { if (tid < s) red[tid] = fmaxf(red[tid], red[tid + s]); __syncthreads(); }
    m = red[0]; __syncthreads();
    float sum = 0.f;
    for (int j = tid; j < n; j += 128) sum += expf(__half2float(row[j]) - m);
    red[tid] = sum; __syncthreads();
    for (int s = 64; s; s >>= 1) { if (tid < s) red[tid] += red[tid + s]; __syncthreads(); }
    float inv = 1.0f / red[0];
    for (int j = tid; j < n; j += 128)
        row[j] = __float2half_rn(expf(__half2float(row[j]) - m) * inv);
    int rup = ((r >> 8) + 1) << 8;
    for (int j = n + tid; j < rup; j += 128) row[j] = __float2half_rn(0.f);
}

// ---------------- MoE ----------------
__global__ void route_kernel(const __half* __restrict__ ln, const float* __restrict__ wr,
                             const float* __restrict__ br, const float* __restrict__ wn,
                             const float* __restrict__ bn, float* __restrict__ route,
                             float* __restrict__ noise) {
    int n = blockIdx.x, tid = threadIdx.x;
    __shared__ float xs[ND];
    for (int d = tid; d < ND; d += 256) xs[d] = __half2float(ln[(size_t)n * ND + d]);
    __syncthreads();
    int w = tid >> 5, lane = tid & 31;
    float sr = 0.f, sn = 0.f;
    for (int d = lane; d < ND; d += 32) {
        float xv = xs[d];
        sr += xv * wr[(size_t)d * NE + w];
        sn += xv * wn[(size_t)d * NE + w];
    }
    for (int o = 16; o; o >>= 1) { sr += __shfl_down_sync(~0u, sr, o); sn += __shfl_down_sync(~0u, sn, o); }
    if (!lane) { route[n * NE + w] = sr + br[w]; noise[n * NE + w] = sn + bn[w]; }
}

__global__ void eps_kernel(unsigned k0, unsigned k1, float* __restrict__ eps) {
    int i = blockIdx.x * 256 + threadIdx.x;
    if (i >= NN * NE) return;
    unsigned o0, o1;
    threefry(k0, k1, 0u, (unsigned)i, o0, o1);
    eps[i] = bits_to_normal(o0 ^ o1);
}

__global__ void topk_kernel(const float* __restrict__ route, const float* __restrict__ noise,
                            const float* __restrict__ eps, float* __restrict__ gate,
                            unsigned char* __restrict__ mask) {
    int n = blockIdx.x * 256 + threadIdx.x;
    if (n >= NN) return;
    float nv[NE];
#pragma unroll
    for (int e = 0; e < NE; e++) {
        float x = noise[n * NE + e];
        float sp = fmaxf(x, 0.f) + log1pf(expf(-fabsf(x)));
        nv[e] = route[n * NE + e] + eps[n * NE + e] * sp;
    }
    int i1 = 0; float v1 = nv[0];
#pragma unroll
    for (int e = 1; e < NE; e++) if (nv[e] > v1) { v1 = nv[e]; i1 = e; }
    int i2 = -1; float v2 = -3.4e38f;
#pragma unroll
    for (int e = 0; e < NE; e++) if (e != i1 && nv[e] > v2) { v2 = nv[e]; i2 = e; }
    float e2 = expf(v2 - v1);
    float Z = 1.0f + e2;
#pragma unroll
    for (int e = 0; e < NE; e++)
        gate[n * NE + e] = (e == i1) ? (1.0f / Z) : ((e == i2) ? (e2 / Z) : 0.f);
    mask[n] = (unsigned char)((1u << i1) | (1u << i2));
}

__global__ void select_kernel(const unsigned char* __restrict__ mask, int* __restrict__ sel,
                              int* __restrict__ slot, int* __restrict__ cnt) {
    int e = blockIdx.x, lane = threadIdx.x;
    int base = 0;
    for (int n0 = 0; n0 < NN; n0 += 32) {
        int n = n0 + lane;
        bool f = (mask[n] >> e) & 1;
        unsigned bal = __ballot_sync(0xffffffffu, f);
        int pos = base + __popc(bal & ((1u << lane) - 1u));
        int sl = (f && pos < NCAP) ? pos : -1;
        slot[(size_t)e * NN + n] = sl;
        if (sl >= 0) sel[e * NCAP + sl] = n;
        base += __popc(bal);
    }
    if (!lane) cnt[e] = base < NCAP ? base : NCAP;
}

__global__ void gather_kernel(const __half* __restrict__ ln, const int* __restrict__ sel,
                              const int* __restrict__ cnt, __half* __restrict__ xt) {
    int s = blockIdx.x;
    int e = s / NCAP, i = s % NCAP;
    int* dst = (int*)(xt + (size_t)s * ND);
    if (i < cnt[e]) {
        const int* src = (const int*)(ln + (size_t)sel[s] * ND);
        for (int d = threadIdx.x; d < ND / 2; d += 256) dst[d] = src[d];
    } else {
        for (int d = threadIdx.x; d < ND / 2; d += 256) dst[d] = 0;
    }
}

__global__ void moe_scatter_kernel(const float* __restrict__ eo, const int* __restrict__ slot,
                                   const float* __restrict__ gate, float* __restrict__ x) {
    int n = blockIdx.x, tid = threadIdx.x;
    __shared__ int ss[NE];
    __shared__ float gg[NE];
    if (tid < NE) { ss[tid] = slot[(size_t)tid * NN + n]; gg[tid] = gate[n * NE + tid]; }
    __syncthreads();
    for (int d = tid; d < ND; d += 256) {
        float acc = 0.f;
#pragma unroll
        for (int e = 0; e < NE; e++) {
            int s = ss[e];
            if (s >= 0) acc += gg[e] * eo[((size_t)e * NCAP + s) * ND + d];
        }
        x[(size_t)n * ND + d] += acc;
    }
}

// ---------------- loss (fp16 logits) ----------------
__global__ void loss_kernel(const __half* __restrict__ logits, const int* __restrict__ ids,
                            float* __restrict__ nll, float* __restrict__ vld) {
    int n = blockIdx.x, tid = threadIdx.x;
    int b = n / NT, t = n % NT;
    if (t == NT - 1) { if (!tid) { nll[n] = 0.f; vld[n] = 0.f; } return; }
    int tgt = ids[b * NT + t + 1];
    const __half2* row2 = (const __half2*)(logits + (size_t)n * NV);
    float m = -3.4e38f, s = 0.f;
    for (int j = tid; j < NV / 2; j += 256) {
        float2 l = __half22float2(row2[j]);
        float mx = fmaxf(l.x, l.y);
        if (mx > m) { s = s * expf(m - mx); m = mx; }
        s += expf(l.x - m) + expf(l.y - m);
    }
    __shared__ float sm[256], ssum[256];
    sm[tid] = m; ssum[tid] = s; __syncthreads();
    for (int st = 128; st; st >>= 1) {
        if (tid < st) {
            float m1 = sm[tid], s1 = ssum[tid], m2 = sm[tid + st], s2 = ssum[tid + st];
            float M = fmaxf(m1, m2);
            ssum[tid] = s1 * expf(m1 - M) + s2 * expf(m2 - M);
            sm[tid] = M;
        }
        __syncthreads();
    }
    if (!tid) {
        float lse = sm[0] + logf(ssum[0]);
        float v = (tgt != 2) ? 1.f : 0.f;
        float lt = __half2float(logits[(size_t)n * NV + tgt]);
        nll[n] = -(lt - lse) * v;
        vld[n] = v;
    }
}

__global__ void reduce_kernel(const float* __restrict__ nll, const float* __restrict__ vld,
                              float* __restrict__ out) {
    __shared__ float s1[256], s2[256];
    int tid = threadIdx.x;
    float a = 0.f, b = 0.f;
    for (int i = tid; i < NN; i += 256) { a += nll[i]; b += vld[i]; }
    s1[tid] = a; s2[tid] = b; __syncthreads();
    for (int st = 128; st; st >>= 1) { if (tid < st) { s1[tid] += s1[tid + st]; s2[tid] += s2[tid + st]; } __syncthreads(); }
    if (!tid) out[0] = s1[0] / fmaxf(s2[0], 1.0f);
}

// ---------------- host launch ----------------
// stage sizes (halves): BNK=true: (BM+BN)*72 ; BNK=false: BM*72 + 64*(BN+8)
#define STG_T(BM, BN) (((BM) + (BN)) * 72)
#define STG_F(BM, BN) ((BM) * 72 + 64 * ((BN) + 8))

extern "C" void kernel_launch(void* const* d_in, const int* in_sizes, int n_in,
                              void* d_out, int out_size) {
    const int*   ids     = (const int*)d_in[0];
    const float* tok_emb = (const float*)d_in[1];
    const float* pos_emb = (const float*)d_in[2];
    const float* ln1_w   = (const float*)d_in[3];
    const float* ln1_b   = (const float*)d_in[4];
    const float* ln2_w   = (const float*)d_in[5];
    const float* ln2_b   = (const float*)d_in[6];
    const float* w_qkv   = (const float*)d_in[7];
    const float* w_out   = (const float*)d_in[8];
    const float* w_route = (const float*)d_in[9];
    const float* b_route = (const float*)d_in[10];
    const float* w_noise = (const float*)d_in[11];
    const float* b_noise = (const float*)d_in[12];
    const float* w_e1    = (const float*)d_in[13];
    const float* b_e1    = (const float*)d_in[14];
    const float* w_e2    = (const float*)d_in[15];
    const float* b_e2    = (const float*)d_in[16];
    const float* lnf_w   = (const float*)d_in[17];
    const float* lnf_b   = (const float*)d_in[18];
    float* out = (float*)d_out;

    float *x, *route, *noise, *eps, *gate, *eo, *nll, *vld;
    __half *ln16, *qkv16, *attn16, *p16, *xt16, *h116, *lg16;
    __half *wqkv16, *wout16, *we116, *we216, *tok16;
    unsigned char* mask; int *sel, *slot, *cnt;
    cudaGetSymbolAddress((void**)&x, g_x);
    cudaGetSymbolAddress((void**)&ln16, g_ln16);
    cudaGetSymbolAddress((void**)&qkv16, g_qkv16);
    cudaGetSymbolAddress((void**)&attn16, g_attn16);
    cudaGetSymbolAddress((void**)&p16, g_p16);
    cudaGetSymbolAddress((void**)&route, g_route);
    cudaGetSymbolAddress((void**)&noise, g_noise);
    cudaGetSymbolAddress((void**)&eps, g_eps);
    cudaGetSymbolAddress((void**)&gate, g_gate);
    cudaGetSymbolAddress((void**)&mask, g_mask);
    cudaGetSymbolAddress((void**)&sel, g_sel);
    cudaGetSymbolAddress((void**)&slot, g_slot);
    cudaGetSymbolAddress((void**)&cnt, g_cnt);
    cudaGetSymbolAddress((void**)&xt16, g_xt16);
    cudaGetSymbolAddress((void**)&h116, g_h116);
    cudaGetSymbolAddress((void**)&eo, g_eo);
    cudaGetSymbolAddress((void**)&lg16, g_log16);
    cudaGetSymbolAddress((void**)&nll, g_nll);
    cudaGetSymbolAddress((void**)&vld, g_vld);
    cudaGetSymbolAddress((void**)&wqkv16, g_wqkv16);
    cudaGetSymbolAddress((void**)&wout16, g_wout16);
    cudaGetSymbolAddress((void**)&we116, g_we116);
    cudaGetSymbolAddress((void**)&we216, g_we216);
    cudaGetSymbolAddress((void**)&tok16, g_tok16);

    constexpr int SM_T = 3 * STG_T(256, 128) * 2;   // 165888 (BNK=true)
    constexpr int SM_F = 3 * STG_F(256, 128) * 2;   // 162816 (BNK=false)
    constexpr int SM_PV = 3 * STG_F(128, 64) * 2;   // 2x(128*72+64*72)... computed below
    auto* kqkv = hgemm_ca<512,256,128,4,4,false,false,false,false,false,false,true >;
    auto* kqk  = hgemm_ca<512,256,128,4,4,true ,false,false,false,true ,false,true >;
    auto* kpv  = hgemm_ca<256,128, 64,4,2,false,false,false,false,false,true ,true >;
    auto* kproj= hgemm_ca<512,256,128,4,4,false,false,false,true ,false,false,false>;
    auto* kfc1 = hgemm_ca<512,256,128,4,4,false,true ,true ,false,false,false,true >;
    auto* kfc2 = hgemm_ca<512,256,128,4,4,false,true ,false,false,false,false,false>;
    auto* kvoc = hgemm_ca<512,256,128,4,4,true ,false,false,false,false,false,true >;
    cudaFuncSetAttribute(kqkv, cudaFuncAttributeMaxDynamicSharedMemorySize, SM_F);
    cudaFuncSetAttribute(kqk,  cudaFuncAttributeMaxDynamicSharedMemorySize, SM_T);
    cudaFuncSetAttribute(kpv,  cudaFuncAttributeMaxDynamicSharedMemorySize, SM_PV);
    cudaFuncSetAttribute(kproj,cudaFuncAttributeMaxDynamicSharedMemorySize, SM_F);
    cudaFuncSetAttribute(kfc1, cudaFuncAttributeMaxDynamicSharedMemorySize, SM_F);
    cudaFuncSetAttribute(kfc2, cudaFuncAttributeMaxDynamicSharedMemorySize, SM_F);
    cudaFuncSetAttribute(kvoc, cudaFuncAttributeMaxDynamicSharedMemorySize, SM_T);

    // weight prep: plain convert (keeps [K,N] layout); tok_emb already [N,K]
    {
        size_t n;
        n = (size_t)NLAY * ND * 3 * ND / 4;
        cvt_h_kernel<<<(unsigned)((n + 255) / 256), 256>>>(w_qkv, wqkv16, n);
        n = (size_t)NLAY * ND * ND / 4;
        cvt_h_kernel<<<(unsigned)((n + 255) / 256), 256>>>(w_out, wout16, n);
        n = (size_t)NLAY * NE * ND * NFF / 4;
        cvt_h_kernel<<<(unsigned)((n + 255) / 256), 256>>>(w_e1, we116, n);
        n = (size_t)NLAY * NE * NFF * ND / 4;
        cvt_h_kernel<<<(unsigned)((n + 255) / 256), 256>>>(w_e2, we216, n);
        n = (size_t)NV * ND / 4;
        cvt_h_kernel<<<(unsigned)((n + 255) / 256), 256>>>(tok_emb, tok16, n);
    }

    embed_kernel<<<NN, 256>>>(ids, tok_emb, pos_emb, x);

    for (int l = 0; l < NLAY; l++) {
        // ---- attention ----
        ln_kernel<<<NN / 8, 256>>>(x, ln1_w + l * ND, ln1_b + l * ND, ln16);
        // qkv = ln @ w_qkv  (B=[K,N]=[1024,3072], ldb=3072)
        kqkv<<<dim3(24, 16, 1), 512, SM_F>>>(
            ln16, wqkv16 + (size_t)l * ND * 3 * ND, nullptr, qkv16,
            ND, ND, 3 * ND, 3 * ND, 1, 0, 0, 0, 0, 0, 0, 0, 1.0f);
        rope_kernel<<<NN, 256>>>(qkv16);
        // scores (B = K-cache [n,k], BNK=true)
        kqk<<<dim3(16, 8, NB * NH), 512, SM_T>>>(
            qkv16, qkv16 + 1024, nullptr, p16,
            64, 3072, 3072, NT, NH,
            (size_t)NT * 3072, 64, (size_t)NT * 3072, 64,
            (size_t)NH * NT * NT, (size_t)NT * NT, 0, 0.125f);
        attn_softmax_kernel<<<dim3(NT, NB * NH), 128>>>(p16);
        // PV (B = V [k,n] rows=token, BNK=false, PVLIM)
        kpv<<<dim3(1, 16, NB * NH), 256, SM_PV>>>(
            p16, qkv16 + 2048, nullptr, attn16,
            NT, NT, 3072, ND, NH,
            (size_t)NH * NT * NT, (size_t)NT * NT, (size_t)NT * 3072, 64,
            (size_t)NT * ND, 64, 0, 1.0f);
        // x += attn @ w_out  (B=[K,N], ldb=1024)
        kproj<<<dim3(8, 16, 1), 512, SM_F>>>(
            attn16, wout16 + (size_t)l * ND * ND, nullptr, x,
            ND, ND, ND, ND, 1, 0, 0, 0, 0, 0, 0, 0, 1.0f);

        // ---- MoE ----
        ln_kernel<<<NN / 8, 256>>>(x, ln2_w + l * ND, ln2_b + l * ND, ln16);
        route_kernel<<<NN, 256>>>(ln16, w_route + (size_t)l * ND * NE, b_route + l * NE,
                                  w_noise + (size_t)l * ND * NE, b_noise + l * NE, route, noise);
        unsigned k0, k1;
        threefry(0u, 1234u, 0u, (unsigned)l, k0, k1);
        eps_kernel<<<(NN * NE + 255) / 256, 256>>>(k0, k1, eps);
        topk_kernel<<<(NN + 255) / 256, 256>>>(route, noise, eps, gate, mask);
        select_kernel<<<NE, 32>>>(mask, sel, slot, cnt);
        gather_kernel<<<NE * NCAP, 256>>>(ln16, sel, cnt, xt16);
        // h1 = relu(xt @ w_e1 + b)  (B=[1024,4096], ldb=4096)
        kfc1<<<dim3(32, 4, NE), 512, SM_F>>>(
            xt16, we116 + (size_t)l * NE * ND * NFF, b_e1 + (size_t)l * NE * NFF, h116,
            ND, ND, NFF, NFF, 1,
            (size_t)NCAP * ND, 0, (size_t)NFF * ND, 0,
            (size_t)NCAP * NFF, 0, NFF, 1.0f);
        // eo = h1 @ w_e2 + b  (B=[4096,1024], ldb=1024)
        kfc2<<<dim3(8, 4, NE), 512, SM_F>>>(
            h116, we216 + (size_t)l * NE * NFF * ND, b_e2 + (size_t)l * NE * ND, eo,
            NFF, NFF, ND, ND, 1,
            (size_t)NCAP * NFF, 0, (size_t)ND * NFF, 0,
            (size_t)NCAP * ND, 0, ND, 1.0f);
        moe_scatter_kernel<<<NN, 256>>>(eo, slot, gate, x);
    }

    ln_kernel<<<NN / 8, 256>>>(x, lnf_w, lnf_b, ln16);
    // vocab: B = tok16 [N,K] (BNK=true), fp16 logits
    kvoc<<<dim3(NV / 128, 16, 1), 512, SM_T>>>(
        ln16, tok16, nullptr, lg16,
        ND, ND, ND, NV, 1, 0, 0, 0, 0, 0, 0, 0, 1.0f);
    loss_kernel<<<NN, 256>>>(lg16, ids, nll, vld);
    reduce_kernel<<<1, 256>>>(nll, vld, out);
}

// round 12
// speedup vs baseline: 2.8064x; 1.0296x over previous
#include <cuda_runtime.h>
#include <cuda_fp16.h>
#include <cstdint>
#include <cstddef>

#define NB 2
#define NT 2048
#define ND 1024
#define NH 16
#define NLAY 2
#define NE 8
#define NV 32000
#define NN (NB*NT)
#define NCAP 1024
#define NFF 4096

// ---------------- device scratch ----------------
__device__ float  g_x   [(size_t)NN*ND];
__device__ __half g_ln16[(size_t)NN*ND];
__device__ __half g_qkv16[(size_t)NN*3*ND];
__device__ __half g_attn16[(size_t)NN*ND];
__device__ __half g_p16 [(size_t)NB*NH*NT*NT];
__device__ float  g_route[NN*NE];
__device__ float  g_noise[NN*NE];
__device__ float  g_eps  [NN*NE];
__device__ float  g_gate [NN*NE];
__device__ unsigned char g_mask[NN];
__device__ int    g_sel [NE*NCAP];
__device__ int    g_slot[NE*NN];
__device__ int    g_cnt [NE];
__device__ __half g_h116[(size_t)NE*NCAP*NFF];
__device__ __half g_eo16[(size_t)NE*NCAP*ND];
__device__ __half g_log16[(size_t)NN*NV];
__device__ float  g_nll [NN];
__device__ float  g_vld [NN];
// fp16 weight copies (ORIGINAL [K,N] layout — no transpose)
__device__ __half g_wqkv16[(size_t)NLAY*ND*3*ND];
__device__ __half g_wout16[(size_t)NLAY*ND*ND];
__device__ __half g_we116 [(size_t)NLAY*NE*ND*NFF];
__device__ __half g_we216 [(size_t)NLAY*NE*NFF*ND];
__device__ __half g_tok16 [(size_t)NV*ND];        // [N,K] naturally

// ---------------- threefry2x32 (matches JAX) ----------------
__host__ __device__ __forceinline__ void threefry(unsigned k0, unsigned k1,
                                                  unsigned x0, unsigned x1,
                                                  unsigned& o0, unsigned& o1) {
    unsigned ks2 = k0 ^ k1 ^ 0x1BD11BDAu;
    x0 += k0; x1 += k1;
#define TFR(r) { x0 += x1; x1 = (x1 << (r)) | (x1 >> (32 - (r))); x1 ^= x0; }
    TFR(13) TFR(15) TFR(26) TFR(6)  x0 += k1;  x1 += ks2 + 1u;
    TFR(17) TFR(29) TFR(16) TFR(24) x0 += ks2; x1 += k0 + 2u;
    TFR(13) TFR(15) TFR(26) TFR(6)  x0 += k0;  x1 += k1 + 3u;
    TFR(17) TFR(29) TFR(16) TFR(24) x0 += k1;  x1 += ks2 + 4u;
    TFR(13) TFR(15) TFR(26) TFR(6)  x0 += ks2; x1 += k0 + 5u;
#undef TFR
    o0 = x0; o1 = x1;
}

__device__ __forceinline__ float xla_erfinv(float x) {
    float w = -log1pf(-x * x);
    float p;
    if (w < 5.f) {
        w -= 2.5f;
        p = 2.81022636e-08f;
        p = fmaf(p, w, 3.43273939e-07f);
        p = fmaf(p, w, -3.5233877e-06f);
        p = fmaf(p, w, -4.39150654e-06f);
        p = fmaf(p, w, 0.00021858087f);
        p = fmaf(p, w, -0.00125372503f);
        p = fmaf(p, w, -0.00417768164f);
        p = fmaf(p, w, 0.246640727f);
        p = fmaf(p, w, 1.50140941f);
    } else {
        w = sqrtf(w) - 3.f;
        p = -0.000200214257f;
        p = fmaf(p, w, 0.000100950558f);
        p = fmaf(p, w, 0.00134934322f);
        p = fmaf(p, w, -0.00367342844f);
        p = fmaf(p, w, 0.00573950773f);
        p = fmaf(p, w, -0.0076224613f);
        p = fmaf(p, w, 0.00943887047f);
        p = fmaf(p, w, 1.00167406f);
        p = fmaf(p, w, 2.83297682f);
    }
    return p * x;
}

__device__ __forceinline__ float bits_to_normal(unsigned bits) {
    float f = __uint_as_float((bits >> 9) | 0x3F800000u) - 1.0f;
    const float lo = -0.99999994f;
    float u = fmaf(f, 2.0f, lo);
    u = fmaxf(u, lo);
    return 1.41421356237f * xla_erfinv(u);
}

// ---------------- mma / ldmatrix / cp.async helpers ----------------
__device__ __forceinline__ void mma_f16(float* c, const unsigned* a, const unsigned* b) {
    asm volatile("mma.sync.aligned.m16n8k16.row.col.f32.f16.f16.f32 "
        "{%0,%1,%2,%3}, {%4,%5,%6,%7}, {%8,%9}, {%0,%1,%2,%3};"
        : "+f"(c[0]), "+f"(c[1]), "+f"(c[2]), "+f"(c[3])
        : "r"(a[0]), "r"(a[1]), "r"(a[2]), "r"(a[3]), "r"(b[0]), "r"(b[1]));
}
__device__ __forceinline__ void ldsm4(unsigned& d0, unsigned& d1, unsigned& d2, unsigned& d3,
                                      uint32_t addr) {
    asm volatile("ldmatrix.sync.aligned.m8n8.x4.shared.b16 {%0,%1,%2,%3}, [%4];"
        : "=r"(d0), "=r"(d1), "=r"(d2), "=r"(d3) : "r"(addr));
}
__device__ __forceinline__ void ldsm4t(unsigned& d0, unsigned& d1, unsigned& d2, unsigned& d3,
                                       uint32_t addr) {
    asm volatile("ldmatrix.sync.aligned.m8n8.x4.trans.shared.b16 {%0,%1,%2,%3}, [%4];"
        : "=r"(d0), "=r"(d1), "=r"(d2), "=r"(d3) : "r"(addr));
}
__device__ __forceinline__ uint32_t smem_u32(const void* p) {
    uint32_t a;
    asm("{ .reg .u64 t; cvta.to.shared.u64 t, %1; cvt.u32.u64 %0, t; }" : "=r"(a) : "l"(p));
    return a;
}
__device__ __forceinline__ void cpa16(uint32_t dst, const void* src) {
    asm volatile("cp.async.ca.shared.global [%0], [%1], 16;" :: "r"(dst), "l"(src));
}
#define CPA_COMMIT() asm volatile("cp.async.commit_group;" ::: "memory")
#define CPA_WAIT(n)  asm volatile("cp.async.wait_group %0;" :: "n"(n) : "memory")

// ---------------- weight prep ----------------
__global__ void cvt_h_kernel(const float* __restrict__ in, __half* __restrict__ out, size_t n4) {
    size_t i = (size_t)blockIdx.x * 256 + threadIdx.x;
    if (i >= n4) return;
    float4 v = ((const float4*)in)[i];
    __half2* o = (__half2*)out;
    o[i * 2] = __floats2half2_rn(v.x, v.y);
    o[i * 2 + 1] = __floats2half2_rn(v.z, v.w);
}

// ---------------- cp.async 3-stage fp16 GEMM ----------------
// C[M,N] = A[M,K](half,row,lda) * B
//   BNK=true : B[N,K] row-major, ldmatrix non-trans
//   BNK=false: B[K,N] row-major, ldmatrix trans
// GATHER: A rows indexed by gsel[blockIdx.z*NCAP + m] (grid.z = expert).
template<int TH, int BM, int BN, int WR, int WC, bool BNK, bool BIAS, bool RELU,
         bool ACCUM, bool CAUSAL, bool PVLIM, bool OUTH, bool GATHER>
__global__ void __launch_bounds__(TH)
hgemm_ca(const __half* __restrict__ A, const __half* __restrict__ B,
         const float* __restrict__ bias, void* __restrict__ Cv,
         const int* __restrict__ gsel,
         int K, int lda, int ldb, int ldc, int zdiv,
         size_t sA, size_t sA2, size_t sB, size_t sB2,
         size_t sC, size_t sC2, size_t sBias, float scale)
{
    constexpr int BK = 64;
    constexpr int LDS = 72;
    constexpr int BNP = BN + 8;
    constexpr int WM = BM / WR, WN = BN / WC;
    constexpr int MT = WM / 16, NT4 = WN / 8, NP = NT4 / 2;
    constexpr int ANV = (BM * 8) / TH;
    constexpr int BNV = BNK ? (BN * 8) / TH : (BK * BN) / (8 * TH);
    constexpr int STG = BNK ? (BM + BN) * LDS : BM * LDS + BK * BNP;

    const int m0 = blockIdx.y * BM, n0 = blockIdx.x * BN;
    if (CAUSAL && n0 >= m0 + BM) return;

    const int tid = threadIdx.x, lane = tid & 31, warp = tid >> 5;
    const int wr = warp / WC, wc = warp % WC;
    const int g = lane >> 2, t = lane & 3;

    {
        int z = blockIdx.z, z1 = z / zdiv, z0 = z - z1 * zdiv;
        A += (size_t)z1 * sA + (size_t)z0 * sA2;
        B += (size_t)z1 * sB + (size_t)z0 * sB2;
        Cv = (char*)Cv + ((size_t)z1 * sC + (size_t)z0 * sC2) * (OUTH ? 2 : 4);
        if (BIAS) bias += (size_t)z1 * sBias;
    }

    int Keff = K;
    if (PVLIM) { int ke = ((int)blockIdx.y + 1) * BM; if (ke < Keff) Keff = ke; }
    const int nk = Keff / BK;

    extern __shared__ __half shh[];
    const uint32_t sbase = smem_u32(shh);

    const int a_r = lane & 15, a_c8 = (lane >> 4) * 8;
    const int b_r = (lane & 7) + (lane >> 4) * 8, b_c8 = ((lane >> 3) & 1) * 8;
    const int q8 = lane & 7, quad = lane >> 3;
    const int bt_k = (quad & 1) * 8 + q8, bt_n8 = (quad >> 1) * 8;
    const int mwb = wr * WM, nwb = wc * WN;

    const int ar = tid >> 3, aq = tid & 7;
    int arows[ANV];
#pragma unroll
    for (int i = 0; i < ANV; i++) {
        int r = m0 + ar + i * (TH >> 3);
        arows[i] = GATHER ? gsel[(size_t)blockIdx.z * NCAP + r] : r;
    }

    auto issue = [&](int ks, int st) {
        uint32_t so = sbase + (uint32_t)(st * STG) * 2;
#pragma unroll
        for (int i = 0; i < ANV; i++) {
            int row = ar + i * (TH >> 3);
            cpa16(so + (uint32_t)(row * LDS + aq * 8) * 2,
                  A + (size_t)arows[i] * lda + ks * BK + aq * 8);
        }
        if (BNK) {
            const __half* Bc = B + (size_t)n0 * ldb + ks * BK;
#pragma unroll
            for (int i = 0; i < BNV; i++) {
                int row = ar + i * (TH >> 3);
                cpa16(so + (uint32_t)((BM + row) * LDS + aq * 8) * 2,
                      Bc + (size_t)row * ldb + aq * 8);
            }
        } else {
            const __half* Bc = B + (size_t)(ks * BK) * ldb + n0;
#pragma unroll
            for (int i = 0; i < BNV; i++) {
                int idx = tid + i * TH;
                int kk = idx / (BN / 8), nq = idx % (BN / 8);
                cpa16(so + (uint32_t)(BM * LDS + kk * BNP + nq * 8) * 2,
                      Bc + (size_t)kk * ldb + nq * 8);
            }
        }
        CPA_COMMIT();
    };

    float acc[MT][NT4][4] = {};

    issue(0, 0);
    if (nk > 1) issue(1, 1);
    if (nk > 1) { CPA_WAIT(1); } else { CPA_WAIT(0); }
    __syncthreads();

    for (int ks = 0; ks < nk; ks++) {
        int cur = ks % 3;
        bool more2 = (ks + 2 < nk);
        if (more2) issue(ks + 2, (ks + 2) % 3);
        uint32_t abase = sbase + (uint32_t)(cur * STG) * 2;
        uint32_t bbase = abase + (uint32_t)(BM * LDS) * 2;
#pragma unroll
        for (int kq = 0; kq < 4; kq++) {
            unsigned af[MT][4], bf[NT4][2];
#pragma unroll
            for (int mt = 0; mt < MT; mt++) {
                uint32_t ad = abase +
                    (uint32_t)(((mwb + mt * 16 + a_r) * LDS + kq * 16 + a_c8) * 2);
                ldsm4(af[mt][0], af[mt][1], af[mt][2], af[mt][3], ad);
            }
            if (BNK) {
#pragma unroll
                for (int np = 0; np < NP; np++) {
                    uint32_t bd = bbase +
                        (uint32_t)(((nwb + np * 16 + b_r) * LDS + kq * 16 + b_c8) * 2);
                    ldsm4(bf[2*np][0], bf[2*np][1], bf[2*np+1][0], bf[2*np+1][1], bd);
                }
            } else {
#pragma unroll
                for (int np = 0; np < NP; np++) {
                    uint32_t bd = bbase +
                        (uint32_t)(((kq * 16 + bt_k) * BNP + nwb + np * 16 + bt_n8) * 2);
                    ldsm4t(bf[2*np][0], bf[2*np][1], bf[2*np+1][0], bf[2*np+1][1], bd);
                }
            }
#pragma unroll
            for (int mt = 0; mt < MT; mt++)
#pragma unroll
                for (int nt = 0; nt < NT4; nt++)
                    mma_f16(acc[mt][nt], af[mt], bf[nt]);
        }
        if (ks + 1 < nk) {
            if (more2) { CPA_WAIT(1); } else { CPA_WAIT(0); }
            __syncthreads();
        }
    }

    __half* Ch = (__half*)Cv;
    float*  Cf = (float*)Cv;
#pragma unroll
    for (int mt = 0; mt < MT; mt++) {
#pragma unroll
        for (int nt = 0; nt < NT4; nt++) {
            int r0 = m0 + mwb + mt * 16 + g;
            int c0 = n0 + nwb + nt * 8 + 2 * t;
            float v0 = acc[mt][nt][0] * scale, v1 = acc[mt][nt][1] * scale;
            float v2 = acc[mt][nt][2] * scale, v3 = acc[mt][nt][3] * scale;
            if (BIAS) {
                float b0 = bias[c0], b1 = bias[c0 + 1];
                v0 += b0; v1 += b1; v2 += b0; v3 += b1;
            }
            if (RELU) {
                v0 = fmaxf(v0, 0.f); v1 = fmaxf(v1, 0.f);
                v2 = fmaxf(v2, 0.f); v3 = fmaxf(v3, 0.f);
            }
            if (OUTH) {
                *(__half2*)(Ch + (size_t)r0 * ldc + c0) = __floats2half2_rn(v0, v1);
                *(__half2*)(Ch + (size_t)(r0 + 8) * ldc + c0) = __floats2half2_rn(v2, v3);
            } else {
                float* p0 = Cf + (size_t)r0 * ldc + c0;
                float* p1 = Cf + (size_t)(r0 + 8) * ldc + c0;
                if (ACCUM) {
                    float2 o0 = *(float2*)p0, o1 = *(float2*)p1;
                    v0 += o0.x; v1 += o0.y; v2 += o1.x; v3 += o1.y;
                }
                *(float2*)p0 = make_float2(v0, v1);
                *(float2*)p1 = make_float2(v2, v3);
            }
        }
    }
}

// ---------------- small kernels ----------------
__global__ void embed_kernel(const int* __restrict__ ids, const float* __restrict__ tok,
                             const float* __restrict__ pos, float* __restrict__ x) {
    int n = blockIdx.x, t = n % NT, id = ids[n];
    const float* te = tok + (size_t)id * ND;
    const float* pe = pos + (size_t)t * ND;
    float* dst = x + (size_t)n * ND;
    for (int d = threadIdx.x; d < ND; d += 256) dst[d] = te[d] + pe[d];
}

__global__ void ln_kernel(const float* __restrict__ x, const float* __restrict__ w,
                          const float* __restrict__ b, __half* __restrict__ out) {
    int row = blockIdx.x * 8 + (threadIdx.x >> 5);
    int lane = threadIdx.x & 31;
    const float4* p = (const float4*)(x + (size_t)row * ND);
    float4 v[8];
    float s = 0.f;
#pragma unroll
    for (int i = 0; i < 8; i++) {
        v[i] = p[lane + i * 32];
        s += v[i].x + v[i].y + v[i].z + v[i].w;
    }
#pragma unroll
    for (int o = 16; o; o >>= 1) s += __shfl_xor_sync(~0u, s, o);
    float mu = s * (1.0f / ND);
    float q = 0.f;
#pragma unroll
    for (int i = 0; i < 8; i++) {
        float a = v[i].x - mu, c = v[i].y - mu, d = v[i].z - mu, e = v[i].w - mu;
        q += a * a + c * c + d * d + e * e;
    }
#pragma unroll
    for (int o = 16; o; o >>= 1) q += __shfl_xor_sync(~0u, q, o);
    float rs = rsqrtf(q * (1.0f / ND) + 1e-5f);
    const float4* wp = (const float4*)w;
    const float4* bp = (const float4*)b;
    __half2* op = (__half2*)(out + (size_t)row * ND);
#pragma unroll
    for (int i = 0; i < 8; i++) {
        int j = lane + i * 32;
        float4 wv = wp[j], bv = bp[j];
        op[j * 2] = __floats2half2_rn((v[i].x - mu) * rs * wv.x + bv.x,
                                      (v[i].y - mu) * rs * wv.y + bv.y);
        op[j * 2 + 1] = __floats2half2_rn((v[i].z - mu) * rs * wv.z + bv.z,
                                          (v[i].w - mu) * rs * wv.w + bv.w);
    }
}

__global__ void rope_kernel(__half* __restrict__ qkv) {
    int n = blockIdx.x, t = n % NT;
    __half* base = qkv + (size_t)n * 3072;
#pragma unroll
    for (int item = threadIdx.x; item < 512; item += 256) {
        int h = item >> 5, i = item & 31;
        float ang = (float)t * expf((float)(2 * i) * (-0.14391156831212806f));
        float s = sinf(ang), c = cosf(ang);
        __half* q = base + h * 64;
        __half* k = q + 1024;
        float q1 = __half2float(q[i]), q2 = __half2float(q[i + 32]);
        q[i] = __float2half_rn(q1 * c - q2 * s);
        q[i + 32] = __float2half_rn(q2 * c + q1 * s);
        float k1 = __half2float(k[i]), k2 = __half2float(k[i + 32]);
        k[i] = __float2half_rn(k1 * c - k2 * s);
        k[i + 32] = __float2half_rn(k2 * c + k1 * s);
    }
}

// register-resident softmax: 1 read + 1 write; zero-pad to 256-half boundary
__global__ void attn_softmax_kernel(__half* __restrict__ sc) {
    int r = blockIdx.x, tid = threadIdx.x;   // 128 threads
    __half2* row2 = (__half2*)(sc + (size_t)blockIdx.y * NT * NT + (size_t)r * NT);
    int n = r + 1;
    float v[8][2];
    float m = -3.4e38f;
#pragma unroll
    for (int i = 0; i < 8; i++) {
        int idx = tid + i * 128;
        float2 f;
        if (idx * 2 < n) {
            f = __half22float2(row2[idx]);
            if (idx * 2 + 1 >= n) f.y = -3.4e38f;
        } else {
            f = make_float2(-3.4e38f, -3.4e38f);
        }
        v[i][0] = f.x; v[i][1] = f.y;
        m = fmaxf(m, fmaxf(f.x, f.y));
    }
    __shared__ float red[128];
    red[tid] = m; __syncthreads();
    for (int s = 64; s; s >>= 1) { if (tid < s) red[tid] = fmaxf(red[tid], red[tid + s]); __syncthreads(); }
    m = red[0]; __syncthreads();
    float sum = 0.f;
#pragma unroll
    for (int i = 0; i < 8; i++) {
        v[i][0] = expf(v[i][0] - m);
        v[i][1] = expf(v[i][1] - m);
        sum += v[i][0] + v[i][1];
    }
    red[tid] = sum; __syncthreads();
    for (int s = 64; s; s >>= 1) { if (tid < s) red[tid] += red[tid + s]; __syncthreads(); }
    float inv = 1.0f / red[0];
    int rup2 = (((r >> 8) + 1) << 8) >> 1;   // pad boundary in half2 units
#pragma unroll
    for (int i = 0; i < 8; i++) {
        int idx = tid + i * 128;
        if (idx < rup2)
            row2[idx] = __floats2half2_rn(v[i][0] * inv, v[i][1] * inv);
    }
}

// ---------------- MoE ----------------
__global__ void route_kernel(const __half* __restrict__ ln, const float* __restrict__ wr,
                             const float* __restrict__ br, const float* __restrict__ wn,
                             const float* __restrict__ bn, float* __restrict__ route,
                             float* __restrict__ noise) {
    int n = blockIdx.x, tid = threadIdx.x;
    __shared__ float xs[ND];
    for (int d = tid; d < ND; d += 256) xs[d] = __half2float(ln[(size_t)n * ND + d]);
    __syncthreads();
    int w = tid >> 5, lane = tid & 31;
    float sr = 0.f, sn = 0.f;
    for (int d = lane; d < ND; d += 32) {
        float xv = xs[d];
        sr += xv * wr[(size_t)d * NE + w];
        sn += xv * wn[(size_t)d * NE + w];
    }
    for (int o = 16; o; o >>= 1) { sr += __shfl_down_sync(~0u, sr, o); sn += __shfl_down_sync(~0u, sn, o); }
    if (!lane) { route[n * NE + w] = sr + br[w]; noise[n * NE + w] = sn + bn[w]; }
}

__global__ void eps_kernel(unsigned k0, unsigned k1, float* __restrict__ eps) {
    int i = blockIdx.x * 256 + threadIdx.x;
    if (i >= NN * NE) return;
    unsigned o0, o1;
    threefry(k0, k1, 0u, (unsigned)i, o0, o1);
    eps[i] = bits_to_normal(o0 ^ o1);
}

__global__ void topk_kernel(const float* __restrict__ route, const float* __restrict__ noise,
                            const float* __restrict__ eps, float* __restrict__ gate,
                            unsigned char* __restrict__ mask) {
    int n = blockIdx.x * 256 + threadIdx.x;
    if (n >= NN) return;
    float nv[NE];
#pragma unroll
    for (int e = 0; e < NE; e++) {
        float x = noise[n * NE + e];
        float sp = fmaxf(x, 0.f) + log1pf(expf(-fabsf(x)));
        nv[e] = route[n * NE + e] + eps[n * NE + e] * sp;
    }
    int i1 = 0; float v1 = nv[0];
#pragma unroll
    for (int e = 1; e < NE; e++) if (nv[e] > v1) { v1 = nv[e]; i1 = e; }
    int i2 = -1; float v2 = -3.4e38f;
#pragma unroll
    for (int e = 0; e < NE; e++) if (e != i1 && nv[e] > v2) { v2 = nv[e]; i2 = e; }
    float e2 = expf(v2 - v1);
    float Z = 1.0f + e2;
#pragma unroll
    for (int e = 0; e < NE; e++)
        gate[n * NE + e] = (e == i1) ? (1.0f / Z) : ((e == i2) ? (e2 / Z) : 0.f);
    mask[n] = (unsigned char)((1u << i1) | (1u << i2));
}

__global__ void select_kernel(const unsigned char* __restrict__ mask, int* __restrict__ sel,
                              int* __restrict__ slot, int* __restrict__ cnt) {
    int e = blockIdx.x, lane = threadIdx.x;
    int base = 0;
    for (int n0 = 0; n0 < NN; n0 += 32) {
        int n = n0 + lane;
        bool f = (mask[n] >> e) & 1;
        unsigned bal = __ballot_sync(0xffffffffu, f);
        int pos = base + __popc(bal & ((1u << lane) - 1u));
        int sl = (f && pos < NCAP) ? pos : -1;
        slot[(size_t)e * NN + n] = sl;
        if (sl >= 0) sel[e * NCAP + sl] = n;
        base += __popc(bal);
    }
    if (!lane) cnt[e] = base < NCAP ? base : NCAP;
}

// fused scatter + LayerNorm (next layer's LN params); writes x and ln16
__global__ void moe_scatter_ln_kernel(const __half* __restrict__ eo, const int* __restrict__ slot,
                                      const float* __restrict__ gate, float* __restrict__ x,
                                      const float* __restrict__ w, const float* __restrict__ b,
                                      __half* __restrict__ lnout) {
    int n = blockIdx.x, tid = threadIdx.x;   // 256 threads, row of ND
    __shared__ int ss[NE];
    __shared__ float gg[NE];
    __shared__ float red[8];
    if (tid < NE) { ss[tid] = slot[(size_t)tid * NN + n]; gg[tid] = gate[n * NE + tid]; }
    __syncthreads();
    float vals[4];
    float s = 0.f;
#pragma unroll
    for (int i = 0; i < 4; i++) {
        int d = tid + i * 256;
        float acc = x[(size_t)n * ND + d];
#pragma unroll
        for (int e = 0; e < NE; e++) {
            int sl = ss[e];
            if (sl >= 0) acc += gg[e] * __half2float(eo[((size_t)e * NCAP + sl) * ND + d]);
        }
        vals[i] = acc; s += acc;
        x[(size_t)n * ND + d] = acc;
    }
    int lane = tid & 31, warp = tid >> 5;
#pragma unroll
    for (int o = 16; o; o >>= 1) s += __shfl_xor_sync(~0u, s, o);
    if (!lane) red[warp] = s;
    __syncthreads();
    if (tid < 8) {
        float t = red[tid];
#pragma unroll
        for (int o = 4; o; o >>= 1) t += __shfl_xor_sync(0xffu, t, o);
        red[tid] = t;
    }
    __syncthreads();
    float mu = red[0] * (1.0f / ND);
    float q = 0.f;
#pragma unroll
    for (int i = 0; i < 4; i++) { float d = vals[i] - mu; q += d * d; }
#pragma unroll
    for (int o = 16; o; o >>= 1) q += __shfl_xor_sync(~0u, q, o);
    __syncthreads();
    if (!lane) red[warp] = q;
    __syncthreads();
    if (tid < 8) {
        float t = red[tid];
#pragma unroll
        for (int o = 4; o; o >>= 1) t += __shfl_xor_sync(0xffu, t, o);
        red[tid] = t;
    }
    __syncthreads();
    float rs = rsqrtf(red[0] * (1.0f / ND) + 1e-5f);
#pragma unroll
    for (int i = 0; i < 4; i++) {
        int d = tid + i * 256;
        lnout[(size_t)n * ND + d] =
            __float2half_rn((vals[i] - mu) * rs * w[d] + b[d]);
    }
}

// ---------------- loss (fp16 logits) ----------------
__global__ void loss_kernel(const __half* __restrict__ logits, const int* __restrict__ ids,
                            float* __restrict__ nll, float* __restrict__ vld) {
    int n = blockIdx.x, tid = threadIdx.x;
    int b = n / NT, t = n % NT;
    if (t == NT - 1) { if (!tid) { nll[n] = 0.f; vld[n] = 0.f; } return; }
    int tgt = ids[b * NT + t + 1];
    const __half2* row2 = (const __half2*)(logits + (size_t)n * NV);
    float m = -3.4e38f, s = 0.f;
    for (int j = tid; j < NV / 2; j += 256) {
        float2 l = __half22float2(row2[j]);
        float mx = fmaxf(l.x, l.y);
        if (mx > m) { s = s * expf(m - mx); m = mx; }
        s += expf(l.x - m) + expf(l.y - m);
    }
    __shared__ float sm[256], ssum[256];
    sm[tid] = m; ssum[tid] = s; __syncthreads();
    for (int st = 128; st; st >>= 1) {
        if (tid < st) {
            float m1 = sm[tid], s1 = ssum[tid], m2 = sm[tid + st], s2 = ssum[tid + st];
            float M = fmaxf(m1, m2);
            ssum[tid] = s1 * expf(m1 - M) + s2 * expf(m2 - M);
            sm[tid] = M;
        }
        __syncthreads();
    }
    if (!tid) {
        float lse = sm[0] + logf(ssum[0]);
        float v = (tgt != 2) ? 1.f : 0.f;
        float lt = __half2float(logits[(size_t)n * NV + tgt]);
        nll[n] = -(lt - lse) * v;
        vld[n] = v;
    }
}

__global__ void reduce_kernel(const float* __restrict__ nll, const float* __restrict__ vld,
                              float* __restrict__ out) {
    __shared__ float s1[256], s2[256];
    int tid = threadIdx.x;
    float a = 0.f, b = 0.f;
    for (int i = tid; i < NN; i += 256) { a += nll[i]; b += vld[i]; }
    s1[tid] = a; s2[tid] = b; __syncthreads();
    for (int st = 128; st; st >>= 1) { if (tid < st) { s1[tid] += s1[tid + st]; s2[tid] += s2[tid + st]; } __syncthreads(); }
    if (!tid) out[0] = s1[0] / fmaxf(s2[0], 1.0f);
}

// ---------------- host launch ----------------
#define STG_T(BM, BN) (((BM) + (BN)) * 72)
#define STG_F(BM, BN) ((BM) * 72 + 64 * ((BN) + 8))

extern "C" void kernel_launch(void* const* d_in, const int* in_sizes, int n_in,
                              void* d_out, int out_size) {
    const int*   ids     = (const int*)d_in[0];
    const float* tok_emb = (const float*)d_in[1];
    const float* pos_emb = (const float*)d_in[2];
    const float* ln1_w   = (const float*)d_in[3];
    const float* ln1_b   = (const float*)d_in[4];
    const float* ln2_w   = (const float*)d_in[5];
    const float* ln2_b   = (const float*)d_in[6];
    const float* w_qkv   = (const float*)d_in[7];
    const float* w_out   = (const float*)d_in[8];
    const float* w_route = (const float*)d_in[9];
    const float* b_route = (const float*)d_in[10];
    const float* w_noise = (const float*)d_in[11];
    const float* b_noise = (const float*)d_in[12];
    const float* w_e1    = (const float*)d_in[13];
    const float* b_e1    = (const float*)d_in[14];
    const float* w_e2    = (const float*)d_in[15];
    const float* b_e2    = (const float*)d_in[16];
    const float* lnf_w   = (const float*)d_in[17];
    const float* lnf_b   = (const float*)d_in[18];
    float* out = (float*)d_out;

    float *x, *route, *noise, *eps, *gate, *nll, *vld;
    __half *ln16, *qkv16, *attn16, *p16, *h116, *eo16, *lg16;
    __half *wqkv16, *wout16, *we116, *we216, *tok16;
    unsigned char* mask; int *sel, *slot, *cnt;
    cudaGetSymbolAddress((void**)&x, g_x);
    cudaGetSymbolAddress((void**)&ln16, g_ln16);
    cudaGetSymbolAddress((void**)&qkv16, g_qkv16);
    cudaGetSymbolAddress((void**)&attn16, g_attn16);
    cudaGetSymbolAddress((void**)&p16, g_p16);
    cudaGetSymbolAddress((void**)&route, g_route);
    cudaGetSymbolAddress((void**)&noise, g_noise);
    cudaGetSymbolAddress((void**)&eps, g_eps);
    cudaGetSymbolAddress((void**)&gate, g_gate);
    cudaGetSymbolAddress((void**)&mask, g_mask);
    cudaGetSymbolAddress((void**)&sel, g_sel);
    cudaGetSymbolAddress((void**)&slot, g_slot);
    cudaGetSymbolAddress((void**)&cnt, g_cnt);
    cudaGetSymbolAddress((void**)&h116, g_h116);
    cudaGetSymbolAddress((void**)&eo16, g_eo16);
    cudaGetSymbolAddress((void**)&lg16, g_log16);
    cudaGetSymbolAddress((void**)&nll, g_nll);
    cudaGetSymbolAddress((void**)&vld, g_vld);
    cudaGetSymbolAddress((void**)&wqkv16, g_wqkv16);
    cudaGetSymbolAddress((void**)&wout16, g_wout16);
    cudaGetSymbolAddress((void**)&we116, g_we116);
    cudaGetSymbolAddress((void**)&we216, g_we216);
    cudaGetSymbolAddress((void**)&tok16, g_tok16);

    constexpr int SM_T = 3 * STG_T(256, 128) * 2;
    constexpr int SM_F = 3 * STG_F(256, 128) * 2;
    constexpr int SM_PV = 3 * STG_F(128, 64) * 2;
    auto* kqkv = hgemm_ca<512,256,128,4,4,false,false,false,false,false,false,true ,false>;
    auto* kqk  = hgemm_ca<512,256,128,4,4,true ,false,false,false,true ,false,true ,false>;
    auto* kpv  = hgemm_ca<256,128, 64,4,2,false,false,false,false,false,true ,true ,false>;
    auto* kproj= hgemm_ca<512,256,128,4,4,false,false,false,true ,false,false,false,false>;
    auto* kfc1 = hgemm_ca<512,256,128,4,4,false,true ,true ,false,false,false,true ,true >;
    auto* kfc2 = hgemm_ca<512,256,128,4,4,false,true ,false,false,false,false,true ,false>;
    auto* kvoc = hgemm_ca<512,256,128,4,4,true ,false,false,false,false,false,true ,false>;
    cudaFuncSetAttribute(kqkv, cudaFuncAttributeMaxDynamicSharedMemorySize, SM_F);
    cudaFuncSetAttribute(kqk,  cudaFuncAttributeMaxDynamicSharedMemorySize, SM_T);
    cudaFuncSetAttribute(kpv,  cudaFuncAttributeMaxDynamicSharedMemorySize, SM_PV);
    cudaFuncSetAttribute(kproj,cudaFuncAttributeMaxDynamicSharedMemorySize, SM_F);
    cudaFuncSetAttribute(kfc1, cudaFuncAttributeMaxDynamicSharedMemorySize, SM_F);
    cudaFuncSetAttribute(kfc2, cudaFuncAttributeMaxDynamicSharedMemorySize, SM_F);
    cudaFuncSetAttribute(kvoc, cudaFuncAttributeMaxDynamicSharedMemorySize, SM_T);

    {
        size_t n;
        n = (size_t)NLAY * ND * 3 * ND / 4;
        cvt_h_kernel<<<(unsigned)((n + 255) / 256), 256>>>(w_qkv, wqkv16, n);
        n = (size_t)NLAY * ND * ND / 4;
        cvt_h_kernel<<<(unsigned)((n + 255) / 256), 256>>>(w_out, wout16, n);
        n = (size_t)NLAY * NE * ND * NFF / 4;
        cvt_h_kernel<<<(unsigned)((n + 255) / 256), 256>>>(w_e1, we116, n);
        n = (size_t)NLAY * NE * NFF * ND / 4;
        cvt_h_kernel<<<(unsigned)((n + 255) / 256), 256>>>(w_e2, we216, n);
        n = (size_t)NV * ND / 4;
        cvt_h_kernel<<<(unsigned)((n + 255) / 256), 256>>>(tok_emb, tok16, n);
    }

    embed_kernel<<<NN, 256>>>(ids, tok_emb, pos_emb, x);
    ln_kernel<<<NN / 8, 256>>>(x, ln1_w, ln1_b, ln16);

    for (int l = 0; l < NLAY; l++) {
        // ---- attention ----
        kqkv<<<dim3(24, 16, 1), 512, SM_F>>>(
            ln16, wqkv16 + (size_t)l * ND * 3 * ND, nullptr, qkv16, nullptr,
            ND, ND, 3 * ND, 3 * ND, 1, 0, 0, 0, 0, 0, 0, 0, 1.0f);
        rope_kernel<<<NN, 256>>>(qkv16);
        kqk<<<dim3(16, 8, NB * NH), 512, SM_T>>>(
            qkv16, qkv16 + 1024, nullptr, p16, nullptr,
            64, 3072, 3072, NT, NH,
            (size_t)NT * 3072, 64, (size_t)NT * 3072, 64,
            (size_t)NH * NT * NT, (size_t)NT * NT, 0, 0.125f);
        attn_softmax_kernel<<<dim3(NT, NB * NH), 128>>>(p16);
        kpv<<<dim3(1, 16, NB * NH), 256, SM_PV>>>(
            p16, qkv16 + 2048, nullptr, attn16, nullptr,
            NT, NT, 3072, ND, NH,
            (size_t)NH * NT * NT, (size_t)NT * NT, (size_t)NT * 3072, 64,
            (size_t)NT * ND, 64, 0, 1.0f);
        kproj<<<dim3(8, 16, 1), 512, SM_F>>>(
            attn16, wout16 + (size_t)l * ND * ND, nullptr, x, nullptr,
            ND, ND, ND, ND, 1, 0, 0, 0, 0, 0, 0, 0, 1.0f);

        // ---- MoE ----
        ln_kernel<<<NN / 8, 256>>>(x, ln2_w + l * ND, ln2_b + l * ND, ln16);
        route_kernel<<<NN, 256>>>(ln16, w_route + (size_t)l * ND * NE, b_route + l * NE,
                                  w_noise + (size_t)l * ND * NE, b_noise + l * NE, route, noise);
        unsigned k0, k1;
        threefry(0u, 1234u, 0u, (unsigned)l, k0, k1);
        eps_kernel<<<(NN * NE + 255) / 256, 256>>>(k0, k1, eps);
        topk_kernel<<<(NN + 255) / 256, 256>>>(route, noise, eps, gate, mask);
        select_kernel<<<NE, 32>>>(mask, sel, slot, cnt);
        // fc1: gathered A rows from ln16 via sel
        kfc1<<<dim3(32, 4, NE), 512, SM_F>>>(
            ln16, we116 + (size_t)l * NE * ND * NFF, b_e1 + (size_t)l * NE * NFF, h116, sel,
            ND, ND, NFF, NFF, 1,
            0, 0, (size_t)NFF * ND, 0,
            (size_t)NCAP * NFF, 0, NFF, 1.0f);
        kfc2<<<dim3(8, 4, NE), 512, SM_F>>>(
            h116, we216 + (size_t)l * NE * NFF * ND, b_e2 + (size_t)l * NE * ND, eo16, nullptr,
            NFF, NFF, ND, ND, 1,
            (size_t)NCAP * NFF, 0, (size_t)ND * NFF, 0,
            (size_t)NCAP * ND, 0, ND, 1.0f);
        // fused scatter + next LN (ln1[l+1] or final lnf)
        const float* nw = (l + 1 < NLAY) ? (ln1_w + (size_t)(l + 1) * ND) : lnf_w;
        const float* nb = (l + 1 < NLAY) ? (ln1_b + (size_t)(l + 1) * ND) : lnf_b;
        moe_scatter_ln_kernel<<<NN, 256>>>(eo16, slot, gate, x, nw, nb, ln16);
    }

    kvoc<<<dim3(NV / 128, 16, 1), 512, SM_T>>>(
        ln16, tok16, nullptr, lg16, nullptr,
        ND, ND, ND, NV, 1, 0, 0, 0, 0, 0, 0, 0, 1.0f);
    loss_kernel<<<NN, 256>>>(lg16, ids, nll, vld);
    reduce_kernel<<<1, 256>>>(nll, vld, out);
}

// round 13
// speedup vs baseline: 3.0741x; 1.0954x over previous
#include <cuda_runtime.h>
#include <cuda_fp16.h>
#include <cstdint>
#include <cstddef>

#define NB 2
#define NT 2048
#define ND 1024
#define NH 16
#define NLAY 2
#define NE 8
#define NV 32000
#define NN (NB*NT)
#define NCAP 1024
#define NFF 4096

// ---------------- device scratch ----------------
__device__ float  g_x   [(size_t)NN*ND];
__device__ __half g_ln16[(size_t)NN*ND];
__device__ __half g_qkv16[(size_t)NN*3*ND];
__device__ __half g_attn16[(size_t)NN*ND];
__device__ float  g_route[NN*NE];
__device__ float  g_noise[NN*NE];
__device__ float  g_eps  [NN*NE];
__device__ float  g_gate [NN*NE];
__device__ unsigned char g_mask[NN];
__device__ int    g_sel [NE*NCAP];
__device__ int    g_slot[NE*NN];
__device__ int    g_cnt [NE];
__device__ __half g_h116[(size_t)NE*NCAP*NFF];
__device__ __half g_eo16[(size_t)NE*NCAP*ND];
__device__ __half g_log16[(size_t)NN*NV];
__device__ float  g_nll [NN];
__device__ float  g_vld [NN];
// fp16 weight copies (ORIGINAL [K,N] layout — no transpose)
__device__ __half g_wqkv16[(size_t)NLAY*ND*3*ND];
__device__ __half g_wout16[(size_t)NLAY*ND*ND];
__device__ __half g_we116 [(size_t)NLAY*NE*ND*NFF];
__device__ __half g_we216 [(size_t)NLAY*NE*NFF*ND];
__device__ __half g_tok16 [(size_t)NV*ND];

// ---------------- threefry2x32 (matches JAX) ----------------
__host__ __device__ __forceinline__ void threefry(unsigned k0, unsigned k1,
                                                  unsigned x0, unsigned x1,
                                                  unsigned& o0, unsigned& o1) {
    unsigned ks2 = k0 ^ k1 ^ 0x1BD11BDAu;
    x0 += k0; x1 += k1;
#define TFR(r) { x0 += x1; x1 = (x1 << (r)) | (x1 >> (32 - (r))); x1 ^= x0; }
    TFR(13) TFR(15) TFR(26) TFR(6)  x0 += k1;  x1 += ks2 + 1u;
    TFR(17) TFR(29) TFR(16) TFR(24) x0 += ks2; x1 += k0 + 2u;
    TFR(13) TFR(15) TFR(26) TFR(6)  x0 += k0;  x1 += k1 + 3u;
    TFR(17) TFR(29) TFR(16) TFR(24) x0 += k1;  x1 += ks2 + 4u;
    TFR(13) TFR(15) TFR(26) TFR(6)  x0 += ks2; x1 += k0 + 5u;
#undef TFR
    o0 = x0; o1 = x1;
}

__device__ __forceinline__ float xla_erfinv(float x) {
    float w = -log1pf(-x * x);
    float p;
    if (w < 5.f) {
        w -= 2.5f;
        p = 2.81022636e-08f;
        p = fmaf(p, w, 3.43273939e-07f);
        p = fmaf(p, w, -3.5233877e-06f);
        p = fmaf(p, w, -4.39150654e-06f);
        p = fmaf(p, w, 0.00021858087f);
        p = fmaf(p, w, -0.00125372503f);
        p = fmaf(p, w, -0.00417768164f);
        p = fmaf(p, w, 0.246640727f);
        p = fmaf(p, w, 1.50140941f);
    } else {
        w = sqrtf(w) - 3.f;
        p = -0.000200214257f;
        p = fmaf(p, w, 0.000100950558f);
        p = fmaf(p, w, 0.00134934322f);
        p = fmaf(p, w, -0.00367342844f);
        p = fmaf(p, w, 0.00573950773f);
        p = fmaf(p, w, -0.0076224613f);
        p = fmaf(p, w, 0.00943887047f);
        p = fmaf(p, w, 1.00167406f);
        p = fmaf(p, w, 2.83297682f);
    }
    return p * x;
}

__device__ __forceinline__ float bits_to_normal(unsigned bits) {
    float f = __uint_as_float((bits >> 9) | 0x3F800000u) - 1.0f;
    const float lo = -0.99999994f;
    float u = fmaf(f, 2.0f, lo);
    u = fmaxf(u, lo);
    return 1.41421356237f * xla_erfinv(u);
}

// ---------------- mma / ldmatrix / cp.async helpers ----------------
__device__ __forceinline__ void mma_f16(float* c, const unsigned* a, const unsigned* b) {
    asm volatile("mma.sync.aligned.m16n8k16.row.col.f32.f16.f16.f32 "
        "{%0,%1,%2,%3}, {%4,%5,%6,%7}, {%8,%9}, {%0,%1,%2,%3};"
        : "+f"(c[0]), "+f"(c[1]), "+f"(c[2]), "+f"(c[3])
        : "r"(a[0]), "r"(a[1]), "r"(a[2]), "r"(a[3]), "r"(b[0]), "r"(b[1]));
}
__device__ __forceinline__ void ldsm4(unsigned& d0, unsigned& d1, unsigned& d2, unsigned& d3,
                                      uint32_t addr) {
    asm volatile("ldmatrix.sync.aligned.m8n8.x4.shared.b16 {%0,%1,%2,%3}, [%4];"
        : "=r"(d0), "=r"(d1), "=r"(d2), "=r"(d3) : "r"(addr));
}
__device__ __forceinline__ void ldsm4t(unsigned& d0, unsigned& d1, unsigned& d2, unsigned& d3,
                                       uint32_t addr) {
    asm volatile("ldmatrix.sync.aligned.m8n8.x4.trans.shared.b16 {%0,%1,%2,%3}, [%4];"
        : "=r"(d0), "=r"(d1), "=r"(d2), "=r"(d3) : "r"(addr));
}
__device__ __forceinline__ uint32_t smem_u32(const void* p) {
    uint32_t a;
    asm("{ .reg .u64 t; cvta.to.shared.u64 t, %1; cvt.u32.u64 %0, t; }" : "=r"(a) : "l"(p));
    return a;
}
__device__ __forceinline__ void cpa16(uint32_t dst, const void* src) {
    asm volatile("cp.async.ca.shared.global [%0], [%1], 16;" :: "r"(dst), "l"(src));
}
#define CPA_COMMIT() asm volatile("cp.async.commit_group;" ::: "memory")
#define CPA_WAIT(n)  asm volatile("cp.async.wait_group %0;" :: "n"(n) : "memory")

// ---------------- weight prep ----------------
__global__ void cvt_h_kernel(const float* __restrict__ in, __half* __restrict__ out, size_t n4) {
    size_t i = (size_t)blockIdx.x * 256 + threadIdx.x;
    if (i >= n4) return;
    float4 v = ((const float4*)in)[i];
    __half2* o = (__half2*)out;
    o[i * 2] = __floats2half2_rn(v.x, v.y);
    o[i * 2 + 1] = __floats2half2_rn(v.z, v.w);
}

// ---------------- cp.async 3-stage fp16 GEMM ----------------
template<int TH, int BM, int BN, int WR, int WC, bool BNK, bool BIAS, bool RELU,
         bool ACCUM, bool OUTH, bool GATHER>
__global__ void __launch_bounds__(TH)
hgemm_ca(const __half* __restrict__ A, const __half* __restrict__ B,
         const float* __restrict__ bias, void* __restrict__ Cv,
         const int* __restrict__ gsel,
         int K, int lda, int ldb, int ldc, int zdiv,
         size_t sA, size_t sA2, size_t sB, size_t sB2,
         size_t sC, size_t sC2, size_t sBias, float scale)
{
    constexpr int BK = 64;
    constexpr int LDS = 72;
    constexpr int BNP = BN + 8;
    constexpr int WM = BM / WR, WN = BN / WC;
    constexpr int MT = WM / 16, NT4 = WN / 8, NP = NT4 / 2;
    constexpr int ANV = (BM * 8) / TH;
    constexpr int BNV = BNK ? (BN * 8) / TH : (BK * BN) / (8 * TH);
    constexpr int STG = BNK ? (BM + BN) * LDS : BM * LDS + BK * BNP;

    const int m0 = blockIdx.y * BM, n0 = blockIdx.x * BN;
    const int tid = threadIdx.x, lane = tid & 31, warp = tid >> 5;
    const int wr = warp / WC, wc = warp % WC;
    const int g = lane >> 2, t = lane & 3;

    {
        int z = blockIdx.z, z1 = z / zdiv, z0 = z - z1 * zdiv;
        A += (size_t)z1 * sA + (size_t)z0 * sA2;
        B += (size_t)z1 * sB + (size_t)z0 * sB2;
        Cv = (char*)Cv + ((size_t)z1 * sC + (size_t)z0 * sC2) * (OUTH ? 2 : 4);
        if (BIAS) bias += (size_t)z1 * sBias;
    }

    const int nk = K / BK;

    extern __shared__ __half shh[];
    const uint32_t sbase = smem_u32(shh);

    const int a_r = lane & 15, a_c8 = (lane >> 4) * 8;
    const int b_r = (lane & 7) + (lane >> 4) * 8, b_c8 = ((lane >> 3) & 1) * 8;
    const int q8 = lane & 7, quad = lane >> 3;
    const int bt_k = (quad & 1) * 8 + q8, bt_n8 = (quad >> 1) * 8;
    const int mwb = wr * WM, nwb = wc * WN;

    const int ar = tid >> 3, aq = tid & 7;
    int arows[ANV];
#pragma unroll
    for (int i = 0; i < ANV; i++) {
        int r = m0 + ar + i * (TH >> 3);
        arows[i] = GATHER ? gsel[(size_t)blockIdx.z * NCAP + r] : r;
    }

    auto issue = [&](int ks, int st) {
        uint32_t so = sbase + (uint32_t)(st * STG) * 2;
#pragma unroll
        for (int i = 0; i < ANV; i++) {
            int row = ar + i * (TH >> 3);
            cpa16(so + (uint32_t)(row * LDS + aq * 8) * 2,
                  A + (size_t)arows[i] * lda + ks * BK + aq * 8);
        }
        if (BNK) {
            const __half* Bc = B + (size_t)n0 * ldb + ks * BK;
#pragma unroll
            for (int i = 0; i < BNV; i++) {
                int row = ar + i * (TH >> 3);
                cpa16(so + (uint32_t)((BM + row) * LDS + aq * 8) * 2,
                      Bc + (size_t)row * ldb + aq * 8);
            }
        } else {
            const __half* Bc = B + (size_t)(ks * BK) * ldb + n0;
#pragma unroll
            for (int i = 0; i < BNV; i++) {
                int idx = tid + i * TH;
                int kk = idx / (BN / 8), nq = idx % (BN / 8);
                cpa16(so + (uint32_t)(BM * LDS + kk * BNP + nq * 8) * 2,
                      Bc + (size_t)kk * ldb + nq * 8);
            }
        }
        CPA_COMMIT();
    };

    float acc[MT][NT4][4] = {};

    issue(0, 0);
    if (nk > 1) issue(1, 1);
    if (nk > 1) { CPA_WAIT(1); } else { CPA_WAIT(0); }
    __syncthreads();

    for (int ks = 0; ks < nk; ks++) {
        int cur = ks % 3;
        bool more2 = (ks + 2 < nk);
        if (more2) issue(ks + 2, (ks + 2) % 3);
        uint32_t abase = sbase + (uint32_t)(cur * STG) * 2;
        uint32_t bbase = abase + (uint32_t)(BM * LDS) * 2;
#pragma unroll
        for (int kq = 0; kq < 4; kq++) {
            unsigned af[MT][4], bf[NT4][2];
#pragma unroll
            for (int mt = 0; mt < MT; mt++) {
                uint32_t ad = abase +
                    (uint32_t)(((mwb + mt * 16 + a_r) * LDS + kq * 16 + a_c8) * 2);
                ldsm4(af[mt][0], af[mt][1], af[mt][2], af[mt][3], ad);
            }
            if (BNK) {
#pragma unroll
                for (int np = 0; np < NP; np++) {
                    uint32_t bd = bbase +
                        (uint32_t)(((nwb + np * 16 + b_r) * LDS + kq * 16 + b_c8) * 2);
                    ldsm4(bf[2*np][0], bf[2*np][1], bf[2*np+1][0], bf[2*np+1][1], bd);
                }
            } else {
#pragma unroll
                for (int np = 0; np < NP; np++) {
                    uint32_t bd = bbase +
                        (uint32_t)(((kq * 16 + bt_k) * BNP + nwb + np * 16 + bt_n8) * 2);
                    ldsm4t(bf[2*np][0], bf[2*np][1], bf[2*np+1][0], bf[2*np+1][1], bd);
                }
            }
#pragma unroll
            for (int mt = 0; mt < MT; mt++)
#pragma unroll
                for (int nt = 0; nt < NT4; nt++)
                    mma_f16(acc[mt][nt], af[mt], bf[nt]);
        }
        if (ks + 1 < nk) {
            if (more2) { CPA_WAIT(1); } else { CPA_WAIT(0); }
            __syncthreads();
        }
    }

    __half* Ch = (__half*)Cv;
    float*  Cf = (float*)Cv;
#pragma unroll
    for (int mt = 0; mt < MT; mt++) {
#pragma unroll
        for (int nt = 0; nt < NT4; nt++) {
            int r0 = m0 + mwb + mt * 16 + g;
            int c0 = n0 + nwb + nt * 8 + 2 * t;
            float v0 = acc[mt][nt][0] * scale, v1 = acc[mt][nt][1] * scale;
            float v2 = acc[mt][nt][2] * scale, v3 = acc[mt][nt][3] * scale;
            if (BIAS) {
                float b0 = bias[c0], b1 = bias[c0 + 1];
                v0 += b0; v1 += b1; v2 += b0; v3 += b1;
            }
            if (RELU) {
                v0 = fmaxf(v0, 0.f); v1 = fmaxf(v1, 0.f);
                v2 = fmaxf(v2, 0.f); v3 = fmaxf(v3, 0.f);
            }
            if (OUTH) {
                *(__half2*)(Ch + (size_t)r0 * ldc + c0) = __floats2half2_rn(v0, v1);
                *(__half2*)(Ch + (size_t)(r0 + 8) * ldc + c0) = __floats2half2_rn(v2, v3);
            } else {
                float* p0 = Cf + (size_t)r0 * ldc + c0;
                float* p1 = Cf + (size_t)(r0 + 8) * ldc + c0;
                if (ACCUM) {
                    float2 o0 = *(float2*)p0, o1 = *(float2*)p1;
                    v0 += o0.x; v1 += o0.y; v2 += o1.x; v3 += o1.y;
                }
                *(float2*)p0 = make_float2(v0, v1);
                *(float2*)p1 = make_float2(v2, v3);
            }
        }
    }
}

// ---------------- FlashAttention-2 (causal, 128-row q-tiles, 256 thr) ----------------
// smem: Q[128][72] + 2 stages of (K[128][72], V[128][72]) = 92160 B
#define FL_PITCH 72
#define FL_QSZ   (128 * FL_PITCH)
#define FL_KVSZ  (2 * 128 * FL_PITCH)
#define FL_SMEM  ((FL_QSZ + 2 * FL_KVSZ) * 2)

__global__ void __launch_bounds__(256)
flash_kernel(const __half* __restrict__ qkv, __half* __restrict__ attn) {
    int z = blockIdx.y, b = z >> 4, h = z & 15;
    int qt = (int)gridDim.x - 1 - (int)blockIdx.x;   // heaviest first
    int m0 = qt * 128;
    const __half* Qg = qkv + (size_t)b * NT * 3072 + h * 64;
    const __half* Kg = Qg + 1024;
    const __half* Vg = Qg + 2048;

    extern __shared__ __half sh[];
    const uint32_t sb = smem_u32(sh);

    int tid = threadIdx.x, lane = tid & 31, warp = tid >> 5;
    int g = lane >> 2, t = lane & 3;
    int lr = tid >> 3, lq = tid & 7;

    // Q load (one group)
#pragma unroll
    for (int i = 0; i < 4; i++) {
        int row = lr + i * 32;
        cpa16(sb + (uint32_t)(row * FL_PITCH + lq * 8) * 2,
              Qg + (size_t)(m0 + row) * 3072 + lq * 8);
    }
    CPA_COMMIT();

    auto issue_kv = [&](int j, int st) {
        uint32_t so = sb + (uint32_t)(FL_QSZ + st * FL_KVSZ) * 2;
#pragma unroll
        for (int i = 0; i < 4; i++) {
            int row = lr + i * 32;
            cpa16(so + (uint32_t)(row * FL_PITCH + lq * 8) * 2,
                  Kg + (size_t)(j * 128 + row) * 3072 + lq * 8);
        }
#pragma unroll
        for (int i = 0; i < 4; i++) {
            int row = lr + i * 32;
            cpa16(so + (uint32_t)((128 + row) * FL_PITCH + lq * 8) * 2,
                  Vg + (size_t)(j * 128 + row) * 3072 + lq * 8);
        }
        CPA_COMMIT();
    };
    issue_kv(0, 0);
    CPA_WAIT(0);
    __syncthreads();

    const int mwb = warp * 16;
    const int a_r = lane & 15, a_c8 = (lane >> 4) * 8;
    unsigned qf[4][4];
#pragma unroll
    for (int kq = 0; kq < 4; kq++) {
        uint32_t ad = sb + (uint32_t)(((mwb + a_r) * FL_PITCH + kq * 16 + a_c8) * 2);
        ldsm4(qf[kq][0], qf[kq][1], qf[kq][2], qf[kq][3], ad);
    }

    const int b_r = (lane & 7) + (lane >> 4) * 8, b_c8 = ((lane >> 3) & 1) * 8;
    const int q8 = lane & 7, quad = lane >> 3;
    const int bt_k = (quad & 1) * 8 + q8, bt_n8 = (quad >> 1) * 8;

    float m_lo = -1e30f, m_hi = -1e30f, l_lo = 0.f, l_hi = 0.f;
    float ao[8][4] = {};
    const int rl_lo = mwb + g, rl_hi = mwb + g + 8;

    for (int j = 0; j <= qt; j++) {
        int st = j & 1;
        __syncthreads();                         // all reads of buffer st^1 done
        if (j < qt) issue_kv(j + 1, st ^ 1);
        if (j < qt) { CPA_WAIT(1); } else { CPA_WAIT(0); }
        __syncthreads();

        uint32_t kbase = sb + (uint32_t)(FL_QSZ + st * FL_KVSZ) * 2;
        uint32_t vbase = kbase + (uint32_t)(128 * FL_PITCH) * 2;

        float as[16][4] = {};
#pragma unroll
        for (int kq = 0; kq < 4; kq++) {
            unsigned bf[16][2];
#pragma unroll
            for (int np = 0; np < 8; np++) {
                uint32_t bd = kbase +
                    (uint32_t)(((np * 16 + b_r) * FL_PITCH + kq * 16 + b_c8) * 2);
                ldsm4(bf[2*np][0], bf[2*np][1], bf[2*np+1][0], bf[2*np+1][1], bd);
            }
#pragma unroll
            for (int nt = 0; nt < 16; nt++)
                mma_f16(as[nt], qf[kq], bf[nt]);
        }

        float rm_lo = -1e30f, rm_hi = -1e30f;
#pragma unroll
        for (int nt = 0; nt < 16; nt++) {
            int c0 = nt * 8 + 2 * t;
            as[nt][0] *= 0.125f; as[nt][1] *= 0.125f;
            as[nt][2] *= 0.125f; as[nt][3] *= 0.125f;
            if (j == qt) {
                if (c0     > rl_lo) as[nt][0] = -1e30f;
                if (c0 + 1 > rl_lo) as[nt][1] = -1e30f;
                if (c0     > rl_hi) as[nt][2] = -1e30f;
                if (c0 + 1 > rl_hi) as[nt][3] = -1e30f;
            }
            rm_lo = fmaxf(rm_lo, fmaxf(as[nt][0], as[nt][1]));
            rm_hi = fmaxf(rm_hi, fmaxf(as[nt][2], as[nt][3]));
        }
        rm_lo = fmaxf(rm_lo, __shfl_xor_sync(~0u, rm_lo, 1));
        rm_lo = fmaxf(rm_lo, __shfl_xor_sync(~0u, rm_lo, 2));
        rm_hi = fmaxf(rm_hi, __shfl_xor_sync(~0u, rm_hi, 1));
        rm_hi = fmaxf(rm_hi, __shfl_xor_sync(~0u, rm_hi, 2));
        float mn_lo = fmaxf(m_lo, rm_lo), mn_hi = fmaxf(m_hi, rm_hi);
        float sf_lo = expf(m_lo - mn_lo), sf_hi = expf(m_hi - mn_hi);
        m_lo = mn_lo; m_hi = mn_hi;

        float rs_lo = 0.f, rs_hi = 0.f;
        unsigned pf[16][2];
#pragma unroll
        for (int nt = 0; nt < 16; nt++) {
            float p0 = expf(as[nt][0] - mn_lo), p1 = expf(as[nt][1] - mn_lo);
            float p2 = expf(as[nt][2] - mn_hi), p3 = expf(as[nt][3] - mn_hi);
            rs_lo += p0 + p1; rs_hi += p2 + p3;
            __half2 h01 = __floats2half2_rn(p0, p1);
            __half2 h23 = __floats2half2_rn(p2, p3);
            pf[nt][0] = *(unsigned*)&h01;
            pf[nt][1] = *(unsigned*)&h23;
        }
        rs_lo += __shfl_xor_sync(~0u, rs_lo, 1);
        rs_lo += __shfl_xor_sync(~0u, rs_lo, 2);
        rs_hi += __shfl_xor_sync(~0u, rs_hi, 1);
        rs_hi += __shfl_xor_sync(~0u, rs_hi, 2);
        l_lo = l_lo * sf_lo + rs_lo;
        l_hi = l_hi * sf_hi + rs_hi;
#pragma unroll
        for (int nt = 0; nt < 8; nt++) {
            ao[nt][0] *= sf_lo; ao[nt][1] *= sf_lo;
            ao[nt][2] *= sf_hi; ao[nt][3] *= sf_hi;
        }
#pragma unroll
        for (int kc = 0; kc < 8; kc++) {
            unsigned af[4] = { pf[2*kc][0], pf[2*kc][1], pf[2*kc+1][0], pf[2*kc+1][1] };
            unsigned vf[8][2];
#pragma unroll
            for (int np = 0; np < 4; np++) {
                uint32_t bd = vbase +
                    (uint32_t)(((kc * 16 + bt_k) * FL_PITCH + np * 16 + bt_n8) * 2);
                ldsm4t(vf[2*np][0], vf[2*np][1], vf[2*np+1][0], vf[2*np+1][1], bd);
            }
#pragma unroll
            for (int nt = 0; nt < 8; nt++)
                mma_f16(ao[nt], af, vf[nt]);
        }
    }

    float il_lo = 1.f / l_lo, il_hi = 1.f / l_hi;
    __half* Ob = attn + (size_t)(b * NT + m0) * ND + h * 64;
#pragma unroll
    for (int nt = 0; nt < 8; nt++) {
        int c0 = nt * 8 + 2 * t;
        *(__half2*)(Ob + (size_t)(mwb + g) * ND + c0) =
            __floats2half2_rn(ao[nt][0] * il_lo, ao[nt][1] * il_lo);
        *(__half2*)(Ob + (size_t)(mwb + g + 8) * ND + c0) =
            __floats2half2_rn(ao[nt][2] * il_hi, ao[nt][3] * il_hi);
    }
}

// ---------------- small kernels ----------------
__global__ void embed_kernel(const int* __restrict__ ids, const float* __restrict__ tok,
                             const float* __restrict__ pos, float* __restrict__ x) {
    int n = blockIdx.x, t = n % NT, id = ids[n];
    const float* te = tok + (size_t)id * ND;
    const float* pe = pos + (size_t)t * ND;
    float* dst = x + (size_t)n * ND;
    for (int d = threadIdx.x; d < ND; d += 256) dst[d] = te[d] + pe[d];
}

__global__ void ln_kernel(const float* __restrict__ x, const float* __restrict__ w,
                          const float* __restrict__ b, __half* __restrict__ out) {
    int row = blockIdx.x * 8 + (threadIdx.x >> 5);
    int lane = threadIdx.x & 31;
    const float4* p = (const float4*)(x + (size_t)row * ND);
    float4 v[8];
    float s = 0.f;
#pragma unroll
    for (int i = 0; i < 8; i++) {
        v[i] = p[lane + i * 32];
        s += v[i].x + v[i].y + v[i].z + v[i].w;
    }
#pragma unroll
    for (int o = 16; o; o >>= 1) s += __shfl_xor_sync(~0u, s, o);
    float mu = s * (1.0f / ND);
    float q = 0.f;
#pragma unroll
    for (int i = 0; i < 8; i++) {
        float a = v[i].x - mu, c = v[i].y - mu, d = v[i].z - mu, e = v[i].w - mu;
        q += a * a + c * c + d * d + e * e;
    }
#pragma unroll
    for (int o = 16; o; o >>= 1) q += __shfl_xor_sync(~0u, q, o);
    float rs = rsqrtf(q * (1.0f / ND) + 1e-5f);
    const float4* wp = (const float4*)w;
    const float4* bp = (const float4*)b;
    __half2* op = (__half2*)(out + (size_t)row * ND);
#pragma unroll
    for (int i = 0; i < 8; i++) {
        int j = lane + i * 32;
        float4 wv = wp[j], bv = bp[j];
        op[j * 2] = __floats2half2_rn((v[i].x - mu) * rs * wv.x + bv.x,
                                      (v[i].y - mu) * rs * wv.y + bv.y);
        op[j * 2 + 1] = __floats2half2_rn((v[i].z - mu) * rs * wv.z + bv.z,
                                          (v[i].w - mu) * rs * wv.w + bv.w);
    }
}

__global__ void rope_kernel(__half* __restrict__ qkv) {
    int n = blockIdx.x, t = n % NT;
    __half* base = qkv + (size_t)n * 3072;
#pragma unroll
    for (int item = threadIdx.x; item < 512; item += 256) {
        int h = item >> 5, i = item & 31;
        float ang = (float)t * expf((float)(2 * i) * (-0.14391156831212806f));
        float s = sinf(ang), c = cosf(ang);
        __half* q = base + h * 64;
        __half* k = q + 1024;
        float q1 = __half2float(q[i]), q2 = __half2float(q[i + 32]);
        q[i] = __float2half_rn(q1 * c - q2 * s);
        q[i + 32] = __float2half_rn(q2 * c + q1 * s);
        float k1 = __half2float(k[i]), k2 = __half2float(k[i + 32]);
        k[i] = __float2half_rn(k1 * c - k2 * s);
        k[i + 32] = __float2half_rn(k2 * c + k1 * s);
    }
}

// ---------------- MoE ----------------
__global__ void route_kernel(const __half* __restrict__ ln, const float* __restrict__ wr,
                             const float* __restrict__ br, const float* __restrict__ wn,
                             const float* __restrict__ bn, float* __restrict__ route,
                             float* __restrict__ noise) {
    int n = blockIdx.x, tid = threadIdx.x;
    __shared__ float xs[ND];
    for (int d = tid; d < ND; d += 256) xs[d] = __half2float(ln[(size_t)n * ND + d]);
    __syncthreads();
    int w = tid >> 5, lane = tid & 31;
    float sr = 0.f, sn = 0.f;
    for (int d = lane; d < ND; d += 32) {
        float xv = xs[d];
        sr += xv * wr[(size_t)d * NE + w];
        sn += xv * wn[(size_t)d * NE + w];
    }
    for (int o = 16; o; o >>= 1) { sr += __shfl_down_sync(~0u, sr, o); sn += __shfl_down_sync(~0u, sn, o); }
    if (!lane) { route[n * NE + w] = sr + br[w]; noise[n * NE + w] = sn + bn[w]; }
}

__global__ void eps_kernel(unsigned k0, unsigned k1, float* __restrict__ eps) {
    int i = blockIdx.x * 256 + threadIdx.x;
    if (i >= NN * NE) return;
    unsigned o0, o1;
    threefry(k0, k1, 0u, (unsigned)i, o0, o1);
    eps[i] = bits_to_normal(o0 ^ o1);
}

__global__ void topk_kernel(const float* __restrict__ route, const float* __restrict__ noise,
                            const float* __restrict__ eps, float* __restrict__ gate,
                            unsigned char* __restrict__ mask) {
    int n = blockIdx.x * 256 + threadIdx.x;
    if (n >= NN) return;
    float nv[NE];
#pragma unroll
    for (int e = 0; e < NE; e++) {
        float x = noise[n * NE + e];
        float sp = fmaxf(x, 0.f) + log1pf(expf(-fabsf(x)));
        nv[e] = route[n * NE + e] + eps[n * NE + e] * sp;
    }
    int i1 = 0; float v1 = nv[0];
#pragma unroll
    for (int e = 1; e < NE; e++) if (nv[e] > v1) { v1 = nv[e]; i1 = e; }
    int i2 = -1; float v2 = -3.4e38f;
#pragma unroll
    for (int e = 0; e < NE; e++) if (e != i1 && nv[e] > v2) { v2 = nv[e]; i2 = e; }
    float e2 = expf(v2 - v1);
    float Z = 1.0f + e2;
#pragma unroll
    for (int e = 0; e < NE; e++)
        gate[n * NE + e] = (e == i1) ? (1.0f / Z) : ((e == i2) ? (e2 / Z) : 0.f);
    mask[n] = (unsigned char)((1u << i1) | (1u << i2));
}

__global__ void select_kernel(const unsigned char* __restrict__ mask, int* __restrict__ sel,
                              int* __restrict__ slot, int* __restrict__ cnt) {
    int e = blockIdx.x, lane = threadIdx.x;
    int base = 0;
    for (int n0 = 0; n0 < NN; n0 += 32) {
        int n = n0 + lane;
        bool f = (mask[n] >> e) & 1;
        unsigned bal = __ballot_sync(0xffffffffu, f);
        int pos = base + __popc(bal & ((1u << lane) - 1u));
        int sl = (f && pos < NCAP) ? pos : -1;
        slot[(size_t)e * NN + n] = sl;
        if (sl >= 0) sel[e * NCAP + sl] = n;
        base += __popc(bal);
    }
    if (!lane) cnt[e] = base < NCAP ? base : NCAP;
}

// fused scatter + next LayerNorm
__global__ void moe_scatter_ln_kernel(const __half* __restrict__ eo, const int* __restrict__ slot,
                                      const float* __restrict__ gate, float* __restrict__ x,
                                      const float* __restrict__ w, const float* __restrict__ b,
                                      __half* __restrict__ lnout) {
    int n = blockIdx.x, tid = threadIdx.x;
    __shared__ int ss[NE];
    __shared__ float gg[NE];
    __shared__ float red[8];
    if (tid < NE) { ss[tid] = slot[(size_t)tid * NN + n]; gg[tid] = gate[n * NE + tid]; }
    __syncthreads();
    float vals[4];
    float s = 0.f;
#pragma unroll
    for (int i = 0; i < 4; i++) {
        int d = tid + i * 256;
        float acc = x[(size_t)n * ND + d];
#pragma unroll
        for (int e = 0; e < NE; e++) {
            int sl = ss[e];
            if (sl >= 0) acc += gg[e] * __half2float(eo[((size_t)e * NCAP + sl) * ND + d]);
        }
        vals[i] = acc; s += acc;
        x[(size_t)n * ND + d] = acc;
    }
    int lane = tid & 31, warp = tid >> 5;
#pragma unroll
    for (int o = 16; o; o >>= 1) s += __shfl_xor_sync(~0u, s, o);
    if (!lane) red[warp] = s;
    __syncthreads();
    if (tid < 8) {
        float t = red[tid];
#pragma unroll
        for (int o = 4; o; o >>= 1) t += __shfl_xor_sync(0xffu, t, o);
        red[tid] = t;
    }
    __syncthreads();
    float mu = red[0] * (1.0f / ND);
    float q = 0.f;
#pragma unroll
    for (int i = 0; i < 4; i++) { float d = vals[i] - mu; q += d * d; }
#pragma unroll
    for (int o = 16; o; o >>= 1) q += __shfl_xor_sync(~0u, q, o);
    __syncthreads();
    if (!lane) red[warp] = q;
    __syncthreads();
    if (tid < 8) {
        float t = red[tid];
#pragma unroll
        for (int o = 4; o; o >>= 1) t += __shfl_xor_sync(0xffu, t, o);
        red[tid] = t;
    }
    __syncthreads();
    float rs = rsqrtf(red[0] * (1.0f / ND) + 1e-5f);
#pragma unroll
    for (int i = 0; i < 4; i++) {
        int d = tid + i * 256;
        lnout[(size_t)n * ND + d] =
            __float2half_rn((vals[i] - mu) * rs * w[d] + b[d]);
    }
}

// ---------------- loss ----------------
__global__ void loss_kernel(const __half* __restrict__ logits, const int* __restrict__ ids,
                            float* __restrict__ nll, float* __restrict__ vld) {
    int n = blockIdx.x, tid = threadIdx.x;
    int b = n / NT, t = n % NT;
    if (t == NT - 1) { if (!tid) { nll[n] = 0.f; vld[n] = 0.f; } return; }
    int tgt = ids[b * NT + t + 1];
    const __half2* row2 = (const __half2*)(logits + (size_t)n * NV);
    float m = -3.4e38f, s = 0.f;
    for (int j = tid; j < NV / 2; j += 256) {
        float2 l = __half22float2(row2[j]);
        float mx = fmaxf(l.x, l.y);
        if (mx > m) { s = s * expf(m - mx); m = mx; }
        s += expf(l.x - m) + expf(l.y - m);
    }
    __shared__ float sm[256], ssum[256];
    sm[tid] = m; ssum[tid] = s; __syncthreads();
    for (int st = 128; st; st >>= 1) {
        if (tid < st) {
            float m1 = sm[tid], s1 = ssum[tid], m2 = sm[tid + st], s2 = ssum[tid + st];
            float M = fmaxf(m1, m2);
            ssum[tid] = s1 * expf(m1 - M) + s2 * expf(m2 - M);
            sm[tid] = M;
        }
        __syncthreads();
    }
    if (!tid) {
        float lse = sm[0] + logf(ssum[0]);
        float v = (tgt != 2) ? 1.f : 0.f;
        float lt = __half2float(logits[(size_t)n * NV + tgt]);
        nll[n] = -(lt - lse) * v;
        vld[n] = v;
    }
}

__global__ void reduce_kernel(const float* __restrict__ nll, const float* __restrict__ vld,
                              float* __restrict__ out) {
    __shared__ float s1[256], s2[256];
    int tid = threadIdx.x;
    float a = 0.f, b = 0.f;
    for (int i = tid; i < NN; i += 256) { a += nll[i]; b += vld[i]; }
    s1[tid] = a; s2[tid] = b; __syncthreads();
    for (int st = 128; st; st >>= 1) { if (tid < st) { s1[tid] += s1[tid + st]; s2[tid] += s2[tid + st]; } __syncthreads(); }
    if (!tid) out[0] = s1[0] / fmaxf(s2[0], 1.0f);
}

// ---------------- host launch ----------------
#define STG_T(BM, BN) (((BM) + (BN)) * 72)
#define STG_F(BM, BN) ((BM) * 72 + 64 * ((BN) + 8))

extern "C" void kernel_launch(void* const* d_in, const int* in_sizes, int n_in,
                              void* d_out, int out_size) {
    const int*   ids     = (const int*)d_in[0];
    const float* tok_emb = (const float*)d_in[1];
    const float* pos_emb = (const float*)d_in[2];
    const float* ln1_w   = (const float*)d_in[3];
    const float* ln1_b   = (const float*)d_in[4];
    const float* ln2_w   = (const float*)d_in[5];
    const float* ln2_b   = (const float*)d_in[6];
    const float* w_qkv   = (const float*)d_in[7];
    const float* w_out   = (const float*)d_in[8];
    const float* w_route = (const float*)d_in[9];
    const float* b_route = (const float*)d_in[10];
    const float* w_noise = (const float*)d_in[11];
    const float* b_noise = (const float*)d_in[12];
    const float* w_e1    = (const float*)d_in[13];
    const float* b_e1    = (const float*)d_in[14];
    const float* w_e2    = (const float*)d_in[15];
    const float* b_e2    = (const float*)d_in[16];
    const float* lnf_w   = (const float*)d_in[17];
    const float* lnf_b   = (const float*)d_in[18];
    float* out = (float*)d_out;

    float *x, *route, *noise, *eps, *gate, *nll, *vld;
    __half *ln16, *qkv16, *attn16, *h116, *eo16, *lg16;
    __half *wqkv16, *wout16, *we116, *we216, *tok16;
    unsigned char* mask; int *sel, *slot, *cnt;
    cudaGetSymbolAddress((void**)&x, g_x);
    cudaGetSymbolAddress((void**)&ln16, g_ln16);
    cudaGetSymbolAddress((void**)&qkv16, g_qkv16);
    cudaGetSymbolAddress((void**)&attn16, g_attn16);
    cudaGetSymbolAddress((void**)&route, g_route);
    cudaGetSymbolAddress((void**)&noise, g_noise);
    cudaGetSymbolAddress((void**)&eps, g_eps);
    cudaGetSymbolAddress((void**)&gate, g_gate);
    cudaGetSymbolAddress((void**)&mask, g_mask);
    cudaGetSymbolAddress((void**)&sel, g_sel);
    cudaGetSymbolAddress((void**)&slot, g_slot);
    cudaGetSymbolAddress((void**)&cnt, g_cnt);
    cudaGetSymbolAddress((void**)&h116, g_h116);
    cudaGetSymbolAddress((void**)&eo16, g_eo16);
    cudaGetSymbolAddress((void**)&lg16, g_log16);
    cudaGetSymbolAddress((void**)&nll, g_nll);
    cudaGetSymbolAddress((void**)&vld, g_vld);
    cudaGetSymbolAddress((void**)&wqkv16, g_wqkv16);
    cudaGetSymbolAddress((void**)&wout16, g_wout16);
    cudaGetSymbolAddress((void**)&we116, g_we116);
    cudaGetSymbolAddress((void**)&we216, g_we216);
    cudaGetSymbolAddress((void**)&tok16, g_tok16);

    constexpr int SM_T = 3 * STG_T(256, 128) * 2;
    constexpr int SM_F = 3 * STG_F(256, 128) * 2;
    auto* kqkv = hgemm_ca<512,256,128,4,4,false,false,false,false,true ,false>;
    auto* kproj= hgemm_ca<512,256,128,4,4,false,false,false,true ,false,false>;
    auto* kfc1 = hgemm_ca<512,256,128,4,4,false,true ,true ,false,true ,true >;
    auto* kfc2 = hgemm_ca<512,256,128,4,4,false,true ,false,false,true ,false>;
    auto* kvoc = hgemm_ca<512,256,128,4,4,true ,false,false,false,true ,false>;
    cudaFuncSetAttribute(kqkv, cudaFuncAttributeMaxDynamicSharedMemorySize, SM_F);
    cudaFuncSetAttribute(kproj,cudaFuncAttributeMaxDynamicSharedMemorySize, SM_F);
    cudaFuncSetAttribute(kfc1, cudaFuncAttributeMaxDynamicSharedMemorySize, SM_F);
    cudaFuncSetAttribute(kfc2, cudaFuncAttributeMaxDynamicSharedMemorySize, SM_F);
    cudaFuncSetAttribute(kvoc, cudaFuncAttributeMaxDynamicSharedMemorySize, SM_T);
    cudaFuncSetAttribute(flash_kernel, cudaFuncAttributeMaxDynamicSharedMemorySize, FL_SMEM);

    {
        size_t n;
        n = (size_t)NLAY * ND * 3 * ND / 4;
        cvt_h_kernel<<<(unsigned)((n + 255) / 256), 256>>>(w_qkv, wqkv16, n);
        n = (size_t)NLAY * ND * ND / 4;
        cvt_h_kernel<<<(unsigned)((n + 255) / 256), 256>>>(w_out, wout16, n);
        n = (size_t)NLAY * NE * ND * NFF / 4;
        cvt_h_kernel<<<(unsigned)((n + 255) / 256), 256>>>(w_e1, we116, n);
        n = (size_t)NLAY * NE * NFF * ND / 4;
        cvt_h_kernel<<<(unsigned)((n + 255) / 256), 256>>>(w_e2, we216, n);
        n = (size_t)NV * ND / 4;
        cvt_h_kernel<<<(unsigned)((n + 255) / 256), 256>>>(tok_emb, tok16, n);
    }

    embed_kernel<<<NN, 256>>>(ids, tok_emb, pos_emb, x);
    ln_kernel<<<NN / 8, 256>>>(x, ln1_w, ln1_b, ln16);

    for (int l = 0; l < NLAY; l++) {
        // ---- attention ----
        kqkv<<<dim3(24, 16, 1), 512, SM_F>>>(
            ln16, wqkv16 + (size_t)l * ND * 3 * ND, nullptr, qkv16, nullptr,
            ND, ND, 3 * ND, 3 * ND, 1, 0, 0, 0, 0, 0, 0, 0, 1.0f);
        rope_kernel<<<NN, 256>>>(qkv16);
        flash_kernel<<<dim3(NT / 128, NB * NH), 256, FL_SMEM>>>(qkv16, attn16);
        kproj<<<dim3(8, 16, 1), 512, SM_F>>>(
            attn16, wout16 + (size_t)l * ND * ND, nullptr, x, nullptr,
            ND, ND, ND, ND, 1, 0, 0, 0, 0, 0, 0, 0, 1.0f);

        // ---- MoE ----
        ln_kernel<<<NN / 8, 256>>>(x, ln2_w + l * ND, ln2_b + l * ND, ln16);
        route_kernel<<<NN, 256>>>(ln16, w_route + (size_t)l * ND * NE, b_route + l * NE,
                                  w_noise + (size_t)l * ND * NE, b_noise + l * NE, route, noise);
        unsigned k0, k1;
        threefry(0u, 1234u, 0u, (unsigned)l, k0, k1);
        eps_kernel<<<(NN * NE + 255) / 256, 256>>>(k0, k1, eps);
        topk_kernel<<<(NN + 255) / 256, 256>>>(route, noise, eps, gate, mask);
        select_kernel<<<NE, 32>>>(mask, sel, slot, cnt);
        kfc1<<<dim3(32, 4, NE), 512, SM_F>>>(
            ln16, we116 + (size_t)l * NE * ND * NFF, b_e1 + (size_t)l * NE * NFF, h116, sel,
            ND, ND, NFF, NFF, 1,
            0, 0, (size_t)NFF * ND, 0,
            (size_t)NCAP * NFF, 0, NFF, 1.0f);
        kfc2<<<dim3(8, 4, NE), 512, SM_F>>>(
            h116, we216 + (size_t)l * NE * NFF * ND, b_e2 + (size_t)l * NE * ND, eo16, nullptr,
            NFF, NFF, ND, ND, 1,
            (size_t)NCAP * NFF, 0, (size_t)ND * NFF, 0,
            (size_t)NCAP * ND, 0, ND, 1.0f);
        const float* nw = (l + 1 < NLAY) ? (ln1_w + (size_t)(l + 1) * ND) : lnf_w;
        const float* nb = (l + 1 < NLAY) ? (ln1_b + (size_t)(l + 1) * ND) : lnf_b;
        moe_scatter_ln_kernel<<<NN, 256>>>(eo16, slot, gate, x, nw, nb, ln16);
    }

    kvoc<<<dim3(NV / 128, 16, 1), 512, SM_T>>>(
        ln16, tok16, nullptr, lg16, nullptr,
        ND, ND, ND, NV, 1, 0, 0, 0, 0, 0, 0, 0, 1.0f);
    loss_kernel<<<NN, 256>>>(lg16, ids, nll, vld);
    reduce_kernel<<<1, 256>>>(nll, vld, out);
}

// round 14
// speedup vs baseline: 3.1662x; 1.0300x over previous
#include <cuda_runtime.h>
#include <cuda_fp16.h>
#include <cstdint>
#include <cstddef>

#define NB 2
#define NT 2048
#define ND 1024
#define NH 16
#define NLAY 2
#define NE 8
#define NV 32000
#define NN (NB*NT)
#define NCAP 1024
#define NFF 4096
#define NPART (NV/128)

// ---------------- device scratch ----------------
__device__ float  g_x   [(size_t)NN*ND];
__device__ __half g_ln16[(size_t)NN*ND];
__device__ __half g_qkv16[(size_t)NN*3*ND];
__device__ __half g_attn16[(size_t)NN*ND];
__device__ float  g_route[NN*NE];
__device__ float  g_noise[NN*NE];
__device__ float  g_eps  [NN*NE];
__device__ float  g_gate [NN*NE];
__device__ unsigned char g_mask[NN];
__device__ int    g_sel [NE*NCAP];
__device__ int    g_slot[NE*NN];
__device__ int    g_cnt [NE];
__device__ __half g_h116[(size_t)NE*NCAP*NFF];
__device__ __half g_eo16[(size_t)NE*NCAP*ND];
__device__ float2 g_part[(size_t)NN*NPART];
__device__ float  g_tlog[NN];
__device__ float  g_nll [NN];
__device__ float  g_vld [NN];
// fp16 weight copies (ORIGINAL [K,N] layout — no transpose)
__device__ __half g_wqkv16[(size_t)NLAY*ND*3*ND];
__device__ __half g_wout16[(size_t)NLAY*ND*ND];
__device__ __half g_we116 [(size_t)NLAY*NE*ND*NFF];
__device__ __half g_we216 [(size_t)NLAY*NE*NFF*ND];
__device__ __half g_tok16 [(size_t)NV*ND];

// ---------------- threefry2x32 (matches JAX) ----------------
__host__ __device__ __forceinline__ void threefry(unsigned k0, unsigned k1,
                                                  unsigned x0, unsigned x1,
                                                  unsigned& o0, unsigned& o1) {
    unsigned ks2 = k0 ^ k1 ^ 0x1BD11BDAu;
    x0 += k0; x1 += k1;
#define TFR(r) { x0 += x1; x1 = (x1 << (r)) | (x1 >> (32 - (r))); x1 ^= x0; }
    TFR(13) TFR(15) TFR(26) TFR(6)  x0 += k1;  x1 += ks2 + 1u;
    TFR(17) TFR(29) TFR(16) TFR(24) x0 += ks2; x1 += k0 + 2u;
    TFR(13) TFR(15) TFR(26) TFR(6)  x0 += k0;  x1 += k1 + 3u;
    TFR(17) TFR(29) TFR(16) TFR(24) x0 += k1;  x1 += ks2 + 4u;
    TFR(13) TFR(15) TFR(26) TFR(6)  x0 += ks2; x1 += k0 + 5u;
#undef TFR
    o0 = x0; o1 = x1;
}

__device__ __forceinline__ float xla_erfinv(float x) {
    float w = -log1pf(-x * x);
    float p;
    if (w < 5.f) {
        w -= 2.5f;
        p = 2.81022636e-08f;
        p = fmaf(p, w, 3.43273939e-07f);
        p = fmaf(p, w, -3.5233877e-06f);
        p = fmaf(p, w, -4.39150654e-06f);
        p = fmaf(p, w, 0.00021858087f);
        p = fmaf(p, w, -0.00125372503f);
        p = fmaf(p, w, -0.00417768164f);
        p = fmaf(p, w, 0.246640727f);
        p = fmaf(p, w, 1.50140941f);
    } else {
        w = sqrtf(w) - 3.f;
        p = -0.000200214257f;
        p = fmaf(p, w, 0.000100950558f);
        p = fmaf(p, w, 0.00134934322f);
        p = fmaf(p, w, -0.00367342844f);
        p = fmaf(p, w, 0.00573950773f);
        p = fmaf(p, w, -0.0076224613f);
        p = fmaf(p, w, 0.00943887047f);
        p = fmaf(p, w, 1.00167406f);
        p = fmaf(p, w, 2.83297682f);
    }
    return p * x;
}

__device__ __forceinline__ float bits_to_normal(unsigned bits) {
    float f = __uint_as_float((bits >> 9) | 0x3F800000u) - 1.0f;
    const float lo = -0.99999994f;
    float u = fmaf(f, 2.0f, lo);
    u = fmaxf(u, lo);
    return 1.41421356237f * xla_erfinv(u);
}

// ---------------- mma / ldmatrix / cp.async helpers ----------------
__device__ __forceinline__ void mma_f16(float* c, const unsigned* a, const unsigned* b) {
    asm volatile("mma.sync.aligned.m16n8k16.row.col.f32.f16.f16.f32 "
        "{%0,%1,%2,%3}, {%4,%5,%6,%7}, {%8,%9}, {%0,%1,%2,%3};"
        : "+f"(c[0]), "+f"(c[1]), "+f"(c[2]), "+f"(c[3])
        : "r"(a[0]), "r"(a[1]), "r"(a[2]), "r"(a[3]), "r"(b[0]), "r"(b[1]));
}
__device__ __forceinline__ void ldsm4(unsigned& d0, unsigned& d1, unsigned& d2, unsigned& d3,
                                      uint32_t addr) {
    asm volatile("ldmatrix.sync.aligned.m8n8.x4.shared.b16 {%0,%1,%2,%3}, [%4];"
        : "=r"(d0), "=r"(d1), "=r"(d2), "=r"(d3) : "r"(addr));
}
__device__ __forceinline__ void ldsm4t(unsigned& d0, unsigned& d1, unsigned& d2, unsigned& d3,
                                       uint32_t addr) {
    asm volatile("ldmatrix.sync.aligned.m8n8.x4.trans.shared.b16 {%0,%1,%2,%3}, [%4];"
        : "=r"(d0), "=r"(d1), "=r"(d2), "=r"(d3) : "r"(addr));
}
__device__ __forceinline__ uint32_t smem_u32(const void* p) {
    uint32_t a;
    asm("{ .reg .u64 t; cvta.to.shared.u64 t, %1; cvt.u32.u64 %0, t; }" : "=r"(a) : "l"(p));
    return a;
}
__device__ __forceinline__ void cpa16(uint32_t dst, const void* src) {
    asm volatile("cp.async.ca.shared.global [%0], [%1], 16;" :: "r"(dst), "l"(src));
}
#define CPA_COMMIT() asm volatile("cp.async.commit_group;" ::: "memory")
#define CPA_WAIT(n)  asm volatile("cp.async.wait_group %0;" :: "n"(n) : "memory")

// ---------------- weight prep ----------------
__global__ void cvt_h_kernel(const float* __restrict__ in, __half* __restrict__ out, size_t n4) {
    size_t i = (size_t)blockIdx.x * 256 + threadIdx.x;
    if (i >= n4) return;
    float4 v = ((const float4*)in)[i];
    __half2* o = (__half2*)out;
    o[i * 2] = __floats2half2_rn(v.x, v.y);
    o[i * 2 + 1] = __floats2half2_rn(v.z, v.w);
}

// ---------------- cp.async 3-stage fp16 GEMM ----------------
// LOSS: no C write; per-row (max,sumexp) partials + target logit capture.
template<int TH, int BM, int BN, int WR, int WC, bool BNK, bool BIAS, bool RELU,
         bool ACCUM, bool OUTH, bool GATHER, bool LOSS>
__global__ void __launch_bounds__(TH)
hgemm_ca(const __half* __restrict__ A, const __half* __restrict__ B,
         const float* __restrict__ bias, void* __restrict__ Cv,
         const int* __restrict__ gsel,
         const int* __restrict__ lids, float2* __restrict__ part,
         float* __restrict__ tlog,
         int K, int lda, int ldb, int ldc, int zdiv,
         size_t sA, size_t sA2, size_t sB, size_t sB2,
         size_t sC, size_t sC2, size_t sBias, float scale)
{
    constexpr int BK = 64;
    constexpr int LDS = 72;
    constexpr int BNP = BN + 8;
    constexpr int WM = BM / WR, WN = BN / WC;
    constexpr int MT = WM / 16, NT4 = WN / 8, NP = NT4 / 2;
    constexpr int ANV = (BM * 8) / TH;
    constexpr int BNV = BNK ? (BN * 8) / TH : (BK * BN) / (8 * TH);
    constexpr int STG = BNK ? (BM + BN) * LDS : BM * LDS + BK * BNP;

    const int m0 = blockIdx.y * BM, n0 = blockIdx.x * BN;
    const int tid = threadIdx.x, lane = tid & 31, warp = tid >> 5;
    const int wr = warp / WC, wc = warp % WC;
    const int g = lane >> 2, t = lane & 3;

    {
        int z = blockIdx.z, z1 = z / zdiv, z0 = z - z1 * zdiv;
        A += (size_t)z1 * sA + (size_t)z0 * sA2;
        B += (size_t)z1 * sB + (size_t)z0 * sB2;
        Cv = (char*)Cv + ((size_t)z1 * sC + (size_t)z0 * sC2) * (OUTH ? 2 : 4);
        if (BIAS) bias += (size_t)z1 * sBias;
    }

    const int nk = K / BK;

    extern __shared__ __half shh[];
    const uint32_t sbase = smem_u32(shh);

    const int a_r = lane & 15, a_c8 = (lane >> 4) * 8;
    const int b_r = (lane & 7) + (lane >> 4) * 8, b_c8 = ((lane >> 3) & 1) * 8;
    const int q8 = lane & 7, quad = lane >> 3;
    const int bt_k = (quad & 1) * 8 + q8, bt_n8 = (quad >> 1) * 8;
    const int mwb = wr * WM, nwb = wc * WN;

    const int ar = tid >> 3, aq = tid & 7;
    int arows[ANV];
#pragma unroll
    for (int i = 0; i < ANV; i++) {
        int r = m0 + ar + i * (TH >> 3);
        arows[i] = GATHER ? gsel[(size_t)blockIdx.z * NCAP + r] : r;
    }

    auto issue = [&](int ks, int st) {
        uint32_t so = sbase + (uint32_t)(st * STG) * 2;
#pragma unroll
        for (int i = 0; i < ANV; i++) {
            int row = ar + i * (TH >> 3);
            cpa16(so + (uint32_t)(row * LDS + aq * 8) * 2,
                  A + (size_t)arows[i] * lda + ks * BK + aq * 8);
        }
        if (BNK) {
            const __half* Bc = B + (size_t)n0 * ldb + ks * BK;
#pragma unroll
            for (int i = 0; i < BNV; i++) {
                int row = ar + i * (TH >> 3);
                cpa16(so + (uint32_t)((BM + row) * LDS + aq * 8) * 2,
                      Bc + (size_t)row * ldb + aq * 8);
            }
        } else {
            const __half* Bc = B + (size_t)(ks * BK) * ldb + n0;
#pragma unroll
            for (int i = 0; i < BNV; i++) {
                int idx = tid + i * TH;
                int kk = idx / (BN / 8), nq = idx % (BN / 8);
                cpa16(so + (uint32_t)(BM * LDS + kk * BNP + nq * 8) * 2,
                      Bc + (size_t)kk * ldb + nq * 8);
            }
        }
        CPA_COMMIT();
    };

    float acc[MT][NT4][4] = {};

    issue(0, 0);
    if (nk > 1) issue(1, 1);
    if (nk > 1) { CPA_WAIT(1); } else { CPA_WAIT(0); }
    __syncthreads();

    for (int ks = 0; ks < nk; ks++) {
        int cur = ks % 3;
        bool more2 = (ks + 2 < nk);
        if (more2) issue(ks + 2, (ks + 2) % 3);
        uint32_t abase = sbase + (uint32_t)(cur * STG) * 2;
        uint32_t bbase = abase + (uint32_t)(BM * LDS) * 2;
#pragma unroll
        for (int kq = 0; kq < 4; kq++) {
            unsigned af[MT][4], bf[NT4][2];
#pragma unroll
            for (int mt = 0; mt < MT; mt++) {
                uint32_t ad = abase +
                    (uint32_t)(((mwb + mt * 16 + a_r) * LDS + kq * 16 + a_c8) * 2);
                ldsm4(af[mt][0], af[mt][1], af[mt][2], af[mt][3], ad);
            }
            if (BNK) {
#pragma unroll
                for (int np = 0; np < NP; np++) {
                    uint32_t bd = bbase +
                        (uint32_t)(((nwb + np * 16 + b_r) * LDS + kq * 16 + b_c8) * 2);
                    ldsm4(bf[2*np][0], bf[2*np][1], bf[2*np+1][0], bf[2*np+1][1], bd);
                }
            } else {
#pragma unroll
                for (int np = 0; np < NP; np++) {
                    uint32_t bd = bbase +
                        (uint32_t)(((kq * 16 + bt_k) * BNP + nwb + np * 16 + bt_n8) * 2);
                    ldsm4t(bf[2*np][0], bf[2*np][1], bf[2*np+1][0], bf[2*np+1][1], bd);
                }
            }
#pragma unroll
            for (int mt = 0; mt < MT; mt++)
#pragma unroll
                for (int nt = 0; nt < NT4; nt++)
                    mma_f16(acc[mt][nt], af[mt], bf[nt]);
        }
        if (ks + 1 < nk) {
            if (more2) { CPA_WAIT(1); } else { CPA_WAIT(0); }
            __syncthreads();
        }
    }

    if (LOSS) {
        // per-row (max, sumexp) over this tile's 128 cols + target logit capture
        __syncthreads();
        float2* psh = (float2*)shh;           // [BM][WC]
#pragma unroll
        for (int mt = 0; mt < MT; mt++) {
            int rl = mwb + mt * 16 + g, rh = rl + 8;
            float ml = -1e30f, mh = -1e30f;
#pragma unroll
            for (int nt = 0; nt < NT4; nt++) {
                ml = fmaxf(ml, fmaxf(acc[mt][nt][0], acc[mt][nt][1]));
                mh = fmaxf(mh, fmaxf(acc[mt][nt][2], acc[mt][nt][3]));
            }
            ml = fmaxf(ml, __shfl_xor_sync(~0u, ml, 1));
            ml = fmaxf(ml, __shfl_xor_sync(~0u, ml, 2));
            mh = fmaxf(mh, __shfl_xor_sync(~0u, mh, 1));
            mh = fmaxf(mh, __shfl_xor_sync(~0u, mh, 2));
            float sl = 0.f, shi = 0.f;
#pragma unroll
            for (int nt = 0; nt < NT4; nt++) {
                sl += expf(acc[mt][nt][0] - ml) + expf(acc[mt][nt][1] - ml);
                shi += expf(acc[mt][nt][2] - mh) + expf(acc[mt][nt][3] - mh);
            }
            sl += __shfl_xor_sync(~0u, sl, 1);
            sl += __shfl_xor_sync(~0u, sl, 2);
            shi += __shfl_xor_sync(~0u, shi, 1);
            shi += __shfl_xor_sync(~0u, shi, 2);
            if (t == 0) {
                psh[rl * WC + wc] = make_float2(ml, sl);
                psh[rh * WC + wc] = make_float2(mh, shi);
            }
            // target logit
            int grl = m0 + rl, grh = m0 + rh;
            int tgl = ((grl % NT) != NT - 1) ? lids[grl + 1] : -1;
            int tgh = ((grh % NT) != NT - 1) ? lids[grh + 1] : -1;
#pragma unroll
            for (int nt = 0; nt < NT4; nt++) {
                int c0 = n0 + nwb + nt * 8 + 2 * t;
                if (c0 == tgl)     tlog[grl] = acc[mt][nt][0];
                if (c0 + 1 == tgl) tlog[grl] = acc[mt][nt][1];
                if (c0 == tgh)     tlog[grh] = acc[mt][nt][2];
                if (c0 + 1 == tgh) tlog[grh] = acc[mt][nt][3];
            }
        }
        __syncthreads();
        if (tid < BM) {
            float m = -1e30f, s = 0.f;
#pragma unroll
            for (int w = 0; w < WC; w++) {
                float2 p = psh[tid * WC + w];
                if (p.x > m) { s = s * expf(m - p.x) + p.y; m = p.x; }
                else s += p.y * expf(p.x - m);
            }
            part[(size_t)(m0 + tid) * NPART + blockIdx.x] = make_float2(m, s);
        }
        return;
    }

    __half* Ch = (__half*)Cv;
    float*  Cf = (float*)Cv;
#pragma unroll
    for (int mt = 0; mt < MT; mt++) {
#pragma unroll
        for (int nt = 0; nt < NT4; nt++) {
            int r0 = m0 + mwb + mt * 16 + g;
            int c0 = n0 + nwb + nt * 8 + 2 * t;
            float v0 = acc[mt][nt][0] * scale, v1 = acc[mt][nt][1] * scale;
            float v2 = acc[mt][nt][2] * scale, v3 = acc[mt][nt][3] * scale;
            if (BIAS) {
                float b0 = bias[c0], b1 = bias[c0 + 1];
                v0 += b0; v1 += b1; v2 += b0; v3 += b1;
            }
            if (RELU) {
                v0 = fmaxf(v0, 0.f); v1 = fmaxf(v1, 0.f);
                v2 = fmaxf(v2, 0.f); v3 = fmaxf(v3, 0.f);
            }
            if (OUTH) {
                *(__half2*)(Ch + (size_t)r0 * ldc + c0) = __floats2half2_rn(v0, v1);
                *(__half2*)(Ch + (size_t)(r0 + 8) * ldc + c0) = __floats2half2_rn(v2, v3);
            } else {
                float* p0 = Cf + (size_t)r0 * ldc + c0;
                float* p1 = Cf + (size_t)(r0 + 8) * ldc + c0;
                if (ACCUM) {
                    float2 o0 = *(float2*)p0, o1 = *(float2*)p1;
                    v0 += o0.x; v1 += o0.y; v2 += o1.x; v3 += o1.y;
                }
                *(float2*)p0 = make_float2(v0, v1);
                *(float2*)p1 = make_float2(v2, v3);
            }
        }
    }
}

// ---------------- FlashAttention-2 (causal, 128-row q-tiles, 256 thr) ----------------
#define FL_PITCH 72
#define FL_QSZ   (128 * FL_PITCH)
#define FL_KVSZ  (2 * 128 * FL_PITCH)
#define FL_SMEM  ((FL_QSZ + 2 * FL_KVSZ) * 2)

__global__ void __launch_bounds__(256)
flash_kernel(const __half* __restrict__ qkv, __half* __restrict__ attn) {
    int z = blockIdx.y, b = z >> 4, h = z & 15;
    int qt = (int)gridDim.x - 1 - (int)blockIdx.x;
    int m0 = qt * 128;
    const __half* Qg = qkv + (size_t)b * NT * 3072 + h * 64;
    const __half* Kg = Qg + 1024;
    const __half* Vg = Qg + 2048;

    extern __shared__ __half sh[];
    const uint32_t sb = smem_u32(sh);

    int tid = threadIdx.x, lane = tid & 31, warp = tid >> 5;
    int g = lane >> 2, t = lane & 3;
    int lr = tid >> 3, lq = tid & 7;

#pragma unroll
    for (int i = 0; i < 4; i++) {
        int row = lr + i * 32;
        cpa16(sb + (uint32_t)(row * FL_PITCH + lq * 8) * 2,
              Qg + (size_t)(m0 + row) * 3072 + lq * 8);
    }
    CPA_COMMIT();

    auto issue_kv = [&](int j, int st) {
        uint32_t so = sb + (uint32_t)(FL_QSZ + st * FL_KVSZ) * 2;
#pragma unroll
        for (int i = 0; i < 4; i++) {
            int row = lr + i * 32;
            cpa16(so + (uint32_t)(row * FL_PITCH + lq * 8) * 2,
                  Kg + (size_t)(j * 128 + row) * 3072 + lq * 8);
        }
#pragma unroll
        for (int i = 0; i < 4; i++) {
            int row = lr + i * 32;
            cpa16(so + (uint32_t)((128 + row) * FL_PITCH + lq * 8) * 2,
                  Vg + (size_t)(j * 128 + row) * 3072 + lq * 8);
        }
        CPA_COMMIT();
    };
    issue_kv(0, 0);
    CPA_WAIT(0);
    __syncthreads();

    const int mwb = warp * 16;
    const int a_r = lane & 15, a_c8 = (lane >> 4) * 8;
    unsigned qf[4][4];
#pragma unroll
    for (int kq = 0; kq < 4; kq++) {
        uint32_t ad = sb + (uint32_t)(((mwb + a_r) * FL_PITCH + kq * 16 + a_c8) * 2);
        ldsm4(qf[kq][0], qf[kq][1], qf[kq][2], qf[kq][3], ad);
    }

    const int b_r = (lane & 7) + (lane >> 4) * 8, b_c8 = ((lane >> 3) & 1) * 8;
    const int q8 = lane & 7, quad = lane >> 3;
    const int bt_k = (quad & 1) * 8 + q8, bt_n8 = (quad >> 1) * 8;

    float m_lo = -1e30f, m_hi = -1e30f, l_lo = 0.f, l_hi = 0.f;
    float ao[8][4] = {};
    const int rl_lo = mwb + g, rl_hi = mwb + g + 8;

    for (int j = 0; j <= qt; j++) {
        int st = j & 1;
        __syncthreads();
        if (j < qt) issue_kv(j + 1, st ^ 1);
        if (j < qt) { CPA_WAIT(1); } else { CPA_WAIT(0); }
        __syncthreads();

        uint32_t kbase = sb + (uint32_t)(FL_QSZ + st * FL_KVSZ) * 2;
        uint32_t vbase = kbase + (uint32_t)(128 * FL_PITCH) * 2;

        float as[16][4] = {};
#pragma unroll
        for (int kq = 0; kq < 4; kq++) {
            unsigned bf[16][2];
#pragma unroll
            for (int np = 0; np < 8; np++) {
                uint32_t bd = kbase +
                    (uint32_t)(((np * 16 + b_r) * FL_PITCH + kq * 16 + b_c8) * 2);
                ldsm4(bf[2*np][0], bf[2*np][1], bf[2*np+1][0], bf[2*np+1][1], bd);
            }
#pragma unroll
            for (int nt = 0; nt < 16; nt++)
                mma_f16(as[nt], qf[kq], bf[nt]);
        }

        float rm_lo = -1e30f, rm_hi = -1e30f;
#pragma unroll
        for (int nt = 0; nt < 16; nt++) {
            int c0 = nt * 8 + 2 * t;
            as[nt][0] *= 0.125f; as[nt][1] *= 0.125f;
            as[nt][2] *= 0.125f; as[nt][3] *= 0.125f;
            if (j == qt) {
                if (c0     > rl_lo) as[nt][0] = -1e30f;
                if (c0 + 1 > rl_lo) as[nt][1] = -1e30f;
                if (c0     > rl_hi) as[nt][2] = -1e30f;
                if (c0 + 1 > rl_hi) as[nt][3] = -1e30f;
            }
            rm_lo = fmaxf(rm_lo, fmaxf(as[nt][0], as[nt][1]));
            rm_hi = fmaxf(rm_hi, fmaxf(as[nt][2], as[nt][3]));
        }
        rm_lo = fmaxf(rm_lo, __shfl_xor_sync(~0u, rm_lo, 1));
        rm_lo = fmaxf(rm_lo, __shfl_xor_sync(~0u, rm_lo, 2));
        rm_hi = fmaxf(rm_hi, __shfl_xor_sync(~0u, rm_hi, 1));
        rm_hi = fmaxf(rm_hi, __shfl_xor_sync(~0u, rm_hi, 2));
        float mn_lo = fmaxf(m_lo, rm_lo), mn_hi = fmaxf(m_hi, rm_hi);
        float sf_lo = expf(m_lo - mn_lo), sf_hi = expf(m_hi - mn_hi);
        m_lo = mn_lo; m_hi = mn_hi;

        float rs_lo = 0.f, rs_hi = 0.f;
        unsigned pf[16][2];
#pragma unroll
        for (int nt = 0; nt < 16; nt++) {
            float p0 = expf(as[nt][0] - mn_lo), p1 = expf(as[nt][1] - mn_lo);
            float p2 = expf(as[nt][2] - mn_hi), p3 = expf(as[nt][3] - mn_hi);
            rs_lo += p0 + p1; rs_hi += p2 + p3;
            __half2 h01 = __floats2half2_rn(p0, p1);
            __half2 h23 = __floats2half2_rn(p2, p3);
            pf[nt][0] = *(unsigned*)&h01;
            pf[nt][1] = *(unsigned*)&h23;
        }
        rs_lo += __shfl_xor_sync(~0u, rs_lo, 1);
        rs_lo += __shfl_xor_sync(~0u, rs_lo, 2);
        rs_hi += __shfl_xor_sync(~0u, rs_hi, 1);
        rs_hi += __shfl_xor_sync(~0u, rs_hi, 2);
        l_lo = l_lo * sf_lo + rs_lo;
        l_hi = l_hi * sf_hi + rs_hi;
#pragma unroll
        for (int nt = 0; nt < 8; nt++) {
            ao[nt][0] *= sf_lo; ao[nt][1] *= sf_lo;
            ao[nt][2] *= sf_hi; ao[nt][3] *= sf_hi;
        }
#pragma unroll
        for (int kc = 0; kc < 8; kc++) {
            unsigned af[4] = { pf[2*kc][0], pf[2*kc][1], pf[2*kc+1][0], pf[2*kc+1][1] };
            unsigned vf[8][2];
#pragma unroll
            for (int np = 0; np < 4; np++) {
                uint32_t bd = vbase +
                    (uint32_t)(((kc * 16 + bt_k) * FL_PITCH + np * 16 + bt_n8) * 2);
                ldsm4t(vf[2*np][0], vf[2*np][1], vf[2*np+1][0], vf[2*np+1][1], bd);
            }
#pragma unroll
            for (int nt = 0; nt < 8; nt++)
                mma_f16(ao[nt], af, vf[nt]);
        }
    }

    float il_lo = 1.f / l_lo, il_hi = 1.f / l_hi;
    __half* Ob = attn + (size_t)(b * NT + m0) * ND + h * 64;
#pragma unroll
    for (int nt = 0; nt < 8; nt++) {
        int c0 = nt * 8 + 2 * t;
        *(__half2*)(Ob + (size_t)(mwb + g) * ND + c0) =
            __floats2half2_rn(ao[nt][0] * il_lo, ao[nt][1] * il_lo);
        *(__half2*)(Ob + (size_t)(mwb + g + 8) * ND + c0) =
            __floats2half2_rn(ao[nt][2] * il_hi, ao[nt][3] * il_hi);
    }
}

// ---------------- small kernels ----------------
__global__ void embed_kernel(const int* __restrict__ ids, const float* __restrict__ tok,
                             const float* __restrict__ pos, float* __restrict__ x) {
    int n = blockIdx.x, t = n % NT, id = ids[n];
    const float* te = tok + (size_t)id * ND;
    const float* pe = pos + (size_t)t * ND;
    float* dst = x + (size_t)n * ND;
    for (int d = threadIdx.x; d < ND; d += 256) dst[d] = te[d] + pe[d];
}

__global__ void ln_kernel(const float* __restrict__ x, const float* __restrict__ w,
                          const float* __restrict__ b, __half* __restrict__ out) {
    int row = blockIdx.x * 8 + (threadIdx.x >> 5);
    int lane = threadIdx.x & 31;
    const float4* p = (const float4*)(x + (size_t)row * ND);
    float4 v[8];
    float s = 0.f;
#pragma unroll
    for (int i = 0; i < 8; i++) {
        v[i] = p[lane + i * 32];
        s += v[i].x + v[i].y + v[i].z + v[i].w;
    }
#pragma unroll
    for (int o = 16; o; o >>= 1) s += __shfl_xor_sync(~0u, s, o);
    float mu = s * (1.0f / ND);
    float q = 0.f;
#pragma unroll
    for (int i = 0; i < 8; i++) {
        float a = v[i].x - mu, c = v[i].y - mu, d = v[i].z - mu, e = v[i].w - mu;
        q += a * a + c * c + d * d + e * e;
    }
#pragma unroll
    for (int o = 16; o; o >>= 1) q += __shfl_xor_sync(~0u, q, o);
    float rs = rsqrtf(q * (1.0f / ND) + 1e-5f);
    const float4* wp = (const float4*)w;
    const float4* bp = (const float4*)b;
    __half2* op = (__half2*)(out + (size_t)row * ND);
#pragma unroll
    for (int i = 0; i < 8; i++) {
        int j = lane + i * 32;
        float4 wv = wp[j], bv = bp[j];
        op[j * 2] = __floats2half2_rn((v[i].x - mu) * rs * wv.x + bv.x,
                                      (v[i].y - mu) * rs * wv.y + bv.y);
        op[j * 2 + 1] = __floats2half2_rn((v[i].z - mu) * rs * wv.z + bv.z,
                                          (v[i].w - mu) * rs * wv.w + bv.w);
    }
}

__global__ void rope_kernel(__half* __restrict__ qkv) {
    int n = blockIdx.x, t = n % NT;
    __half* base = qkv + (size_t)n * 3072;
#pragma unroll
    for (int item = threadIdx.x; item < 512; item += 256) {
        int h = item >> 5, i = item & 31;
        float ang = (float)t * expf((float)(2 * i) * (-0.14391156831212806f));
        float s = sinf(ang), c = cosf(ang);
        __half* q = base + h * 64;
        __half* k = q + 1024;
        float q1 = __half2float(q[i]), q2 = __half2float(q[i + 32]);
        q[i] = __float2half_rn(q1 * c - q2 * s);
        q[i + 32] = __float2half_rn(q2 * c + q1 * s);
        float k1 = __half2float(k[i]), k2 = __half2float(k[i + 32]);
        k[i] = __float2half_rn(k1 * c - k2 * s);
        k[i + 32] = __float2half_rn(k2 * c + k1 * s);
    }
}

// ---------------- MoE ----------------
__global__ void route_kernel(const __half* __restrict__ ln, const float* __restrict__ wr,
                             const float* __restrict__ br, const float* __restrict__ wn,
                             const float* __restrict__ bn, float* __restrict__ route,
                             float* __restrict__ noise) {
    int n = blockIdx.x, tid = threadIdx.x;
    __shared__ float xs[ND];
    for (int d = tid; d < ND; d += 256) xs[d] = __half2float(ln[(size_t)n * ND + d]);
    __syncthreads();
    int w = tid >> 5, lane = tid & 31;
    float sr = 0.f, sn = 0.f;
    for (int d = lane; d < ND; d += 32) {
        float xv = xs[d];
        sr += xv * wr[(size_t)d * NE + w];
        sn += xv * wn[(size_t)d * NE + w];
    }
    for (int o = 16; o; o >>= 1) { sr += __shfl_down_sync(~0u, sr, o); sn += __shfl_down_sync(~0u, sn, o); }
    if (!lane) { route[n * NE + w] = sr + br[w]; noise[n * NE + w] = sn + bn[w]; }
}

__global__ void eps_kernel(unsigned k0, unsigned k1, float* __restrict__ eps) {
    int i = blockIdx.x * 256 + threadIdx.x;
    if (i >= NN * NE) return;
    unsigned o0, o1;
    threefry(k0, k1, 0u, (unsigned)i, o0, o1);
    eps[i] = bits_to_normal(o0 ^ o1);
}

__global__ void topk_kernel(const float* __restrict__ route, const float* __restrict__ noise,
                            const float* __restrict__ eps, float* __restrict__ gate,
                            unsigned char* __restrict__ mask) {
    int n = blockIdx.x * 256 + threadIdx.x;
    if (n >= NN) return;
    float nv[NE];
#pragma unroll
    for (int e = 0; e < NE; e++) {
        float x = noise[n * NE + e];
        float sp = fmaxf(x, 0.f) + log1pf(expf(-fabsf(x)));
        nv[e] = route[n * NE + e] + eps[n * NE + e] * sp;
    }
    int i1 = 0; float v1 = nv[0];
#pragma unroll
    for (int e = 1; e < NE; e++) if (nv[e] > v1) { v1 = nv[e]; i1 = e; }
    int i2 = -1; float v2 = -3.4e38f;
#pragma unroll
    for (int e = 0; e < NE; e++) if (e != i1 && nv[e] > v2) { v2 = nv[e]; i2 = e; }
    float e2 = expf(v2 - v1);
    float Z = 1.0f + e2;
#pragma unroll
    for (int e = 0; e < NE; e++)
        gate[n * NE + e] = (e == i1) ? (1.0f / Z) : ((e == i2) ? (e2 / Z) : 0.f);
    mask[n] = (unsigned char)((1u << i1) | (1u << i2));
}

__global__ void select_kernel(const unsigned char* __restrict__ mask, int* __restrict__ sel,
                              int* __restrict__ slot, int* __restrict__ cnt) {
    int e = blockIdx.x, lane = threadIdx.x;
    int base = 0;
    for (int n0 = 0; n0 < NN; n0 += 32) {
        int n = n0 + lane;
        bool f = (mask[n] >> e) & 1;
        unsigned bal = __ballot_sync(0xffffffffu, f);
        int pos = base + __popc(bal & ((1u << lane) - 1u));
        int sl = (f && pos < NCAP) ? pos : -1;
        slot[(size_t)e * NN + n] = sl;
        if (sl >= 0) sel[e * NCAP + sl] = n;
        base += __popc(bal);
    }
    if (!lane) cnt[e] = base < NCAP ? base : NCAP;
}

// fused scatter + next LayerNorm
__global__ void moe_scatter_ln_kernel(const __half* __restrict__ eo, const int* __restrict__ slot,
                                      const float* __restrict__ gate, float* __restrict__ x,
                                      const float* __restrict__ w, const float* __restrict__ b,
                                      __half* __restrict__ lnout) {
    int n = blockIdx.x, tid = threadIdx.x;
    __shared__ int ss[NE];
    __shared__ float gg[NE];
    __shared__ float red[8];
    if (tid < NE) { ss[tid] = slot[(size_t)tid * NN + n]; gg[tid] = gate[n * NE + tid]; }
    __syncthreads();
    float vals[4];
    float s = 0.f;
#pragma unroll
    for (int i = 0; i < 4; i++) {
        int d = tid + i * 256;
        float acc = x[(size_t)n * ND + d];
#pragma unroll
        for (int e = 0; e < NE; e++) {
            int sl = ss[e];
            if (sl >= 0) acc += gg[e] * __half2float(eo[((size_t)e * NCAP + sl) * ND + d]);
        }
        vals[i] = acc; s += acc;
        x[(size_t)n * ND + d] = acc;
    }
    int lane = tid & 31, warp = tid >> 5;
#pragma unroll
    for (int o = 16; o; o >>= 1) s += __shfl_xor_sync(~0u, s, o);
    if (!lane) red[warp] = s;
    __syncthreads();
    if (tid < 8) {
        float t = red[tid];
#pragma unroll
        for (int o = 4; o; o >>= 1) t += __shfl_xor_sync(0xffu, t, o);
        red[tid] = t;
    }
    __syncthreads();
    float mu = red[0] * (1.0f / ND);
    float q = 0.f;
#pragma unroll
    for (int i = 0; i < 4; i++) { float d = vals[i] - mu; q += d * d; }
#pragma unroll
    for (int o = 16; o; o >>= 1) q += __shfl_xor_sync(~0u, q, o);
    __syncthreads();
    if (!lane) red[warp] = q;
    __syncthreads();
    if (tid < 8) {
        float t = red[tid];
#pragma unroll
        for (int o = 4; o; o >>= 1) t += __shfl_xor_sync(0xffu, t, o);
        red[tid] = t;
    }
    __syncthreads();
    float rs = rsqrtf(red[0] * (1.0f / ND) + 1e-5f);
#pragma unroll
    for (int i = 0; i < 4; i++) {
        int d = tid + i * 256;
        lnout[(size_t)n * ND + d] =
            __float2half_rn((vals[i] - mu) * rs * w[d] + b[d]);
    }
}

// ---------------- loss final (merge 250 partials per row) ----------------
__global__ void loss_final_kernel(const float2* __restrict__ part, const float* __restrict__ tlog,
                                  const int* __restrict__ ids, float* __restrict__ nll,
                                  float* __restrict__ vld) {
    int n = blockIdx.x, lane = threadIdx.x;   // 32 threads
    int t = n % NT;
    if (t == NT - 1) { if (!lane) { nll[n] = 0.f; vld[n] = 0.f; } return; }
    float m = -1e30f, s = 0.f;
    for (int j = lane; j < NPART; j += 32) {
        float2 p = part[(size_t)n * NPART + j];
        if (p.x > m) { s = s * expf(m - p.x) + p.y; m = p.x; }
        else s += p.y * expf(p.x - m);
    }
#pragma unroll
    for (int o = 16; o; o >>= 1) {
        float m2 = __shfl_xor_sync(~0u, m, o);
        float s2 = __shfl_xor_sync(~0u, s, o);
        float M = fmaxf(m, m2);
        s = s * expf(m - M) + s2 * expf(m2 - M);
        m = M;
    }
    if (!lane) {
        float lse = m + logf(s);
        int tgt = ids[n + 1];
        float v = (tgt != 2) ? 1.f : 0.f;
        nll[n] = -(tlog[n] - lse) * v;
        vld[n] = v;
    }
}

__global__ void reduce_kernel(const float* __restrict__ nll, const float* __restrict__ vld,
                              float* __restrict__ out) {
    __shared__ float s1[256], s2[256];
    int tid = threadIdx.x;
    float a = 0.f, b = 0.f;
    for (int i = tid; i < NN; i += 256) { a += nll[i]; b += vld[i]; }
    s1[tid] = a; s2[tid] = b; __syncthreads();
    for (int st = 128; st; st >>= 1) { if (tid < st) { s1[tid] += s1[tid + st]; s2[tid] += s2[tid + st]; } __syncthreads(); }
    if (!tid) out[0] = s1[0] / fmaxf(s2[0], 1.0f);
}

// ---------------- host launch ----------------
#define STG_T(BM, BN) (((BM) + (BN)) * 72)
#define STG_F(BM, BN) ((BM) * 72 + 64 * ((BN) + 8))

extern "C" void kernel_launch(void* const* d_in, const int* in_sizes, int n_in,
                              void* d_out, int out_size) {
    const int*   ids     = (const int*)d_in[0];
    const float* tok_emb = (const float*)d_in[1];
    const float* pos_emb = (const float*)d_in[2];
    const float* ln1_w   = (const float*)d_in[3];
    const float* ln1_b   = (const float*)d_in[4];
    const float* ln2_w   = (const float*)d_in[5];
    const float* ln2_b   = (const float*)d_in[6];
    const float* w_qkv   = (const float*)d_in[7];
    const float* w_out   = (const float*)d_in[8];
    const float* w_route = (const float*)d_in[9];
    const float* b_route = (const float*)d_in[10];
    const float* w_noise = (const float*)d_in[11];
    const float* b_noise = (const float*)d_in[12];
    const float* w_e1    = (const float*)d_in[13];
    const float* b_e1    = (const float*)d_in[14];
    const float* w_e2    = (const float*)d_in[15];
    const float* b_e2    = (const float*)d_in[16];
    const float* lnf_w   = (const float*)d_in[17];
    const float* lnf_b   = (const float*)d_in[18];
    float* out = (float*)d_out;

    float *x, *route, *noise, *eps, *gate, *nll, *vld, *tlog;
    float2* part;
    __half *ln16, *qkv16, *attn16, *h116, *eo16;
    __half *wqkv16, *wout16, *we116, *we216, *tok16;
    unsigned char* mask; int *sel, *slot, *cnt;
    cudaGetSymbolAddress((void**)&x, g_x);
    cudaGetSymbolAddress((void**)&ln16, g_ln16);
    cudaGetSymbolAddress((void**)&qkv16, g_qkv16);
    cudaGetSymbolAddress((void**)&attn16, g_attn16);
    cudaGetSymbolAddress((void**)&route, g_route);
    cudaGetSymbolAddress((void**)&noise, g_noise);
    cudaGetSymbolAddress((void**)&eps, g_eps);
    cudaGetSymbolAddress((void**)&gate, g_gate);
    cudaGetSymbolAddress((void**)&mask, g_mask);
    cudaGetSymbolAddress((void**)&sel, g_sel);
    cudaGetSymbolAddress((void**)&slot, g_slot);
    cudaGetSymbolAddress((void**)&cnt, g_cnt);
    cudaGetSymbolAddress((void**)&h116, g_h116);
    cudaGetSymbolAddress((void**)&eo16, g_eo16);
    cudaGetSymbolAddress((void**)&part, g_part);
    cudaGetSymbolAddress((void**)&tlog, g_tlog);
    cudaGetSymbolAddress((void**)&nll, g_nll);
    cudaGetSymbolAddress((void**)&vld, g_vld);
    cudaGetSymbolAddress((void**)&wqkv16, g_wqkv16);
    cudaGetSymbolAddress((void**)&wout16, g_wout16);
    cudaGetSymbolAddress((void**)&we116, g_we116);
    cudaGetSymbolAddress((void**)&we216, g_we216);
    cudaGetSymbolAddress((void**)&tok16, g_tok16);

    constexpr int SM_T = 3 * STG_T(256, 128) * 2;
    constexpr int SM_F = 3 * STG_F(256, 128) * 2;
    auto* kqkv = hgemm_ca<512,256,128,4,4,false,false,false,false,true ,false,false>;
    auto* kproj= hgemm_ca<512,256,128,4,4,false,false,false,true ,false,false,false>;
    auto* kfc1 = hgemm_ca<512,256,128,4,4,false,true ,true ,false,true ,true ,false>;
    auto* kfc2 = hgemm_ca<512,256,128,4,4,false,true ,false,false,true ,false,false>;
    auto* kvoc = hgemm_ca<512,256,128,4,4,true ,false,false,false,false,false,true >;
    cudaFuncSetAttribute(kqkv, cudaFuncAttributeMaxDynamicSharedMemorySize, SM_F);
    cudaFuncSetAttribute(kproj,cudaFuncAttributeMaxDynamicSharedMemorySize, SM_F);
    cudaFuncSetAttribute(kfc1, cudaFuncAttributeMaxDynamicSharedMemorySize, SM_F);
    cudaFuncSetAttribute(kfc2, cudaFuncAttributeMaxDynamicSharedMemorySize, SM_F);
    cudaFuncSetAttribute(kvoc, cudaFuncAttributeMaxDynamicSharedMemorySize, SM_T);
    cudaFuncSetAttribute(flash_kernel, cudaFuncAttributeMaxDynamicSharedMemorySize, FL_SMEM);

    {
        size_t n;
        n = (size_t)NLAY * ND * 3 * ND / 4;
        cvt_h_kernel<<<(unsigned)((n + 255) / 256), 256>>>(w_qkv, wqkv16, n);
        n = (size_t)NLAY * ND * ND / 4;
        cvt_h_kernel<<<(unsigned)((n + 255) / 256), 256>>>(w_out, wout16, n);
        n = (size_t)NLAY * NE * ND * NFF / 4;
        cvt_h_kernel<<<(unsigned)((n + 255) / 256), 256>>>(w_e1, we116, n);
        n = (size_t)NLAY * NE * NFF * ND / 4;
        cvt_h_kernel<<<(unsigned)((n + 255) / 256), 256>>>(w_e2, we216, n);
        n = (size_t)NV * ND / 4;
        cvt_h_kernel<<<(unsigned)((n + 255) / 256), 256>>>(tok_emb, tok16, n);
    }

    embed_kernel<<<NN, 256>>>(ids, tok_emb, pos_emb, x);
    ln_kernel<<<NN / 8, 256>>>(x, ln1_w, ln1_b, ln16);

    for (int l = 0; l < NLAY; l++) {
        // ---- attention ----
        kqkv<<<dim3(24, 16, 1), 512, SM_F>>>(
            ln16, wqkv16 + (size_t)l * ND * 3 * ND, nullptr, qkv16, nullptr,
            nullptr, nullptr, nullptr,
            ND, ND, 3 * ND, 3 * ND, 1, 0, 0, 0, 0, 0, 0, 0, 1.0f);
        rope_kernel<<<NN, 256>>>(qkv16);
        flash_kernel<<<dim3(NT / 128, NB * NH), 256, FL_SMEM>>>(qkv16, attn16);
        kproj<<<dim3(8, 16, 1), 512, SM_F>>>(
            attn16, wout16 + (size_t)l * ND * ND, nullptr, x, nullptr,
            nullptr, nullptr, nullptr,
            ND, ND, ND, ND, 1, 0, 0, 0, 0, 0, 0, 0, 1.0f);

        // ---- MoE ----
        ln_kernel<<<NN / 8, 256>>>(x, ln2_w + l * ND, ln2_b + l * ND, ln16);
        route_kernel<<<NN, 256>>>(ln16, w_route + (size_t)l * ND * NE, b_route + l * NE,
                                  w_noise + (size_t)l * ND * NE, b_noise + l * NE, route, noise);
        unsigned k0, k1;
        threefry(0u, 1234u, 0u, (unsigned)l, k0, k1);
        eps_kernel<<<(NN * NE + 255) / 256, 256>>>(k0, k1, eps);
        topk_kernel<<<(NN + 255) / 256, 256>>>(route, noise, eps, gate, mask);
        select_kernel<<<NE, 32>>>(mask, sel, slot, cnt);
        kfc1<<<dim3(32, 4, NE), 512, SM_F>>>(
            ln16, we116 + (size_t)l * NE * ND * NFF, b_e1 + (size_t)l * NE * NFF, h116, sel,
            nullptr, nullptr, nullptr,
            ND, ND, NFF, NFF, 1,
            0, 0, (size_t)NFF * ND, 0,
            (size_t)NCAP * NFF, 0, NFF, 1.0f);
        kfc2<<<dim3(8, 4, NE), 512, SM_F>>>(
            h116, we216 + (size_t)l * NE * NFF * ND, b_e2 + (size_t)l * NE * ND, eo16, nullptr,
            nullptr, nullptr, nullptr,
            NFF, NFF, ND, ND, 1,
            (size_t)NCAP * NFF, 0, (size_t)ND * NFF, 0,
            (size_t)NCAP * ND, 0, ND, 1.0f);
        const float* nw = (l + 1 < NLAY) ? (ln1_w + (size_t)(l + 1) * ND) : lnf_w;
        const float* nb = (l + 1 < NLAY) ? (ln1_b + (size_t)(l + 1) * ND) : lnf_b;
        moe_scatter_ln_kernel<<<NN, 256>>>(eo16, slot, gate, x, nw, nb, ln16);
    }

    // vocab GEMM with fused loss partials (no logits write)
    kvoc<<<dim3(NPART, 16, 1), 512, SM_T>>>(
        ln16, tok16, nullptr, nullptr, nullptr,
        ids, part, tlog,
        ND, ND, ND, NV, 1, 0, 0, 0, 0, 0, 0, 0, 1.0f);
    loss_final_kernel<<<NN, 32>>>(part, tlog, ids, nll, vld);
    reduce_kernel<<<1, 256>>>(nll, vld, out);
}

// round 15
// speedup vs baseline: 3.2146x; 1.0153x over previous
#include <cuda_runtime.h>
#include <cuda_fp16.h>
#include <cstdint>
#include <cstddef>

#define NB 2
#define NT 2048
#define ND 1024
#define NH 16
#define NLAY 2
#define NE 8
#define NV 32000
#define NN (NB*NT)
#define NCAP 1024
#define NFF 4096
#define NPART (NV/128)

// ---------------- device scratch ----------------
__device__ float  g_x   [(size_t)NN*ND];
__device__ __half g_ln16[(size_t)NN*ND];
__device__ __half g_qkv16[(size_t)NN*3*ND];
__device__ __half g_attn16[(size_t)NN*ND];
__device__ float  g_route[NN*NE];
__device__ float  g_noise[NN*NE];
__device__ float  g_eps  [NN*NE];
__device__ float  g_gate [NN*NE];
__device__ unsigned char g_mask[NN];
__device__ int    g_sel [NE*NCAP];
__device__ int    g_slot[NE*NN];
__device__ int    g_cnt [NE];
__device__ __half g_h116[(size_t)NE*NCAP*NFF];
__device__ __half g_eo16[(size_t)NE*NCAP*ND];
__device__ float2 g_part[(size_t)NN*NPART];
__device__ float  g_tlog[NN];
__device__ float  g_nll [NN];
__device__ float  g_vld [NN];
// fp16 weight copies (ORIGINAL [K,N] layout — no transpose)
__device__ __half g_wqkv16[(size_t)NLAY*ND*3*ND];
__device__ __half g_wout16[(size_t)NLAY*ND*ND];
__device__ __half g_we116 [(size_t)NLAY*NE*ND*NFF];
__device__ __half g_we216 [(size_t)NLAY*NE*NFF*ND];
__device__ __half g_tok16 [(size_t)NV*ND];

// ---------------- threefry2x32 (matches JAX) ----------------
__host__ __device__ __forceinline__ void threefry(unsigned k0, unsigned k1,
                                                  unsigned x0, unsigned x1,
                                                  unsigned& o0, unsigned& o1) {
    unsigned ks2 = k0 ^ k1 ^ 0x1BD11BDAu;
    x0 += k0; x1 += k1;
#define TFR(r) { x0 += x1; x1 = (x1 << (r)) | (x1 >> (32 - (r))); x1 ^= x0; }
    TFR(13) TFR(15) TFR(26) TFR(6)  x0 += k1;  x1 += ks2 + 1u;
    TFR(17) TFR(29) TFR(16) TFR(24) x0 += ks2; x1 += k0 + 2u;
    TFR(13) TFR(15) TFR(26) TFR(6)  x0 += k0;  x1 += k1 + 3u;
    TFR(17) TFR(29) TFR(16) TFR(24) x0 += k1;  x1 += ks2 + 4u;
    TFR(13) TFR(15) TFR(26) TFR(6)  x0 += ks2; x1 += k0 + 5u;
#undef TFR
    o0 = x0; o1 = x1;
}

__device__ __forceinline__ float xla_erfinv(float x) {
    float w = -log1pf(-x * x);
    float p;
    if (w < 5.f) {
        w -= 2.5f;
        p = 2.81022636e-08f;
        p = fmaf(p, w, 3.43273939e-07f);
        p = fmaf(p, w, -3.5233877e-06f);
        p = fmaf(p, w, -4.39150654e-06f);
        p = fmaf(p, w, 0.00021858087f);
        p = fmaf(p, w, -0.00125372503f);
        p = fmaf(p, w, -0.00417768164f);
        p = fmaf(p, w, 0.246640727f);
        p = fmaf(p, w, 1.50140941f);
    } else {
        w = sqrtf(w) - 3.f;
        p = -0.000200214257f;
        p = fmaf(p, w, 0.000100950558f);
        p = fmaf(p, w, 0.00134934322f);
        p = fmaf(p, w, -0.00367342844f);
        p = fmaf(p, w, 0.00573950773f);
        p = fmaf(p, w, -0.0076224613f);
        p = fmaf(p, w, 0.00943887047f);
        p = fmaf(p, w, 1.00167406f);
        p = fmaf(p, w, 2.83297682f);
    }
    return p * x;
}

__device__ __forceinline__ float bits_to_normal(unsigned bits) {
    float f = __uint_as_float((bits >> 9) | 0x3F800000u) - 1.0f;
    const float lo = -0.99999994f;
    float u = fmaf(f, 2.0f, lo);
    u = fmaxf(u, lo);
    return 1.41421356237f * xla_erfinv(u);
}

// ---------------- mma / ldmatrix / cp.async helpers ----------------
__device__ __forceinline__ void mma_f16(float* c, const unsigned* a, const unsigned* b) {
    asm volatile("mma.sync.aligned.m16n8k16.row.col.f32.f16.f16.f32 "
        "{%0,%1,%2,%3}, {%4,%5,%6,%7}, {%8,%9}, {%0,%1,%2,%3};"
        : "+f"(c[0]), "+f"(c[1]), "+f"(c[2]), "+f"(c[3])
        : "r"(a[0]), "r"(a[1]), "r"(a[2]), "r"(a[3]), "r"(b[0]), "r"(b[1]));
}
__device__ __forceinline__ void ldsm4(unsigned& d0, unsigned& d1, unsigned& d2, unsigned& d3,
                                      uint32_t addr) {
    asm volatile("ldmatrix.sync.aligned.m8n8.x4.shared.b16 {%0,%1,%2,%3}, [%4];"
        : "=r"(d0), "=r"(d1), "=r"(d2), "=r"(d3) : "r"(addr));
}
__device__ __forceinline__ void ldsm4t(unsigned& d0, unsigned& d1, unsigned& d2, unsigned& d3,
                                       uint32_t addr) {
    asm volatile("ldmatrix.sync.aligned.m8n8.x4.trans.shared.b16 {%0,%1,%2,%3}, [%4];"
        : "=r"(d0), "=r"(d1), "=r"(d2), "=r"(d3) : "r"(addr));
}
__device__ __forceinline__ uint32_t smem_u32(const void* p) {
    uint32_t a;
    asm("{ .reg .u64 t; cvta.to.shared.u64 t, %1; cvt.u32.u64 %0, t; }" : "=r"(a) : "l"(p));
    return a;
}
__device__ __forceinline__ void cpa16(uint32_t dst, const void* src) {
    asm volatile("cp.async.ca.shared.global [%0], [%1], 16;" :: "r"(dst), "l"(src));
}
#define CPA_COMMIT() asm volatile("cp.async.commit_group;" ::: "memory")
#define CPA_WAIT(n)  asm volatile("cp.async.wait_group %0;" :: "n"(n) : "memory")

// ---------------- weight prep ----------------
__global__ void cvt_h_kernel(const float* __restrict__ in, __half* __restrict__ out, size_t n4) {
    size_t i = (size_t)blockIdx.x * 256 + threadIdx.x;
    if (i >= n4) return;
    float4 v = ((const float4*)in)[i];
    __half2* o = (__half2*)out;
    o[i * 2] = __floats2half2_rn(v.x, v.y);
    o[i * 2 + 1] = __floats2half2_rn(v.z, v.w);
}

// ---------------- cp.async 3-stage fp16 GEMM ----------------
// LOSS: no C write; per-row (max,sumexp) partials + target logit capture.
template<int TH, int BM, int BN, int WR, int WC, bool BNK, bool BIAS, bool RELU,
         bool ACCUM, bool OUTH, bool GATHER, bool LOSS>
__global__ void __launch_bounds__(TH)
hgemm_ca(const __half* __restrict__ A, const __half* __restrict__ B,
         const float* __restrict__ bias, void* __restrict__ Cv,
         const int* __restrict__ gsel,
         const int* __restrict__ lids, float2* __restrict__ part,
         float* __restrict__ tlog,
         int K, int lda, int ldb, int ldc, int zdiv,
         size_t sA, size_t sA2, size_t sB, size_t sB2,
         size_t sC, size_t sC2, size_t sBias, float scale)
{
    constexpr int BK = 64;
    constexpr int LDS = 72;
    constexpr int BNP = BN + 8;
    constexpr int WM = BM / WR, WN = BN / WC;
    constexpr int MT = WM / 16, NT4 = WN / 8, NP = NT4 / 2;
    constexpr int ANV = (BM * 8) / TH;
    constexpr int BNV = BNK ? (BN * 8) / TH : (BK * BN) / (8 * TH);
    constexpr int STG = BNK ? (BM + BN) * LDS : BM * LDS + BK * BNP;

    const int m0 = blockIdx.y * BM, n0 = blockIdx.x * BN;
    const int tid = threadIdx.x, lane = tid & 31, warp = tid >> 5;
    const int wr = warp / WC, wc = warp % WC;
    const int g = lane >> 2, t = lane & 3;

    {
        int z = blockIdx.z, z1 = z / zdiv, z0 = z - z1 * zdiv;
        A += (size_t)z1 * sA + (size_t)z0 * sA2;
        B += (size_t)z1 * sB + (size_t)z0 * sB2;
        Cv = (char*)Cv + ((size_t)z1 * sC + (size_t)z0 * sC2) * (OUTH ? 2 : 4);
        if (BIAS) bias += (size_t)z1 * sBias;
    }

    const int nk = K / BK;

    extern __shared__ __half shh[];
    const uint32_t sbase = smem_u32(shh);

    const int a_r = lane & 15, a_c8 = (lane >> 4) * 8;
    const int b_r = (lane & 7) + (lane >> 4) * 8, b_c8 = ((lane >> 3) & 1) * 8;
    const int q8 = lane & 7, quad = lane >> 3;
    const int bt_k = (quad & 1) * 8 + q8, bt_n8 = (quad >> 1) * 8;
    const int mwb = wr * WM, nwb = wc * WN;

    const int ar = tid >> 3, aq = tid & 7;
    int arows[ANV];
#pragma unroll
    for (int i = 0; i < ANV; i++) {
        int r = m0 + ar + i * (TH >> 3);
        arows[i] = GATHER ? gsel[(size_t)blockIdx.z * NCAP + r] : r;
    }

    auto issue = [&](int ks, int st) {
        uint32_t so = sbase + (uint32_t)(st * STG) * 2;
#pragma unroll
        for (int i = 0; i < ANV; i++) {
            int row = ar + i * (TH >> 3);
            cpa16(so + (uint32_t)(row * LDS + aq * 8) * 2,
                  A + (size_t)arows[i] * lda + ks * BK + aq * 8);
        }
        if (BNK) {
            const __half* Bc = B + (size_t)n0 * ldb + ks * BK;
#pragma unroll
            for (int i = 0; i < BNV; i++) {
                int row = ar + i * (TH >> 3);
                cpa16(so + (uint32_t)((BM + row) * LDS + aq * 8) * 2,
                      Bc + (size_t)row * ldb + aq * 8);
            }
        } else {
            const __half* Bc = B + (size_t)(ks * BK) * ldb + n0;
#pragma unroll
            for (int i = 0; i < BNV; i++) {
                int idx = tid + i * TH;
                int kk = idx / (BN / 8), nq = idx % (BN / 8);
                cpa16(so + (uint32_t)(BM * LDS + kk * BNP + nq * 8) * 2,
                      Bc + (size_t)kk * ldb + nq * 8);
            }
        }
        CPA_COMMIT();
    };

    float acc[MT][NT4][4] = {};

    issue(0, 0);
    if (nk > 1) issue(1, 1);
    if (nk > 1) { CPA_WAIT(1); } else { CPA_WAIT(0); }
    __syncthreads();

    for (int ks = 0; ks < nk; ks++) {
        int cur = ks % 3;
        bool more2 = (ks + 2 < nk);
        if (more2) issue(ks + 2, (ks + 2) % 3);
        uint32_t abase = sbase + (uint32_t)(cur * STG) * 2;
        uint32_t bbase = abase + (uint32_t)(BM * LDS) * 2;
#pragma unroll
        for (int kq = 0; kq < 4; kq++) {
            unsigned af[MT][4], bf[NT4][2];
#pragma unroll
            for (int mt = 0; mt < MT; mt++) {
                uint32_t ad = abase +
                    (uint32_t)(((mwb + mt * 16 + a_r) * LDS + kq * 16 + a_c8) * 2);
                ldsm4(af[mt][0], af[mt][1], af[mt][2], af[mt][3], ad);
            }
            if (BNK) {
#pragma unroll
                for (int np = 0; np < NP; np++) {
                    uint32_t bd = bbase +
                        (uint32_t)(((nwb + np * 16 + b_r) * LDS + kq * 16 + b_c8) * 2);
                    ldsm4(bf[2*np][0], bf[2*np][1], bf[2*np+1][0], bf[2*np+1][1], bd);
                }
            } else {
#pragma unroll
                for (int np = 0; np < NP; np++) {
                    uint32_t bd = bbase +
                        (uint32_t)(((kq * 16 + bt_k) * BNP + nwb + np * 16 + bt_n8) * 2);
                    ldsm4t(bf[2*np][0], bf[2*np][1], bf[2*np+1][0], bf[2*np+1][1], bd);
                }
            }
#pragma unroll
            for (int mt = 0; mt < MT; mt++)
#pragma unroll
                for (int nt = 0; nt < NT4; nt++)
                    mma_f16(acc[mt][nt], af[mt], bf[nt]);
        }
        if (ks + 1 < nk) {
            if (more2) { CPA_WAIT(1); } else { CPA_WAIT(0); }
            __syncthreads();
        }
    }

    if (LOSS) {
        __syncthreads();
        float2* psh = (float2*)shh;           // [BM][WC]
#pragma unroll
        for (int mt = 0; mt < MT; mt++) {
            int rl = mwb + mt * 16 + g, rh = rl + 8;
            float ml = -1e30f, mh = -1e30f;
#pragma unroll
            for (int nt = 0; nt < NT4; nt++) {
                ml = fmaxf(ml, fmaxf(acc[mt][nt][0], acc[mt][nt][1]));
                mh = fmaxf(mh, fmaxf(acc[mt][nt][2], acc[mt][nt][3]));
            }
            ml = fmaxf(ml, __shfl_xor_sync(~0u, ml, 1));
            ml = fmaxf(ml, __shfl_xor_sync(~0u, ml, 2));
            mh = fmaxf(mh, __shfl_xor_sync(~0u, mh, 1));
            mh = fmaxf(mh, __shfl_xor_sync(~0u, mh, 2));
            float sl = 0.f, shi = 0.f;
#pragma unroll
            for (int nt = 0; nt < NT4; nt++) {
                sl += __expf(acc[mt][nt][0] - ml) + __expf(acc[mt][nt][1] - ml);
                shi += __expf(acc[mt][nt][2] - mh) + __expf(acc[mt][nt][3] - mh);
            }
            sl += __shfl_xor_sync(~0u, sl, 1);
            sl += __shfl_xor_sync(~0u, sl, 2);
            shi += __shfl_xor_sync(~0u, shi, 1);
            shi += __shfl_xor_sync(~0u, shi, 2);
            if (t == 0) {
                psh[rl * WC + wc] = make_float2(ml, sl);
                psh[rh * WC + wc] = make_float2(mh, shi);
            }
            int grl = m0 + rl, grh = m0 + rh;
            int tgl = ((grl % NT) != NT - 1) ? lids[grl + 1] : -1;
            int tgh = ((grh % NT) != NT - 1) ? lids[grh + 1] : -1;
#pragma unroll
            for (int nt = 0; nt < NT4; nt++) {
                int c0 = n0 + nwb + nt * 8 + 2 * t;
                if (c0 == tgl)     tlog[grl] = acc[mt][nt][0];
                if (c0 + 1 == tgl) tlog[grl] = acc[mt][nt][1];
                if (c0 == tgh)     tlog[grh] = acc[mt][nt][2];
                if (c0 + 1 == tgh) tlog[grh] = acc[mt][nt][3];
            }
        }
        __syncthreads();
        if (tid < BM) {
            float m = -1e30f, s = 0.f;
#pragma unroll
            for (int w = 0; w < WC; w++) {
                float2 p = psh[tid * WC + w];
                if (p.x > m) { s = s * __expf(m - p.x) + p.y; m = p.x; }
                else s += p.y * __expf(p.x - m);
            }
            part[(size_t)(m0 + tid) * NPART + blockIdx.x] = make_float2(m, s);
        }
        return;
    }

    __half* Ch = (__half*)Cv;
    float*  Cf = (float*)Cv;
#pragma unroll
    for (int mt = 0; mt < MT; mt++) {
#pragma unroll
        for (int nt = 0; nt < NT4; nt++) {
            int r0 = m0 + mwb + mt * 16 + g;
            int c0 = n0 + nwb + nt * 8 + 2 * t;
            float v0 = acc[mt][nt][0] * scale, v1 = acc[mt][nt][1] * scale;
            float v2 = acc[mt][nt][2] * scale, v3 = acc[mt][nt][3] * scale;
            if (BIAS) {
                float b0 = bias[c0], b1 = bias[c0 + 1];
                v0 += b0; v1 += b1; v2 += b0; v3 += b1;
            }
            if (RELU) {
                v0 = fmaxf(v0, 0.f); v1 = fmaxf(v1, 0.f);
                v2 = fmaxf(v2, 0.f); v3 = fmaxf(v3, 0.f);
            }
            if (OUTH) {
                *(__half2*)(Ch + (size_t)r0 * ldc + c0) = __floats2half2_rn(v0, v1);
                *(__half2*)(Ch + (size_t)(r0 + 8) * ldc + c0) = __floats2half2_rn(v2, v3);
            } else {
                float* p0 = Cf + (size_t)r0 * ldc + c0;
                float* p1 = Cf + (size_t)(r0 + 8) * ldc + c0;
                if (ACCUM) {
                    float2 o0 = *(float2*)p0, o1 = *(float2*)p1;
                    v0 += o0.x; v1 += o0.y; v2 += o1.x; v3 += o1.y;
                }
                *(float2*)p0 = make_float2(v0, v1);
                *(float2*)p1 = make_float2(v2, v3);
            }
        }
    }
}

// ---------------- FlashAttention-2 (causal, 128-row q-tiles, 256 thr) ----------------
#define FL_PITCH 72
#define FL_QSZ   (128 * FL_PITCH)
#define FL_KVSZ  (2 * 128 * FL_PITCH)
#define FL_SMEM  ((FL_QSZ + 2 * FL_KVSZ) * 2)

__global__ void __launch_bounds__(256)
flash_kernel(const __half* __restrict__ qkv, __half* __restrict__ attn) {
    int z = blockIdx.y, b = z >> 4, h = z & 15;
    int qt = (int)gridDim.x - 1 - (int)blockIdx.x;
    int m0 = qt * 128;
    const __half* Qg = qkv + (size_t)b * NT * 3072 + h * 64;
    const __half* Kg = Qg + 1024;
    const __half* Vg = Qg + 2048;

    extern __shared__ __half sh[];
    const uint32_t sb = smem_u32(sh);

    int tid = threadIdx.x, lane = tid & 31, warp = tid >> 5;
    int g = lane >> 2, t = lane & 3;
    int lr = tid >> 3, lq = tid & 7;

#pragma unroll
    for (int i = 0; i < 4; i++) {
        int row = lr + i * 32;
        cpa16(sb + (uint32_t)(row * FL_PITCH + lq * 8) * 2,
              Qg + (size_t)(m0 + row) * 3072 + lq * 8);
    }
    CPA_COMMIT();

    auto issue_kv = [&](int j, int st) {
        uint32_t so = sb + (uint32_t)(FL_QSZ + st * FL_KVSZ) * 2;
#pragma unroll
        for (int i = 0; i < 4; i++) {
            int row = lr + i * 32;
            cpa16(so + (uint32_t)(row * FL_PITCH + lq * 8) * 2,
                  Kg + (size_t)(j * 128 + row) * 3072 + lq * 8);
        }
#pragma unroll
        for (int i = 0; i < 4; i++) {
            int row = lr + i * 32;
            cpa16(so + (uint32_t)((128 + row) * FL_PITCH + lq * 8) * 2,
                  Vg + (size_t)(j * 128 + row) * 3072 + lq * 8);
        }
        CPA_COMMIT();
    };
    issue_kv(0, 0);
    CPA_WAIT(0);
    __syncthreads();

    const int mwb = warp * 16;
    const int a_r = lane & 15, a_c8 = (lane >> 4) * 8;
    unsigned qf[4][4];
#pragma unroll
    for (int kq = 0; kq < 4; kq++) {
        uint32_t ad = sb + (uint32_t)(((mwb + a_r) * FL_PITCH + kq * 16 + a_c8) * 2);
        ldsm4(qf[kq][0], qf[kq][1], qf[kq][2], qf[kq][3], ad);
    }

    const int b_r = (lane & 7) + (lane >> 4) * 8, b_c8 = ((lane >> 3) & 1) * 8;
    const int q8 = lane & 7, quad = lane >> 3;
    const int bt_k = (quad & 1) * 8 + q8, bt_n8 = (quad >> 1) * 8;

    float m_lo = -1e30f, m_hi = -1e30f, l_lo = 0.f, l_hi = 0.f;
    float ao[8][4] = {};
    const int rl_lo = mwb + g, rl_hi = mwb + g + 8;

    for (int j = 0; j <= qt; j++) {
        int st = j & 1;
        __syncthreads();
        if (j < qt) issue_kv(j + 1, st ^ 1);
        if (j < qt) { CPA_WAIT(1); } else { CPA_WAIT(0); }
        __syncthreads();

        uint32_t kbase = sb + (uint32_t)(FL_QSZ + st * FL_KVSZ) * 2;
        uint32_t vbase = kbase + (uint32_t)(128 * FL_PITCH) * 2;

        float as[16][4] = {};
#pragma unroll
        for (int kq = 0; kq < 4; kq++) {
            unsigned bf[16][2];
#pragma unroll
            for (int np = 0; np < 8; np++) {
                uint32_t bd = kbase +
                    (uint32_t)(((np * 16 + b_r) * FL_PITCH + kq * 16 + b_c8) * 2);
                ldsm4(bf[2*np][0], bf[2*np][1], bf[2*np+1][0], bf[2*np+1][1], bd);
            }
#pragma unroll
            for (int nt = 0; nt < 16; nt++)
                mma_f16(as[nt], qf[kq], bf[nt]);
        }

        float rm_lo = -1e30f, rm_hi = -1e30f;
#pragma unroll
        for (int nt = 0; nt < 16; nt++) {
            int c0 = nt * 8 + 2 * t;
            as[nt][0] *= 0.125f; as[nt][1] *= 0.125f;
            as[nt][2] *= 0.125f; as[nt][3] *= 0.125f;
            if (j == qt) {
                if (c0     > rl_lo) as[nt][0] = -1e30f;
                if (c0 + 1 > rl_lo) as[nt][1] = -1e30f;
                if (c0     > rl_hi) as[nt][2] = -1e30f;
                if (c0 + 1 > rl_hi) as[nt][3] = -1e30f;
            }
            rm_lo = fmaxf(rm_lo, fmaxf(as[nt][0], as[nt][1]));
            rm_hi = fmaxf(rm_hi, fmaxf(as[nt][2], as[nt][3]));
        }
        rm_lo = fmaxf(rm_lo, __shfl_xor_sync(~0u, rm_lo, 1));
        rm_lo = fmaxf(rm_lo, __shfl_xor_sync(~0u, rm_lo, 2));
        rm_hi = fmaxf(rm_hi, __shfl_xor_sync(~0u, rm_hi, 1));
        rm_hi = fmaxf(rm_hi, __shfl_xor_sync(~0u, rm_hi, 2));
        float mn_lo = fmaxf(m_lo, rm_lo), mn_hi = fmaxf(m_hi, rm_hi);
        float sf_lo = __expf(m_lo - mn_lo), sf_hi = __expf(m_hi - mn_hi);
        m_lo = mn_lo; m_hi = mn_hi;

        float rs_lo = 0.f, rs_hi = 0.f;
        unsigned pf[16][2];
#pragma unroll
        for (int nt = 0; nt < 16; nt++) {
            float p0 = __expf(as[nt][0] - mn_lo), p1 = __expf(as[nt][1] - mn_lo);
            float p2 = __expf(as[nt][2] - mn_hi), p3 = __expf(as[nt][3] - mn_hi);
            rs_lo += p0 + p1; rs_hi += p2 + p3;
            __half2 h01 = __floats2half2_rn(p0, p1);
            __half2 h23 = __floats2half2_rn(p2, p3);
            pf[nt][0] = *(unsigned*)&h01;
            pf[nt][1] = *(unsigned*)&h23;
        }
        rs_lo += __shfl_xor_sync(~0u, rs_lo, 1);
        rs_lo += __shfl_xor_sync(~0u, rs_lo, 2);
        rs_hi += __shfl_xor_sync(~0u, rs_hi, 1);
        rs_hi += __shfl_xor_sync(~0u, rs_hi, 2);
        l_lo = l_lo * sf_lo + rs_lo;
        l_hi = l_hi * sf_hi + rs_hi;
#pragma unroll
        for (int nt = 0; nt < 8; nt++) {
            ao[nt][0] *= sf_lo; ao[nt][1] *= sf_lo;
            ao[nt][2] *= sf_hi; ao[nt][3] *= sf_hi;
        }
#pragma unroll
        for (int kc = 0; kc < 8; kc++) {
            unsigned af[4] = { pf[2*kc][0], pf[2*kc][1], pf[2*kc+1][0], pf[2*kc+1][1] };
            unsigned vf[8][2];
#pragma unroll
            for (int np = 0; np < 4; np++) {
                uint32_t bd = vbase +
                    (uint32_t)(((kc * 16 + bt_k) * FL_PITCH + np * 16 + bt_n8) * 2);
                ldsm4t(vf[2*np][0], vf[2*np][1], vf[2*np+1][0], vf[2*np+1][1], bd);
            }
#pragma unroll
            for (int nt = 0; nt < 8; nt++)
                mma_f16(ao[nt], af, vf[nt]);
        }
    }

    float il_lo = 1.f / l_lo, il_hi = 1.f / l_hi;
    __half* Ob = attn + (size_t)(b * NT + m0) * ND + h * 64;
#pragma unroll
    for (int nt = 0; nt < 8; nt++) {
        int c0 = nt * 8 + 2 * t;
        *(__half2*)(Ob + (size_t)(mwb + g) * ND + c0) =
            __floats2half2_rn(ao[nt][0] * il_lo, ao[nt][1] * il_lo);
        *(__half2*)(Ob + (size_t)(mwb + g + 8) * ND + c0) =
            __floats2half2_rn(ao[nt][2] * il_hi, ao[nt][3] * il_hi);
    }
}

// ---------------- small kernels ----------------
__global__ void embed_kernel(const int* __restrict__ ids, const float* __restrict__ tok,
                             const float* __restrict__ pos, float* __restrict__ x) {
    int n = blockIdx.x, t = n % NT, id = ids[n];
    const float* te = tok + (size_t)id * ND;
    const float* pe = pos + (size_t)t * ND;
    float* dst = x + (size_t)n * ND;
    for (int d = threadIdx.x; d < ND; d += 256) dst[d] = te[d] + pe[d];
}

__global__ void ln_kernel(const float* __restrict__ x, const float* __restrict__ w,
                          const float* __restrict__ b, __half* __restrict__ out) {
    int row = blockIdx.x * 8 + (threadIdx.x >> 5);
    int lane = threadIdx.x & 31;
    const float4* p = (const float4*)(x + (size_t)row * ND);
    float4 v[8];
    float s = 0.f;
#pragma unroll
    for (int i = 0; i < 8; i++) {
        v[i] = p[lane + i * 32];
        s += v[i].x + v[i].y + v[i].z + v[i].w;
    }
#pragma unroll
    for (int o = 16; o; o >>= 1) s += __shfl_xor_sync(~0u, s, o);
    float mu = s * (1.0f / ND);
    float q = 0.f;
#pragma unroll
    for (int i = 0; i < 8; i++) {
        float a = v[i].x - mu, c = v[i].y - mu, d = v[i].z - mu, e = v[i].w - mu;
        q += a * a + c * c + d * d + e * e;
    }
#pragma unroll
    for (int o = 16; o; o >>= 1) q += __shfl_xor_sync(~0u, q, o);
    float rs = rsqrtf(q * (1.0f / ND) + 1e-5f);
    const float4* wp = (const float4*)w;
    const float4* bp = (const float4*)b;
    __half2* op = (__half2*)(out + (size_t)row * ND);
#pragma unroll
    for (int i = 0; i < 8; i++) {
        int j = lane + i * 32;
        float4 wv = wp[j], bv = bp[j];
        op[j * 2] = __floats2half2_rn((v[i].x - mu) * rs * wv.x + bv.x,
                                      (v[i].y - mu) * rs * wv.y + bv.y);
        op[j * 2 + 1] = __floats2half2_rn((v[i].z - mu) * rs * wv.z + bv.z,
                                          (v[i].w - mu) * rs * wv.w + bv.w);
    }
}

__global__ void rope_kernel(__half* __restrict__ qkv) {
    int n = blockIdx.x, t = n % NT;
    __half* base = qkv + (size_t)n * 3072;
#pragma unroll
    for (int item = threadIdx.x; item < 512; item += 256) {
        int h = item >> 5, i = item & 31;
        float ang = (float)t * expf((float)(2 * i) * (-0.14391156831212806f));
        float s = sinf(ang), c = cosf(ang);
        __half* q = base + h * 64;
        __half* k = q + 1024;
        float q1 = __half2float(q[i]), q2 = __half2float(q[i + 32]);
        q[i] = __float2half_rn(q1 * c - q2 * s);
        q[i + 32] = __float2half_rn(q2 * c + q1 * s);
        float k1 = __half2float(k[i]), k2 = __half2float(k[i + 32]);
        k[i] = __float2half_rn(k1 * c - k2 * s);
        k[i + 32] = __float2half_rn(k2 * c + k1 * s);
    }
}

// ---------------- MoE ----------------
__global__ void route_kernel(const __half* __restrict__ ln, const float* __restrict__ wr,
                             const float* __restrict__ br, const float* __restrict__ wn,
                             const float* __restrict__ bn, float* __restrict__ route,
                             float* __restrict__ noise) {
    int n = blockIdx.x, tid = threadIdx.x;
    __shared__ float xs[ND];
    for (int d = tid; d < ND; d += 256) xs[d] = __half2float(ln[(size_t)n * ND + d]);
    __syncthreads();
    int w = tid >> 5, lane = tid & 31;
    float sr = 0.f, sn = 0.f;
    for (int d = lane; d < ND; d += 32) {
        float xv = xs[d];
        sr += xv * wr[(size_t)d * NE + w];
        sn += xv * wn[(size_t)d * NE + w];
    }
    for (int o = 16; o; o >>= 1) { sr += __shfl_down_sync(~0u, sr, o); sn += __shfl_down_sync(~0u, sn, o); }
    if (!lane) { route[n * NE + w] = sr + br[w]; noise[n * NE + w] = sn + bn[w]; }
}

__global__ void eps_kernel(unsigned k0, unsigned k1, float* __restrict__ eps) {
    int i = blockIdx.x * 256 + threadIdx.x;
    if (i >= NN * NE) return;
    unsigned o0, o1;
    threefry(k0, k1, 0u, (unsigned)i, o0, o1);
    eps[i] = bits_to_normal(o0 ^ o1);
}

__global__ void topk_kernel(const float* __restrict__ route, const float* __restrict__ noise,
                            const float* __restrict__ eps, float* __restrict__ gate,
                            unsigned char* __restrict__ mask) {
    int n = blockIdx.x * 256 + threadIdx.x;
    if (n >= NN) return;
    float nv[NE];
#pragma unroll
    for (int e = 0; e < NE; e++) {
        float x = noise[n * NE + e];
        float sp = fmaxf(x, 0.f) + log1pf(expf(-fabsf(x)));
        nv[e] = route[n * NE + e] + eps[n * NE + e] * sp;
    }
    int i1 = 0; float v1 = nv[0];
#pragma unroll
    for (int e = 1; e < NE; e++) if (nv[e] > v1) { v1 = nv[e]; i1 = e; }
    int i2 = -1; float v2 = -3.4e38f;
#pragma unroll
    for (int e = 0; e < NE; e++) if (e != i1 && nv[e] > v2) { v2 = nv[e]; i2 = e; }
    float e2 = expf(v2 - v1);
    float Z = 1.0f + e2;
#pragma unroll
    for (int e = 0; e < NE; e++)
        gate[n * NE + e] = (e == i1) ? (1.0f / Z) : ((e == i2) ? (e2 / Z) : 0.f);
    mask[n] = (unsigned char)((1u << i1) | (1u << i2));
}

__global__ void select_kernel(const unsigned char* __restrict__ mask, int* __restrict__ sel,
                              int* __restrict__ slot, int* __restrict__ cnt) {
    int e = blockIdx.x, lane = threadIdx.x;
    int base = 0;
    for (int n0 = 0; n0 < NN; n0 += 32) {
        int n = n0 + lane;
        bool f = (mask[n] >> e) & 1;
        unsigned bal = __ballot_sync(0xffffffffu, f);
        int pos = base + __popc(bal & ((1u << lane) - 1u));
        int sl = (f && pos < NCAP) ? pos : -1;
        slot[(size_t)e * NN + n] = sl;
        if (sl >= 0) sel[e * NCAP + sl] = n;
        base += __popc(bal);
    }
    if (!lane) cnt[e] = base < NCAP ? base : NCAP;
}

// fused scatter + next LayerNorm
__global__ void moe_scatter_ln_kernel(const __half* __restrict__ eo, const int* __restrict__ slot,
                                      const float* __restrict__ gate, float* __restrict__ x,
                                      const float* __restrict__ w, const float* __restrict__ b,
                                      __half* __restrict__ lnout) {
    int n = blockIdx.x, tid = threadIdx.x;
    __shared__ int ss[NE];
    __shared__ float gg[NE];
    __shared__ float red[8];
    if (tid < NE) { ss[tid] = slot[(size_t)tid * NN + n]; gg[tid] = gate[n * NE + tid]; }
    __syncthreads();
    float vals[4];
    float s = 0.f;
#pragma unroll
    for (int i = 0; i < 4; i++) {
        int d = tid + i * 256;
        float acc = x[(size_t)n * ND + d];
#pragma unroll
        for (int e = 0; e < NE; e++) {
            int sl = ss[e];
            if (sl >= 0) acc += gg[e] * __half2float(eo[((size_t)e * NCAP + sl) * ND + d]);
        }
        vals[i] = acc; s += acc;
        x[(size_t)n * ND + d] = acc;
    }
    int lane = tid & 31, warp = tid >> 5;
#pragma unroll
    for (int o = 16; o; o >>= 1) s += __shfl_xor_sync(~0u, s, o);
    if (!lane) red[warp] = s;
    __syncthreads();
    if (tid < 8) {
        float t = red[tid];
#pragma unroll
        for (int o = 4; o; o >>= 1) t += __shfl_xor_sync(0xffu, t, o);
        red[tid] = t;
    }
    __syncthreads();
    float mu = red[0] * (1.0f / ND);
    float q = 0.f;
#pragma unroll
    for (int i = 0; i < 4; i++) { float d = vals[i] - mu; q += d * d; }
#pragma unroll
    for (int o = 16; o; o >>= 1) q += __shfl_xor_sync(~0u, q, o);
    __syncthreads();
    if (!lane) red[warp] = q;
    __syncthreads();
    if (tid < 8) {
        float t = red[tid];
#pragma unroll
        for (int o = 4; o; o >>= 1) t += __shfl_xor_sync(0xffu, t, o);
        red[tid] = t;
    }
    __syncthreads();
    float rs = rsqrtf(red[0] * (1.0f / ND) + 1e-5f);
#pragma unroll
    for (int i = 0; i < 4; i++) {
        int d = tid + i * 256;
        lnout[(size_t)n * ND + d] =
            __float2half_rn((vals[i] - mu) * rs * w[d] + b[d]);
    }
}

// ---------------- loss final (merge 250 partials per row) ----------------
__global__ void loss_final_kernel(const float2* __restrict__ part, const float* __restrict__ tlog,
                                  const int* __restrict__ ids, float* __restrict__ nll,
                                  float* __restrict__ vld) {
    int n = blockIdx.x, lane = threadIdx.x;   // 32 threads
    int t = n % NT;
    if (t == NT - 1) { if (!lane) { nll[n] = 0.f; vld[n] = 0.f; } return; }
    float m = -1e30f, s = 0.f;
    for (int j = lane; j < NPART; j += 32) {
        float2 p = part[(size_t)n * NPART + j];
        if (p.x > m) { s = s * __expf(m - p.x) + p.y; m = p.x; }
        else s += p.y * __expf(p.x - m);
    }
#pragma unroll
    for (int o = 16; o; o >>= 1) {
        float m2 = __shfl_xor_sync(~0u, m, o);
        float s2 = __shfl_xor_sync(~0u, s, o);
        float M = fmaxf(m, m2);
        s = s * __expf(m - M) + s2 * __expf(m2 - M);
        m = M;
    }
    if (!lane) {
        float lse = m + logf(s);
        int tgt = ids[n + 1];
        float v = (tgt != 2) ? 1.f : 0.f;
        nll[n] = -(tlog[n] - lse) * v;
        vld[n] = v;
    }
}

__global__ void reduce_kernel(const float* __restrict__ nll, const float* __restrict__ vld,
                              float* __restrict__ out) {
    __shared__ float s1[256], s2[256];
    int tid = threadIdx.x;
    float a = 0.f, b = 0.f;
    for (int i = tid; i < NN; i += 256) { a += nll[i]; b += vld[i]; }
    s1[tid] = a; s2[tid] = b; __syncthreads();
    for (int st = 128; st; st >>= 1) { if (tid < st) { s1[tid] += s1[tid + st]; s2[tid] += s2[tid + st]; } __syncthreads(); }
    if (!tid) out[0] = s1[0] / fmaxf(s2[0], 1.0f);
}

// ---------------- host launch ----------------
#define STG_T(BM, BN) (((BM) + (BN)) * 72)
#define STG_F(BM, BN) ((BM) * 72 + 64 * ((BN) + 8))

extern "C" void kernel_launch(void* const* d_in, const int* in_sizes, int n_in,
                              void* d_out, int out_size) {
    const int*   ids     = (const int*)d_in[0];
    const float* tok_emb = (const float*)d_in[1];
    const float* pos_emb = (const float*)d_in[2];
    const float* ln1_w   = (const float*)d_in[3];
    const float* ln1_b   = (const float*)d_in[4];
    const float* ln2_w   = (const float*)d_in[5];
    const float* ln2_b   = (const float*)d_in[6];
    const float* w_qkv   = (const float*)d_in[7];
    const float* w_out   = (const float*)d_in[8];
    const float* w_route = (const float*)d_in[9];
    const float* b_route = (const float*)d_in[10];
    const float* w_noise = (const float*)d_in[11];
    const float* b_noise = (const float*)d_in[12];
    const float* w_e1    = (const float*)d_in[13];
    const float* b_e1    = (const float*)d_in[14];
    const float* w_e2    = (const float*)d_in[15];
    const float* b_e2    = (const float*)d_in[16];
    const float* lnf_w   = (const float*)d_in[17];
    const float* lnf_b   = (const float*)d_in[18];
    float* out = (float*)d_out;

    float *x, *route, *noise, *eps, *gate, *nll, *vld, *tlog;
    float2* part;
    __half *ln16, *qkv16, *attn16, *h116, *eo16;
    __half *wqkv16, *wout16, *we116, *we216, *tok16;
    unsigned char* mask; int *sel, *slot, *cnt;
    cudaGetSymbolAddress((void**)&x, g_x);
    cudaGetSymbolAddress((void**)&ln16, g_ln16);
    cudaGetSymbolAddress((void**)&qkv16, g_qkv16);
    cudaGetSymbolAddress((void**)&attn16, g_attn16);
    cudaGetSymbolAddress((void**)&route, g_route);
    cudaGetSymbolAddress((void**)&noise, g_noise);
    cudaGetSymbolAddress((void**)&eps, g_eps);
    cudaGetSymbolAddress((void**)&gate, g_gate);
    cudaGetSymbolAddress((void**)&mask, g_mask);
    cudaGetSymbolAddress((void**)&sel, g_sel);
    cudaGetSymbolAddress((void**)&slot, g_slot);
    cudaGetSymbolAddress((void**)&cnt, g_cnt);
    cudaGetSymbolAddress((void**)&h116, g_h116);
    cudaGetSymbolAddress((void**)&eo16, g_eo16);
    cudaGetSymbolAddress((void**)&part, g_part);
    cudaGetSymbolAddress((void**)&tlog, g_tlog);
    cudaGetSymbolAddress((void**)&nll, g_nll);
    cudaGetSymbolAddress((void**)&vld, g_vld);
    cudaGetSymbolAddress((void**)&wqkv16, g_wqkv16);
    cudaGetSymbolAddress((void**)&wout16, g_wout16);
    cudaGetSymbolAddress((void**)&we116, g_we116);
    cudaGetSymbolAddress((void**)&we216, g_we216);
    cudaGetSymbolAddress((void**)&tok16, g_tok16);

    constexpr int SM_T = 3 * STG_T(256, 128) * 2;
    constexpr int SM_F = 3 * STG_F(256, 128) * 2;
    auto* kqkv = hgemm_ca<512,256,128,4,4,false,false,false,false,true ,false,false>;
    auto* kproj= hgemm_ca<512,256,128,4,4,false,false,false,true ,false,false,false>;
    auto* kfc1 = hgemm_ca<512,256,128,4,4,false,true ,true ,false,true ,true ,false>;
    auto* kfc2 = hgemm_ca<512,256,128,4,4,false,true ,false,false,true ,false,false>;
    auto* kvoc = hgemm_ca<512,256,128,4,4,true ,false,false,false,false,false,true >;
    cudaFuncSetAttribute(kqkv, cudaFuncAttributeMaxDynamicSharedMemorySize, SM_F);
    cudaFuncSetAttribute(kproj,cudaFuncAttributeMaxDynamicSharedMemorySize, SM_F);
    cudaFuncSetAttribute(kfc1, cudaFuncAttributeMaxDynamicSharedMemorySize, SM_F);
    cudaFuncSetAttribute(kfc2, cudaFuncAttributeMaxDynamicSharedMemorySize, SM_F);
    cudaFuncSetAttribute(kvoc, cudaFuncAttributeMaxDynamicSharedMemorySize, SM_T);
    cudaFuncSetAttribute(flash_kernel, cudaFuncAttributeMaxDynamicSharedMemorySize, FL_SMEM);

    {
        size_t n;
        n = (size_t)NLAY * ND * 3 * ND / 4;
        cvt_h_kernel<<<(unsigned)((n + 255) / 256), 256>>>(w_qkv, wqkv16, n);
        n = (size_t)NLAY * ND * ND / 4;
        cvt_h_kernel<<<(unsigned)((n + 255) / 256), 256>>>(w_out, wout16, n);
        n = (size_t)NLAY * NE * ND * NFF / 4;
        cvt_h_kernel<<<(unsigned)((n + 255) / 256), 256>>>(w_e1, we116, n);
        n = (size_t)NLAY * NE * NFF * ND / 4;
        cvt_h_kernel<<<(unsigned)((n + 255) / 256), 256>>>(w_e2, we216, n);
        n = (size_t)NV * ND / 4;
        cvt_h_kernel<<<(unsigned)((n + 255) / 256), 256>>>(tok_emb, tok16, n);
    }

    embed_kernel<<<NN, 256>>>(ids, tok_emb, pos_emb, x);
    ln_kernel<<<NN / 8, 256>>>(x, ln1_w, ln1_b, ln16);

    for (int l = 0; l < NLAY; l++) {
        // ---- attention ----
        kqkv<<<dim3(24, 16, 1), 512, SM_F>>>(
            ln16, wqkv16 + (size_t)l * ND * 3 * ND, nullptr, qkv16, nullptr,
            nullptr, nullptr, nullptr,
            ND, ND, 3 * ND, 3 * ND, 1, 0, 0, 0, 0, 0, 0, 0, 1.0f);
        rope_kernel<<<NN, 256>>>(qkv16);
        flash_kernel<<<dim3(NT / 128, NB * NH), 256, FL_SMEM>>>(qkv16, attn16);
        kproj<<<dim3(8, 16, 1), 512, SM_F>>>(
            attn16, wout16 + (size_t)l * ND * ND, nullptr, x, nullptr,
            nullptr, nullptr, nullptr,
            ND, ND, ND, ND, 1, 0, 0, 0, 0, 0, 0, 0, 1.0f);

        // ---- MoE ----
        ln_kernel<<<NN / 8, 256>>>(x, ln2_w + l * ND, ln2_b + l * ND, ln16);
        route_kernel<<<NN, 256>>>(ln16, w_route + (size_t)l * ND * NE, b_route + l * NE,
                                  w_noise + (size_t)l * ND * NE, b_noise + l * NE, route, noise);
        unsigned k0, k1;
        threefry(0u, 1234u, 0u, (unsigned)l, k0, k1);
        eps_kernel<<<(NN * NE + 255) / 256, 256>>>(k0, k1, eps);
        topk_kernel<<<(NN + 255) / 256, 256>>>(route, noise, eps, gate, mask);
        select_kernel<<<NE, 32>>>(mask, sel, slot, cnt);
        kfc1<<<dim3(32, 4, NE), 512, SM_F>>>(
            ln16, we116 + (size_t)l * NE * ND * NFF, b_e1 + (size_t)l * NE * NFF, h116, sel,
            nullptr, nullptr, nullptr,
            ND, ND, NFF, NFF, 1,
            0, 0, (size_t)NFF * ND, 0,
            (size_t)NCAP * NFF, 0, NFF, 1.0f);
        kfc2<<<dim3(8, 4, NE), 512, SM_F>>>(
            h116, we216 + (size_t)l * NE * NFF * ND, b_e2 + (size_t)l * NE * ND, eo16, nullptr,
            nullptr, nullptr, nullptr,
            NFF, NFF, ND, ND, 1,
            (size_t)NCAP * NFF, 0, (size_t)ND * NFF, 0,
            (size_t)NCAP * ND, 0, ND, 1.0f);
        const float* nw = (l + 1 < NLAY) ? (ln1_w + (size_t)(l + 1) * ND) : lnf_w;
        const float* nb = (l + 1 < NLAY) ? (ln1_b + (size_t)(l + 1) * ND) : lnf_b;
        moe_scatter_ln_kernel<<<NN, 256>>>(eo16, slot, gate, x, nw, nb, ln16);
    }

    // vocab GEMM with fused loss partials (no logits write)
    kvoc<<<dim3(NPART, 16, 1), 512, SM_T>>>(
        ln16, tok16, nullptr, nullptr, nullptr,
        ids, part, tlog,
        ND, ND, ND, NV, 1, 0, 0, 0, 0, 0, 0, 0, 1.0f);
    loss_final_kernel<<<NN, 32>>>(part, tlog, ids, nll, vld);
    reduce_kernel<<<1, 256>>>(nll, vld, out);
}

// round 16
// speedup vs baseline: 3.2266x; 1.0037x over previous
#include <cuda_runtime.h>
#include <cuda_fp16.h>
#include <cstdint>
#include <cstddef>

#define NB 2
#define NT 2048
#define ND 1024
#define NH 16
#define NLAY 2
#define NE 8
#define NV 32000
#define NN (NB*NT)
#define NCAP 1024
#define NFF 4096
#define NPART (NV/128)

// ---------------- device scratch ----------------
__device__ float  g_x   [(size_t)NN*ND];
__device__ __half g_ln16[(size_t)NN*ND];
__device__ __half g_qkv16[(size_t)NN*3*ND];
__device__ __half g_attn16[(size_t)NN*ND];
__device__ float  g_route[NN*NE];
__device__ float  g_noise[NN*NE];
__device__ float  g_gate [NN*NE];
__device__ unsigned char g_mask[NN];
__device__ int    g_sel [NE*NCAP];
__device__ int    g_slot[NE*NN];
__device__ int    g_cnt [NE];
__device__ __half g_h116[(size_t)NE*NCAP*NFF];
__device__ __half g_eo16[(size_t)NE*NCAP*ND];
__device__ float2 g_part[(size_t)NN*NPART];
__device__ float  g_tlog[NN];
__device__ float  g_nll [NN];
__device__ float  g_vld [NN];
// fp16 weight copies (ORIGINAL [K,N] layout — no transpose)
__device__ __half g_wqkv16[(size_t)NLAY*ND*3*ND];
__device__ __half g_wout16[(size_t)NLAY*ND*ND];
__device__ __half g_we116 [(size_t)NLAY*NE*ND*NFF];
__device__ __half g_we216 [(size_t)NLAY*NE*NFF*ND];
__device__ __half g_tok16 [(size_t)NV*ND];

// ---------------- threefry2x32 (matches JAX) ----------------
__host__ __device__ __forceinline__ void threefry(unsigned k0, unsigned k1,
                                                  unsigned x0, unsigned x1,
                                                  unsigned& o0, unsigned& o1) {
    unsigned ks2 = k0 ^ k1 ^ 0x1BD11BDAu;
    x0 += k0; x1 += k1;
#define TFR(r) { x0 += x1; x1 = (x1 << (r)) | (x1 >> (32 - (r))); x1 ^= x0; }
    TFR(13) TFR(15) TFR(26) TFR(6)  x0 += k1;  x1 += ks2 + 1u;
    TFR(17) TFR(29) TFR(16) TFR(24) x0 += ks2; x1 += k0 + 2u;
    TFR(13) TFR(15) TFR(26) TFR(6)  x0 += k0;  x1 += k1 + 3u;
    TFR(17) TFR(29) TFR(16) TFR(24) x0 += k1;  x1 += ks2 + 4u;
    TFR(13) TFR(15) TFR(26) TFR(6)  x0 += ks2; x1 += k0 + 5u;
#undef TFR
    o0 = x0; o1 = x1;
}

__device__ __forceinline__ float xla_erfinv(float x) {
    float w = -log1pf(-x * x);
    float p;
    if (w < 5.f) {
        w -= 2.5f;
        p = 2.81022636e-08f;
        p = fmaf(p, w, 3.43273939e-07f);
        p = fmaf(p, w, -3.5233877e-06f);
        p = fmaf(p, w, -4.39150654e-06f);
        p = fmaf(p, w, 0.00021858087f);
        p = fmaf(p, w, -0.00125372503f);
        p = fmaf(p, w, -0.00417768164f);
        p = fmaf(p, w, 0.246640727f);
        p = fmaf(p, w, 1.50140941f);
    } else {
        w = sqrtf(w) - 3.f;
        p = -0.000200214257f;
        p = fmaf(p, w, 0.000100950558f);
        p = fmaf(p, w, 0.00134934322f);
        p = fmaf(p, w, -0.00367342844f);
        p = fmaf(p, w, 0.00573950773f);
        p = fmaf(p, w, -0.0076224613f);
        p = fmaf(p, w, 0.00943887047f);
        p = fmaf(p, w, 1.00167406f);
        p = fmaf(p, w, 2.83297682f);
    }
    return p * x;
}

__device__ __forceinline__ float bits_to_normal(unsigned bits) {
    float f = __uint_as_float((bits >> 9) | 0x3F800000u) - 1.0f;
    const float lo = -0.99999994f;
    float u = fmaf(f, 2.0f, lo);
    u = fmaxf(u, lo);
    return 1.41421356237f * xla_erfinv(u);
}

// ---------------- mma / ldmatrix / cp.async helpers ----------------
__device__ __forceinline__ void mma_f16(float* c, const unsigned* a, const unsigned* b) {
    asm volatile("mma.sync.aligned.m16n8k16.row.col.f32.f16.f16.f32 "
        "{%0,%1,%2,%3}, {%4,%5,%6,%7}, {%8,%9}, {%0,%1,%2,%3};"
        : "+f"(c[0]), "+f"(c[1]), "+f"(c[2]), "+f"(c[3])
        : "r"(a[0]), "r"(a[1]), "r"(a[2]), "r"(a[3]), "r"(b[0]), "r"(b[1]));
}
__device__ __forceinline__ void ldsm4(unsigned& d0, unsigned& d1, unsigned& d2, unsigned& d3,
                                      uint32_t addr) {
    asm volatile("ldmatrix.sync.aligned.m8n8.x4.shared.b16 {%0,%1,%2,%3}, [%4];"
        : "=r"(d0), "=r"(d1), "=r"(d2), "=r"(d3) : "r"(addr));
}
__device__ __forceinline__ void ldsm4t(unsigned& d0, unsigned& d1, unsigned& d2, unsigned& d3,
                                       uint32_t addr) {
    asm volatile("ldmatrix.sync.aligned.m8n8.x4.trans.shared.b16 {%0,%1,%2,%3}, [%4];"
        : "=r"(d0), "=r"(d1), "=r"(d2), "=r"(d3) : "r"(addr));
}
__device__ __forceinline__ uint32_t smem_u32(const void* p) {
    uint32_t a;
    asm("{ .reg .u64 t; cvta.to.shared.u64 t, %1; cvt.u32.u64 %0, t; }" : "=r"(a) : "l"(p));
    return a;
}
__device__ __forceinline__ void cpa16(uint32_t dst, const void* src) {
    asm volatile("cp.async.ca.shared.global [%0], [%1], 16;" :: "r"(dst), "l"(src));
}
#define CPA_COMMIT() asm volatile("cp.async.commit_group;" ::: "memory")
#define CPA_WAIT(n)  asm volatile("cp.async.wait_group %0;" :: "n"(n) : "memory")

// ---------------- weight prep (streaming, 2x float4/thread) ----------------
__global__ void cvt_h_kernel(const float* __restrict__ in, __half* __restrict__ out, size_t n4) {
    size_t half4 = n4 >> 1;
    size_t i = (size_t)blockIdx.x * 256 + threadIdx.x;
    if (i >= half4) return;
    __half2* o = (__half2*)out;
#pragma unroll
    for (int r = 0; r < 2; r++) {
        size_t idx = i + r * half4;
        float4 v = __ldcs((const float4*)in + idx);
        __stcs(o + idx * 2, __floats2half2_rn(v.x, v.y));
        __stcs(o + idx * 2 + 1, __floats2half2_rn(v.z, v.w));
    }
}

// ---------------- cp.async 3-stage fp16 GEMM ----------------
// LOSS: no C write; per-row (max,sumexp) partials + target logit capture.
template<int TH, int BM, int BN, int WR, int WC, bool BNK, bool BIAS, bool RELU,
         bool ACCUM, bool OUTH, bool GATHER, bool LOSS>
__global__ void __launch_bounds__(TH)
hgemm_ca(const __half* __restrict__ A, const __half* __restrict__ B,
         const float* __restrict__ bias, void* __restrict__ Cv,
         const int* __restrict__ gsel,
         const int* __restrict__ lids, float2* __restrict__ part,
         float* __restrict__ tlog,
         int K, int lda, int ldb, int ldc, int zdiv,
         size_t sA, size_t sA2, size_t sB, size_t sB2,
         size_t sC, size_t sC2, size_t sBias, float scale)
{
    constexpr int BK = 64;
    constexpr int LDS = 72;
    constexpr int BNP = BN + 8;
    constexpr int WM = BM / WR, WN = BN / WC;
    constexpr int MT = WM / 16, NT4 = WN / 8, NP = NT4 / 2;
    constexpr int ANV = (BM * 8) / TH;
    constexpr int BNV = BNK ? (BN * 8) / TH : (BK * BN) / (8 * TH);
    constexpr int STG = BNK ? (BM + BN) * LDS : BM * LDS + BK * BNP;

    const int m0 = blockIdx.y * BM, n0 = blockIdx.x * BN;
    const int tid = threadIdx.x, lane = tid & 31, warp = tid >> 5;
    const int wr = warp / WC, wc = warp % WC;
    const int g = lane >> 2, t = lane & 3;

    {
        int z = blockIdx.z, z1 = z / zdiv, z0 = z - z1 * zdiv;
        A += (size_t)z1 * sA + (size_t)z0 * sA2;
        B += (size_t)z1 * sB + (size_t)z0 * sB2;
        Cv = (char*)Cv + ((size_t)z1 * sC + (size_t)z0 * sC2) * (OUTH ? 2 : 4);
        if (BIAS) bias += (size_t)z1 * sBias;
    }

    const int nk = K / BK;

    extern __shared__ __half shh[];
    const uint32_t sbase = smem_u32(shh);

    const int a_r = lane & 15, a_c8 = (lane >> 4) * 8;
    const int b_r = (lane & 7) + (lane >> 4) * 8, b_c8 = ((lane >> 3) & 1) * 8;
    const int q8 = lane & 7, quad = lane >> 3;
    const int bt_k = (quad & 1) * 8 + q8, bt_n8 = (quad >> 1) * 8;
    const int mwb = wr * WM, nwb = wc * WN;

    const int ar = tid >> 3, aq = tid & 7;
    int arows[ANV];
#pragma unroll
    for (int i = 0; i < ANV; i++) {
        int r = m0 + ar + i * (TH >> 3);
        arows[i] = GATHER ? gsel[(size_t)blockIdx.z * NCAP + r] : r;
    }

    auto issue = [&](int ks, int st) {
        uint32_t so = sbase + (uint32_t)(st * STG) * 2;
#pragma unroll
        for (int i = 0; i < ANV; i++) {
            int row = ar + i * (TH >> 3);
            cpa16(so + (uint32_t)(row * LDS + aq * 8) * 2,
                  A + (size_t)arows[i] * lda + ks * BK + aq * 8);
        }
        if (BNK) {
            const __half* Bc = B + (size_t)n0 * ldb + ks * BK;
#pragma unroll
            for (int i = 0; i < BNV; i++) {
                int row = ar + i * (TH >> 3);
                cpa16(so + (uint32_t)((BM + row) * LDS + aq * 8) * 2,
                      Bc + (size_t)row * ldb + aq * 8);
            }
        } else {
            const __half* Bc = B + (size_t)(ks * BK) * ldb + n0;
#pragma unroll
            for (int i = 0; i < BNV; i++) {
                int idx = tid + i * TH;
                int kk = idx / (BN / 8), nq = idx % (BN / 8);
                cpa16(so + (uint32_t)(BM * LDS + kk * BNP + nq * 8) * 2,
                      Bc + (size_t)kk * ldb + nq * 8);
            }
        }
        CPA_COMMIT();
    };

    float acc[MT][NT4][4] = {};

    issue(0, 0);
    if (nk > 1) issue(1, 1);
    if (nk > 1) { CPA_WAIT(1); } else { CPA_WAIT(0); }
    __syncthreads();

    for (int ks = 0; ks < nk; ks++) {
        int cur = ks % 3;
        bool more2 = (ks + 2 < nk);
        if (more2) issue(ks + 2, (ks + 2) % 3);
        uint32_t abase = sbase + (uint32_t)(cur * STG) * 2;
        uint32_t bbase = abase + (uint32_t)(BM * LDS) * 2;
#pragma unroll
        for (int kq = 0; kq < 4; kq++) {
            unsigned af[MT][4], bf[NT4][2];
#pragma unroll
            for (int mt = 0; mt < MT; mt++) {
                uint32_t ad = abase +
                    (uint32_t)(((mwb + mt * 16 + a_r) * LDS + kq * 16 + a_c8) * 2);
                ldsm4(af[mt][0], af[mt][1], af[mt][2], af[mt][3], ad);
            }
            if (BNK) {
#pragma unroll
                for (int np = 0; np < NP; np++) {
                    uint32_t bd = bbase +
                        (uint32_t)(((nwb + np * 16 + b_r) * LDS + kq * 16 + b_c8) * 2);
                    ldsm4(bf[2*np][0], bf[2*np][1], bf[2*np+1][0], bf[2*np+1][1], bd);
                }
            } else {
#pragma unroll
                for (int np = 0; np < NP; np++) {
                    uint32_t bd = bbase +
                        (uint32_t)(((kq * 16 + bt_k) * BNP + nwb + np * 16 + bt_n8) * 2);
                    ldsm4t(bf[2*np][0], bf[2*np][1], bf[2*np+1][0], bf[2*np+1][1], bd);
                }
            }
#pragma unroll
            for (int mt = 0; mt < MT; mt++)
#pragma unroll
                for (int nt = 0; nt < NT4; nt++)
                    mma_f16(acc[mt][nt], af[mt], bf[nt]);
        }
        if (ks + 1 < nk) {
            if (more2) { CPA_WAIT(1); } else { CPA_WAIT(0); }
            __syncthreads();
        }
    }

    if (LOSS) {
        __syncthreads();
        float2* psh = (float2*)shh;           // [BM][WC]
#pragma unroll
        for (int mt = 0; mt < MT; mt++) {
            int rl = mwb + mt * 16 + g, rh = rl + 8;
            float ml = -1e30f, mh = -1e30f;
#pragma unroll
            for (int nt = 0; nt < NT4; nt++) {
                ml = fmaxf(ml, fmaxf(acc[mt][nt][0], acc[mt][nt][1]));
                mh = fmaxf(mh, fmaxf(acc[mt][nt][2], acc[mt][nt][3]));
            }
            ml = fmaxf(ml, __shfl_xor_sync(~0u, ml, 1));
            ml = fmaxf(ml, __shfl_xor_sync(~0u, ml, 2));
            mh = fmaxf(mh, __shfl_xor_sync(~0u, mh, 1));
            mh = fmaxf(mh, __shfl_xor_sync(~0u, mh, 2));
            float sl = 0.f, shi = 0.f;
#pragma unroll
            for (int nt = 0; nt < NT4; nt++) {
                sl += __expf(acc[mt][nt][0] - ml) + __expf(acc[mt][nt][1] - ml);
                shi += __expf(acc[mt][nt][2] - mh) + __expf(acc[mt][nt][3] - mh);
            }
            sl += __shfl_xor_sync(~0u, sl, 1);
            sl += __shfl_xor_sync(~0u, sl, 2);
            shi += __shfl_xor_sync(~0u, shi, 1);
            shi += __shfl_xor_sync(~0u, shi, 2);
            if (t == 0) {
                psh[rl * WC + wc] = make_float2(ml, sl);
                psh[rh * WC + wc] = make_float2(mh, shi);
            }
            int grl = m0 + rl, grh = m0 + rh;
            int tgl = ((grl % NT) != NT - 1) ? lids[grl + 1] : -1;
            int tgh = ((grh % NT) != NT - 1) ? lids[grh + 1] : -1;
#pragma unroll
            for (int nt = 0; nt < NT4; nt++) {
                int c0 = n0 + nwb + nt * 8 + 2 * t;
                if (c0 == tgl)     tlog[grl] = acc[mt][nt][0];
                if (c0 + 1 == tgl) tlog[grl] = acc[mt][nt][1];
                if (c0 == tgh)     tlog[grh] = acc[mt][nt][2];
                if (c0 + 1 == tgh) tlog[grh] = acc[mt][nt][3];
            }
        }
        __syncthreads();
        if (tid < BM) {
            float m = -1e30f, s = 0.f;
#pragma unroll
            for (int w = 0; w < WC; w++) {
                float2 p = psh[tid * WC + w];
                if (p.x > m) { s = s * __expf(m - p.x) + p.y; m = p.x; }
                else s += p.y * __expf(p.x - m);
            }
            part[(size_t)(m0 + tid) * NPART + blockIdx.x] = make_float2(m, s);
        }
        return;
    }

    __half* Ch = (__half*)Cv;
    float*  Cf = (float*)Cv;
#pragma unroll
    for (int mt = 0; mt < MT; mt++) {
#pragma unroll
        for (int nt = 0; nt < NT4; nt++) {
            int r0 = m0 + mwb + mt * 16 + g;
            int c0 = n0 + nwb + nt * 8 + 2 * t;
            float v0 = acc[mt][nt][0] * scale, v1 = acc[mt][nt][1] * scale;
            float v2 = acc[mt][nt][2] * scale, v3 = acc[mt][nt][3] * scale;
            if (BIAS) {
                float b0 = bias[c0], b1 = bias[c0 + 1];
                v0 += b0; v1 += b1; v2 += b0; v3 += b1;
            }
            if (RELU) {
                v0 = fmaxf(v0, 0.f); v1 = fmaxf(v1, 0.f);
                v2 = fmaxf(v2, 0.f); v3 = fmaxf(v3, 0.f);
            }
            if (OUTH) {
                *(__half2*)(Ch + (size_t)r0 * ldc + c0) = __floats2half2_rn(v0, v1);
                *(__half2*)(Ch + (size_t)(r0 + 8) * ldc + c0) = __floats2half2_rn(v2, v3);
            } else {
                float* p0 = Cf + (size_t)r0 * ldc + c0;
                float* p1 = Cf + (size_t)(r0 + 8) * ldc + c0;
                if (ACCUM) {
                    float2 o0 = *(float2*)p0, o1 = *(float2*)p1;
                    v0 += o0.x; v1 += o0.y; v2 += o1.x; v3 += o1.y;
                }
                *(float2*)p0 = make_float2(v0, v1);
                *(float2*)p1 = make_float2(v2, v3);
            }
        }
    }
}

// ---------------- FlashAttention-2 (causal, 128-row q-tiles, 256 thr) ----------------
#define FL_PITCH 72
#define FL_QSZ   (128 * FL_PITCH)
#define FL_KVSZ  (2 * 128 * FL_PITCH)
#define FL_SMEM  ((FL_QSZ + 2 * FL_KVSZ) * 2)

__global__ void __launch_bounds__(256)
flash_kernel(const __half* __restrict__ qkv, __half* __restrict__ attn) {
    int z = blockIdx.y, b = z >> 4, h = z & 15;
    int qt = (int)gridDim.x - 1 - (int)blockIdx.x;
    int m0 = qt * 128;
    const __half* Qg = qkv + (size_t)b * NT * 3072 + h * 64;
    const __half* Kg = Qg + 1024;
    const __half* Vg = Qg + 2048;

    extern __shared__ __half sh[];
    const uint32_t sb = smem_u32(sh);

    int tid = threadIdx.x, lane = tid & 31, warp = tid >> 5;
    int g = lane >> 2, t = lane & 3;
    int lr = tid >> 3, lq = tid & 7;

#pragma unroll
    for (int i = 0; i < 4; i++) {
        int row = lr + i * 32;
        cpa16(sb + (uint32_t)(row * FL_PITCH + lq * 8) * 2,
              Qg + (size_t)(m0 + row) * 3072 + lq * 8);
    }
    CPA_COMMIT();

    auto issue_kv = [&](int j, int st) {
        uint32_t so = sb + (uint32_t)(FL_QSZ + st * FL_KVSZ) * 2;
#pragma unroll
        for (int i = 0; i < 4; i++) {
            int row = lr + i * 32;
            cpa16(so + (uint32_t)(row * FL_PITCH + lq * 8) * 2,
                  Kg + (size_t)(j * 128 + row) * 3072 + lq * 8);
        }
#pragma unroll
        for (int i = 0; i < 4; i++) {
            int row = lr + i * 32;
            cpa16(so + (uint32_t)((128 + row) * FL_PITCH + lq * 8) * 2,
                  Vg + (size_t)(j * 128 + row) * 3072 + lq * 8);
        }
        CPA_COMMIT();
    };
    issue_kv(0, 0);
    CPA_WAIT(0);
    __syncthreads();

    const int mwb = warp * 16;
    const int a_r = lane & 15, a_c8 = (lane >> 4) * 8;
    unsigned qf[4][4];
#pragma unroll
    for (int kq = 0; kq < 4; kq++) {
        uint32_t ad = sb + (uint32_t)(((mwb + a_r) * FL_PITCH + kq * 16 + a_c8) * 2);
        ldsm4(qf[kq][0], qf[kq][1], qf[kq][2], qf[kq][3], ad);
    }

    const int b_r = (lane & 7) + (lane >> 4) * 8, b_c8 = ((lane >> 3) & 1) * 8;
    const int q8 = lane & 7, quad = lane >> 3;
    const int bt_k = (quad & 1) * 8 + q8, bt_n8 = (quad >> 1) * 8;

    float m_lo = -1e30f, m_hi = -1e30f, l_lo = 0.f, l_hi = 0.f;
    float ao[8][4] = {};
    const int rl_lo = mwb + g, rl_hi = mwb + g + 8;

    for (int j = 0; j <= qt; j++) {
        int st = j & 1;
        __syncthreads();
        if (j < qt) issue_kv(j + 1, st ^ 1);
        if (j < qt) { CPA_WAIT(1); } else { CPA_WAIT(0); }
        __syncthreads();

        uint32_t kbase = sb + (uint32_t)(FL_QSZ + st * FL_KVSZ) * 2;
        uint32_t vbase = kbase + (uint32_t)(128 * FL_PITCH) * 2;

        float as[16][4] = {};
#pragma unroll
        for (int kq = 0; kq < 4; kq++) {
            unsigned bf[16][2];
#pragma unroll
            for (int np = 0; np < 8; np++) {
                uint32_t bd = kbase +
                    (uint32_t)(((np * 16 + b_r) * FL_PITCH + kq * 16 + b_c8) * 2);
                ldsm4(bf[2*np][0], bf[2*np][1], bf[2*np+1][0], bf[2*np+1][1], bd);
            }
#pragma unroll
            for (int nt = 0; nt < 16; nt++)
                mma_f16(as[nt], qf[kq], bf[nt]);
        }

        float rm_lo = -1e30f, rm_hi = -1e30f;
#pragma unroll
        for (int nt = 0; nt < 16; nt++) {
            int c0 = nt * 8 + 2 * t;
            as[nt][0] *= 0.125f; as[nt][1] *= 0.125f;
            as[nt][2] *= 0.125f; as[nt][3] *= 0.125f;
            if (j == qt) {
                if (c0     > rl_lo) as[nt][0] = -1e30f;
                if (c0 + 1 > rl_lo) as[nt][1] = -1e30f;
                if (c0     > rl_hi) as[nt][2] = -1e30f;
                if (c0 + 1 > rl_hi) as[nt][3] = -1e30f;
            }
            rm_lo = fmaxf(rm_lo, fmaxf(as[nt][0], as[nt][1]));
            rm_hi = fmaxf(rm_hi, fmaxf(as[nt][2], as[nt][3]));
        }
        rm_lo = fmaxf(rm_lo, __shfl_xor_sync(~0u, rm_lo, 1));
        rm_lo = fmaxf(rm_lo, __shfl_xor_sync(~0u, rm_lo, 2));
        rm_hi = fmaxf(rm_hi, __shfl_xor_sync(~0u, rm_hi, 1));
        rm_hi = fmaxf(rm_hi, __shfl_xor_sync(~0u, rm_hi, 2));
        float mn_lo = fmaxf(m_lo, rm_lo), mn_hi = fmaxf(m_hi, rm_hi);
        float sf_lo = __expf(m_lo - mn_lo), sf_hi = __expf(m_hi - mn_hi);
        m_lo = mn_lo; m_hi = mn_hi;

        float rs_lo = 0.f, rs_hi = 0.f;
        unsigned pf[16][2];
#pragma unroll
        for (int nt = 0; nt < 16; nt++) {
            float p0 = __expf(as[nt][0] - mn_lo), p1 = __expf(as[nt][1] - mn_lo);
            float p2 = __expf(as[nt][2] - mn_hi), p3 = __expf(as[nt][3] - mn_hi);
            rs_lo += p0 + p1; rs_hi += p2 + p3;
            __half2 h01 = __floats2half2_rn(p0, p1);
            __half2 h23 = __floats2half2_rn(p2, p3);
            pf[nt][0] = *(unsigned*)&h01;
            pf[nt][1] = *(unsigned*)&h23;
        }
        rs_lo += __shfl_xor_sync(~0u, rs_lo, 1);
        rs_lo += __shfl_xor_sync(~0u, rs_lo, 2);
        rs_hi += __shfl_xor_sync(~0u, rs_hi, 1);
        rs_hi += __shfl_xor_sync(~0u, rs_hi, 2);
        l_lo = l_lo * sf_lo + rs_lo;
        l_hi = l_hi * sf_hi + rs_hi;
#pragma unroll
        for (int nt = 0; nt < 8; nt++) {
            ao[nt][0] *= sf_lo; ao[nt][1] *= sf_lo;
            ao[nt][2] *= sf_hi; ao[nt][3] *= sf_hi;
        }
#pragma unroll
        for (int kc = 0; kc < 8; kc++) {
            unsigned af[4] = { pf[2*kc][0], pf[2*kc][1], pf[2*kc+1][0], pf[2*kc+1][1] };
            unsigned vf[8][2];
#pragma unroll
            for (int np = 0; np < 4; np++) {
                uint32_t bd = vbase +
                    (uint32_t)(((kc * 16 + bt_k) * FL_PITCH + np * 16 + bt_n8) * 2);
                ldsm4t(vf[2*np][0], vf[2*np][1], vf[2*np+1][0], vf[2*np+1][1], bd);
            }
#pragma unroll
            for (int nt = 0; nt < 8; nt++)
                mma_f16(ao[nt], af, vf[nt]);
        }
    }

    float il_lo = 1.f / l_lo, il_hi = 1.f / l_hi;
    __half* Ob = attn + (size_t)(b * NT + m0) * ND + h * 64;
#pragma unroll
    for (int nt = 0; nt < 8; nt++) {
        int c0 = nt * 8 + 2 * t;
        *(__half2*)(Ob + (size_t)(mwb + g) * ND + c0) =
            __floats2half2_rn(ao[nt][0] * il_lo, ao[nt][1] * il_lo);
        *(__half2*)(Ob + (size_t)(mwb + g + 8) * ND + c0) =
            __floats2half2_rn(ao[nt][2] * il_hi, ao[nt][3] * il_hi);
    }
}

// ---------------- small kernels ----------------
__global__ void embed_kernel(const int* __restrict__ ids, const float* __restrict__ tok,
                             const float* __restrict__ pos, float* __restrict__ x) {
    int n = blockIdx.x, t = n % NT, id = ids[n];
    const float* te = tok + (size_t)id * ND;
    const float* pe = pos + (size_t)t * ND;
    float* dst = x + (size_t)n * ND;
    for (int d = threadIdx.x; d < ND; d += 256) dst[d] = te[d] + pe[d];
}

__global__ void ln_kernel(const float* __restrict__ x, const float* __restrict__ w,
                          const float* __restrict__ b, __half* __restrict__ out) {
    int row = blockIdx.x * 8 + (threadIdx.x >> 5);
    int lane = threadIdx.x & 31;
    const float4* p = (const float4*)(x + (size_t)row * ND);
    float4 v[8];
    float s = 0.f;
#pragma unroll
    for (int i = 0; i < 8; i++) {
        v[i] = p[lane + i * 32];
        s += v[i].x + v[i].y + v[i].z + v[i].w;
    }
#pragma unroll
    for (int o = 16; o; o >>= 1) s += __shfl_xor_sync(~0u, s, o);
    float mu = s * (1.0f / ND);
    float q = 0.f;
#pragma unroll
    for (int i = 0; i < 8; i++) {
        float a = v[i].x - mu, c = v[i].y - mu, d = v[i].z - mu, e = v[i].w - mu;
        q += a * a + c * c + d * d + e * e;
    }
#pragma unroll
    for (int o = 16; o; o >>= 1) q += __shfl_xor_sync(~0u, q, o);
    float rs = rsqrtf(q * (1.0f / ND) + 1e-5f);
    const float4* wp = (const float4*)w;
    const float4* bp = (const float4*)b;
    __half2* op = (__half2*)(out + (size_t)row * ND);
#pragma unroll
    for (int i = 0; i < 8; i++) {
        int j = lane + i * 32;
        float4 wv = wp[j], bv = bp[j];
        op[j * 2] = __floats2half2_rn((v[i].x - mu) * rs * wv.x + bv.x,
                                      (v[i].y - mu) * rs * wv.y + bv.y);
        op[j * 2 + 1] = __floats2half2_rn((v[i].z - mu) * rs * wv.z + bv.z,
                                          (v[i].w - mu) * rs * wv.w + bv.w);
    }
}

__global__ void rope_kernel(__half* __restrict__ qkv) {
    int n = blockIdx.x, t = n % NT;
    __half* base = qkv + (size_t)n * 3072;
#pragma unroll
    for (int item = threadIdx.x; item < 512; item += 256) {
        int h = item >> 5, i = item & 31;
        float ang = (float)t * expf((float)(2 * i) * (-0.14391156831212806f));
        float s = sinf(ang), c = cosf(ang);
        __half* q = base + h * 64;
        __half* k = q + 1024;
        float q1 = __half2float(q[i]), q2 = __half2float(q[i + 32]);
        q[i] = __float2half_rn(q1 * c - q2 * s);
        q[i + 32] = __float2half_rn(q2 * c + q1 * s);
        float k1 = __half2float(k[i]), k2 = __half2float(k[i + 32]);
        k[i] = __float2half_rn(k1 * c - k2 * s);
        k[i + 32] = __float2half_rn(k2 * c + k1 * s);
    }
}

// ---------------- MoE ----------------
__global__ void route_kernel(const __half* __restrict__ ln, const float* __restrict__ wr,
                             const float* __restrict__ br, const float* __restrict__ wn,
                             const float* __restrict__ bn, float* __restrict__ route,
                             float* __restrict__ noise) {
    int n = blockIdx.x, tid = threadIdx.x;
    __shared__ float xs[ND];
    for (int d = tid; d < ND; d += 256) xs[d] = __half2float(ln[(size_t)n * ND + d]);
    __syncthreads();
    int w = tid >> 5, lane = tid & 31;
    float sr = 0.f, sn = 0.f;
    for (int d = lane; d < ND; d += 32) {
        float xv = xs[d];
        sr += xv * wr[(size_t)d * NE + w];
        sn += xv * wn[(size_t)d * NE + w];
    }
    for (int o = 16; o; o >>= 1) { sr += __shfl_down_sync(~0u, sr, o); sn += __shfl_down_sync(~0u, sn, o); }
    if (!lane) { route[n * NE + w] = sr + br[w]; noise[n * NE + w] = sn + bn[w]; }
}

// topk with inline threefry eps (replaces eps_kernel)
__global__ void topk_kernel(const float* __restrict__ route, const float* __restrict__ noise,
                            unsigned k0, unsigned k1, float* __restrict__ gate,
                            unsigned char* __restrict__ mask) {
    int n = blockIdx.x * 256 + threadIdx.x;
    if (n >= NN) return;
    float nv[NE];
#pragma unroll
    for (int e = 0; e < NE; e++) {
        unsigned o0, o1;
        threefry(k0, k1, 0u, (unsigned)(n * NE + e), o0, o1);
        float ep = bits_to_normal(o0 ^ o1);
        float x = noise[n * NE + e];
        float sp = fmaxf(x, 0.f) + log1pf(expf(-fabsf(x)));
        nv[e] = route[n * NE + e] + ep * sp;
    }
    int i1 = 0; float v1 = nv[0];
#pragma unroll
    for (int e = 1; e < NE; e++) if (nv[e] > v1) { v1 = nv[e]; i1 = e; }
    int i2 = -1; float v2 = -3.4e38f;
#pragma unroll
    for (int e = 0; e < NE; e++) if (e != i1 && nv[e] > v2) { v2 = nv[e]; i2 = e; }
    float e2 = expf(v2 - v1);
    float Z = 1.0f + e2;
#pragma unroll
    for (int e = 0; e < NE; e++)
        gate[n * NE + e] = (e == i1) ? (1.0f / Z) : ((e == i2) ? (e2 / Z) : 0.f);
    mask[n] = (unsigned char)((1u << i1) | (1u << i2));
}

__global__ void select_kernel(const unsigned char* __restrict__ mask, int* __restrict__ sel,
                              int* __restrict__ slot, int* __restrict__ cnt) {
    int e = blockIdx.x, lane = threadIdx.x;
    int base = 0;
    for (int n0 = 0; n0 < NN; n0 += 32) {
        int n = n0 + lane;
        bool f = (mask[n] >> e) & 1;
        unsigned bal = __ballot_sync(0xffffffffu, f);
        int pos = base + __popc(bal & ((1u << lane) - 1u));
        int sl = (f && pos < NCAP) ? pos : -1;
        slot[(size_t)e * NN + n] = sl;
        if (sl >= 0) sel[e * NCAP + sl] = n;
        base += __popc(bal);
    }
    if (!lane) cnt[e] = base < NCAP ? base : NCAP;
}

// fused scatter + next LayerNorm
__global__ void moe_scatter_ln_kernel(const __half* __restrict__ eo, const int* __restrict__ slot,
                                      const float* __restrict__ gate, float* __restrict__ x,
                                      const float* __restrict__ w, const float* __restrict__ b,
                                      __half* __restrict__ lnout) {
    int n = blockIdx.x, tid = threadIdx.x;
    __shared__ int ss[NE];
    __shared__ float gg[NE];
    __shared__ float red[8];
    if (tid < NE) { ss[tid] = slot[(size_t)tid * NN + n]; gg[tid] = gate[n * NE + tid]; }
    __syncthreads();
    float vals[4];
    float s = 0.f;
#pragma unroll
    for (int i = 0; i < 4; i++) {
        int d = tid + i * 256;
        float acc = x[(size_t)n * ND + d];
#pragma unroll
        for (int e = 0; e < NE; e++) {
            int sl = ss[e];
            if (sl >= 0) acc += gg[e] * __half2float(eo[((size_t)e * NCAP + sl) * ND + d]);
        }
        vals[i] = acc; s += acc;
        x[(size_t)n * ND + d] = acc;
    }
    int lane = tid & 31, warp = tid >> 5;
#pragma unroll
    for (int o = 16; o; o >>= 1) s += __shfl_xor_sync(~0u, s, o);
    if (!lane) red[warp] = s;
    __syncthreads();
    if (tid < 8) {
        float t = red[tid];
#pragma unroll
        for (int o = 4; o; o >>= 1) t += __shfl_xor_sync(0xffu, t, o);
        red[tid] = t;
    }
    __syncthreads();
    float mu = red[0] * (1.0f / ND);
    float q = 0.f;
#pragma unroll
    for (int i = 0; i < 4; i++) { float d = vals[i] - mu; q += d * d; }
#pragma unroll
    for (int o = 16; o; o >>= 1) q += __shfl_xor_sync(~0u, q, o);
    __syncthreads();
    if (!lane) red[warp] = q;
    __syncthreads();
    if (tid < 8) {
        float t = red[tid];
#pragma unroll
        for (int o = 4; o; o >>= 1) t += __shfl_xor_sync(0xffu, t, o);
        red[tid] = t;
    }
    __syncthreads();
    float rs = rsqrtf(red[0] * (1.0f / ND) + 1e-5f);
#pragma unroll
    for (int i = 0; i < 4; i++) {
        int d = tid + i * 256;
        lnout[(size_t)n * ND + d] =
            __float2half_rn((vals[i] - mu) * rs * w[d] + b[d]);
    }
}

// ---------------- loss final ----------------
__global__ void loss_final_kernel(const float2* __restrict__ part, const float* __restrict__ tlog,
                                  const int* __restrict__ ids, float* __restrict__ nll,
                                  float* __restrict__ vld) {
    int n = blockIdx.x, lane = threadIdx.x;
    int t = n % NT;
    if (t == NT - 1) { if (!lane) { nll[n] = 0.f; vld[n] = 0.f; } return; }
    float m = -1e30f, s = 0.f;
    for (int j = lane; j < NPART; j += 32) {
        float2 p = part[(size_t)n * NPART + j];
        if (p.x > m) { s = s * __expf(m - p.x) + p.y; m = p.x; }
        else s += p.y * __expf(p.x - m);
    }
#pragma unroll
    for (int o = 16; o; o >>= 1) {
        float m2 = __shfl_xor_sync(~0u, m, o);
        float s2 = __shfl_xor_sync(~0u, s, o);
        float M = fmaxf(m, m2);
        s = s * __expf(m - M) + s2 * __expf(m2 - M);
        m = M;
    }
    if (!lane) {
        float lse = m + logf(s);
        int tgt = ids[n + 1];
        float v = (tgt != 2) ? 1.f : 0.f;
        nll[n] = -(tlog[n] - lse) * v;
        vld[n] = v;
    }
}

__global__ void reduce_kernel(const float* __restrict__ nll, const float* __restrict__ vld,
                              float* __restrict__ out) {
    __shared__ float s1[256], s2[256];
    int tid = threadIdx.x;
    float a = 0.f, b = 0.f;
    for (int i = tid; i < NN; i += 256) { a += nll[i]; b += vld[i]; }
    s1[tid] = a; s2[tid] = b; __syncthreads();
    for (int st = 128; st; st >>= 1) { if (tid < st) { s1[tid] += s1[tid + st]; s2[tid] += s2[tid + st]; } __syncthreads(); }
    if (!tid) out[0] = s1[0] / fmaxf(s2[0], 1.0f);
}

// ---------------- host launch ----------------
#define STG_T(BM, BN) (((BM) + (BN)) * 72)
#define STG_F(BM, BN) ((BM) * 72 + 64 * ((BN) + 8))

extern "C" void kernel_launch(void* const* d_in, const int* in_sizes, int n_in,
                              void* d_out, int out_size) {
    const int*   ids     = (const int*)d_in[0];
    const float* tok_emb = (const float*)d_in[1];
    const float* pos_emb = (const float*)d_in[2];
    const float* ln1_w   = (const float*)d_in[3];
    const float* ln1_b   = (const float*)d_in[4];
    const float* ln2_w   = (const float*)d_in[5];
    const float* ln2_b   = (const float*)d_in[6];
    const float* w_qkv   = (const float*)d_in[7];
    const float* w_out   = (const float*)d_in[8];
    const float* w_route = (const float*)d_in[9];
    const float* b_route = (const float*)d_in[10];
    const float* w_noise = (const float*)d_in[11];
    const float* b_noise = (const float*)d_in[12];
    const float* w_e1    = (const float*)d_in[13];
    const float* b_e1    = (const float*)d_in[14];
    const float* w_e2    = (const float*)d_in[15];
    const float* b_e2    = (const float*)d_in[16];
    const float* lnf_w   = (const float*)d_in[17];
    const float* lnf_b   = (const float*)d_in[18];
    float* out = (float*)d_out;

    float *x, *route, *noise, *gate, *nll, *vld, *tlog;
    float2* part;
    __half *ln16, *qkv16, *attn16, *h116, *eo16;
    __half *wqkv16, *wout16, *we116, *we216, *tok16;
    unsigned char* mask; int *sel, *slot, *cnt;
    cudaGetSymbolAddress((void**)&x, g_x);
    cudaGetSymbolAddress((void**)&ln16, g_ln16);
    cudaGetSymbolAddress((void**)&qkv16, g_qkv16);
    cudaGetSymbolAddress((void**)&attn16, g_attn16);
    cudaGetSymbolAddress((void**)&route, g_route);
    cudaGetSymbolAddress((void**)&noise, g_noise);
    cudaGetSymbolAddress((void**)&gate, g_gate);
    cudaGetSymbolAddress((void**)&mask, g_mask);
    cudaGetSymbolAddress((void**)&sel, g_sel);
    cudaGetSymbolAddress((void**)&slot, g_slot);
    cudaGetSymbolAddress((void**)&cnt, g_cnt);
    cudaGetSymbolAddress((void**)&h116, g_h116);
    cudaGetSymbolAddress((void**)&eo16, g_eo16);
    cudaGetSymbolAddress((void**)&part, g_part);
    cudaGetSymbolAddress((void**)&tlog, g_tlog);
    cudaGetSymbolAddress((void**)&nll, g_nll);
    cudaGetSymbolAddress((void**)&vld, g_vld);
    cudaGetSymbolAddress((void**)&wqkv16, g_wqkv16);
    cudaGetSymbolAddress((void**)&wout16, g_wout16);
    cudaGetSymbolAddress((void**)&we116, g_we116);
    cudaGetSymbolAddress((void**)&we216, g_we216);
    cudaGetSymbolAddress((void**)&tok16, g_tok16);

    constexpr int SM_T = 3 * STG_T(256, 128) * 2;
    constexpr int SM_F = 3 * STG_F(256, 128) * 2;
    auto* kqkv = hgemm_ca<512,256,128,4,4,false,false,false,false,true ,false,false>;
    auto* kproj= hgemm_ca<512,256,128,4,4,false,false,false,true ,false,false,false>;
    auto* kfc1 = hgemm_ca<512,256,128,4,4,false,true ,true ,false,true ,true ,false>;
    auto* kfc2 = hgemm_ca<512,256,128,4,4,false,true ,false,false,true ,false,false>;
    auto* kvoc = hgemm_ca<512,256,128,4,4,true ,false,false,false,false,false,true >;
    cudaFuncSetAttribute(kqkv, cudaFuncAttributeMaxDynamicSharedMemorySize, SM_F);
    cudaFuncSetAttribute(kproj,cudaFuncAttributeMaxDynamicSharedMemorySize, SM_F);
    cudaFuncSetAttribute(kfc1, cudaFuncAttributeMaxDynamicSharedMemorySize, SM_F);
    cudaFuncSetAttribute(kfc2, cudaFuncAttributeMaxDynamicSharedMemorySize, SM_F);
    cudaFuncSetAttribute(kvoc, cudaFuncAttributeMaxDynamicSharedMemorySize, SM_T);
    cudaFuncSetAttribute(flash_kernel, cudaFuncAttributeMaxDynamicSharedMemorySize, FL_SMEM);

    // side stream + events (created once; identical work per call)
    static cudaStream_t s1 = [] { cudaStream_t s; cudaStreamCreateWithFlags(&s, cudaStreamNonBlocking); return s; }();
    static cudaEvent_t evF = [] { cudaEvent_t e; cudaEventCreateWithFlags(&e, cudaEventDisableTiming); return e; }();
    static cudaEvent_t evJ = [] { cudaEvent_t e; cudaEventCreateWithFlags(&e, cudaEventDisableTiming); return e; }();

    // fork: big weight conversions (not needed until fc1/vocab) run on s1
    cudaEventRecord(evF, 0);
    cudaStreamWaitEvent(s1, evF, 0);
    {
        size_t n;
        n = (size_t)NLAY * NE * ND * NFF / 4;
        cvt_h_kernel<<<(unsigned)((n / 2 + 255) / 256), 256, 0, s1>>>(w_e1, we116, n);
        n = (size_t)NLAY * NE * NFF * ND / 4;
        cvt_h_kernel<<<(unsigned)((n / 2 + 255) / 256), 256, 0, s1>>>(w_e2, we216, n);
        n = (size_t)NV * ND / 4;
        cvt_h_kernel<<<(unsigned)((n / 2 + 255) / 256), 256, 0, s1>>>(tok_emb, tok16, n);
    }
    cudaEventRecord(evJ, s1);

    // main stream: early weights + embed/ln
    {
        size_t n;
        n = (size_t)NLAY * ND * 3 * ND / 4;
        cvt_h_kernel<<<(unsigned)((n / 2 + 255) / 256), 256>>>(w_qkv, wqkv16, n);
        n = (size_t)NLAY * ND * ND / 4;
        cvt_h_kernel<<<(unsigned)((n / 2 + 255) / 256), 256>>>(w_out, wout16, n);
    }
    embed_kernel<<<NN, 256>>>(ids, tok_emb, pos_emb, x);
    ln_kernel<<<NN / 8, 256>>>(x, ln1_w, ln1_b, ln16);

    for (int l = 0; l < NLAY; l++) {
        // ---- attention ----
        kqkv<<<dim3(24, 16, 1), 512, SM_F>>>(
            ln16, wqkv16 + (size_t)l * ND * 3 * ND, nullptr, qkv16, nullptr,
            nullptr, nullptr, nullptr,
            ND, ND, 3 * ND, 3 * ND, 1, 0, 0, 0, 0, 0, 0, 0, 1.0f);
        rope_kernel<<<NN, 256>>>(qkv16);
        flash_kernel<<<dim3(NT / 128, NB * NH), 256, FL_SMEM>>>(qkv16, attn16);
        kproj<<<dim3(8, 16, 1), 512, SM_F>>>(
            attn16, wout16 + (size_t)l * ND * ND, nullptr, x, nullptr,
            nullptr, nullptr, nullptr,
            ND, ND, ND, ND, 1, 0, 0, 0, 0, 0, 0, 0, 1.0f);

        // ---- MoE ----
        ln_kernel<<<NN / 8, 256>>>(x, ln2_w + l * ND, ln2_b + l * ND, ln16);
        route_kernel<<<NN, 256>>>(ln16, w_route + (size_t)l * ND * NE, b_route + l * NE,
                                  w_noise + (size_t)l * ND * NE, b_noise + l * NE, route, noise);
        unsigned k0, k1;
        threefry(0u, 1234u, 0u, (unsigned)l, k0, k1);
        topk_kernel<<<(NN + 255) / 256, 256>>>(route, noise, k0, k1, gate, mask);
        select_kernel<<<NE, 32>>>(mask, sel, slot, cnt);
        if (l == 0) cudaStreamWaitEvent(0, evJ, 0);   // join: expert/vocab weights ready
        kfc1<<<dim3(32, 4, NE), 512, SM_F>>>(
            ln16, we116 + (size_t)l * NE * ND * NFF, b_e1 + (size_t)l * NE * NFF, h116, sel,
            nullptr, nullptr, nullptr,
            ND, ND, NFF, NFF, 1,
            0, 0, (size_t)NFF * ND, 0,
            (size_t)NCAP * NFF, 0, NFF, 1.0f);
        kfc2<<<dim3(8, 4, NE), 512, SM_F>>>(
            h116, we216 + (size_t)l * NE * NFF * ND, b_e2 + (size_t)l * NE * ND, eo16, nullptr,
            nullptr, nullptr, nullptr,
            NFF, NFF, ND, ND, 1,
            (size_t)NCAP * NFF, 0, (size_t)ND * NFF, 0,
            (size_t)NCAP * ND, 0, ND, 1.0f);
        const float* nw = (l + 1 < NLAY) ? (ln1_w + (size_t)(l + 1) * ND) : lnf_w;
        const float* nb = (l + 1 < NLAY) ? (ln1_b + (size_t)(l + 1) * ND) : lnf_b;
        moe_scatter_ln_kernel<<<NN, 256>>>(eo16, slot, gate, x, nw, nb, ln16);
    }

    // vocab GEMM with fused loss partials
    kvoc<<<dim3(NPART, 16, 1), 512, SM_T>>>(
        ln16, tok16, nullptr, nullptr, nullptr,
        ids, part, tlog,
        ND, ND, ND, NV, 1, 0, 0, 0, 0, 0, 0, 0, 1.0f);
    loss_final_kernel<<<NN, 32>>>(part, tlog, ids, nll, vld);
    reduce_kernel<<<1, 256>>>(nll, vld, out);
}